// round 2
// baseline (speedup 1.0000x reference)
#include <cuda_runtime.h>
#include <math.h>

#define HEADS 8
#define HD 64
#define CCH 512
#define HW 56
#define NTOK 3136
#define AG 49
#define NB 16
#define MROWS (NB*NTOK)

// ---------------- scratch (static device globals; no allocations) ----------------
__device__ float g_Q[(size_t)MROWS * CCH];        // q projection   (B*n, C)
__device__ float g_KV[(size_t)MROWS * 2 * CCH];   // kv projection  (B*n, 2C): k | v
__device__ float g_AT[NB * AG * CCH];             // agent tokens   (B, 49, C)
__device__ float g_PB1[HEADS * AG * NTOK];        // resized an_bias
__device__ float g_NB1[HEADS * AG * NTOK];        // resized na_bias
__device__ float g_LOG[(size_t)NB * HEADS * AG * NTOK]; // agent logits -> attn
__device__ float g_AV[NB * HEADS * AG * HD];      // agent_v
__device__ float g_AOUT[(size_t)MROWS * CCH];     // attention out + dwc (B*n, C)

// ---------------- generic fp32 NT GEMM: C[m,j] = sum_k A[m,k]*B[j,k] (+bias[j]) ----
// A: (M,K) row-major, B: (N,K) row-major. M%128==0, N%128==0, K%16==0 guaranteed.
__global__ __launch_bounds__(256) void gemm_nt(
    const float* __restrict__ A, const float* __restrict__ Bm,
    float* __restrict__ Cm, const float* __restrict__ bias,
    int M, int N, int K)
{
    __shared__ float As[16][128];
    __shared__ float Bs[16][128];
    int bm = blockIdx.y * 128;
    int bn = blockIdx.x * 128;
    int tid = threadIdx.x;
    int tx = tid & 15, ty = tid >> 4;
    float acc[8][8] = {};

    for (int k0 = 0; k0 < K; k0 += 16) {
#pragma unroll
        for (int it = 0; it < 2; it++) {
            int l = tid + it * 256;            // 512 float4 loads cover 128x16
            int r = l >> 2, kq = (l & 3) << 2;
            float4 va = *(const float4*)(A + (size_t)(bm + r) * K + k0 + kq);
            As[kq + 0][r] = va.x; As[kq + 1][r] = va.y;
            As[kq + 2][r] = va.z; As[kq + 3][r] = va.w;
            float4 vb = *(const float4*)(Bm + (size_t)(bn + r) * K + k0 + kq);
            Bs[kq + 0][r] = vb.x; Bs[kq + 1][r] = vb.y;
            Bs[kq + 2][r] = vb.z; Bs[kq + 3][r] = vb.w;
        }
        __syncthreads();
#pragma unroll
        for (int kk = 0; kk < 16; kk++) {
            float af[8], bf[8];
#pragma unroll
            for (int i = 0; i < 8; i++) af[i] = As[kk][ty * 8 + i];
#pragma unroll
            for (int j = 0; j < 8; j++) bf[j] = Bs[kk][tx * 8 + j];
#pragma unroll
            for (int i = 0; i < 8; i++)
#pragma unroll
                for (int j = 0; j < 8; j++)
                    acc[i][j] += af[i] * bf[j];
        }
        __syncthreads();
    }
#pragma unroll
    for (int i = 0; i < 8; i++) {
        int m = bm + ty * 8 + i;
#pragma unroll
        for (int j = 0; j < 8; j += 4) {
            int nn = bn + tx * 8 + j;
            float4 v = make_float4(acc[i][j], acc[i][j + 1], acc[i][j + 2], acc[i][j + 3]);
            if (bias) { v.x += bias[nn]; v.y += bias[nn + 1]; v.z += bias[nn + 2]; v.w += bias[nn + 3]; }
            *(float4*)(Cm + (size_t)m * N + nn) = v;
        }
    }
}

// ---------------- agent token pooling: mean over 8x8 windows of q ----------------
__global__ __launch_bounds__(256) void pool_kernel()
{
    int blk = blockIdx.x;
    int b = blk / AG, a = blk % AG;
    int p1 = a / 7, p2 = a % 7;
    for (int c = threadIdx.x; c < CCH; c += 256) {
        float s = 0.f;
#pragma unroll
        for (int r = 0; r < 8; r++)
#pragma unroll
            for (int ss = 0; ss < 8; ss++)
                s += g_Q[((size_t)(b * NTOK + (p1 * 8 + r) * HW + p2 * 8 + ss)) * CCH + c];
        g_AT[(b * AG + a) * CCH + c] = s * (1.0f / 64.0f);
    }
}

// ---------------- jax bilinear resize weights (half-pixel, renormalized=clamped) --
__device__ __forceinline__ void lin_w(int o, int& i0, int& i1, float& w0, float& w1)
{
    float p = (o + 0.5f) * 0.125f - 0.5f;   // scale 7->56
    float fp = floorf(p);
    int i = (int)fp;
    float f = p - fp;
    if (i < 0)       { i0 = 0; i1 = 0; w0 = 1.f; w1 = 0.f; }
    else if (i >= 6) { i0 = 6; i1 = 6; w0 = 1.f; w1 = 0.f; }
    else             { i0 = i; i1 = i + 1; w0 = 1.f - f; w1 = f; }
}

__global__ __launch_bounds__(256) void bias_resize_kernel(
    const float* __restrict__ an, const float* __restrict__ na)
{
    int a = blockIdx.x, h = blockIdx.y, src = blockIdx.z;
    const float* S = (src == 0 ? an : na) + (h * AG + a) * 49;
    float* D = (src == 0 ? g_PB1 : g_NB1) + (size_t)(h * AG + a) * NTOK;
    __shared__ float s[49];
    if (threadIdx.x < 49) s[threadIdx.x] = S[threadIdx.x];
    __syncthreads();
    for (int o = threadIdx.x; o < NTOK; o += 256) {
        int oh = o / HW, ow = o % HW;
        int r0, r1, c0, c1; float wr0, wr1, wc0, wc1;
        lin_w(oh, r0, r1, wr0, wr1);
        lin_w(ow, c0, c1, wc0, wc1);
        D[o] = wr0 * (wc0 * s[r0 * 7 + c0] + wc1 * s[r0 * 7 + c1]) +
               wr1 * (wc0 * s[r1 * 7 + c0] + wc1 * s[r1 * 7 + c1]);
    }
}

// ---------------- agent logits: (49pad64 x 64tok) GEMM over d=64 + biases --------
__global__ __launch_bounds__(256) void agent_logits_kernel(
    const float* __restrict__ ahb, const float* __restrict__ awb)
{
    int bh = blockIdx.y;
    int b = bh >> 3, h = bh & 7;
    int i0 = blockIdx.x * 64;
    __shared__ float ahT[64 * 65];   // [d][a] scaled agent tokens
    __shared__ float ksT[64 * 65];   // [d][il] keys
    int tid = threadIdx.x;
    for (int t = tid; t < 64 * 64; t += 256) {
        int a = t >> 6, d = t & 63;
        ahT[d * 65 + a] = (a < AG) ? g_AT[(b * AG + a) * CCH + h * HD + d] * 0.125f : 0.f;
    }
    for (int t = tid; t < 64 * 64; t += 256) {
        int il = t >> 6, d = t & 63;
        ksT[d * 65 + il] = g_KV[((size_t)(b * NTOK + i0 + il)) * (2 * CCH) + h * HD + d];
    }
    __syncthreads();
    int tx = tid & 15, ty = tid >> 4;
    float acc[4][4] = {};
#pragma unroll
    for (int d = 0; d < 64; d++) {
        float af[4], bf[4];
#pragma unroll
        for (int r = 0; r < 4; r++) af[r] = ahT[d * 65 + ty * 4 + r];
#pragma unroll
        for (int c = 0; c < 4; c++) bf[c] = ksT[d * 65 + tx * 4 + c];
#pragma unroll
        for (int r = 0; r < 4; r++)
#pragma unroll
            for (int c = 0; c < 4; c++)
                acc[r][c] += af[r] * bf[c];
    }
#pragma unroll
    for (int r = 0; r < 4; r++) {
        int a = ty * 4 + r;
        if (a >= AG) continue;
#pragma unroll
        for (int c = 0; c < 4; c++) {
            int i = i0 + tx * 4 + c;
            int oh = i / HW, ow = i % HW;
            float lg = acc[r][c] + g_PB1[(h * AG + a) * NTOK + i]
                     + ahb[(h * AG + a) * HW + oh] + awb[(h * AG + a) * HW + ow];
            g_LOG[((size_t)(bh * AG + a)) * NTOK + i] = lg;
        }
    }
}

// ---------------- row softmax over n=3136 ---------------------------------------
__global__ __launch_bounds__(256) void softmax_n_kernel()
{
    size_t row = blockIdx.x;
    float* p = g_LOG + row * NTOK;
    __shared__ float buf[NTOK];
    __shared__ float red[8];
    int tid = threadIdx.x;
    float m = -1e30f;
    for (int i = tid; i < NTOK; i += 256) { float v = p[i]; buf[i] = v; m = fmaxf(m, v); }
#pragma unroll
    for (int o = 16; o; o >>= 1) m = fmaxf(m, __shfl_xor_sync(~0u, m, o));
    if ((tid & 31) == 0) red[tid >> 5] = m;
    __syncthreads();
    m = fmaxf(fmaxf(fmaxf(red[0], red[1]), fmaxf(red[2], red[3])),
              fmaxf(fmaxf(red[4], red[5]), fmaxf(red[6], red[7])));
    __syncthreads();
    float s = 0.f;
    for (int i = tid; i < NTOK; i += 256) { float e = __expf(buf[i] - m); buf[i] = e; s += e; }
#pragma unroll
    for (int o = 16; o; o >>= 1) s += __shfl_xor_sync(~0u, s, o);
    if ((tid & 31) == 0) red[tid >> 5] = s;
    __syncthreads();
    s = red[0] + red[1] + red[2] + red[3] + red[4] + red[5] + red[6] + red[7];
    float inv = 1.0f / s;
    for (int i = tid; i < NTOK; i += 256) p[i] = buf[i] * inv;
}

// ---------------- agent_v = attn(49 x n) @ v(n x 64), per (b,h) -----------------
__global__ __launch_bounds__(256) void agent_v_kernel()
{
    int bh = blockIdx.x;
    int b = bh >> 3, h = bh & 7;
    __shared__ float at_s[32 * 65];  // [kk][a]
    __shared__ float vt_s[32 * 65];  // [kk][d]
    int tid = threadIdx.x, tx = tid & 15, ty = tid >> 4;
    float acc[4][4] = {};
    for (int k0 = 0; k0 < NTOK; k0 += 32) {
        for (int t = tid; t < 64 * 32; t += 256) {
            int a = t >> 5, kk = t & 31;
            at_s[kk * 65 + a] = (a < AG) ? g_LOG[((size_t)(bh * AG + a)) * NTOK + k0 + kk] : 0.f;
        }
        for (int t = tid; t < 32 * 64; t += 256) {
            int kk = t >> 6, d = t & 63;
            vt_s[kk * 65 + d] = g_KV[((size_t)(b * NTOK + k0 + kk)) * (2 * CCH) + CCH + h * HD + d];
        }
        __syncthreads();
#pragma unroll
        for (int kk = 0; kk < 32; kk++) {
            float af[4], bf[4];
#pragma unroll
            for (int r = 0; r < 4; r++) af[r] = at_s[kk * 65 + ty * 4 + r];
#pragma unroll
            for (int c = 0; c < 4; c++) bf[c] = vt_s[kk * 65 + tx * 4 + c];
#pragma unroll
            for (int r = 0; r < 4; r++)
#pragma unroll
                for (int c = 0; c < 4; c++)
                    acc[r][c] += af[r] * bf[c];
        }
        __syncthreads();
    }
#pragma unroll
    for (int r = 0; r < 4; r++) {
        int a = ty * 4 + r;
        if (a >= AG) continue;
#pragma unroll
        for (int c = 0; c < 4; c++)
            g_AV[(bh * AG + a) * HD + tx * 4 + c] = acc[r][c];
    }
}

// ---------------- q-side: logits(49) + softmax + @agent_v, fused, warp per token -
__global__ __launch_bounds__(256) void qside_kernel(
    const float* __restrict__ hab, const float* __restrict__ wab)
{
    int bh = blockIdx.y;
    int b = bh >> 3, h = bh & 7;
    int i0 = blockIdx.x * 32;
    __shared__ float ah_s[64 * 65];  // scaled agent tokens [a][d], rows>=49 zero
    __shared__ float av_s[AG * 65];  // agent_v [a][d]
    __shared__ float q_s[32 * 65];   // q tile [il][d]
    __shared__ float p_s[8 * 64];    // per-warp probs
    int tid = threadIdx.x;
    for (int t = tid; t < 64 * 64; t += 256) {
        int a = t >> 6, d = t & 63;
        ah_s[a * 65 + d] = (a < AG) ? g_AT[(b * AG + a) * CCH + h * HD + d] * 0.125f : 0.f;
    }
    for (int t = tid; t < AG * 64; t += 256) {
        int a = t >> 6, d = t & 63;
        av_s[a * 65 + d] = g_AV[(bh * AG + a) * HD + d];
    }
    for (int t = tid; t < 32 * 64; t += 256) {
        int il = t >> 6, d = t & 63;
        q_s[il * 65 + d] = g_Q[((size_t)(b * NTOK + i0 + il)) * CCH + h * HD + d];
    }
    __syncthreads();
    int w = tid >> 5, l = tid & 31;
    for (int rep = 0; rep < 4; rep++) {
        int il = w * 4 + rep;
        int i = i0 + il;
        int oh = i / HW, ow = i % HW;
        int a1 = l, a2 = l + 32;
        float lg1 = 0.f, lg2 = 0.f;
#pragma unroll
        for (int d = 0; d < 64; d++) {
            float qv = q_s[il * 65 + d];
            lg1 += qv * ah_s[a1 * 65 + d];
            lg2 += qv * ah_s[a2 * 65 + d];
        }
        lg1 += g_NB1[(h * AG + a1) * NTOK + i]
             + hab[(h * HW + oh) * AG + a1] + wab[(h * HW + ow) * AG + a1];
        if (a2 < AG)
            lg2 += g_NB1[(h * AG + a2) * NTOK + i]
                 + hab[(h * HW + oh) * AG + a2] + wab[(h * HW + ow) * AG + a2];
        else
            lg2 = -INFINITY;
        float mx = fmaxf(lg1, lg2);
#pragma unroll
        for (int o = 16; o; o >>= 1) mx = fmaxf(mx, __shfl_xor_sync(~0u, mx, o));
        float p1 = __expf(lg1 - mx);
        float p2 = __expf(lg2 - mx);   // exp(-inf)=0 for invalid lanes
        float sm = p1 + p2;
#pragma unroll
        for (int o = 16; o; o >>= 1) sm += __shfl_xor_sync(~0u, sm, o);
        float inv = 1.0f / sm;
        __syncwarp();
        p_s[w * 64 + a1] = p1 * inv;
        p_s[w * 64 + a2] = p2 * inv;
        __syncwarp();
        float o1 = 0.f, o2 = 0.f;
#pragma unroll
        for (int a = 0; a < AG; a++) {
            float pv = p_s[w * 64 + a];
            o1 += pv * av_s[a * 65 + l];
            o2 += pv * av_s[a * 65 + l + 32];
        }
        size_t base = ((size_t)(b * NTOK + i)) * CCH + h * HD;
        g_AOUT[base + l] = o1;
        g_AOUT[base + l + 32] = o2;
        __syncwarp();
    }
}

// ---------------- 3x3 depthwise conv on v, accumulated into AOUT ----------------
__global__ __launch_bounds__(256) void dwc_kernel(
    const float* __restrict__ dwc_w, const float* __restrict__ dwc_b)
{
    int oh = blockIdx.x, b = blockIdx.y;
    __shared__ float w_s[CCH * 9];
    __shared__ float b_s[CCH];
    int tid = threadIdx.x;
    for (int t = tid; t < CCH * 9; t += 256) w_s[t] = dwc_w[t];
    for (int t = tid; t < CCH; t += 256) b_s[t] = dwc_b[t];
    __syncthreads();
    for (int idx = tid; idx < HW * CCH; idx += 256) {
        int ow = idx >> 9, c = idx & 511;
        float acc = b_s[c];
#pragma unroll
        for (int ky = 0; ky < 3; ky++) {
            int h2 = oh + ky - 1;
            if (h2 < 0 || h2 >= HW) continue;
#pragma unroll
            for (int kx = 0; kx < 3; kx++) {
                int w2 = ow + kx - 1;
                if (w2 < 0 || w2 >= HW) continue;
                acc += g_KV[((size_t)(b * NTOK + h2 * HW + w2)) * (2 * CCH) + CCH + c]
                     * w_s[c * 9 + ky * 3 + kx];
            }
        }
        g_AOUT[((size_t)(b * NTOK + oh * HW + ow)) * CCH + c] += acc;
    }
}

// ---------------- launch ---------------------------------------------------------
extern "C" void kernel_launch(void* const* d_in, const int* in_sizes, int n_in,
                              void* d_out, int out_size)
{
    const float* x = (const float*)d_in[0];
    int off = 1;
    if (n_in >= 15 && in_sizes[1] == 1) off = 3;  // skip scalar H, W if present
    const float* q_w    = (const float*)d_in[off + 0];
    const float* kv_w   = (const float*)d_in[off + 1];
    const float* proj_w = (const float*)d_in[off + 2];
    const float* proj_b = (const float*)d_in[off + 3];
    const float* dwc_w  = (const float*)d_in[off + 4];
    const float* dwc_b  = (const float*)d_in[off + 5];
    const float* an_b   = (const float*)d_in[off + 6];
    const float* na_b   = (const float*)d_in[off + 7];
    const float* ah_b   = (const float*)d_in[off + 8];
    const float* aw_b   = (const float*)d_in[off + 9];
    const float* ha_b   = (const float*)d_in[off + 10];
    const float* wa_b   = (const float*)d_in[off + 11];
    float* out = (float*)d_out;

    float *Qp, *KVp, *AOUTp;
    cudaGetSymbolAddress((void**)&Qp, g_Q);
    cudaGetSymbolAddress((void**)&KVp, g_KV);
    cudaGetSymbolAddress((void**)&AOUTp, g_AOUT);

    dim3 gq(CCH / 128, MROWS / 128);
    dim3 gkv(2 * CCH / 128, MROWS / 128);

    gemm_nt<<<gq, 256>>>(x, q_w, Qp, nullptr, MROWS, CCH, CCH);
    gemm_nt<<<gkv, 256>>>(x, kv_w, KVp, nullptr, MROWS, 2 * CCH, CCH);
    pool_kernel<<<NB * AG, 256>>>();
    bias_resize_kernel<<<dim3(AG, HEADS, 2), 256>>>(an_b, na_b);
    agent_logits_kernel<<<dim3(NTOK / 64, NB * HEADS), 256>>>(ah_b, aw_b);
    softmax_n_kernel<<<NB * HEADS * AG, 256>>>();
    agent_v_kernel<<<NB * HEADS, 256>>>();
    qside_kernel<<<dim3(NTOK / 32, NB * HEADS), 256>>>(ha_b, wa_b);
    dwc_kernel<<<dim3(HW, NB), 256>>>(dwc_w, dwc_b);
    gemm_nt<<<gq, 256>>>(AOUTp, proj_w, out, proj_b, MROWS, CCH, CCH);
}

// round 4
// speedup vs baseline: 1.2243x; 1.2243x over previous
#include <cuda_runtime.h>
#include <cuda_bf16.h>
#include <math.h>
#include <stdint.h>

#define HEADS 8
#define HD 64
#define CCH 512
#define HW 56
#define NTOK 3136
#define AG 49
#define NB 16
#define MROWS (NB*NTOK)
#define KDIM 512

// ---------------- scratch (static device globals; no allocations) ----------------
__device__ float g_Q[(size_t)MROWS * CCH];
__device__ float g_KV[(size_t)MROWS * 2 * CCH];
__device__ float g_AT[NB * AG * CCH];
__device__ float g_PB1[HEADS * AG * NTOK];
__device__ float g_NB1[HEADS * AG * NTOK];
__device__ float g_LOG[(size_t)NB * HEADS * AG * NTOK];
__device__ float g_AV[NB * HEADS * AG * HD];
__device__ float g_AVP[7 * NB * HEADS * AG * HD];
__device__ float g_AOUT[(size_t)MROWS * CCH];
__device__ __nv_bfloat16 g_xhi[(size_t)MROWS * CCH];
__device__ __nv_bfloat16 g_xlo[(size_t)MROWS * CCH];
__device__ __nv_bfloat16 g_ahi[(size_t)MROWS * CCH];
__device__ __nv_bfloat16 g_alo[(size_t)MROWS * CCH];
__device__ __nv_bfloat16 g_wqhi[CCH * CCH];
__device__ __nv_bfloat16 g_wqlo[CCH * CCH];
__device__ __nv_bfloat16 g_wkvhi[2 * CCH * CCH];
__device__ __nv_bfloat16 g_wkvlo[2 * CCH * CCH];
__device__ __nv_bfloat16 g_wphi[CCH * CCH];
__device__ __nv_bfloat16 g_wplo[CCH * CCH];

// ================= low-level helpers =================
__device__ __forceinline__ uint32_t smem_u32(const void* p) {
    uint32_t a;
    asm("{ .reg .u64 t; cvta.to.shared.u64 t, %1; cvt.u32.u64 %0, t; }" : "=r"(a) : "l"(p));
    return a;
}
__device__ __forceinline__ void cpa16(uint32_t s, const void* g) {
    asm volatile("cp.async.cg.shared.global [%0], [%1], 16;" :: "r"(s), "l"(g));
}
#define CP_COMMIT() asm volatile("cp.async.commit_group;" ::: "memory")

#define LDSM_X4(r0, r1, r2, r3, a) \
    asm volatile("ldmatrix.sync.aligned.m8n8.x4.shared.b16 {%0,%1,%2,%3}, [%4];" \
                 : "=r"(r0), "=r"(r1), "=r"(r2), "=r"(r3) : "r"(a))

#define MMA16816(d, a, b) \
    asm volatile("mma.sync.aligned.m16n8k16.row.col.f32.bf16.bf16.f32 " \
                 "{%0,%1,%2,%3}, {%4,%5,%6,%7}, {%8,%9}, {%0,%1,%2,%3};" \
                 : "+f"((d)[0]), "+f"((d)[1]), "+f"((d)[2]), "+f"((d)[3]) \
                 : "r"((a)[0]), "r"((a)[1]), "r"((a)[2]), "r"((a)[3]), \
                   "r"((b)[0]), "r"((b)[1]))

// smem chunk swizzle: row r (0-127), 16B-chunk c (0-3) within 64B row
#define SWZC(r, c) ((c) ^ (((r) >> 1) & 3))

// ================= split-bf16 tensor-core GEMM (mma.sync path) =================
// C[m, n] = sum_k A[m,k]*B[n,k] (+bias[n]); A = Ahi+Alo, B = Bhi+Blo (bf16 pairs)
// grid: (Nout/128, M/128); 256 threads; 64KB dynamic smem (double-buffered).
__global__ __launch_bounds__(256) void gemm_tc(
    const __nv_bfloat16* __restrict__ Ahi, const __nv_bfloat16* __restrict__ Alo,
    const __nv_bfloat16* __restrict__ Bhi, const __nv_bfloat16* __restrict__ Blo,
    float* __restrict__ C, const float* __restrict__ bias, int Nout)
{
    extern __shared__ __align__(1024) char smem[];
    int tid = threadIdx.x;
    int wid = tid >> 5, lane = tid & 31;
    int bn0 = blockIdx.x * 128, m0 = blockIdx.y * 128;
    int wr = wid >> 2, wc = wid & 3;        // warp tile: rows wr*64, cols wc*32
    uint32_t sbase = smem_u32(smem);

    float acc[4][4][4] = {};

    // per-thread load coordinates (2 iterations x 4 tiles)
    int q0 = tid, q1 = tid + 256;
    int r0l = q0 >> 2, c0l = q0 & 3;
    int r1l = q1 >> 2, c1l = q1 & 3;
    uint32_t so0 = r0l * 64 + (SWZC(r0l, c0l) << 4);
    uint32_t so1 = r1l * 64 + (SWZC(r1l, c1l) << 4);

    const __nv_bfloat16* srcs[4] = { Ahi, Alo, Bhi, Blo };
    int rb[4] = { m0, m0, bn0, bn0 };

    // prologue: chunk 0 -> buffer 0
    {
        int k0 = 0;
#pragma unroll
        for (int t = 0; t < 4; t++) {
            cpa16(sbase + t * 8192 + so0, srcs[t] + (size_t)(rb[t] + r0l) * KDIM + k0 + c0l * 8);
            cpa16(sbase + t * 8192 + so1, srcs[t] + (size_t)(rb[t] + r1l) * KDIM + k0 + c1l * 8);
        }
        CP_COMMIT();
    }

    int g = lane >> 3, lr = lane & 7;

    for (int ch = 0; ch < 16; ch++) {
        int b = ch & 1;
        // issue next chunk into other buffer
        if (ch < 15) {
            int k0 = (ch + 1) * 32;
            uint32_t nb = sbase + (b ^ 1) * 32768;
#pragma unroll
            for (int t = 0; t < 4; t++) {
                cpa16(nb + t * 8192 + so0, srcs[t] + (size_t)(rb[t] + r0l) * KDIM + k0 + c0l * 8);
                cpa16(nb + t * 8192 + so1, srcs[t] + (size_t)(rb[t] + r1l) * KDIM + k0 + c1l * 8);
            }
            CP_COMMIT();
            asm volatile("cp.async.wait_group 1;" ::: "memory");
        } else {
            asm volatile("cp.async.wait_group 0;" ::: "memory");
        }
        __syncthreads();

        uint32_t base = sbase + b * 32768;
        uint32_t aAhi = base, aAlo = base + 8192, aBhi = base + 16384, aBlo = base + 24576;

#pragma unroll
        for (int ks = 0; ks < 2; ks++) {
            uint32_t af[4][4], al[4][4], bf[4][2], bl[4][2];
            // A fragments: 4 m16 tiles
#pragma unroll
            for (int mt = 0; mt < 4; mt++) {
                int row = wr * 64 + mt * 16 + ((g & 1) << 3) + lr;
                int c = (ks * 32 + ((g >> 1) << 4)) >> 4;
                uint32_t off = row * 64 + (SWZC(row, c) << 4);
                LDSM_X4(af[mt][0], af[mt][1], af[mt][2], af[mt][3], aAhi + off);
                LDSM_X4(al[mt][0], al[mt][1], al[mt][2], al[mt][3], aAlo + off);
            }
            // B fragments: 2 n16 groups -> 4 n8 frags
#pragma unroll
            for (int np = 0; np < 2; np++) {
                int row = wc * 32 + np * 16 + ((g >> 1) << 3) + lr;
                int c = (ks * 32 + ((g & 1) << 4)) >> 4;
                uint32_t off = row * 64 + (SWZC(row, c) << 4);
                uint32_t r0, r1, r2, r3;
                LDSM_X4(r0, r1, r2, r3, aBhi + off);
                bf[np * 2][0] = r0; bf[np * 2][1] = r1;
                bf[np * 2 + 1][0] = r2; bf[np * 2 + 1][1] = r3;
                LDSM_X4(r0, r1, r2, r3, aBlo + off);
                bl[np * 2][0] = r0; bl[np * 2][1] = r1;
                bl[np * 2 + 1][0] = r2; bl[np * 2 + 1][1] = r3;
            }
#pragma unroll
            for (int mt = 0; mt < 4; mt++)
#pragma unroll
                for (int nt = 0; nt < 4; nt++) {
                    MMA16816(acc[mt][nt], af[mt], bf[nt]);
                    MMA16816(acc[mt][nt], al[mt], bf[nt]);
                    MMA16816(acc[mt][nt], af[mt], bl[nt]);
                }
        }
        __syncthreads();
    }

    // epilogue
#pragma unroll
    for (int mt = 0; mt < 4; mt++) {
#pragma unroll
        for (int nt = 0; nt < 4; nt++) {
            int gm = m0 + wr * 64 + mt * 16 + (lane >> 2);
            int gn = bn0 + wc * 32 + nt * 8 + ((lane & 3) << 1);
            float2 v0 = make_float2(acc[mt][nt][0], acc[mt][nt][1]);
            float2 v1 = make_float2(acc[mt][nt][2], acc[mt][nt][3]);
            if (bias) {
                float b0 = bias[gn], b1 = bias[gn + 1];
                v0.x += b0; v0.y += b1; v1.x += b0; v1.y += b1;
            }
            *(float2*)(C + (size_t)gm * Nout + gn) = v0;
            *(float2*)(C + (size_t)(gm + 8) * Nout + gn) = v1;
        }
    }
}

// ---------------- fp32 -> (bf16 hi, bf16 lo) split conversion --------------------
__global__ __launch_bounds__(256) void cvt_split(
    const float* __restrict__ src, __nv_bfloat16* __restrict__ hi,
    __nv_bfloat16* __restrict__ lo, int n4)
{
    for (int i = blockIdx.x * 256 + threadIdx.x; i < n4; i += gridDim.x * 256) {
        float4 v = ((const float4*)src)[i];
        __nv_bfloat16 h0 = __float2bfloat16(v.x);
        __nv_bfloat16 h1 = __float2bfloat16(v.y);
        __nv_bfloat16 h2 = __float2bfloat16(v.z);
        __nv_bfloat16 h3 = __float2bfloat16(v.w);
        __nv_bfloat16 l0 = __float2bfloat16(v.x - __bfloat162float(h0));
        __nv_bfloat16 l1 = __float2bfloat16(v.y - __bfloat162float(h1));
        __nv_bfloat16 l2 = __float2bfloat16(v.z - __bfloat162float(h2));
        __nv_bfloat16 l3 = __float2bfloat16(v.w - __bfloat162float(h3));
        ((__nv_bfloat162*)hi)[2 * i]     = __halves2bfloat162(h0, h1);
        ((__nv_bfloat162*)hi)[2 * i + 1] = __halves2bfloat162(h2, h3);
        ((__nv_bfloat162*)lo)[2 * i]     = __halves2bfloat162(l0, l1);
        ((__nv_bfloat162*)lo)[2 * i + 1] = __halves2bfloat162(l2, l3);
    }
}

// ---------------- agent token pooling -------------------------------------------
__global__ __launch_bounds__(256) void pool_kernel()
{
    int blk = blockIdx.x;
    int b = blk / AG, a = blk % AG;
    int p1 = a / 7, p2 = a % 7;
    for (int c = threadIdx.x; c < CCH; c += 256) {
        float s = 0.f;
#pragma unroll
        for (int r = 0; r < 8; r++)
#pragma unroll
            for (int ss = 0; ss < 8; ss++)
                s += g_Q[((size_t)(b * NTOK + (p1 * 8 + r) * HW + p2 * 8 + ss)) * CCH + c];
        g_AT[(b * AG + a) * CCH + c] = s * (1.0f / 64.0f);
    }
}

// ---------------- jax bilinear resize -------------------------------------------
__device__ __forceinline__ void lin_w(int o, int& i0, int& i1, float& w0, float& w1)
{
    float p = (o + 0.5f) * 0.125f - 0.5f;
    float fp = floorf(p);
    int i = (int)fp;
    float f = p - fp;
    if (i < 0)       { i0 = 0; i1 = 0; w0 = 1.f; w1 = 0.f; }
    else if (i >= 6) { i0 = 6; i1 = 6; w0 = 1.f; w1 = 0.f; }
    else             { i0 = i; i1 = i + 1; w0 = 1.f - f; w1 = f; }
}

__global__ __launch_bounds__(256) void bias_resize_kernel(
    const float* __restrict__ an, const float* __restrict__ na)
{
    int a = blockIdx.x, h = blockIdx.y, src = blockIdx.z;
    const float* S = (src == 0 ? an : na) + (h * AG + a) * 49;
    float* D = (src == 0 ? g_PB1 : g_NB1) + (size_t)(h * AG + a) * NTOK;
    __shared__ float s[49];
    if (threadIdx.x < 49) s[threadIdx.x] = S[threadIdx.x];
    __syncthreads();
    for (int o = threadIdx.x; o < NTOK; o += 256) {
        int oh = o / HW, ow = o % HW;
        int r0, r1, c0, c1; float wr0, wr1, wc0, wc1;
        lin_w(oh, r0, r1, wr0, wr1);
        lin_w(ow, c0, c1, wc0, wc1);
        D[o] = wr0 * (wc0 * s[r0 * 7 + c0] + wc1 * s[r0 * 7 + c1]) +
               wr1 * (wc0 * s[r1 * 7 + c0] + wc1 * s[r1 * 7 + c1]);
    }
}

// ---------------- agent logits ---------------------------------------------------
__global__ __launch_bounds__(256) void agent_logits_kernel(
    const float* __restrict__ ahb, const float* __restrict__ awb)
{
    int bh = blockIdx.y;
    int b = bh >> 3, h = bh & 7;
    int i0 = blockIdx.x * 64;
    __shared__ float ahT[64 * 65];
    __shared__ float ksT[64 * 65];
    int tid = threadIdx.x;
    for (int t = tid; t < 64 * 64; t += 256) {
        int a = t >> 6, d = t & 63;
        ahT[d * 65 + a] = (a < AG) ? g_AT[(b * AG + a) * CCH + h * HD + d] * 0.125f : 0.f;
    }
    for (int t = tid; t < 64 * 64; t += 256) {
        int il = t >> 6, d = t & 63;
        ksT[d * 65 + il] = g_KV[((size_t)(b * NTOK + i0 + il)) * (2 * CCH) + h * HD + d];
    }
    __syncthreads();
    int tx = tid & 15, ty = tid >> 4;
    float acc[4][4] = {};
#pragma unroll
    for (int d = 0; d < 64; d++) {
        float af[4], bf[4];
#pragma unroll
        for (int r = 0; r < 4; r++) af[r] = ahT[d * 65 + ty * 4 + r];
#pragma unroll
        for (int c = 0; c < 4; c++) bf[c] = ksT[d * 65 + tx * 4 + c];
#pragma unroll
        for (int r = 0; r < 4; r++)
#pragma unroll
            for (int c = 0; c < 4; c++)
                acc[r][c] += af[r] * bf[c];
    }
#pragma unroll
    for (int r = 0; r < 4; r++) {
        int a = ty * 4 + r;
        if (a >= AG) continue;
#pragma unroll
        for (int c = 0; c < 4; c++) {
            int i = i0 + tx * 4 + c;
            int oh = i / HW, ow = i % HW;
            float lg = acc[r][c] + g_PB1[(h * AG + a) * NTOK + i]
                     + ahb[(h * AG + a) * HW + oh] + awb[(h * AG + a) * HW + ow];
            g_LOG[((size_t)(bh * AG + a)) * NTOK + i] = lg;
        }
    }
}

// ---------------- row softmax over n=3136 ----------------------------------------
__global__ __launch_bounds__(256) void softmax_n_kernel()
{
    size_t row = blockIdx.x;
    float* p = g_LOG + row * NTOK;
    __shared__ float buf[NTOK];
    __shared__ float red[8];
    int tid = threadIdx.x;
    float m = -1e30f;
    for (int i = tid; i < NTOK; i += 256) { float v = p[i]; buf[i] = v; m = fmaxf(m, v); }
#pragma unroll
    for (int o = 16; o; o >>= 1) m = fmaxf(m, __shfl_xor_sync(~0u, m, o));
    if ((tid & 31) == 0) red[tid >> 5] = m;
    __syncthreads();
    m = fmaxf(fmaxf(fmaxf(red[0], red[1]), fmaxf(red[2], red[3])),
              fmaxf(fmaxf(red[4], red[5]), fmaxf(red[6], red[7])));
    __syncthreads();
    float s = 0.f;
    for (int i = tid; i < NTOK; i += 256) { float e = __expf(buf[i] - m); buf[i] = e; s += e; }
#pragma unroll
    for (int o = 16; o; o >>= 1) s += __shfl_xor_sync(~0u, s, o);
    if ((tid & 31) == 0) red[tid >> 5] = s;
    __syncthreads();
    s = red[0] + red[1] + red[2] + red[3] + red[4] + red[5] + red[6] + red[7];
    float inv = 1.0f / s;
    for (int i = tid; i < NTOK; i += 256) p[i] = buf[i] * inv;
}

// ---------------- agent_v split over K + deterministic reduce --------------------
__global__ __launch_bounds__(256) void agent_v_split_kernel()
{
    int bh = blockIdx.x;
    int sp = blockIdx.y;
    int b = bh >> 3, h = bh & 7;
    __shared__ float at_s[32 * 65];
    __shared__ float vt_s[32 * 65];
    int tid = threadIdx.x, tx = tid & 15, ty = tid >> 4;
    float acc[4][4] = {};
    int kbeg = sp * 448, kend = kbeg + 448;
    for (int k0 = kbeg; k0 < kend; k0 += 32) {
        for (int t = tid; t < 64 * 32; t += 256) {
            int a = t >> 5, kk = t & 31;
            at_s[kk * 65 + a] = (a < AG) ? g_LOG[((size_t)(bh * AG + a)) * NTOK + k0 + kk] : 0.f;
        }
        for (int t = tid; t < 32 * 64; t += 256) {
            int kk = t >> 6, d = t & 63;
            vt_s[kk * 65 + d] = g_KV[((size_t)(b * NTOK + k0 + kk)) * (2 * CCH) + CCH + h * HD + d];
        }
        __syncthreads();
#pragma unroll
        for (int kk = 0; kk < 32; kk++) {
            float af[4], bf[4];
#pragma unroll
            for (int r = 0; r < 4; r++) af[r] = at_s[kk * 65 + ty * 4 + r];
#pragma unroll
            for (int c = 0; c < 4; c++) bf[c] = vt_s[kk * 65 + tx * 4 + c];
#pragma unroll
            for (int r = 0; r < 4; r++)
#pragma unroll
                for (int c = 0; c < 4; c++)
                    acc[r][c] += af[r] * bf[c];
        }
        __syncthreads();
    }
#pragma unroll
    for (int r = 0; r < 4; r++) {
        int a = ty * 4 + r;
        if (a >= AG) continue;
#pragma unroll
        for (int c = 0; c < 4; c++)
            g_AVP[((size_t)sp * NB * HEADS + bh) * AG * HD + (a * HD + tx * 4 + c)] = acc[r][c];
    }
}

__global__ __launch_bounds__(256) void avp_reduce_kernel()
{
    int i = blockIdx.x * 256 + threadIdx.x;
    const int tot = NB * HEADS * AG * HD;
    if (i < tot) {
        int bh = i / (AG * HD), rest = i % (AG * HD);
        float s = 0.f;
#pragma unroll
        for (int sp = 0; sp < 7; sp++)
            s += g_AVP[((size_t)sp * NB * HEADS + bh) * AG * HD + rest];
        g_AV[i] = s;
    }
}

// ---------------- q-side fused softmax + @agent_v --------------------------------
__global__ __launch_bounds__(256) void qside_kernel(
    const float* __restrict__ hab, const float* __restrict__ wab)
{
    int bh = blockIdx.y;
    int b = bh >> 3, h = bh & 7;
    int i0 = blockIdx.x * 32;
    __shared__ float ah_s[64 * 65];
    __shared__ float av_s[AG * 65];
    __shared__ float q_s[32 * 65];
    __shared__ float p_s[8 * 64];
    int tid = threadIdx.x;
    for (int t = tid; t < 64 * 64; t += 256) {
        int a = t >> 6, d = t & 63;
        ah_s[a * 65 + d] = (a < AG) ? g_AT[(b * AG + a) * CCH + h * HD + d] * 0.125f : 0.f;
    }
    for (int t = tid; t < AG * 64; t += 256) {
        int a = t >> 6, d = t & 63;
        av_s[a * 65 + d] = g_AV[(bh * AG + a) * HD + d];
    }
    for (int t = tid; t < 32 * 64; t += 256) {
        int il = t >> 6, d = t & 63;
        q_s[il * 65 + d] = g_Q[((size_t)(b * NTOK + i0 + il)) * CCH + h * HD + d];
    }
    __syncthreads();
    int w = tid >> 5, l = tid & 31;
    for (int rep = 0; rep < 4; rep++) {
        int il = w * 4 + rep;
        int i = i0 + il;
        int oh = i / HW, ow = i % HW;
        int a1 = l, a2 = l + 32;
        float lg1 = 0.f, lg2 = 0.f;
#pragma unroll
        for (int d = 0; d < 64; d++) {
            float qv = q_s[il * 65 + d];
            lg1 += qv * ah_s[a1 * 65 + d];
            lg2 += qv * ah_s[a2 * 65 + d];
        }
        lg1 += g_NB1[(h * AG + a1) * NTOK + i]
             + hab[(h * HW + oh) * AG + a1] + wab[(h * HW + ow) * AG + a1];
        if (a2 < AG)
            lg2 += g_NB1[(h * AG + a2) * NTOK + i]
                 + hab[(h * HW + oh) * AG + a2] + wab[(h * HW + ow) * AG + a2];
        else
            lg2 = -INFINITY;
        float mx = fmaxf(lg1, lg2);
#pragma unroll
        for (int o = 16; o; o >>= 1) mx = fmaxf(mx, __shfl_xor_sync(~0u, mx, o));
        float p1 = __expf(lg1 - mx);
        float p2 = __expf(lg2 - mx);
        float sm = p1 + p2;
#pragma unroll
        for (int o = 16; o; o >>= 1) sm += __shfl_xor_sync(~0u, sm, o);
        float inv = 1.0f / sm;
        __syncwarp();
        p_s[w * 64 + a1] = p1 * inv;
        p_s[w * 64 + a2] = p2 * inv;
        __syncwarp();
        float o1 = 0.f, o2 = 0.f;
#pragma unroll
        for (int a = 0; a < AG; a++) {
            float pv = p_s[w * 64 + a];
            o1 += pv * av_s[a * 65 + l];
            o2 += pv * av_s[a * 65 + l + 32];
        }
        size_t base = ((size_t)(b * NTOK + i)) * CCH + h * HD;
        g_AOUT[base + l] = o1;
        g_AOUT[base + l + 32] = o2;
        __syncwarp();
    }
}

// ---------------- 3x3 depthwise conv on v ---------------------------------------
__global__ __launch_bounds__(256) void dwc_kernel(
    const float* __restrict__ dwc_w, const float* __restrict__ dwc_b)
{
    int oh = blockIdx.x, b = blockIdx.y;
    __shared__ float w_s[CCH * 9];
    __shared__ float b_s[CCH];
    int tid = threadIdx.x;
    for (int t = tid; t < CCH * 9; t += 256) w_s[t] = dwc_w[t];
    for (int t = tid; t < CCH; t += 256) b_s[t] = dwc_b[t];
    __syncthreads();
    for (int idx = tid; idx < HW * CCH; idx += 256) {
        int ow = idx >> 9, c = idx & 511;
        float acc = b_s[c];
#pragma unroll
        for (int ky = 0; ky < 3; ky++) {
            int h2 = oh + ky - 1;
            if (h2 < 0 || h2 >= HW) continue;
#pragma unroll
            for (int kx = 0; kx < 3; kx++) {
                int w2 = ow + kx - 1;
                if (w2 < 0 || w2 >= HW) continue;
                acc += g_KV[((size_t)(b * NTOK + h2 * HW + w2)) * (2 * CCH) + CCH + c]
                     * w_s[c * 9 + ky * 3 + kx];
            }
        }
        g_AOUT[((size_t)(b * NTOK + oh * HW + ow)) * CCH + c] += acc;
    }
}

// ---------------- launch ---------------------------------------------------------
extern "C" void kernel_launch(void* const* d_in, const int* in_sizes, int n_in,
                              void* d_out, int out_size)
{
    const float* x = (const float*)d_in[0];
    int off = 1;
    if (n_in >= 15 && in_sizes[1] == 1) off = 3;
    const float* q_w    = (const float*)d_in[off + 0];
    const float* kv_w   = (const float*)d_in[off + 1];
    const float* proj_w = (const float*)d_in[off + 2];
    const float* proj_b = (const float*)d_in[off + 3];
    const float* dwc_w  = (const float*)d_in[off + 4];
    const float* dwc_b  = (const float*)d_in[off + 5];
    const float* an_b   = (const float*)d_in[off + 6];
    const float* na_b   = (const float*)d_in[off + 7];
    const float* ah_b   = (const float*)d_in[off + 8];
    const float* aw_b   = (const float*)d_in[off + 9];
    const float* ha_b   = (const float*)d_in[off + 10];
    const float* wa_b   = (const float*)d_in[off + 11];
    float* out = (float*)d_out;

    float *Qp, *KVp, *AOUTp;
    __nv_bfloat16 *xhi, *xlo, *ahi, *alo, *wqhi, *wqlo, *wkvhi, *wkvlo, *wphi, *wplo;
    cudaGetSymbolAddress((void**)&Qp, g_Q);
    cudaGetSymbolAddress((void**)&KVp, g_KV);
    cudaGetSymbolAddress((void**)&AOUTp, g_AOUT);
    cudaGetSymbolAddress((void**)&xhi, g_xhi);
    cudaGetSymbolAddress((void**)&xlo, g_xlo);
    cudaGetSymbolAddress((void**)&ahi, g_ahi);
    cudaGetSymbolAddress((void**)&alo, g_alo);
    cudaGetSymbolAddress((void**)&wqhi, g_wqhi);
    cudaGetSymbolAddress((void**)&wqlo, g_wqlo);
    cudaGetSymbolAddress((void**)&wkvhi, g_wkvhi);
    cudaGetSymbolAddress((void**)&wkvlo, g_wkvlo);
    cudaGetSymbolAddress((void**)&wphi, g_wphi);
    cudaGetSymbolAddress((void**)&wplo, g_wplo);

    static int smem_set = 0;
    if (!smem_set) {
        cudaFuncSetAttribute(gemm_tc, cudaFuncAttributeMaxDynamicSharedMemorySize, 65536);
        smem_set = 1;
    }

    cvt_split<<<4096, 256>>>(x, xhi, xlo, MROWS * CCH / 4);
    cvt_split<<<256, 256>>>(q_w, wqhi, wqlo, CCH * CCH / 4);
    cvt_split<<<512, 256>>>(kv_w, wkvhi, wkvlo, 2 * CCH * CCH / 4);
    cvt_split<<<256, 256>>>(proj_w, wphi, wplo, CCH * CCH / 4);

    gemm_tc<<<dim3(4, MROWS / 128), 256, 65536>>>(xhi, xlo, wqhi, wqlo, Qp, nullptr, 512);
    gemm_tc<<<dim3(8, MROWS / 128), 256, 65536>>>(xhi, xlo, wkvhi, wkvlo, KVp, nullptr, 1024);

    pool_kernel<<<NB * AG, 256>>>();
    bias_resize_kernel<<<dim3(AG, HEADS, 2), 256>>>(an_b, na_b);
    agent_logits_kernel<<<dim3(NTOK / 64, NB * HEADS), 256>>>(ah_b, aw_b);
    softmax_n_kernel<<<NB * HEADS * AG, 256>>>();
    agent_v_split_kernel<<<dim3(NB * HEADS, 7), 256>>>();
    avp_reduce_kernel<<<(NB * HEADS * AG * HD + 255) / 256, 256>>>();
    qside_kernel<<<dim3(NTOK / 32, NB * HEADS), 256>>>(ha_b, wa_b);
    dwc_kernel<<<dim3(HW, NB), 256>>>(dwc_w, dwc_b);

    cvt_split<<<4096, 256>>>(AOUTp, ahi, alo, MROWS * CCH / 4);
    gemm_tc<<<dim3(4, MROWS / 128), 256, 65536>>>(ahi, alo, wphi, wplo, out, proj_b, 512);
}

// round 5
// speedup vs baseline: 1.8212x; 1.4875x over previous
#include <cuda_runtime.h>
#include <cuda_bf16.h>
#include <math.h>
#include <stdint.h>

#define HEADS 8
#define HD 64
#define CCH 512
#define HW 56
#define NTOK 3136
#define AG 49
#define NB 16
#define MROWS (NB*NTOK)
#define KDIM 512

// ---------------- scratch (static device globals; no allocations) ----------------
__device__ float g_Q[(size_t)MROWS * CCH];
__device__ float g_KV[(size_t)MROWS * 2 * CCH];
__device__ float g_AT[NB * AG * CCH];
__device__ float g_PB1[HEADS * AG * NTOK];
__device__ float g_NB1[HEADS * AG * NTOK];
__device__ float g_LOG[(size_t)NB * HEADS * AG * NTOK];
__device__ float g_AV[NB * HEADS * AG * HD];
__device__ float g_AVP[7 * NB * HEADS * AG * HD];
__device__ float g_AOUT[(size_t)MROWS * CCH];
__device__ __nv_bfloat16 g_xhi[(size_t)MROWS * CCH];
__device__ __nv_bfloat16 g_xlo[(size_t)MROWS * CCH];
__device__ __nv_bfloat16 g_ahi[(size_t)MROWS * CCH];
__device__ __nv_bfloat16 g_alo[(size_t)MROWS * CCH];
__device__ __nv_bfloat16 g_wqhi[CCH * CCH];
__device__ __nv_bfloat16 g_wqlo[CCH * CCH];
__device__ __nv_bfloat16 g_wkvhi[2 * CCH * CCH];
__device__ __nv_bfloat16 g_wkvlo[2 * CCH * CCH];
__device__ __nv_bfloat16 g_wphi[CCH * CCH];
__device__ __nv_bfloat16 g_wplo[CCH * CCH];

// ================= low-level helpers =================
__device__ __forceinline__ uint32_t smem_u32(const void* p) {
    uint32_t a;
    asm("{ .reg .u64 t; cvta.to.shared.u64 t, %1; cvt.u32.u64 %0, t; }" : "=r"(a) : "l"(p));
    return a;
}
__device__ __forceinline__ void cpa16(uint32_t s, const void* g) {
    asm volatile("cp.async.cg.shared.global [%0], [%1], 16;" :: "r"(s), "l"(g));
}
#define CP_COMMIT() asm volatile("cp.async.commit_group;" ::: "memory")

#define LDSM_X4(r0, r1, r2, r3, a) \
    asm volatile("ldmatrix.sync.aligned.m8n8.x4.shared.b16 {%0,%1,%2,%3}, [%4];" \
                 : "=r"(r0), "=r"(r1), "=r"(r2), "=r"(r3) : "r"(a))

#define MMA16816(d, a, b) \
    asm volatile("mma.sync.aligned.m16n8k16.row.col.f32.bf16.bf16.f32 " \
                 "{%0,%1,%2,%3}, {%4,%5,%6,%7}, {%8,%9}, {%0,%1,%2,%3};" \
                 : "+f"((d)[0]), "+f"((d)[1]), "+f"((d)[2]), "+f"((d)[3]) \
                 : "r"((a)[0]), "r"((a)[1]), "r"((a)[2]), "r"((a)[3]), \
                   "r"((b)[0]), "r"((b)[1]))

// smem chunk swizzle: row r (0-127), 16B-chunk c (0-3) within 64B row
#define SWZC(r, c) ((c) ^ (((r) >> 1) & 3))

#define STAGE_BYTES 32768   // 4 tiles x 8KB per pipeline stage
#define NSTAGE 3

// ================= split-bf16 tensor-core GEMM (mma.sync path) =================
// C[m, n] = sum_k A[m,k]*B[n,k] (+bias[n]); A = Ahi+Alo, B = Bhi+Blo (bf16 pairs)
// grid: (Nout/128, M/128); 256 threads; 96KB dynamic smem (3-stage pipeline).
__global__ __launch_bounds__(256) void gemm_tc(
    const __nv_bfloat16* __restrict__ Ahi, const __nv_bfloat16* __restrict__ Alo,
    const __nv_bfloat16* __restrict__ Bhi, const __nv_bfloat16* __restrict__ Blo,
    float* __restrict__ C, const float* __restrict__ bias, int Nout)
{
    extern __shared__ __align__(1024) char smem[];
    int tid = threadIdx.x;
    int wid = tid >> 5, lane = tid & 31;
    int bn0 = blockIdx.x * 128, m0 = blockIdx.y * 128;
    int wr = wid >> 2, wc = wid & 3;        // warp tile: rows wr*64, cols wc*32
    uint32_t sbase = smem_u32(smem);

    float acc[4][4][4] = {};

    // per-thread load coordinates (2 iterations x 4 tiles)
    int q0 = tid, q1 = tid + 256;
    int r0l = q0 >> 2, c0l = q0 & 3;
    int r1l = q1 >> 2, c1l = q1 & 3;
    uint32_t so0 = r0l * 64 + (SWZC(r0l, c0l) << 4);
    uint32_t so1 = r1l * 64 + (SWZC(r1l, c1l) << 4);

    const __nv_bfloat16* srcs[4] = { Ahi, Alo, Bhi, Blo };
    int rb[4] = { m0, m0, bn0, bn0 };

    // prologue: issue chunks 0 and 1
#pragma unroll
    for (int pc = 0; pc < 2; pc++) {
        int k0 = pc * 32;
        uint32_t sb = sbase + pc * STAGE_BYTES;
#pragma unroll
        for (int t = 0; t < 4; t++) {
            cpa16(sb + t * 8192 + so0, srcs[t] + (size_t)(rb[t] + r0l) * KDIM + k0 + c0l * 8);
            cpa16(sb + t * 8192 + so1, srcs[t] + (size_t)(rb[t] + r1l) * KDIM + k0 + c1l * 8);
        }
        CP_COMMIT();
    }

    int g = lane >> 3, lr = lane & 7;

    for (int ch = 0; ch < 16; ch++) {
        __syncthreads();   // all reads of the buffer being overwritten finished
        if (ch + 2 < 16) {
            int k0 = (ch + 2) * 32;
            uint32_t nb = sbase + ((ch + 2) % NSTAGE) * STAGE_BYTES;
#pragma unroll
            for (int t = 0; t < 4; t++) {
                cpa16(nb + t * 8192 + so0, srcs[t] + (size_t)(rb[t] + r0l) * KDIM + k0 + c0l * 8);
                cpa16(nb + t * 8192 + so1, srcs[t] + (size_t)(rb[t] + r1l) * KDIM + k0 + c1l * 8);
            }
            CP_COMMIT();
        }
        if (ch <= 13)      asm volatile("cp.async.wait_group 2;" ::: "memory");
        else if (ch == 14) asm volatile("cp.async.wait_group 1;" ::: "memory");
        else               asm volatile("cp.async.wait_group 0;" ::: "memory");
        __syncthreads();

        uint32_t base = sbase + (ch % NSTAGE) * STAGE_BYTES;
        uint32_t aAhi = base, aAlo = base + 8192, aBhi = base + 16384, aBlo = base + 24576;

#pragma unroll
        for (int ks = 0; ks < 2; ks++) {
            uint32_t af[4][4], al[4][4], bf[4][2], bl[4][2];
#pragma unroll
            for (int mt = 0; mt < 4; mt++) {
                int row = wr * 64 + mt * 16 + ((g & 1) << 3) + lr;
                int c = (ks * 32 + ((g >> 1) << 4)) >> 4;
                uint32_t off = row * 64 + (SWZC(row, c) << 4);
                LDSM_X4(af[mt][0], af[mt][1], af[mt][2], af[mt][3], aAhi + off);
                LDSM_X4(al[mt][0], al[mt][1], al[mt][2], al[mt][3], aAlo + off);
            }
#pragma unroll
            for (int np = 0; np < 2; np++) {
                int row = wc * 32 + np * 16 + ((g >> 1) << 3) + lr;
                int c = (ks * 32 + ((g & 1) << 4)) >> 4;
                uint32_t off = row * 64 + (SWZC(row, c) << 4);
                uint32_t r0, r1, r2, r3;
                LDSM_X4(r0, r1, r2, r3, aBhi + off);
                bf[np * 2][0] = r0; bf[np * 2][1] = r1;
                bf[np * 2 + 1][0] = r2; bf[np * 2 + 1][1] = r3;
                LDSM_X4(r0, r1, r2, r3, aBlo + off);
                bl[np * 2][0] = r0; bl[np * 2][1] = r1;
                bl[np * 2 + 1][0] = r2; bl[np * 2 + 1][1] = r3;
            }
            // term-major order: dependency distance to same acc = 16 MMAs
#pragma unroll
            for (int mt = 0; mt < 4; mt++)
#pragma unroll
                for (int nt = 0; nt < 4; nt++)
                    MMA16816(acc[mt][nt], af[mt], bf[nt]);
#pragma unroll
            for (int mt = 0; mt < 4; mt++)
#pragma unroll
                for (int nt = 0; nt < 4; nt++)
                    MMA16816(acc[mt][nt], al[mt], bf[nt]);
#pragma unroll
            for (int mt = 0; mt < 4; mt++)
#pragma unroll
                for (int nt = 0; nt < 4; nt++)
                    MMA16816(acc[mt][nt], af[mt], bl[nt]);
        }
    }

    // epilogue
#pragma unroll
    for (int mt = 0; mt < 4; mt++) {
#pragma unroll
        for (int nt = 0; nt < 4; nt++) {
            int gm = m0 + wr * 64 + mt * 16 + (lane >> 2);
            int gn = bn0 + wc * 32 + nt * 8 + ((lane & 3) << 1);
            float2 v0 = make_float2(acc[mt][nt][0], acc[mt][nt][1]);
            float2 v1 = make_float2(acc[mt][nt][2], acc[mt][nt][3]);
            if (bias) {
                float b0 = bias[gn], b1 = bias[gn + 1];
                v0.x += b0; v0.y += b1; v1.x += b0; v1.y += b1;
            }
            *(float2*)(C + (size_t)gm * Nout + gn) = v0;
            *(float2*)(C + (size_t)(gm + 8) * Nout + gn) = v1;
        }
    }
}

// ---------------- fp32 -> (bf16 hi, bf16 lo) split conversion --------------------
__global__ __launch_bounds__(256) void cvt_split(
    const float* __restrict__ src, __nv_bfloat16* __restrict__ hi,
    __nv_bfloat16* __restrict__ lo, int n4)
{
    for (int i = blockIdx.x * 256 + threadIdx.x; i < n4; i += gridDim.x * 256) {
        float4 v = ((const float4*)src)[i];
        __nv_bfloat16 h0 = __float2bfloat16(v.x);
        __nv_bfloat16 h1 = __float2bfloat16(v.y);
        __nv_bfloat16 h2 = __float2bfloat16(v.z);
        __nv_bfloat16 h3 = __float2bfloat16(v.w);
        __nv_bfloat16 l0 = __float2bfloat16(v.x - __bfloat162float(h0));
        __nv_bfloat16 l1 = __float2bfloat16(v.y - __bfloat162float(h1));
        __nv_bfloat16 l2 = __float2bfloat16(v.z - __bfloat162float(h2));
        __nv_bfloat16 l3 = __float2bfloat16(v.w - __bfloat162float(h3));
        ((__nv_bfloat162*)hi)[2 * i]     = __halves2bfloat162(h0, h1);
        ((__nv_bfloat162*)hi)[2 * i + 1] = __halves2bfloat162(h2, h3);
        ((__nv_bfloat162*)lo)[2 * i]     = __halves2bfloat162(l0, l1);
        ((__nv_bfloat162*)lo)[2 * i + 1] = __halves2bfloat162(l2, l3);
    }
}

// ---------------- agent token pooling -------------------------------------------
__global__ __launch_bounds__(256) void pool_kernel()
{
    int blk = blockIdx.x;
    int b = blk / AG, a = blk % AG;
    int p1 = a / 7, p2 = a % 7;
    for (int c = threadIdx.x; c < CCH; c += 256) {
        float s = 0.f;
#pragma unroll
        for (int r = 0; r < 8; r++)
#pragma unroll
            for (int ss = 0; ss < 8; ss++)
                s += g_Q[((size_t)(b * NTOK + (p1 * 8 + r) * HW + p2 * 8 + ss)) * CCH + c];
        g_AT[(b * AG + a) * CCH + c] = s * (1.0f / 64.0f);
    }
}

// ---------------- jax bilinear resize -------------------------------------------
__device__ __forceinline__ void lin_w(int o, int& i0, int& i1, float& w0, float& w1)
{
    float p = (o + 0.5f) * 0.125f - 0.5f;
    float fp = floorf(p);
    int i = (int)fp;
    float f = p - fp;
    if (i < 0)       { i0 = 0; i1 = 0; w0 = 1.f; w1 = 0.f; }
    else if (i >= 6) { i0 = 6; i1 = 6; w0 = 1.f; w1 = 0.f; }
    else             { i0 = i; i1 = i + 1; w0 = 1.f - f; w1 = f; }
}

__global__ __launch_bounds__(256) void bias_resize_kernel(
    const float* __restrict__ an, const float* __restrict__ na)
{
    int a = blockIdx.x, h = blockIdx.y, src = blockIdx.z;
    const float* S = (src == 0 ? an : na) + (h * AG + a) * 49;
    float* D = (src == 0 ? g_PB1 : g_NB1) + (size_t)(h * AG + a) * NTOK;
    __shared__ float s[49];
    if (threadIdx.x < 49) s[threadIdx.x] = S[threadIdx.x];
    __syncthreads();
    for (int o = threadIdx.x; o < NTOK; o += 256) {
        int oh = o / HW, ow = o % HW;
        int r0, r1, c0, c1; float wr0, wr1, wc0, wc1;
        lin_w(oh, r0, r1, wr0, wr1);
        lin_w(ow, c0, c1, wc0, wc1);
        D[o] = wr0 * (wc0 * s[r0 * 7 + c0] + wc1 * s[r0 * 7 + c1]) +
               wr1 * (wc0 * s[r1 * 7 + c0] + wc1 * s[r1 * 7 + c1]);
    }
}

// ---------------- agent logits ---------------------------------------------------
__global__ __launch_bounds__(256) void agent_logits_kernel(
    const float* __restrict__ ahb, const float* __restrict__ awb)
{
    int bh = blockIdx.y;
    int b = bh >> 3, h = bh & 7;
    int i0 = blockIdx.x * 64;
    __shared__ float ahT[64 * 65];
    __shared__ float ksT[64 * 65];
    int tid = threadIdx.x;
    for (int t = tid; t < 64 * 64; t += 256) {
        int a = t >> 6, d = t & 63;
        ahT[d * 65 + a] = (a < AG) ? g_AT[(b * AG + a) * CCH + h * HD + d] * 0.125f : 0.f;
    }
    for (int t = tid; t < 64 * 64; t += 256) {
        int il = t >> 6, d = t & 63;
        ksT[d * 65 + il] = g_KV[((size_t)(b * NTOK + i0 + il)) * (2 * CCH) + h * HD + d];
    }
    __syncthreads();
    int tx = tid & 15, ty = tid >> 4;
    float acc[4][4] = {};
#pragma unroll
    for (int d = 0; d < 64; d++) {
        float af[4], bf[4];
#pragma unroll
        for (int r = 0; r < 4; r++) af[r] = ahT[d * 65 + ty * 4 + r];
#pragma unroll
        for (int c = 0; c < 4; c++) bf[c] = ksT[d * 65 + tx * 4 + c];
#pragma unroll
        for (int r = 0; r < 4; r++)
#pragma unroll
            for (int c = 0; c < 4; c++)
                acc[r][c] += af[r] * bf[c];
    }
#pragma unroll
    for (int r = 0; r < 4; r++) {
        int a = ty * 4 + r;
        if (a >= AG) continue;
#pragma unroll
        for (int c = 0; c < 4; c++) {
            int i = i0 + tx * 4 + c;
            int oh = i / HW, ow = i % HW;
            float lg = acc[r][c] + g_PB1[(h * AG + a) * NTOK + i]
                     + ahb[(h * AG + a) * HW + oh] + awb[(h * AG + a) * HW + ow];
            g_LOG[((size_t)(bh * AG + a)) * NTOK + i] = lg;
        }
    }
}

// ---------------- row softmax over n=3136 ----------------------------------------
__global__ __launch_bounds__(256) void softmax_n_kernel()
{
    size_t row = blockIdx.x;
    float* p = g_LOG + row * NTOK;
    __shared__ float buf[NTOK];
    __shared__ float red[8];
    int tid = threadIdx.x;
    float m = -1e30f;
    for (int i = tid; i < NTOK; i += 256) { float v = p[i]; buf[i] = v; m = fmaxf(m, v); }
#pragma unroll
    for (int o = 16; o; o >>= 1) m = fmaxf(m, __shfl_xor_sync(~0u, m, o));
    if ((tid & 31) == 0) red[tid >> 5] = m;
    __syncthreads();
    m = fmaxf(fmaxf(fmaxf(red[0], red[1]), fmaxf(red[2], red[3])),
              fmaxf(fmaxf(red[4], red[5]), fmaxf(red[6], red[7])));
    __syncthreads();
    float s = 0.f;
    for (int i = tid; i < NTOK; i += 256) { float e = __expf(buf[i] - m); buf[i] = e; s += e; }
#pragma unroll
    for (int o = 16; o; o >>= 1) s += __shfl_xor_sync(~0u, s, o);
    if ((tid & 31) == 0) red[tid >> 5] = s;
    __syncthreads();
    s = red[0] + red[1] + red[2] + red[3] + red[4] + red[5] + red[6] + red[7];
    float inv = 1.0f / s;
    for (int i = tid; i < NTOK; i += 256) p[i] = buf[i] * inv;
}

// ---------------- agent_v split over K + deterministic reduce --------------------
__global__ __launch_bounds__(256) void agent_v_split_kernel()
{
    int bh = blockIdx.x;
    int sp = blockIdx.y;
    int b = bh >> 3, h = bh & 7;
    __shared__ float at_s[32 * 65];
    __shared__ float vt_s[32 * 65];
    int tid = threadIdx.x, tx = tid & 15, ty = tid >> 4;
    float acc[4][4] = {};
    int kbeg = sp * 448, kend = kbeg + 448;
    for (int k0 = kbeg; k0 < kend; k0 += 32) {
        for (int t = tid; t < 64 * 32; t += 256) {
            int a = t >> 5, kk = t & 31;
            at_s[kk * 65 + a] = (a < AG) ? g_LOG[((size_t)(bh * AG + a)) * NTOK + k0 + kk] : 0.f;
        }
        for (int t = tid; t < 32 * 64; t += 256) {
            int kk = t >> 6, d = t & 63;
            vt_s[kk * 65 + d] = g_KV[((size_t)(b * NTOK + k0 + kk)) * (2 * CCH) + CCH + h * HD + d];
        }
        __syncthreads();
#pragma unroll
        for (int kk = 0; kk < 32; kk++) {
            float af[4], bf[4];
#pragma unroll
            for (int r = 0; r < 4; r++) af[r] = at_s[kk * 65 + ty * 4 + r];
#pragma unroll
            for (int c = 0; c < 4; c++) bf[c] = vt_s[kk * 65 + tx * 4 + c];
#pragma unroll
            for (int r = 0; r < 4; r++)
#pragma unroll
                for (int c = 0; c < 4; c++)
                    acc[r][c] += af[r] * bf[c];
        }
        __syncthreads();
    }
#pragma unroll
    for (int r = 0; r < 4; r++) {
        int a = ty * 4 + r;
        if (a >= AG) continue;
#pragma unroll
        for (int c = 0; c < 4; c++)
            g_AVP[((size_t)sp * NB * HEADS + bh) * AG * HD + (a * HD + tx * 4 + c)] = acc[r][c];
    }
}

__global__ __launch_bounds__(256) void avp_reduce_kernel()
{
    int i = blockIdx.x * 256 + threadIdx.x;
    const int tot = NB * HEADS * AG * HD;
    if (i < tot) {
        int bh = i / (AG * HD), rest = i % (AG * HD);
        float s = 0.f;
#pragma unroll
        for (int sp = 0; sp < 7; sp++)
            s += g_AVP[((size_t)sp * NB * HEADS + bh) * AG * HD + rest];
        g_AV[i] = s;
    }
}

// ---------------- q-side fused softmax + @agent_v --------------------------------
__global__ __launch_bounds__(256) void qside_kernel(
    const float* __restrict__ hab, const float* __restrict__ wab)
{
    int bh = blockIdx.y;
    int b = bh >> 3, h = bh & 7;
    int i0 = blockIdx.x * 32;
    __shared__ float ah_s[64 * 65];
    __shared__ float av_s[AG * 65];
    __shared__ float q_s[32 * 65];
    __shared__ float p_s[8 * 64];
    int tid = threadIdx.x;
    for (int t = tid; t < 64 * 64; t += 256) {
        int a = t >> 6, d = t & 63;
        ah_s[a * 65 + d] = (a < AG) ? g_AT[(b * AG + a) * CCH + h * HD + d] * 0.125f : 0.f;
    }
    for (int t = tid; t < AG * 64; t += 256) {
        int a = t >> 6, d = t & 63;
        av_s[a * 65 + d] = g_AV[(bh * AG + a) * HD + d];
    }
    for (int t = tid; t < 32 * 64; t += 256) {
        int il = t >> 6, d = t & 63;
        q_s[il * 65 + d] = g_Q[((size_t)(b * NTOK + i0 + il)) * CCH + h * HD + d];
    }
    __syncthreads();
    int w = tid >> 5, l = tid & 31;
    for (int rep = 0; rep < 4; rep++) {
        int il = w * 4 + rep;
        int i = i0 + il;
        int oh = i / HW, ow = i % HW;
        int a1 = l, a2 = l + 32;
        float lg1 = 0.f, lg2 = 0.f;
#pragma unroll
        for (int d = 0; d < 64; d++) {
            float qv = q_s[il * 65 + d];
            lg1 += qv * ah_s[a1 * 65 + d];
            lg2 += qv * ah_s[a2 * 65 + d];
        }
        lg1 += g_NB1[(h * AG + a1) * NTOK + i]
             + hab[(h * HW + oh) * AG + a1] + wab[(h * HW + ow) * AG + a1];
        if (a2 < AG)
            lg2 += g_NB1[(h * AG + a2) * NTOK + i]
                 + hab[(h * HW + oh) * AG + a2] + wab[(h * HW + ow) * AG + a2];
        else
            lg2 = -INFINITY;
        float mx = fmaxf(lg1, lg2);
#pragma unroll
        for (int o = 16; o; o >>= 1) mx = fmaxf(mx, __shfl_xor_sync(~0u, mx, o));
        float p1 = __expf(lg1 - mx);
        float p2 = __expf(lg2 - mx);
        float sm = p1 + p2;
#pragma unroll
        for (int o = 16; o; o >>= 1) sm += __shfl_xor_sync(~0u, sm, o);
        float inv = 1.0f / sm;
        __syncwarp();
        p_s[w * 64 + a1] = p1 * inv;
        p_s[w * 64 + a2] = p2 * inv;
        __syncwarp();
        float o1 = 0.f, o2 = 0.f;
#pragma unroll
        for (int a = 0; a < AG; a++) {
            float pv = p_s[w * 64 + a];
            o1 += pv * av_s[a * 65 + l];
            o2 += pv * av_s[a * 65 + l + 32];
        }
        size_t base = ((size_t)(b * NTOK + i)) * CCH + h * HD;
        g_AOUT[base + l] = o1;
        g_AOUT[base + l + 32] = o2;
        __syncwarp();
    }
}

// ---------------- 3x3 depthwise conv on v ---------------------------------------
__global__ __launch_bounds__(256) void dwc_kernel(
    const float* __restrict__ dwc_w, const float* __restrict__ dwc_b)
{
    int oh = blockIdx.x, b = blockIdx.y;
    __shared__ float w_s[CCH * 9];
    __shared__ float b_s[CCH];
    int tid = threadIdx.x;
    for (int t = tid; t < CCH * 9; t += 256) w_s[t] = dwc_w[t];
    for (int t = tid; t < CCH; t += 256) b_s[t] = dwc_b[t];
    __syncthreads();
    for (int idx = tid; idx < HW * CCH; idx += 256) {
        int ow = idx >> 9, c = idx & 511;
        float acc = b_s[c];
#pragma unroll
        for (int ky = 0; ky < 3; ky++) {
            int h2 = oh + ky - 1;
            if (h2 < 0 || h2 >= HW) continue;
#pragma unroll
            for (int kx = 0; kx < 3; kx++) {
                int w2 = ow + kx - 1;
                if (w2 < 0 || w2 >= HW) continue;
                acc += g_KV[((size_t)(b * NTOK + h2 * HW + w2)) * (2 * CCH) + CCH + c]
                     * w_s[c * 9 + ky * 3 + kx];
            }
        }
        g_AOUT[((size_t)(b * NTOK + oh * HW + ow)) * CCH + c] += acc;
    }
}

// ---------------- launch ---------------------------------------------------------
extern "C" void kernel_launch(void* const* d_in, const int* in_sizes, int n_in,
                              void* d_out, int out_size)
{
    const float* x = (const float*)d_in[0];
    int off = 1;
    if (n_in >= 15 && in_sizes[1] == 1) off = 3;
    const float* q_w    = (const float*)d_in[off + 0];
    const float* kv_w   = (const float*)d_in[off + 1];
    const float* proj_w = (const float*)d_in[off + 2];
    const float* proj_b = (const float*)d_in[off + 3];
    const float* dwc_w  = (const float*)d_in[off + 4];
    const float* dwc_b  = (const float*)d_in[off + 5];
    const float* an_b   = (const float*)d_in[off + 6];
    const float* na_b   = (const float*)d_in[off + 7];
    const float* ah_b   = (const float*)d_in[off + 8];
    const float* aw_b   = (const float*)d_in[off + 9];
    const float* ha_b   = (const float*)d_in[off + 10];
    const float* wa_b   = (const float*)d_in[off + 11];
    float* out = (float*)d_out;

    float *Qp, *KVp, *AOUTp;
    __nv_bfloat16 *xhi, *xlo, *ahi, *alo, *wqhi, *wqlo, *wkvhi, *wkvlo, *wphi, *wplo;
    cudaGetSymbolAddress((void**)&Qp, g_Q);
    cudaGetSymbolAddress((void**)&KVp, g_KV);
    cudaGetSymbolAddress((void**)&AOUTp, g_AOUT);
    cudaGetSymbolAddress((void**)&xhi, g_xhi);
    cudaGetSymbolAddress((void**)&xlo, g_xlo);
    cudaGetSymbolAddress((void**)&ahi, g_ahi);
    cudaGetSymbolAddress((void**)&alo, g_alo);
    cudaGetSymbolAddress((void**)&wqhi, g_wqhi);
    cudaGetSymbolAddress((void**)&wqlo, g_wqlo);
    cudaGetSymbolAddress((void**)&wkvhi, g_wkvhi);
    cudaGetSymbolAddress((void**)&wkvlo, g_wkvlo);
    cudaGetSymbolAddress((void**)&wphi, g_wphi);
    cudaGetSymbolAddress((void**)&wplo, g_wplo);

    static int smem_set = 0;
    if (!smem_set) {
        cudaFuncSetAttribute(gemm_tc, cudaFuncAttributeMaxDynamicSharedMemorySize, NSTAGE * STAGE_BYTES);
        smem_set = 1;
    }

    cvt_split<<<4096, 256>>>(x, xhi, xlo, MROWS * CCH / 4);
    cvt_split<<<256, 256>>>(q_w, wqhi, wqlo, CCH * CCH / 4);
    cvt_split<<<512, 256>>>(kv_w, wkvhi, wkvlo, 2 * CCH * CCH / 4);
    cvt_split<<<256, 256>>>(proj_w, wphi, wplo, CCH * CCH / 4);

    gemm_tc<<<dim3(4, MROWS / 128), 256, NSTAGE * STAGE_BYTES>>>(xhi, xlo, wqhi, wqlo, Qp, nullptr, 512);
    gemm_tc<<<dim3(8, MROWS / 128), 256, NSTAGE * STAGE_BYTES>>>(xhi, xlo, wkvhi, wkvlo, KVp, nullptr, 1024);

    pool_kernel<<<NB * AG, 256>>>();
    bias_resize_kernel<<<dim3(AG, HEADS, 2), 256>>>(an_b, na_b);
    agent_logits_kernel<<<dim3(NTOK / 64, NB * HEADS), 256>>>(ah_b, aw_b);
    softmax_n_kernel<<<NB * HEADS * AG, 256>>>();
    agent_v_split_kernel<<<dim3(NB * HEADS, 7), 256>>>();
    avp_reduce_kernel<<<(NB * HEADS * AG * HD + 255) / 256, 256>>>();
    qside_kernel<<<dim3(NTOK / 32, NB * HEADS), 256>>>(ha_b, wa_b);
    dwc_kernel<<<dim3(HW, NB), 256>>>(dwc_w, dwc_b);

    cvt_split<<<4096, 256>>>(AOUTp, ahi, alo, MROWS * CCH / 4);
    gemm_tc<<<dim3(4, MROWS / 128), 256, NSTAGE * STAGE_BYTES>>>(ahi, alo, wphi, wplo, out, proj_b, 512);
}

// round 7
// speedup vs baseline: 1.9143x; 1.0511x over previous
#include <cuda_runtime.h>
#include <cuda_bf16.h>
#include <math.h>
#include <stdint.h>

#define HEADS 8
#define HD 64
#define CCH 512
#define HW 56
#define NTOK 3136
#define AG 49
#define NB 16
#define MROWS (NB*NTOK)
#define KDIM 512

// ---------------- scratch (static device globals; no allocations) ----------------
__device__ float g_Q[(size_t)MROWS * CCH];
__device__ float g_KV[(size_t)MROWS * 2 * CCH];
__device__ float g_AT[NB * AG * CCH];
__device__ float g_PB1[HEADS * AG * NTOK];
__device__ float g_NB1[HEADS * AG * NTOK];
__device__ float g_LOG[(size_t)NB * HEADS * AG * NTOK];
__device__ float g_AV[NB * HEADS * AG * HD];
__device__ float g_AVP[7 * NB * HEADS * AG * HD];
__device__ float g_AOUT[(size_t)MROWS * CCH];
__device__ __nv_bfloat16 g_xhi[(size_t)MROWS * CCH];
__device__ __nv_bfloat16 g_xlo[(size_t)MROWS * CCH];
__device__ __nv_bfloat16 g_ahi[(size_t)MROWS * CCH];
__device__ __nv_bfloat16 g_alo[(size_t)MROWS * CCH];
__device__ __nv_bfloat16 g_wqhi[CCH * CCH];
__device__ __nv_bfloat16 g_wqlo[CCH * CCH];
__device__ __nv_bfloat16 g_wkvhi[2 * CCH * CCH];
__device__ __nv_bfloat16 g_wkvlo[2 * CCH * CCH];
__device__ __nv_bfloat16 g_wphi[CCH * CCH];
__device__ __nv_bfloat16 g_wplo[CCH * CCH];

// ================= low-level helpers =================
__device__ __forceinline__ uint32_t smem_u32(const void* p) {
    uint32_t a;
    asm("{ .reg .u64 t; cvta.to.shared.u64 t, %1; cvt.u32.u64 %0, t; }" : "=r"(a) : "l"(p));
    return a;
}
__device__ __forceinline__ void cpa16(uint32_t s, const void* g) {
    asm volatile("cp.async.cg.shared.global [%0], [%1], 16;" :: "r"(s), "l"(g));
}
#define CP_COMMIT() asm volatile("cp.async.commit_group;" ::: "memory")

#define LDSM_X4(r0, r1, r2, r3, a) \
    asm volatile("ldmatrix.sync.aligned.m8n8.x4.shared.b16 {%0,%1,%2,%3}, [%4];" \
                 : "=r"(r0), "=r"(r1), "=r"(r2), "=r"(r3) : "r"(a))

#define MMA16816(d, a, b) \
    asm volatile("mma.sync.aligned.m16n8k16.row.col.f32.bf16.bf16.f32 " \
                 "{%0,%1,%2,%3}, {%4,%5,%6,%7}, {%8,%9}, {%0,%1,%2,%3};" \
                 : "+f"((d)[0]), "+f"((d)[1]), "+f"((d)[2]), "+f"((d)[3]) \
                 : "r"((a)[0]), "r"((a)[1]), "r"((a)[2]), "r"((a)[3]), \
                   "r"((b)[0]), "r"((b)[1]))

// smem chunk swizzle: row r, 16B-chunk c (0-3) within 64B row
#define SWZC(r, c) ((c) ^ (((r) >> 1) & 3))

// stage layout: [Ahi 8KB][Alo 8KB][Bhi 4KB][Blo 4KB]
#define STG_BYTES 24576
#define NST 3

// ================= split-bf16 tensor-core GEMM (mma.sync, 2 CTAs/SM) ============
// C[m, n] = sum_k A[m,k]*B[n,k] (+bias[n]); A = Ahi+Alo, B = Bhi+Blo (bf16 pairs)
// CTA tile 128(M) x 64(N); 8 warps of 32x32; grid (Nout/64, M/128).
__global__ void __launch_bounds__(256, 2) gemm_tc(
    const __nv_bfloat16* __restrict__ Ahi, const __nv_bfloat16* __restrict__ Alo,
    const __nv_bfloat16* __restrict__ Bhi, const __nv_bfloat16* __restrict__ Blo,
    float* __restrict__ C, const float* __restrict__ bias, int Nout)
{
    extern __shared__ __align__(1024) char smem[];
    int tid = threadIdx.x;
    int wid = tid >> 5, lane = tid & 31;
    int bn0 = blockIdx.x * 64, m0 = blockIdx.y * 128;
    int wr = wid >> 1, wc = wid & 1;        // warp tile: rows wr*32, cols wc*32
    uint32_t sbase = smem_u32(smem);

    float acc[2][4][4] = {};

    // loader coords: A has 512 16B-chunks per operand (2/thread), B has 256 (1/thread)
    int rA0 = tid >> 2,        cA0 = tid & 3;
    int rA1 = (tid + 256) >> 2, cA1 = tid & 3;   // tid+256: c = (tid+256)&3 == tid&3
    int rB  = tid >> 2,        cB  = tid & 3;    // rB < 64 only for tid<256 ✓
    uint32_t soA0 = rA0 * 64 + (SWZC(rA0, cA0) << 4);
    uint32_t soA1 = rA1 * 64 + (SWZC(rA1, cA1) << 4);
    uint32_t soB  = rB * 64 + (SWZC(rB, cB) << 4);

    // prologue: issue chunks 0 and 1
#pragma unroll
    for (int pc = 0; pc < 2; pc++) {
        int k0 = pc * 32;
        uint32_t sb = sbase + pc * STG_BYTES;
        cpa16(sb + soA0,         Ahi + (size_t)(m0 + rA0) * KDIM + k0 + cA0 * 8);
        cpa16(sb + soA1,         Ahi + (size_t)(m0 + rA1) * KDIM + k0 + cA1 * 8);
        cpa16(sb + 8192 + soA0,  Alo + (size_t)(m0 + rA0) * KDIM + k0 + cA0 * 8);
        cpa16(sb + 8192 + soA1,  Alo + (size_t)(m0 + rA1) * KDIM + k0 + cA1 * 8);
        cpa16(sb + 16384 + soB,  Bhi + (size_t)(bn0 + rB) * KDIM + k0 + cB * 8);
        cpa16(sb + 20480 + soB,  Blo + (size_t)(bn0 + rB) * KDIM + k0 + cB * 8);
        CP_COMMIT();
    }

    int g = lane >> 3, lr = lane & 7;

    for (int ch = 0; ch < 16; ch++) {
        __syncthreads();
        if (ch + 2 < 16) {
            int k0 = (ch + 2) * 32;
            uint32_t nb = sbase + ((ch + 2) % NST) * STG_BYTES;
            cpa16(nb + soA0,        Ahi + (size_t)(m0 + rA0) * KDIM + k0 + cA0 * 8);
            cpa16(nb + soA1,        Ahi + (size_t)(m0 + rA1) * KDIM + k0 + cA1 * 8);
            cpa16(nb + 8192 + soA0, Alo + (size_t)(m0 + rA0) * KDIM + k0 + cA0 * 8);
            cpa16(nb + 8192 + soA1, Alo + (size_t)(m0 + rA1) * KDIM + k0 + cA1 * 8);
            cpa16(nb + 16384 + soB, Bhi + (size_t)(bn0 + rB) * KDIM + k0 + cB * 8);
            cpa16(nb + 20480 + soB, Blo + (size_t)(bn0 + rB) * KDIM + k0 + cB * 8);
            CP_COMMIT();
        }
        if (ch <= 13)      asm volatile("cp.async.wait_group 2;" ::: "memory");
        else if (ch == 14) asm volatile("cp.async.wait_group 1;" ::: "memory");
        else               asm volatile("cp.async.wait_group 0;" ::: "memory");
        __syncthreads();

        uint32_t base = sbase + (ch % NST) * STG_BYTES;

#pragma unroll
        for (int ks = 0; ks < 2; ks++) {
            uint32_t af[2][4], al[2][4], bf[4][2], bl[4][2];
#pragma unroll
            for (int mt = 0; mt < 2; mt++) {
                int row = wr * 32 + mt * 16 + ((g & 1) << 3) + lr;
                int c = ks * 2 + (g >> 1);
                uint32_t off = row * 64 + (SWZC(row, c) << 4);
                LDSM_X4(af[mt][0], af[mt][1], af[mt][2], af[mt][3], base + off);
                LDSM_X4(al[mt][0], al[mt][1], al[mt][2], al[mt][3], base + 8192 + off);
            }
#pragma unroll
            for (int np = 0; np < 2; np++) {
                int row = wc * 32 + np * 16 + ((g >> 1) << 3) + lr;
                int c = ks * 2 + (g & 1);
                uint32_t off = row * 64 + (SWZC(row, c) << 4);
                uint32_t r0, r1, r2, r3;
                LDSM_X4(r0, r1, r2, r3, base + 16384 + off);
                bf[np * 2][0] = r0; bf[np * 2][1] = r1;
                bf[np * 2 + 1][0] = r2; bf[np * 2 + 1][1] = r3;
                LDSM_X4(r0, r1, r2, r3, base + 20480 + off);
                bl[np * 2][0] = r0; bl[np * 2][1] = r1;
                bl[np * 2 + 1][0] = r2; bl[np * 2 + 1][1] = r3;
            }
            // term-major: dependency distance to same acc = 8 MMAs
#pragma unroll
            for (int mt = 0; mt < 2; mt++)
#pragma unroll
                for (int nt = 0; nt < 4; nt++)
                    MMA16816(acc[mt][nt], af[mt], bf[nt]);
#pragma unroll
            for (int mt = 0; mt < 2; mt++)
#pragma unroll
                for (int nt = 0; nt < 4; nt++)
                    MMA16816(acc[mt][nt], al[mt], bf[nt]);
#pragma unroll
            for (int mt = 0; mt < 2; mt++)
#pragma unroll
                for (int nt = 0; nt < 4; nt++)
                    MMA16816(acc[mt][nt], af[mt], bl[nt]);
        }
    }

    // epilogue
#pragma unroll
    for (int mt = 0; mt < 2; mt++) {
#pragma unroll
        for (int nt = 0; nt < 4; nt++) {
            int gm = m0 + wr * 32 + mt * 16 + (lane >> 2);
            int gn = bn0 + wc * 32 + nt * 8 + ((lane & 3) << 1);
            float2 v0 = make_float2(acc[mt][nt][0], acc[mt][nt][1]);
            float2 v1 = make_float2(acc[mt][nt][2], acc[mt][nt][3]);
            if (bias) {
                float b0 = bias[gn], b1 = bias[gn + 1];
                v0.x += b0; v0.y += b1; v1.x += b0; v1.y += b1;
            }
            *(float2*)(C + (size_t)gm * Nout + gn) = v0;
            *(float2*)(C + (size_t)(gm + 8) * Nout + gn) = v1;
        }
    }
}

// ---------------- fp32 -> (bf16 hi, bf16 lo) split conversion --------------------
__global__ __launch_bounds__(256) void cvt_split(
    const float* __restrict__ src, __nv_bfloat16* __restrict__ hi,
    __nv_bfloat16* __restrict__ lo, int n4)
{
    for (int i = blockIdx.x * 256 + threadIdx.x; i < n4; i += gridDim.x * 256) {
        float4 v = ((const float4*)src)[i];
        __nv_bfloat16 h0 = __float2bfloat16(v.x);
        __nv_bfloat16 h1 = __float2bfloat16(v.y);
        __nv_bfloat16 h2 = __float2bfloat16(v.z);
        __nv_bfloat16 h3 = __float2bfloat16(v.w);
        __nv_bfloat16 l0 = __float2bfloat16(v.x - __bfloat162float(h0));
        __nv_bfloat16 l1 = __float2bfloat16(v.y - __bfloat162float(h1));
        __nv_bfloat16 l2 = __float2bfloat16(v.z - __bfloat162float(h2));
        __nv_bfloat16 l3 = __float2bfloat16(v.w - __bfloat162float(h3));
        ((__nv_bfloat162*)hi)[2 * i]     = __halves2bfloat162(h0, h1);
        ((__nv_bfloat162*)hi)[2 * i + 1] = __halves2bfloat162(h2, h3);
        ((__nv_bfloat162*)lo)[2 * i]     = __halves2bfloat162(l0, l1);
        ((__nv_bfloat162*)lo)[2 * i + 1] = __halves2bfloat162(l2, l3);
    }
}

// ---------------- agent token pooling -------------------------------------------
__global__ __launch_bounds__(256) void pool_kernel()
{
    int blk = blockIdx.x;
    int b = blk / AG, a = blk % AG;
    int p1 = a / 7, p2 = a % 7;
    for (int c = threadIdx.x; c < CCH; c += 256) {
        float s = 0.f;
#pragma unroll
        for (int r = 0; r < 8; r++)
#pragma unroll
            for (int ss = 0; ss < 8; ss++)
                s += g_Q[((size_t)(b * NTOK + (p1 * 8 + r) * HW + p2 * 8 + ss)) * CCH + c];
        g_AT[(b * AG + a) * CCH + c] = s * (1.0f / 64.0f);
    }
}

// ---------------- jax bilinear resize -------------------------------------------
__device__ __forceinline__ void lin_w(int o, int& i0, int& i1, float& w0, float& w1)
{
    float p = (o + 0.5f) * 0.125f - 0.5f;
    float fp = floorf(p);
    int i = (int)fp;
    float f = p - fp;
    if (i < 0)       { i0 = 0; i1 = 0; w0 = 1.f; w1 = 0.f; }
    else if (i >= 6) { i0 = 6; i1 = 6; w0 = 1.f; w1 = 0.f; }
    else             { i0 = i; i1 = i + 1; w0 = 1.f - f; w1 = f; }
}

__global__ __launch_bounds__(256) void bias_resize_kernel(
    const float* __restrict__ an, const float* __restrict__ na)
{
    int a = blockIdx.x, h = blockIdx.y, src = blockIdx.z;
    const float* S = (src == 0 ? an : na) + (h * AG + a) * 49;
    float* D = (src == 0 ? g_PB1 : g_NB1) + (size_t)(h * AG + a) * NTOK;
    __shared__ float s[49];
    if (threadIdx.x < 49) s[threadIdx.x] = S[threadIdx.x];
    __syncthreads();
    for (int o = threadIdx.x; o < NTOK; o += 256) {
        int oh = o / HW, ow = o % HW;
        int r0, r1, c0, c1; float wr0, wr1, wc0, wc1;
        lin_w(oh, r0, r1, wr0, wr1);
        lin_w(ow, c0, c1, wc0, wc1);
        D[o] = wr0 * (wc0 * s[r0 * 7 + c0] + wc1 * s[r0 * 7 + c1]) +
               wr1 * (wc0 * s[r1 * 7 + c0] + wc1 * s[r1 * 7 + c1]);
    }
}

// ---------------- agent logits ---------------------------------------------------
__global__ __launch_bounds__(256) void agent_logits_kernel(
    const float* __restrict__ ahb, const float* __restrict__ awb)
{
    int bh = blockIdx.y;
    int b = bh >> 3, h = bh & 7;
    int i0 = blockIdx.x * 64;
    __shared__ float ahT[64 * 65];
    __shared__ float ksT[64 * 65];
    int tid = threadIdx.x;
    for (int t = tid; t < 64 * 64; t += 256) {
        int a = t >> 6, d = t & 63;
        ahT[d * 65 + a] = (a < AG) ? g_AT[(b * AG + a) * CCH + h * HD + d] * 0.125f : 0.f;
    }
    for (int t = tid; t < 64 * 64; t += 256) {
        int il = t >> 6, d = t & 63;
        ksT[d * 65 + il] = g_KV[((size_t)(b * NTOK + i0 + il)) * (2 * CCH) + h * HD + d];
    }
    __syncthreads();
    int tx = tid & 15, ty = tid >> 4;
    float acc[4][4] = {};
#pragma unroll
    for (int d = 0; d < 64; d++) {
        float af[4], bf[4];
#pragma unroll
        for (int r = 0; r < 4; r++) af[r] = ahT[d * 65 + ty * 4 + r];
#pragma unroll
        for (int c = 0; c < 4; c++) bf[c] = ksT[d * 65 + tx * 4 + c];
#pragma unroll
        for (int r = 0; r < 4; r++)
#pragma unroll
            for (int c = 0; c < 4; c++)
                acc[r][c] += af[r] * bf[c];
    }
#pragma unroll
    for (int r = 0; r < 4; r++) {
        int a = ty * 4 + r;
        if (a >= AG) continue;
#pragma unroll
        for (int c = 0; c < 4; c++) {
            int i = i0 + tx * 4 + c;
            int oh = i / HW, ow = i % HW;
            float lg = acc[r][c] + g_PB1[(h * AG + a) * NTOK + i]
                     + ahb[(h * AG + a) * HW + oh] + awb[(h * AG + a) * HW + ow];
            g_LOG[((size_t)(bh * AG + a)) * NTOK + i] = lg;
        }
    }
}

// ---------------- row softmax over n=3136 ----------------------------------------
__global__ __launch_bounds__(256) void softmax_n_kernel()
{
    size_t row = blockIdx.x;
    float* p = g_LOG + row * NTOK;
    __shared__ float buf[NTOK];
    __shared__ float red[8];
    int tid = threadIdx.x;
    float m = -1e30f;
    for (int i = tid; i < NTOK; i += 256) { float v = p[i]; buf[i] = v; m = fmaxf(m, v); }
#pragma unroll
    for (int o = 16; o; o >>= 1) m = fmaxf(m, __shfl_xor_sync(~0u, m, o));
    if ((tid & 31) == 0) red[tid >> 5] = m;
    __syncthreads();
    m = fmaxf(fmaxf(fmaxf(red[0], red[1]), fmaxf(red[2], red[3])),
              fmaxf(fmaxf(red[4], red[5]), fmaxf(red[6], red[7])));
    __syncthreads();
    float s = 0.f;
    for (int i = tid; i < NTOK; i += 256) { float e = __expf(buf[i] - m); buf[i] = e; s += e; }
#pragma unroll
    for (int o = 16; o; o >>= 1) s += __shfl_xor_sync(~0u, s, o);
    if ((tid & 31) == 0) red[tid >> 5] = s;
    __syncthreads();
    s = red[0] + red[1] + red[2] + red[3] + red[4] + red[5] + red[6] + red[7];
    float inv = 1.0f / s;
    for (int i = tid; i < NTOK; i += 256) p[i] = buf[i] * inv;
}

// ---------------- agent_v split over K + deterministic reduce --------------------
__global__ __launch_bounds__(256) void agent_v_split_kernel()
{
    int bh = blockIdx.x;
    int sp = blockIdx.y;
    int b = bh >> 3, h = bh & 7;
    __shared__ float at_s[32 * 65];
    __shared__ float vt_s[32 * 65];
    int tid = threadIdx.x, tx = tid & 15, ty = tid >> 4;
    float acc[4][4] = {};
    int kbeg = sp * 448, kend = kbeg + 448;
    for (int k0 = kbeg; k0 < kend; k0 += 32) {
        for (int t = tid; t < 64 * 32; t += 256) {
            int a = t >> 5, kk = t & 31;
            at_s[kk * 65 + a] = (a < AG) ? g_LOG[((size_t)(bh * AG + a)) * NTOK + k0 + kk] : 0.f;
        }
        for (int t = tid; t < 32 * 64; t += 256) {
            int kk = t >> 6, d = t & 63;
            vt_s[kk * 65 + d] = g_KV[((size_t)(b * NTOK + k0 + kk)) * (2 * CCH) + CCH + h * HD + d];
        }
        __syncthreads();
#pragma unroll
        for (int kk = 0; kk < 32; kk++) {
            float af[4], bf[4];
#pragma unroll
            for (int r = 0; r < 4; r++) af[r] = at_s[kk * 65 + ty * 4 + r];
#pragma unroll
            for (int c = 0; c < 4; c++) bf[c] = vt_s[kk * 65 + tx * 4 + c];
#pragma unroll
            for (int r = 0; r < 4; r++)
#pragma unroll
                for (int c = 0; c < 4; c++)
                    acc[r][c] += af[r] * bf[c];
        }
        __syncthreads();
    }
#pragma unroll
    for (int r = 0; r < 4; r++) {
        int a = ty * 4 + r;
        if (a >= AG) continue;
#pragma unroll
        for (int c = 0; c < 4; c++)
            g_AVP[((size_t)sp * NB * HEADS + bh) * AG * HD + (a * HD + tx * 4 + c)] = acc[r][c];
    }
}

__global__ __launch_bounds__(256) void avp_reduce_kernel()
{
    int i = blockIdx.x * 256 + threadIdx.x;
    const int tot = NB * HEADS * AG * HD;
    if (i < tot) {
        int bh = i / (AG * HD), rest = i % (AG * HD);
        float s = 0.f;
#pragma unroll
        for (int sp = 0; sp < 7; sp++)
            s += g_AVP[((size_t)sp * NB * HEADS + bh) * AG * HD + rest];
        g_AV[i] = s;
    }
}

// ---------------- q-side fused softmax + @agent_v --------------------------------
__global__ __launch_bounds__(256) void qside_kernel(
    const float* __restrict__ hab, const float* __restrict__ wab)
{
    int bh = blockIdx.y;
    int b = bh >> 3, h = bh & 7;
    int i0 = blockIdx.x * 32;
    __shared__ float ah_s[64 * 65];
    __shared__ float av_s[AG * 65];
    __shared__ float q_s[32 * 65];
    __shared__ float p_s[8 * 64];
    int tid = threadIdx.x;
    for (int t = tid; t < 64 * 64; t += 256) {
        int a = t >> 6, d = t & 63;
        ah_s[a * 65 + d] = (a < AG) ? g_AT[(b * AG + a) * CCH + h * HD + d] * 0.125f : 0.f;
    }
    for (int t = tid; t < AG * 64; t += 256) {
        int a = t >> 6, d = t & 63;
        av_s[a * 65 + d] = g_AV[(bh * AG + a) * HD + d];
    }
    for (int t = tid; t < 32 * 64; t += 256) {
        int il = t >> 6, d = t & 63;
        q_s[il * 65 + d] = g_Q[((size_t)(b * NTOK + i0 + il)) * CCH + h * HD + d];
    }
    __syncthreads();
    int w = tid >> 5, l = tid & 31;
    for (int rep = 0; rep < 4; rep++) {
        int il = w * 4 + rep;
        int i = i0 + il;
        int oh = i / HW, ow = i % HW;
        int a1 = l, a2 = l + 32;
        float lg1 = 0.f, lg2 = 0.f;
#pragma unroll
        for (int d = 0; d < 64; d++) {
            float qv = q_s[il * 65 + d];
            lg1 += qv * ah_s[a1 * 65 + d];
            lg2 += qv * ah_s[a2 * 65 + d];
        }
        lg1 += g_NB1[(h * AG + a1) * NTOK + i]
             + hab[(h * HW + oh) * AG + a1] + wab[(h * HW + ow) * AG + a1];
        if (a2 < AG)
            lg2 += g_NB1[(h * AG + a2) * NTOK + i]
                 + hab[(h * HW + oh) * AG + a2] + wab[(h * HW + ow) * AG + a2];
        else
            lg2 = -INFINITY;
        float mx = fmaxf(lg1, lg2);
#pragma unroll
        for (int o = 16; o; o >>= 1) mx = fmaxf(mx, __shfl_xor_sync(~0u, mx, o));
        float p1 = __expf(lg1 - mx);
        float p2 = __expf(lg2 - mx);
        float sm = p1 + p2;
#pragma unroll
        for (int o = 16; o; o >>= 1) sm += __shfl_xor_sync(~0u, sm, o);
        float inv = 1.0f / sm;
        __syncwarp();
        p_s[w * 64 + a1] = p1 * inv;
        p_s[w * 64 + a2] = p2 * inv;
        __syncwarp();
        float o1 = 0.f, o2 = 0.f;
#pragma unroll
        for (int a = 0; a < AG; a++) {
            float pv = p_s[w * 64 + a];
            o1 += pv * av_s[a * 65 + l];
            o2 += pv * av_s[a * 65 + l + 32];
        }
        size_t base = ((size_t)(b * NTOK + i)) * CCH + h * HD;
        g_AOUT[base + l] = o1;
        g_AOUT[base + l + 32] = o2;
        __syncwarp();
    }
}

// ---------------- 3x3 depthwise conv on v; fused bf16 split output ---------------
__global__ __launch_bounds__(256) void dwc_kernel(
    const float* __restrict__ dwc_w, const float* __restrict__ dwc_b)
{
    int oh = blockIdx.x, b = blockIdx.y;
    __shared__ float w_s[CCH * 9];
    __shared__ float b_s[CCH];
    int tid = threadIdx.x;
    for (int t = tid; t < CCH * 9; t += 256) w_s[t] = dwc_w[t];
    for (int t = tid; t < CCH; t += 256) b_s[t] = dwc_b[t];
    __syncthreads();
    for (int idx = tid; idx < HW * CCH; idx += 256) {
        int ow = idx >> 9, c = idx & 511;
        float acc = b_s[c];
#pragma unroll
        for (int ky = 0; ky < 3; ky++) {
            int h2 = oh + ky - 1;
            if (h2 < 0 || h2 >= HW) continue;
#pragma unroll
            for (int kx = 0; kx < 3; kx++) {
                int w2 = ow + kx - 1;
                if (w2 < 0 || w2 >= HW) continue;
                acc += g_KV[((size_t)(b * NTOK + h2 * HW + w2)) * (2 * CCH) + CCH + c]
                     * w_s[c * 9 + ky * 3 + kx];
            }
        }
        size_t gi = ((size_t)(b * NTOK + oh * HW + ow)) * CCH + c;
        float v = g_AOUT[gi] + acc;
        __nv_bfloat16 h = __float2bfloat16(v);
        g_ahi[gi] = h;
        g_alo[gi] = __float2bfloat16(v - __bfloat162float(h));
    }
}

// ---------------- launch ---------------------------------------------------------
extern "C" void kernel_launch(void* const* d_in, const int* in_sizes, int n_in,
                              void* d_out, int out_size)
{
    const float* x = (const float*)d_in[0];
    int off = 1;
    if (n_in >= 15 && in_sizes[1] == 1) off = 3;
    const float* q_w    = (const float*)d_in[off + 0];
    const float* kv_w   = (const float*)d_in[off + 1];
    const float* proj_w = (const float*)d_in[off + 2];
    const float* proj_b = (const float*)d_in[off + 3];
    const float* dwc_w  = (const float*)d_in[off + 4];
    const float* dwc_b  = (const float*)d_in[off + 5];
    const float* an_b   = (const float*)d_in[off + 6];
    const float* na_b   = (const float*)d_in[off + 7];
    const float* ah_b   = (const float*)d_in[off + 8];
    const float* aw_b   = (const float*)d_in[off + 9];
    const float* ha_b   = (const float*)d_in[off + 10];
    const float* wa_b   = (const float*)d_in[off + 11];
    float* out = (float*)d_out;

    float *Qp, *KVp;
    __nv_bfloat16 *xhi, *xlo, *ahi, *alo, *wqhi, *wqlo, *wkvhi, *wkvlo, *wphi, *wplo;
    cudaGetSymbolAddress((void**)&Qp, g_Q);
    cudaGetSymbolAddress((void**)&KVp, g_KV);
    cudaGetSymbolAddress((void**)&xhi, g_xhi);
    cudaGetSymbolAddress((void**)&xlo, g_xlo);
    cudaGetSymbolAddress((void**)&ahi, g_ahi);
    cudaGetSymbolAddress((void**)&alo, g_alo);
    cudaGetSymbolAddress((void**)&wqhi, g_wqhi);
    cudaGetSymbolAddress((void**)&wqlo, g_wqlo);
    cudaGetSymbolAddress((void**)&wkvhi, g_wkvhi);
    cudaGetSymbolAddress((void**)&wkvlo, g_wkvlo);
    cudaGetSymbolAddress((void**)&wphi, g_wphi);
    cudaGetSymbolAddress((void**)&wplo, g_wplo);

    static int smem_set = 0;
    if (!smem_set) {
        cudaFuncSetAttribute(gemm_tc, cudaFuncAttributeMaxDynamicSharedMemorySize, NST * STG_BYTES);
        smem_set = 1;
    }

    cvt_split<<<4096, 256>>>(x, xhi, xlo, MROWS * CCH / 4);
    cvt_split<<<256, 256>>>(q_w, wqhi, wqlo, CCH * CCH / 4);
    cvt_split<<<512, 256>>>(kv_w, wkvhi, wkvlo, 2 * CCH * CCH / 4);
    cvt_split<<<256, 256>>>(proj_w, wphi, wplo, CCH * CCH / 4);

    gemm_tc<<<dim3(8, MROWS / 128), 256, NST * STG_BYTES>>>(xhi, xlo, wqhi, wqlo, Qp, nullptr, 512);
    gemm_tc<<<dim3(16, MROWS / 128), 256, NST * STG_BYTES>>>(xhi, xlo, wkvhi, wkvlo, KVp, nullptr, 1024);

    pool_kernel<<<NB * AG, 256>>>();
    bias_resize_kernel<<<dim3(AG, HEADS, 2), 256>>>(an_b, na_b);
    agent_logits_kernel<<<dim3(NTOK / 64, NB * HEADS), 256>>>(ah_b, aw_b);
    softmax_n_kernel<<<NB * HEADS * AG, 256>>>();
    agent_v_split_kernel<<<dim3(NB * HEADS, 7), 256>>>();
    avp_reduce_kernel<<<(NB * HEADS * AG * HD + 255) / 256, 256>>>();
    qside_kernel<<<dim3(NTOK / 32, NB * HEADS), 256>>>(ha_b, wa_b);
    dwc_kernel<<<dim3(HW, NB), 256>>>(dwc_w, dwc_b);

    gemm_tc<<<dim3(8, MROWS / 128), 256, NST * STG_BYTES>>>(ahi, alo, wphi, wplo, out, proj_b, 512);
}

// round 8
// speedup vs baseline: 2.1699x; 1.1335x over previous
#include <cuda_runtime.h>
#include <cuda_fp16.h>
#include <math.h>
#include <stdint.h>

#define HEADS 8
#define HD 64
#define CCH 512
#define HW 56
#define NTOK 3136
#define AG 49
#define NB 16
#define MROWS (NB*NTOK)
#define KDIM 512

// ---------------- scratch (static device globals; no allocations) ----------------
__device__ float g_Q[(size_t)MROWS * CCH];
__device__ float g_KV[(size_t)MROWS * 2 * CCH];
__device__ float g_AT[NB * AG * CCH];
__device__ float g_PB1[HEADS * AG * NTOK];
__device__ float g_NB1[HEADS * AG * NTOK];
__device__ float g_LOG[(size_t)NB * HEADS * AG * NTOK];
__device__ float g_AV[NB * HEADS * AG * HD];
__device__ float g_AVP[7 * NB * HEADS * AG * HD];
__device__ float g_AOUT[(size_t)MROWS * CCH];
// fp16 operand buffers
__device__ __half g_xhi[(size_t)MROWS * CCH];
__device__ __half g_xlo[(size_t)MROWS * CCH];
__device__ __half g_ahi[(size_t)MROWS * CCH];
__device__ __half g_alo[(size_t)MROWS * CCH];
__device__ __half g_wq16[CCH * CCH];
__device__ __half g_wkv16[2 * CCH * CCH];
__device__ __half g_wp16[CCH * CCH];

// ================= low-level helpers =================
__device__ __forceinline__ uint32_t smem_u32(const void* p) {
    uint32_t a;
    asm("{ .reg .u64 t; cvta.to.shared.u64 t, %1; cvt.u32.u64 %0, t; }" : "=r"(a) : "l"(p));
    return a;
}
__device__ __forceinline__ void cpa16(uint32_t s, const void* g) {
    asm volatile("cp.async.cg.shared.global [%0], [%1], 16;" :: "r"(s), "l"(g));
}
#define CP_COMMIT() asm volatile("cp.async.commit_group;" ::: "memory")

#define LDSM_X4(r0, r1, r2, r3, a) \
    asm volatile("ldmatrix.sync.aligned.m8n8.x4.shared.b16 {%0,%1,%2,%3}, [%4];" \
                 : "=r"(r0), "=r"(r1), "=r"(r2), "=r"(r3) : "r"(a))

#define MMA16816(d, a, b) \
    asm volatile("mma.sync.aligned.m16n8k16.row.col.f32.f16.f16.f32 " \
                 "{%0,%1,%2,%3}, {%4,%5,%6,%7}, {%8,%9}, {%0,%1,%2,%3};" \
                 : "+f"((d)[0]), "+f"((d)[1]), "+f"((d)[2]), "+f"((d)[3]) \
                 : "r"((a)[0]), "r"((a)[1]), "r"((a)[2]), "r"((a)[3]), \
                   "r"((b)[0]), "r"((b)[1]))

// smem chunk swizzle: row r, 16B-chunk c (0-3) within 64B row
#define SWZC(r, c) ((c) ^ (((r) >> 1) & 3))

// stage layout: [Ahi 8KB][Alo 8KB][B 4KB]
#define STG_BYTES 20480
#define NST 3

// ================= 2-term fp16 tensor-core GEMM (mma.sync, 2 CTAs/SM) ===========
// C[m, n] = sum_k (Ahi+Alo)[m,k]*B[n,k] (+bias[n])
// CTA tile 128(M) x 64(N); 8 warps of 32x32; grid (Nout/64, M/128).
__global__ void __launch_bounds__(256, 2) gemm_tc(
    const __half* __restrict__ Ahi, const __half* __restrict__ Alo,
    const __half* __restrict__ B16,
    float* __restrict__ C, const float* __restrict__ bias, int Nout)
{
    extern __shared__ __align__(1024) char smem[];
    int tid = threadIdx.x;
    int wid = tid >> 5, lane = tid & 31;
    int bn0 = blockIdx.x * 64, m0 = blockIdx.y * 128;
    int wr = wid >> 1, wc = wid & 1;        // warp tile: rows wr*32, cols wc*32
    uint32_t sbase = smem_u32(smem);

    float acc[2][4][4] = {};

    // loader coords
    int rA0 = tid >> 2,         cA0 = tid & 3;
    int rA1 = (tid + 256) >> 2, cA1 = tid & 3;
    int rB  = tid >> 2,         cB  = tid & 3;
    uint32_t soA0 = rA0 * 64 + (SWZC(rA0, cA0) << 4);
    uint32_t soA1 = rA1 * 64 + (SWZC(rA1, cA1) << 4);
    uint32_t soB  = rB * 64 + (SWZC(rB, cB) << 4);

    // prologue: issue chunks 0 and 1
#pragma unroll
    for (int pc = 0; pc < 2; pc++) {
        int k0 = pc * 32;
        uint32_t sb = sbase + pc * STG_BYTES;
        cpa16(sb + soA0,         Ahi + (size_t)(m0 + rA0) * KDIM + k0 + cA0 * 8);
        cpa16(sb + soA1,         Ahi + (size_t)(m0 + rA1) * KDIM + k0 + cA1 * 8);
        cpa16(sb + 8192 + soA0,  Alo + (size_t)(m0 + rA0) * KDIM + k0 + cA0 * 8);
        cpa16(sb + 8192 + soA1,  Alo + (size_t)(m0 + rA1) * KDIM + k0 + cA1 * 8);
        cpa16(sb + 16384 + soB,  B16 + (size_t)(bn0 + rB) * KDIM + k0 + cB * 8);
        CP_COMMIT();
    }

    int g = lane >> 3, lr = lane & 7;

    for (int ch = 0; ch < 16; ch++) {
        __syncthreads();
        if (ch + 2 < 16) {
            int k0 = (ch + 2) * 32;
            uint32_t nb = sbase + ((ch + 2) % NST) * STG_BYTES;
            cpa16(nb + soA0,        Ahi + (size_t)(m0 + rA0) * KDIM + k0 + cA0 * 8);
            cpa16(nb + soA1,        Ahi + (size_t)(m0 + rA1) * KDIM + k0 + cA1 * 8);
            cpa16(nb + 8192 + soA0, Alo + (size_t)(m0 + rA0) * KDIM + k0 + cA0 * 8);
            cpa16(nb + 8192 + soA1, Alo + (size_t)(m0 + rA1) * KDIM + k0 + cA1 * 8);
            cpa16(nb + 16384 + soB, B16 + (size_t)(bn0 + rB) * KDIM + k0 + cB * 8);
            CP_COMMIT();
        }
        if (ch <= 13)      asm volatile("cp.async.wait_group 2;" ::: "memory");
        else if (ch == 14) asm volatile("cp.async.wait_group 1;" ::: "memory");
        else               asm volatile("cp.async.wait_group 0;" ::: "memory");
        __syncthreads();

        uint32_t base = sbase + (ch % NST) * STG_BYTES;

#pragma unroll
        for (int ks = 0; ks < 2; ks++) {
            uint32_t af[2][4], al[2][4], bf[4][2];
#pragma unroll
            for (int mt = 0; mt < 2; mt++) {
                int row = wr * 32 + mt * 16 + ((g & 1) << 3) + lr;
                int c = ks * 2 + (g >> 1);
                uint32_t off = row * 64 + (SWZC(row, c) << 4);
                LDSM_X4(af[mt][0], af[mt][1], af[mt][2], af[mt][3], base + off);
                LDSM_X4(al[mt][0], al[mt][1], al[mt][2], al[mt][3], base + 8192 + off);
            }
#pragma unroll
            for (int np = 0; np < 2; np++) {
                int row = wc * 32 + np * 16 + ((g >> 1) << 3) + lr;
                int c = ks * 2 + (g & 1);
                uint32_t off = row * 64 + (SWZC(row, c) << 4);
                uint32_t r0, r1, r2, r3;
                LDSM_X4(r0, r1, r2, r3, base + 16384 + off);
                bf[np * 2][0] = r0; bf[np * 2][1] = r1;
                bf[np * 2 + 1][0] = r2; bf[np * 2 + 1][1] = r3;
            }
            // term-major: dependency distance to same acc = 8 MMAs
#pragma unroll
            for (int mt = 0; mt < 2; mt++)
#pragma unroll
                for (int nt = 0; nt < 4; nt++)
                    MMA16816(acc[mt][nt], af[mt], bf[nt]);
#pragma unroll
            for (int mt = 0; mt < 2; mt++)
#pragma unroll
                for (int nt = 0; nt < 4; nt++)
                    MMA16816(acc[mt][nt], al[mt], bf[nt]);
        }
    }

    // epilogue
#pragma unroll
    for (int mt = 0; mt < 2; mt++) {
#pragma unroll
        for (int nt = 0; nt < 4; nt++) {
            int gm = m0 + wr * 32 + mt * 16 + (lane >> 2);
            int gn = bn0 + wc * 32 + nt * 8 + ((lane & 3) << 1);
            float2 v0 = make_float2(acc[mt][nt][0], acc[mt][nt][1]);
            float2 v1 = make_float2(acc[mt][nt][2], acc[mt][nt][3]);
            if (bias) {
                float b0 = bias[gn], b1 = bias[gn + 1];
                v0.x += b0; v0.y += b1; v1.x += b0; v1.y += b1;
            }
            *(float2*)(C + (size_t)gm * Nout + gn) = v0;
            *(float2*)(C + (size_t)(gm + 8) * Nout + gn) = v1;
        }
    }
}

// ---------------- fp32 -> (fp16 hi, fp16 lo) split conversion --------------------
__global__ __launch_bounds__(256) void cvt_split(
    const float* __restrict__ src, __half* __restrict__ hi,
    __half* __restrict__ lo, int n4)
{
    for (int i = blockIdx.x * 256 + threadIdx.x; i < n4; i += gridDim.x * 256) {
        float4 v = ((const float4*)src)[i];
        __half h0 = __float2half_rn(v.x);
        __half h1 = __float2half_rn(v.y);
        __half h2 = __float2half_rn(v.z);
        __half h3 = __float2half_rn(v.w);
        __half l0 = __float2half_rn(v.x - __half2float(h0));
        __half l1 = __float2half_rn(v.y - __half2float(h1));
        __half l2 = __float2half_rn(v.z - __half2float(h2));
        __half l3 = __float2half_rn(v.w - __half2float(h3));
        ((__half2*)hi)[2 * i]     = __halves2half2(h0, h1);
        ((__half2*)hi)[2 * i + 1] = __halves2half2(h2, h3);
        ((__half2*)lo)[2 * i]     = __halves2half2(l0, l1);
        ((__half2*)lo)[2 * i + 1] = __halves2half2(l2, l3);
    }
}

// ---------------- fp32 -> single fp16 (weights) ----------------------------------
__global__ __launch_bounds__(256) void cvt_w16(
    const float* __restrict__ src, __half* __restrict__ dst, int n4)
{
    for (int i = blockIdx.x * 256 + threadIdx.x; i < n4; i += gridDim.x * 256) {
        float4 v = ((const float4*)src)[i];
        ((__half2*)dst)[2 * i]     = __halves2half2(__float2half_rn(v.x), __float2half_rn(v.y));
        ((__half2*)dst)[2 * i + 1] = __halves2half2(__float2half_rn(v.z), __float2half_rn(v.w));
    }
}

// ---------------- agent token pooling -------------------------------------------
__global__ __launch_bounds__(256) void pool_kernel()
{
    int blk = blockIdx.x;
    int b = blk / AG, a = blk % AG;
    int p1 = a / 7, p2 = a % 7;
    for (int c = threadIdx.x; c < CCH; c += 256) {
        float s = 0.f;
#pragma unroll
        for (int r = 0; r < 8; r++)
#pragma unroll
            for (int ss = 0; ss < 8; ss++)
                s += g_Q[((size_t)(b * NTOK + (p1 * 8 + r) * HW + p2 * 8 + ss)) * CCH + c];
        g_AT[(b * AG + a) * CCH + c] = s * (1.0f / 64.0f);
    }
}

// ---------------- jax bilinear resize -------------------------------------------
__device__ __forceinline__ void lin_w(int o, int& i0, int& i1, float& w0, float& w1)
{
    float p = (o + 0.5f) * 0.125f - 0.5f;
    float fp = floorf(p);
    int i = (int)fp;
    float f = p - fp;
    if (i < 0)       { i0 = 0; i1 = 0; w0 = 1.f; w1 = 0.f; }
    else if (i >= 6) { i0 = 6; i1 = 6; w0 = 1.f; w1 = 0.f; }
    else             { i0 = i; i1 = i + 1; w0 = 1.f - f; w1 = f; }
}

__global__ __launch_bounds__(256) void bias_resize_kernel(
    const float* __restrict__ an, const float* __restrict__ na)
{
    int a = blockIdx.x, h = blockIdx.y, src = blockIdx.z;
    const float* S = (src == 0 ? an : na) + (h * AG + a) * 49;
    float* D = (src == 0 ? g_PB1 : g_NB1) + (size_t)(h * AG + a) * NTOK;
    __shared__ float s[49];
    if (threadIdx.x < 49) s[threadIdx.x] = S[threadIdx.x];
    __syncthreads();
    for (int o = threadIdx.x; o < NTOK; o += 256) {
        int oh = o / HW, ow = o % HW;
        int r0, r1, c0, c1; float wr0, wr1, wc0, wc1;
        lin_w(oh, r0, r1, wr0, wr1);
        lin_w(ow, c0, c1, wc0, wc1);
        D[o] = wr0 * (wc0 * s[r0 * 7 + c0] + wc1 * s[r0 * 7 + c1]) +
               wr1 * (wc0 * s[r1 * 7 + c0] + wc1 * s[r1 * 7 + c1]);
    }
}

// ---------------- agent logits ---------------------------------------------------
__global__ __launch_bounds__(256) void agent_logits_kernel(
    const float* __restrict__ ahb, const float* __restrict__ awb)
{
    int bh = blockIdx.y;
    int b = bh >> 3, h = bh & 7;
    int i0 = blockIdx.x * 64;
    __shared__ float ahT[64 * 65];
    __shared__ float ksT[64 * 65];
    int tid = threadIdx.x;
    for (int t = tid; t < 64 * 64; t += 256) {
        int a = t >> 6, d = t & 63;
        ahT[d * 65 + a] = (a < AG) ? g_AT[(b * AG + a) * CCH + h * HD + d] * 0.125f : 0.f;
    }
    for (int t = tid; t < 64 * 64; t += 256) {
        int il = t >> 6, d = t & 63;
        ksT[d * 65 + il] = g_KV[((size_t)(b * NTOK + i0 + il)) * (2 * CCH) + h * HD + d];
    }
    __syncthreads();
    int tx = tid & 15, ty = tid >> 4;
    float acc[4][4] = {};
#pragma unroll
    for (int d = 0; d < 64; d++) {
        float af[4], bf[4];
#pragma unroll
        for (int r = 0; r < 4; r++) af[r] = ahT[d * 65 + ty * 4 + r];
#pragma unroll
        for (int c = 0; c < 4; c++) bf[c] = ksT[d * 65 + tx * 4 + c];
#pragma unroll
        for (int r = 0; r < 4; r++)
#pragma unroll
            for (int c = 0; c < 4; c++)
                acc[r][c] += af[r] * bf[c];
    }
#pragma unroll
    for (int r = 0; r < 4; r++) {
        int a = ty * 4 + r;
        if (a >= AG) continue;
#pragma unroll
        for (int c = 0; c < 4; c++) {
            int i = i0 + tx * 4 + c;
            int oh = i / HW, ow = i % HW;
            float lg = acc[r][c] + g_PB1[(h * AG + a) * NTOK + i]
                     + ahb[(h * AG + a) * HW + oh] + awb[(h * AG + a) * HW + ow];
            g_LOG[((size_t)(bh * AG + a)) * NTOK + i] = lg;
        }
    }
}

// ---------------- row softmax over n=3136 ----------------------------------------
__global__ __launch_bounds__(256) void softmax_n_kernel()
{
    size_t row = blockIdx.x;
    float* p = g_LOG + row * NTOK;
    __shared__ float buf[NTOK];
    __shared__ float red[8];
    int tid = threadIdx.x;
    float m = -1e30f;
    for (int i = tid; i < NTOK; i += 256) { float v = p[i]; buf[i] = v; m = fmaxf(m, v); }
#pragma unroll
    for (int o = 16; o; o >>= 1) m = fmaxf(m, __shfl_xor_sync(~0u, m, o));
    if ((tid & 31) == 0) red[tid >> 5] = m;
    __syncthreads();
    m = fmaxf(fmaxf(fmaxf(red[0], red[1]), fmaxf(red[2], red[3])),
              fmaxf(fmaxf(red[4], red[5]), fmaxf(red[6], red[7])));
    __syncthreads();
    float s = 0.f;
    for (int i = tid; i < NTOK; i += 256) { float e = __expf(buf[i] - m); buf[i] = e; s += e; }
#pragma unroll
    for (int o = 16; o; o >>= 1) s += __shfl_xor_sync(~0u, s, o);
    if ((tid & 31) == 0) red[tid >> 5] = s;
    __syncthreads();
    s = red[0] + red[1] + red[2] + red[3] + red[4] + red[5] + red[6] + red[7];
    float inv = 1.0f / s;
    for (int i = tid; i < NTOK; i += 256) p[i] = buf[i] * inv;
}

// ---------------- agent_v split over K + deterministic reduce --------------------
__global__ __launch_bounds__(256) void agent_v_split_kernel()
{
    int bh = blockIdx.x;
    int sp = blockIdx.y;
    int b = bh >> 3, h = bh & 7;
    __shared__ float at_s[32 * 65];
    __shared__ float vt_s[32 * 65];
    int tid = threadIdx.x, tx = tid & 15, ty = tid >> 4;
    float acc[4][4] = {};
    int kbeg = sp * 448, kend = kbeg + 448;
    for (int k0 = kbeg; k0 < kend; k0 += 32) {
        for (int t = tid; t < 64 * 32; t += 256) {
            int a = t >> 5, kk = t & 31;
            at_s[kk * 65 + a] = (a < AG) ? g_LOG[((size_t)(bh * AG + a)) * NTOK + k0 + kk] : 0.f;
        }
        for (int t = tid; t < 32 * 64; t += 256) {
            int kk = t >> 6, d = t & 63;
            vt_s[kk * 65 + d] = g_KV[((size_t)(b * NTOK + k0 + kk)) * (2 * CCH) + CCH + h * HD + d];
        }
        __syncthreads();
#pragma unroll
        for (int kk = 0; kk < 32; kk++) {
            float af[4], bf[4];
#pragma unroll
            for (int r = 0; r < 4; r++) af[r] = at_s[kk * 65 + ty * 4 + r];
#pragma unroll
            for (int c = 0; c < 4; c++) bf[c] = vt_s[kk * 65 + tx * 4 + c];
#pragma unroll
            for (int r = 0; r < 4; r++)
#pragma unroll
                for (int c = 0; c < 4; c++)
                    acc[r][c] += af[r] * bf[c];
        }
        __syncthreads();
    }
#pragma unroll
    for (int r = 0; r < 4; r++) {
        int a = ty * 4 + r;
        if (a >= AG) continue;
#pragma unroll
        for (int c = 0; c < 4; c++)
            g_AVP[((size_t)sp * NB * HEADS + bh) * AG * HD + (a * HD + tx * 4 + c)] = acc[r][c];
    }
}

__global__ __launch_bounds__(256) void avp_reduce_kernel()
{
    int i = blockIdx.x * 256 + threadIdx.x;
    const int tot = NB * HEADS * AG * HD;
    if (i < tot) {
        int bh = i / (AG * HD), rest = i % (AG * HD);
        float s = 0.f;
#pragma unroll
        for (int sp = 0; sp < 7; sp++)
            s += g_AVP[((size_t)sp * NB * HEADS + bh) * AG * HD + rest];
        g_AV[i] = s;
    }
}

// ---------------- q-side fused softmax + @agent_v --------------------------------
__global__ __launch_bounds__(256) void qside_kernel(
    const float* __restrict__ hab, const float* __restrict__ wab)
{
    int bh = blockIdx.y;
    int b = bh >> 3, h = bh & 7;
    int i0 = blockIdx.x * 32;
    __shared__ float ah_s[64 * 65];
    __shared__ float av_s[AG * 65];
    __shared__ float q_s[32 * 65];
    __shared__ float p_s[8 * 64];
    int tid = threadIdx.x;
    for (int t = tid; t < 64 * 64; t += 256) {
        int a = t >> 6, d = t & 63;
        ah_s[a * 65 + d] = (a < AG) ? g_AT[(b * AG + a) * CCH + h * HD + d] * 0.125f : 0.f;
    }
    for (int t = tid; t < AG * 64; t += 256) {
        int a = t >> 6, d = t & 63;
        av_s[a * 65 + d] = g_AV[(bh * AG + a) * HD + d];
    }
    for (int t = tid; t < 32 * 64; t += 256) {
        int il = t >> 6, d = t & 63;
        q_s[il * 65 + d] = g_Q[((size_t)(b * NTOK + i0 + il)) * CCH + h * HD + d];
    }
    __syncthreads();
    int w = tid >> 5, l = tid & 31;
    for (int rep = 0; rep < 4; rep++) {
        int il = w * 4 + rep;
        int i = i0 + il;
        int oh = i / HW, ow = i % HW;
        int a1 = l, a2 = l + 32;
        float lg1 = 0.f, lg2 = 0.f;
#pragma unroll
        for (int d = 0; d < 64; d++) {
            float qv = q_s[il * 65 + d];
            lg1 += qv * ah_s[a1 * 65 + d];
            lg2 += qv * ah_s[a2 * 65 + d];
        }
        lg1 += g_NB1[(h * AG + a1) * NTOK + i]
             + hab[(h * HW + oh) * AG + a1] + wab[(h * HW + ow) * AG + a1];
        if (a2 < AG)
            lg2 += g_NB1[(h * AG + a2) * NTOK + i]
                 + hab[(h * HW + oh) * AG + a2] + wab[(h * HW + ow) * AG + a2];
        else
            lg2 = -INFINITY;
        float mx = fmaxf(lg1, lg2);
#pragma unroll
        for (int o = 16; o; o >>= 1) mx = fmaxf(mx, __shfl_xor_sync(~0u, mx, o));
        float p1 = __expf(lg1 - mx);
        float p2 = __expf(lg2 - mx);
        float sm = p1 + p2;
#pragma unroll
        for (int o = 16; o; o >>= 1) sm += __shfl_xor_sync(~0u, sm, o);
        float inv = 1.0f / sm;
        __syncwarp();
        p_s[w * 64 + a1] = p1 * inv;
        p_s[w * 64 + a2] = p2 * inv;
        __syncwarp();
        float o1 = 0.f, o2 = 0.f;
#pragma unroll
        for (int a = 0; a < AG; a++) {
            float pv = p_s[w * 64 + a];
            o1 += pv * av_s[a * 65 + l];
            o2 += pv * av_s[a * 65 + l + 32];
        }
        size_t base = ((size_t)(b * NTOK + i)) * CCH + h * HD;
        g_AOUT[base + l] = o1;
        g_AOUT[base + l + 32] = o2;
        __syncwarp();
    }
}

// ---------------- 3x3 depthwise conv on v; fused fp16 split output ---------------
__global__ __launch_bounds__(256) void dwc_kernel(
    const float* __restrict__ dwc_w, const float* __restrict__ dwc_b)
{
    int oh = blockIdx.x, b = blockIdx.y;
    __shared__ float w_s[CCH * 9];
    __shared__ float b_s[CCH];
    int tid = threadIdx.x;
    for (int t = tid; t < CCH * 9; t += 256) w_s[t] = dwc_w[t];
    for (int t = tid; t < CCH; t += 256) b_s[t] = dwc_b[t];
    __syncthreads();
    for (int idx = tid; idx < HW * CCH; idx += 256) {
        int ow = idx >> 9, c = idx & 511;
        float acc = b_s[c];
#pragma unroll
        for (int ky = 0; ky < 3; ky++) {
            int h2 = oh + ky - 1;
            if (h2 < 0 || h2 >= HW) continue;
#pragma unroll
            for (int kx = 0; kx < 3; kx++) {
                int w2 = ow + kx - 1;
                if (w2 < 0 || w2 >= HW) continue;
                acc += g_KV[((size_t)(b * NTOK + h2 * HW + w2)) * (2 * CCH) + CCH + c]
                     * w_s[c * 9 + ky * 3 + kx];
            }
        }
        size_t gi = ((size_t)(b * NTOK + oh * HW + ow)) * CCH + c;
        float v = g_AOUT[gi] + acc;
        __half h = __float2half_rn(v);
        g_ahi[gi] = h;
        g_alo[gi] = __float2half_rn(v - __half2float(h));
    }
}

// ---------------- launch ---------------------------------------------------------
extern "C" void kernel_launch(void* const* d_in, const int* in_sizes, int n_in,
                              void* d_out, int out_size)
{
    const float* x = (const float*)d_in[0];
    int off = 1;
    if (n_in >= 15 && in_sizes[1] == 1) off = 3;
    const float* q_w    = (const float*)d_in[off + 0];
    const float* kv_w   = (const float*)d_in[off + 1];
    const float* proj_w = (const float*)d_in[off + 2];
    const float* proj_b = (const float*)d_in[off + 3];
    const float* dwc_w  = (const float*)d_in[off + 4];
    const float* dwc_b  = (const float*)d_in[off + 5];
    const float* an_b   = (const float*)d_in[off + 6];
    const float* na_b   = (const float*)d_in[off + 7];
    const float* ah_b   = (const float*)d_in[off + 8];
    const float* aw_b   = (const float*)d_in[off + 9];
    const float* ha_b   = (const float*)d_in[off + 10];
    const float* wa_b   = (const float*)d_in[off + 11];
    float* out = (float*)d_out;

    float *Qp, *KVp;
    __half *xhi, *xlo, *ahi, *alo, *wq16, *wkv16, *wp16;
    cudaGetSymbolAddress((void**)&Qp, g_Q);
    cudaGetSymbolAddress((void**)&KVp, g_KV);
    cudaGetSymbolAddress((void**)&xhi, g_xhi);
    cudaGetSymbolAddress((void**)&xlo, g_xlo);
    cudaGetSymbolAddress((void**)&ahi, g_ahi);
    cudaGetSymbolAddress((void**)&alo, g_alo);
    cudaGetSymbolAddress((void**)&wq16, g_wq16);
    cudaGetSymbolAddress((void**)&wkv16, g_wkv16);
    cudaGetSymbolAddress((void**)&wp16, g_wp16);

    static int smem_set = 0;
    if (!smem_set) {
        cudaFuncSetAttribute(gemm_tc, cudaFuncAttributeMaxDynamicSharedMemorySize, NST * STG_BYTES);
        smem_set = 1;
    }

    cvt_split<<<4096, 256>>>(x, xhi, xlo, MROWS * CCH / 4);
    cvt_w16<<<256, 256>>>(q_w, wq16, CCH * CCH / 4);
    cvt_w16<<<512, 256>>>(kv_w, wkv16, 2 * CCH * CCH / 4);
    cvt_w16<<<256, 256>>>(proj_w, wp16, CCH * CCH / 4);

    gemm_tc<<<dim3(8, MROWS / 128), 256, NST * STG_BYTES>>>(xhi, xlo, wq16, Qp, nullptr, 512);
    gemm_tc<<<dim3(16, MROWS / 128), 256, NST * STG_BYTES>>>(xhi, xlo, wkv16, KVp, nullptr, 1024);

    pool_kernel<<<NB * AG, 256>>>();
    bias_resize_kernel<<<dim3(AG, HEADS, 2), 256>>>(an_b, na_b);
    agent_logits_kernel<<<dim3(NTOK / 64, NB * HEADS), 256>>>(ah_b, aw_b);
    softmax_n_kernel<<<NB * HEADS * AG, 256>>>();
    agent_v_split_kernel<<<dim3(NB * HEADS, 7), 256>>>();
    avp_reduce_kernel<<<(NB * HEADS * AG * HD + 255) / 256, 256>>>();
    qside_kernel<<<dim3(NTOK / 32, NB * HEADS), 256>>>(ha_b, wa_b);
    dwc_kernel<<<dim3(HW, NB), 256>>>(dwc_w, dwc_b);

    gemm_tc<<<dim3(8, MROWS / 128), 256, NST * STG_BYTES>>>(ahi, alo, wp16, out, proj_b, 512);
}

// round 9
// speedup vs baseline: 2.4348x; 1.1221x over previous
#include <cuda_runtime.h>
#include <cuda_fp16.h>
#include <math.h>
#include <stdint.h>

#define HEADS 8
#define HD 64
#define CCH 512
#define HW 56
#define NTOK 3136
#define AG 49
#define NB 16
#define MROWS (NB*NTOK)
#define KDIM 512

// ---------------- scratch (static device globals; no allocations) ----------------
__device__ float g_Q[(size_t)MROWS * CCH];
__device__ float g_KV[(size_t)MROWS * 2 * CCH];
__device__ float g_AT[NB * AG * CCH];
__device__ float g_PB1[HEADS * AG * NTOK];
__device__ float g_NB1[HEADS * AG * NTOK];
__device__ float g_LOG[(size_t)NB * HEADS * AG * NTOK];
__device__ float g_AV[NB * HEADS * AG * HD];
__device__ float g_AVP[7 * NB * HEADS * AG * HD];
__device__ float g_AOUT[(size_t)MROWS * CCH];
// fp16 operand buffers
__device__ __half g_x16[(size_t)MROWS * CCH];
__device__ __half g_ahi[(size_t)MROWS * CCH];
__device__ __half g_alo[(size_t)MROWS * CCH];
__device__ __half g_wq16[CCH * CCH];
__device__ __half g_wkv16[2 * CCH * CCH];
__device__ __half g_wp16[CCH * CCH];

// ================= low-level helpers =================
__device__ __forceinline__ uint32_t smem_u32(const void* p) {
    uint32_t a;
    asm("{ .reg .u64 t; cvta.to.shared.u64 t, %1; cvt.u32.u64 %0, t; }" : "=r"(a) : "l"(p));
    return a;
}
__device__ __forceinline__ void cpa16(uint32_t s, const void* g) {
    asm volatile("cp.async.cg.shared.global [%0], [%1], 16;" :: "r"(s), "l"(g));
}
#define CP_COMMIT() asm volatile("cp.async.commit_group;" ::: "memory")

#define LDSM_X4(r0, r1, r2, r3, a) \
    asm volatile("ldmatrix.sync.aligned.m8n8.x4.shared.b16 {%0,%1,%2,%3}, [%4];" \
                 : "=r"(r0), "=r"(r1), "=r"(r2), "=r"(r3) : "r"(a))

#define MMA16816(d, a, b) \
    asm volatile("mma.sync.aligned.m16n8k16.row.col.f32.f16.f16.f32 " \
                 "{%0,%1,%2,%3}, {%4,%5,%6,%7}, {%8,%9}, {%0,%1,%2,%3};" \
                 : "+f"((d)[0]), "+f"((d)[1]), "+f"((d)[2]), "+f"((d)[3]) \
                 : "r"((a)[0]), "r"((a)[1]), "r"((a)[2]), "r"((a)[3]), \
                   "r"((b)[0]), "r"((b)[1]))

// smem chunk swizzle: row r, 16B-chunk c (0-3) within 64B row
#define SWZC(r, c) ((c) ^ (((r) >> 1) & 3))

#define NST 3

// ================= fp16 tensor-core GEMM, NT = #A terms (mma.sync) ==============
// C[m, n] = sum_k (Ahi [+ Alo])[m,k] * B[n,k] (+bias[n])
// CTA tile 128(M) x 64(N); 8 warps of 32x32; grid (Nout/64, M/128).
// stage: [Ahi 8KB][Alo 8KB if NT==2][B 4KB]
template<int NT>
__global__ void __launch_bounds__(256, (NT == 1) ? 3 : 2) gemm_tc(
    const __half* __restrict__ Ahi, const __half* __restrict__ Alo,
    const __half* __restrict__ B16,
    float* __restrict__ C, const float* __restrict__ bias, int Nout)
{
    constexpr uint32_t STG = (NT == 2) ? 20480u : 12288u;
    constexpr uint32_t BOFF = NT * 8192u;
    extern __shared__ __align__(1024) char smem[];
    int tid = threadIdx.x;
    int wid = tid >> 5, lane = tid & 31;
    int bn0 = blockIdx.x * 64, m0 = blockIdx.y * 128;
    int wr = wid >> 1, wc = wid & 1;        // warp tile: rows wr*32, cols wc*32
    uint32_t sbase = smem_u32(smem);

    float acc[2][4][4] = {};

    // loader coords
    int rA0 = tid >> 2,         cA0 = tid & 3;
    int rA1 = (tid + 256) >> 2, cA1 = tid & 3;
    int rB  = tid >> 2,         cB  = tid & 3;
    uint32_t soA0 = rA0 * 64 + (SWZC(rA0, cA0) << 4);
    uint32_t soA1 = rA1 * 64 + (SWZC(rA1, cA1) << 4);
    uint32_t soB  = rB * 64 + (SWZC(rB, cB) << 4);

    // prologue: issue chunks 0 and 1
#pragma unroll
    for (int pc = 0; pc < 2; pc++) {
        int k0 = pc * 32;
        uint32_t sb = sbase + pc * STG;
        cpa16(sb + soA0, Ahi + (size_t)(m0 + rA0) * KDIM + k0 + cA0 * 8);
        cpa16(sb + soA1, Ahi + (size_t)(m0 + rA1) * KDIM + k0 + cA1 * 8);
        if (NT == 2) {
            cpa16(sb + 8192 + soA0, Alo + (size_t)(m0 + rA0) * KDIM + k0 + cA0 * 8);
            cpa16(sb + 8192 + soA1, Alo + (size_t)(m0 + rA1) * KDIM + k0 + cA1 * 8);
        }
        cpa16(sb + BOFF + soB, B16 + (size_t)(bn0 + rB) * KDIM + k0 + cB * 8);
        CP_COMMIT();
    }

    int g = lane >> 3, lr = lane & 7;

    for (int ch = 0; ch < 16; ch++) {
        __syncthreads();
        if (ch + 2 < 16) {
            int k0 = (ch + 2) * 32;
            uint32_t nb = sbase + ((ch + 2) % NST) * STG;
            cpa16(nb + soA0, Ahi + (size_t)(m0 + rA0) * KDIM + k0 + cA0 * 8);
            cpa16(nb + soA1, Ahi + (size_t)(m0 + rA1) * KDIM + k0 + cA1 * 8);
            if (NT == 2) {
                cpa16(nb + 8192 + soA0, Alo + (size_t)(m0 + rA0) * KDIM + k0 + cA0 * 8);
                cpa16(nb + 8192 + soA1, Alo + (size_t)(m0 + rA1) * KDIM + k0 + cA1 * 8);
            }
            cpa16(nb + BOFF + soB, B16 + (size_t)(bn0 + rB) * KDIM + k0 + cB * 8);
            CP_COMMIT();
        }
        if (ch <= 13)      asm volatile("cp.async.wait_group 2;" ::: "memory");
        else if (ch == 14) asm volatile("cp.async.wait_group 1;" ::: "memory");
        else               asm volatile("cp.async.wait_group 0;" ::: "memory");
        __syncthreads();

        uint32_t base = sbase + (ch % NST) * STG;

#pragma unroll
        for (int ks = 0; ks < 2; ks++) {
            uint32_t af[2][4], al[2][4], bf[4][2];
#pragma unroll
            for (int mt = 0; mt < 2; mt++) {
                int row = wr * 32 + mt * 16 + ((g & 1) << 3) + lr;
                int c = ks * 2 + (g >> 1);
                uint32_t off = row * 64 + (SWZC(row, c) << 4);
                LDSM_X4(af[mt][0], af[mt][1], af[mt][2], af[mt][3], base + off);
                if (NT == 2)
                    LDSM_X4(al[mt][0], al[mt][1], al[mt][2], al[mt][3], base + 8192 + off);
            }
#pragma unroll
            for (int np = 0; np < 2; np++) {
                int row = wc * 32 + np * 16 + ((g >> 1) << 3) + lr;
                int c = ks * 2 + (g & 1);
                uint32_t off = row * 64 + (SWZC(row, c) << 4);
                uint32_t r0, r1, r2, r3;
                LDSM_X4(r0, r1, r2, r3, base + BOFF + off);
                bf[np * 2][0] = r0; bf[np * 2][1] = r1;
                bf[np * 2 + 1][0] = r2; bf[np * 2 + 1][1] = r3;
            }
            // term-major: dependency distance to same acc = 8 MMAs
#pragma unroll
            for (int mt = 0; mt < 2; mt++)
#pragma unroll
                for (int nt = 0; nt < 4; nt++)
                    MMA16816(acc[mt][nt], af[mt], bf[nt]);
            if (NT == 2) {
#pragma unroll
                for (int mt = 0; mt < 2; mt++)
#pragma unroll
                    for (int nt = 0; nt < 4; nt++)
                        MMA16816(acc[mt][nt], al[mt], bf[nt]);
            }
        }
    }

    // epilogue
#pragma unroll
    for (int mt = 0; mt < 2; mt++) {
#pragma unroll
        for (int nt = 0; nt < 4; nt++) {
            int gm = m0 + wr * 32 + mt * 16 + (lane >> 2);
            int gn = bn0 + wc * 32 + nt * 8 + ((lane & 3) << 1);
            float2 v0 = make_float2(acc[mt][nt][0], acc[mt][nt][1]);
            float2 v1 = make_float2(acc[mt][nt][2], acc[mt][nt][3]);
            if (bias) {
                float b0 = bias[gn], b1 = bias[gn + 1];
                v0.x += b0; v0.y += b1; v1.x += b0; v1.y += b1;
            }
            *(float2*)(C + (size_t)gm * Nout + gn) = v0;
            *(float2*)(C + (size_t)(gm + 8) * Nout + gn) = v1;
        }
    }
}

// ---------------- fp32 -> single fp16 --------------------------------------------
__global__ __launch_bounds__(256) void cvt_w16(
    const float* __restrict__ src, __half* __restrict__ dst, int n4)
{
    for (int i = blockIdx.x * 256 + threadIdx.x; i < n4; i += gridDim.x * 256) {
        float4 v = ((const float4*)src)[i];
        ((__half2*)dst)[2 * i]     = __halves2half2(__float2half_rn(v.x), __float2half_rn(v.y));
        ((__half2*)dst)[2 * i + 1] = __halves2half2(__float2half_rn(v.z), __float2half_rn(v.w));
    }
}

// ---------------- agent token pooling -------------------------------------------
__global__ __launch_bounds__(256) void pool_kernel()
{
    int blk = blockIdx.x;
    int b = blk / AG, a = blk % AG;
    int p1 = a / 7, p2 = a % 7;
    for (int c = threadIdx.x; c < CCH; c += 256) {
        float s = 0.f;
#pragma unroll
        for (int r = 0; r < 8; r++)
#pragma unroll
            for (int ss = 0; ss < 8; ss++)
                s += g_Q[((size_t)(b * NTOK + (p1 * 8 + r) * HW + p2 * 8 + ss)) * CCH + c];
        g_AT[(b * AG + a) * CCH + c] = s * (1.0f / 64.0f);
    }
}

// ---------------- jax bilinear resize -------------------------------------------
__device__ __forceinline__ void lin_w(int o, int& i0, int& i1, float& w0, float& w1)
{
    float p = (o + 0.5f) * 0.125f - 0.5f;
    float fp = floorf(p);
    int i = (int)fp;
    float f = p - fp;
    if (i < 0)       { i0 = 0; i1 = 0; w0 = 1.f; w1 = 0.f; }
    else if (i >= 6) { i0 = 6; i1 = 6; w0 = 1.f; w1 = 0.f; }
    else             { i0 = i; i1 = i + 1; w0 = 1.f - f; w1 = f; }
}

__global__ __launch_bounds__(256) void bias_resize_kernel(
    const float* __restrict__ an, const float* __restrict__ na)
{
    int a = blockIdx.x, h = blockIdx.y, src = blockIdx.z;
    const float* S = (src == 0 ? an : na) + (h * AG + a) * 49;
    float* D = (src == 0 ? g_PB1 : g_NB1) + (size_t)(h * AG + a) * NTOK;
    __shared__ float s[49];
    if (threadIdx.x < 49) s[threadIdx.x] = S[threadIdx.x];
    __syncthreads();
    for (int o = threadIdx.x; o < NTOK; o += 256) {
        int oh = o / HW, ow = o % HW;
        int r0, r1, c0, c1; float wr0, wr1, wc0, wc1;
        lin_w(oh, r0, r1, wr0, wr1);
        lin_w(ow, c0, c1, wc0, wc1);
        D[o] = wr0 * (wc0 * s[r0 * 7 + c0] + wc1 * s[r0 * 7 + c1]) +
               wr1 * (wc0 * s[r1 * 7 + c0] + wc1 * s[r1 * 7 + c1]);
    }
}

// ---------------- agent logits ---------------------------------------------------
__global__ __launch_bounds__(256) void agent_logits_kernel(
    const float* __restrict__ ahb, const float* __restrict__ awb)
{
    int bh = blockIdx.y;
    int b = bh >> 3, h = bh & 7;
    int i0 = blockIdx.x * 64;
    __shared__ float ahT[64 * 65];
    __shared__ float ksT[64 * 65];
    int tid = threadIdx.x;
    for (int t = tid; t < 64 * 64; t += 256) {
        int a = t >> 6, d = t & 63;
        ahT[d * 65 + a] = (a < AG) ? g_AT[(b * AG + a) * CCH + h * HD + d] * 0.125f : 0.f;
    }
    for (int t = tid; t < 64 * 64; t += 256) {
        int il = t >> 6, d = t & 63;
        ksT[d * 65 + il] = g_KV[((size_t)(b * NTOK + i0 + il)) * (2 * CCH) + h * HD + d];
    }
    __syncthreads();
    int tx = tid & 15, ty = tid >> 4;
    float acc[4][4] = {};
#pragma unroll
    for (int d = 0; d < 64; d++) {
        float af[4], bf[4];
#pragma unroll
        for (int r = 0; r < 4; r++) af[r] = ahT[d * 65 + ty * 4 + r];
#pragma unroll
        for (int c = 0; c < 4; c++) bf[c] = ksT[d * 65 + tx * 4 + c];
#pragma unroll
        for (int r = 0; r < 4; r++)
#pragma unroll
            for (int c = 0; c < 4; c++)
                acc[r][c] += af[r] * bf[c];
    }
#pragma unroll
    for (int r = 0; r < 4; r++) {
        int a = ty * 4 + r;
        if (a >= AG) continue;
#pragma unroll
        for (int c = 0; c < 4; c++) {
            int i = i0 + tx * 4 + c;
            int oh = i / HW, ow = i % HW;
            float lg = acc[r][c] + g_PB1[(h * AG + a) * NTOK + i]
                     + ahb[(h * AG + a) * HW + oh] + awb[(h * AG + a) * HW + ow];
            g_LOG[((size_t)(bh * AG + a)) * NTOK + i] = lg;
        }
    }
}

// ---------------- row softmax over n=3136 ----------------------------------------
__global__ __launch_bounds__(256) void softmax_n_kernel()
{
    size_t row = blockIdx.x;
    float* p = g_LOG + row * NTOK;
    __shared__ float buf[NTOK];
    __shared__ float red[8];
    int tid = threadIdx.x;
    float m = -1e30f;
    for (int i = tid; i < NTOK; i += 256) { float v = p[i]; buf[i] = v; m = fmaxf(m, v); }
#pragma unroll
    for (int o = 16; o; o >>= 1) m = fmaxf(m, __shfl_xor_sync(~0u, m, o));
    if ((tid & 31) == 0) red[tid >> 5] = m;
    __syncthreads();
    m = fmaxf(fmaxf(fmaxf(red[0], red[1]), fmaxf(red[2], red[3])),
              fmaxf(fmaxf(red[4], red[5]), fmaxf(red[6], red[7])));
    __syncthreads();
    float s = 0.f;
    for (int i = tid; i < NTOK; i += 256) { float e = __expf(buf[i] - m); buf[i] = e; s += e; }
#pragma unroll
    for (int o = 16; o; o >>= 1) s += __shfl_xor_sync(~0u, s, o);
    if ((tid & 31) == 0) red[tid >> 5] = s;
    __syncthreads();
    s = red[0] + red[1] + red[2] + red[3] + red[4] + red[5] + red[6] + red[7];
    float inv = 1.0f / s;
    for (int i = tid; i < NTOK; i += 256) p[i] = buf[i] * inv;
}

// ---------------- agent_v split over K + deterministic reduce --------------------
__global__ __launch_bounds__(256) void agent_v_split_kernel()
{
    int bh = blockIdx.x;
    int sp = blockIdx.y;
    int b = bh >> 3, h = bh & 7;
    __shared__ float at_s[32 * 65];
    __shared__ float vt_s[32 * 65];
    int tid = threadIdx.x, tx = tid & 15, ty = tid >> 4;
    float acc[4][4] = {};
    int kbeg = sp * 448, kend = kbeg + 448;
    for (int k0 = kbeg; k0 < kend; k0 += 32) {
        for (int t = tid; t < 64 * 32; t += 256) {
            int a = t >> 5, kk = t & 31;
            at_s[kk * 65 + a] = (a < AG) ? g_LOG[((size_t)(bh * AG + a)) * NTOK + k0 + kk] : 0.f;
        }
        for (int t = tid; t < 32 * 64; t += 256) {
            int kk = t >> 6, d = t & 63;
            vt_s[kk * 65 + d] = g_KV[((size_t)(b * NTOK + k0 + kk)) * (2 * CCH) + CCH + h * HD + d];
        }
        __syncthreads();
#pragma unroll
        for (int kk = 0; kk < 32; kk++) {
            float af[4], bf[4];
#pragma unroll
            for (int r = 0; r < 4; r++) af[r] = at_s[kk * 65 + ty * 4 + r];
#pragma unroll
            for (int c = 0; c < 4; c++) bf[c] = vt_s[kk * 65 + tx * 4 + c];
#pragma unroll
            for (int r = 0; r < 4; r++)
#pragma unroll
                for (int c = 0; c < 4; c++)
                    acc[r][c] += af[r] * bf[c];
        }
        __syncthreads();
    }
#pragma unroll
    for (int r = 0; r < 4; r++) {
        int a = ty * 4 + r;
        if (a >= AG) continue;
#pragma unroll
        for (int c = 0; c < 4; c++)
            g_AVP[((size_t)sp * NB * HEADS + bh) * AG * HD + (a * HD + tx * 4 + c)] = acc[r][c];
    }
}

__global__ __launch_bounds__(256) void avp_reduce_kernel()
{
    int i = blockIdx.x * 256 + threadIdx.x;
    const int tot = NB * HEADS * AG * HD;
    if (i < tot) {
        int bh = i / (AG * HD), rest = i % (AG * HD);
        float s = 0.f;
#pragma unroll
        for (int sp = 0; sp < 7; sp++)
            s += g_AVP[((size_t)sp * NB * HEADS + bh) * AG * HD + rest];
        g_AV[i] = s;
    }
}

// ---------------- q-side fused softmax + @agent_v --------------------------------
__global__ __launch_bounds__(256) void qside_kernel(
    const float* __restrict__ hab, const float* __restrict__ wab)
{
    int bh = blockIdx.y;
    int b = bh >> 3, h = bh & 7;
    int i0 = blockIdx.x * 32;
    __shared__ float ah_s[64 * 65];
    __shared__ float av_s[AG * 65];
    __shared__ float q_s[32 * 65];
    __shared__ float p_s[8 * 64];
    int tid = threadIdx.x;
    for (int t = tid; t < 64 * 64; t += 256) {
        int a = t >> 6, d = t & 63;
        ah_s[a * 65 + d] = (a < AG) ? g_AT[(b * AG + a) * CCH + h * HD + d] * 0.125f : 0.f;
    }
    for (int t = tid; t < AG * 64; t += 256) {
        int a = t >> 6, d = t & 63;
        av_s[a * 65 + d] = g_AV[(bh * AG + a) * HD + d];
    }
    for (int t = tid; t < 32 * 64; t += 256) {
        int il = t >> 6, d = t & 63;
        q_s[il * 65 + d] = g_Q[((size_t)(b * NTOK + i0 + il)) * CCH + h * HD + d];
    }
    __syncthreads();
    int w = tid >> 5, l = tid & 31;
    for (int rep = 0; rep < 4; rep++) {
        int il = w * 4 + rep;
        int i = i0 + il;
        int oh = i / HW, ow = i % HW;
        int a1 = l, a2 = l + 32;
        float lg1 = 0.f, lg2 = 0.f;
#pragma unroll
        for (int d = 0; d < 64; d++) {
            float qv = q_s[il * 65 + d];
            lg1 += qv * ah_s[a1 * 65 + d];
            lg2 += qv * ah_s[a2 * 65 + d];
        }
        lg1 += g_NB1[(h * AG + a1) * NTOK + i]
             + hab[(h * HW + oh) * AG + a1] + wab[(h * HW + ow) * AG + a1];
        if (a2 < AG)
            lg2 += g_NB1[(h * AG + a2) * NTOK + i]
                 + hab[(h * HW + oh) * AG + a2] + wab[(h * HW + ow) * AG + a2];
        else
            lg2 = -INFINITY;
        float mx = fmaxf(lg1, lg2);
#pragma unroll
        for (int o = 16; o; o >>= 1) mx = fmaxf(mx, __shfl_xor_sync(~0u, mx, o));
        float p1 = __expf(lg1 - mx);
        float p2 = __expf(lg2 - mx);
        float sm = p1 + p2;
#pragma unroll
        for (int o = 16; o; o >>= 1) sm += __shfl_xor_sync(~0u, sm, o);
        float inv = 1.0f / sm;
        __syncwarp();
        p_s[w * 64 + a1] = p1 * inv;
        p_s[w * 64 + a2] = p2 * inv;
        __syncwarp();
        float o1 = 0.f, o2 = 0.f;
#pragma unroll
        for (int a = 0; a < AG; a++) {
            float pv = p_s[w * 64 + a];
            o1 += pv * av_s[a * 65 + l];
            o2 += pv * av_s[a * 65 + l + 32];
        }
        size_t base = ((size_t)(b * NTOK + i)) * CCH + h * HD;
        g_AOUT[base + l] = o1;
        g_AOUT[base + l + 32] = o2;
        __syncwarp();
    }
}

// ---------------- 3x3 depthwise conv on v; fused fp16 split output ---------------
__global__ __launch_bounds__(256) void dwc_kernel(
    const float* __restrict__ dwc_w, const float* __restrict__ dwc_b)
{
    int oh = blockIdx.x, b = blockIdx.y;
    __shared__ float w_s[CCH * 9];
    __shared__ float b_s[CCH];
    int tid = threadIdx.x;
    for (int t = tid; t < CCH * 9; t += 256) w_s[t] = dwc_w[t];
    for (int t = tid; t < CCH; t += 256) b_s[t] = dwc_b[t];
    __syncthreads();
    for (int idx = tid; idx < HW * CCH; idx += 256) {
        int ow = idx >> 9, c = idx & 511;
        float acc = b_s[c];
#pragma unroll
        for (int ky = 0; ky < 3; ky++) {
            int h2 = oh + ky - 1;
            if (h2 < 0 || h2 >= HW) continue;
#pragma unroll
            for (int kx = 0; kx < 3; kx++) {
                int w2 = ow + kx - 1;
                if (w2 < 0 || w2 >= HW) continue;
                acc += g_KV[((size_t)(b * NTOK + h2 * HW + w2)) * (2 * CCH) + CCH + c]
                     * w_s[c * 9 + ky * 3 + kx];
            }
        }
        size_t gi = ((size_t)(b * NTOK + oh * HW + ow)) * CCH + c;
        float v = g_AOUT[gi] + acc;
        __half h = __float2half_rn(v);
        g_ahi[gi] = h;
        g_alo[gi] = __float2half_rn(v - __half2float(h));
    }
}

// ---------------- launch ---------------------------------------------------------
extern "C" void kernel_launch(void* const* d_in, const int* in_sizes, int n_in,
                              void* d_out, int out_size)
{
    const float* x = (const float*)d_in[0];
    int off = 1;
    if (n_in >= 15 && in_sizes[1] == 1) off = 3;
    const float* q_w    = (const float*)d_in[off + 0];
    const float* kv_w   = (const float*)d_in[off + 1];
    const float* proj_w = (const float*)d_in[off + 2];
    const float* proj_b = (const float*)d_in[off + 3];
    const float* dwc_w  = (const float*)d_in[off + 4];
    const float* dwc_b  = (const float*)d_in[off + 5];
    const float* an_b   = (const float*)d_in[off + 6];
    const float* na_b   = (const float*)d_in[off + 7];
    const float* ah_b   = (const float*)d_in[off + 8];
    const float* aw_b   = (const float*)d_in[off + 9];
    const float* ha_b   = (const float*)d_in[off + 10];
    const float* wa_b   = (const float*)d_in[off + 11];
    float* out = (float*)d_out;

    float *Qp, *KVp;
    __half *x16, *ahi, *alo, *wq16, *wkv16, *wp16;
    cudaGetSymbolAddress((void**)&Qp, g_Q);
    cudaGetSymbolAddress((void**)&KVp, g_KV);
    cudaGetSymbolAddress((void**)&x16, g_x16);
    cudaGetSymbolAddress((void**)&ahi, g_ahi);
    cudaGetSymbolAddress((void**)&alo, g_alo);
    cudaGetSymbolAddress((void**)&wq16, g_wq16);
    cudaGetSymbolAddress((void**)&wkv16, g_wkv16);
    cudaGetSymbolAddress((void**)&wp16, g_wp16);

    static int smem_set = 0;
    if (!smem_set) {
        cudaFuncSetAttribute(gemm_tc<1>, cudaFuncAttributeMaxDynamicSharedMemorySize, NST * 12288);
        cudaFuncSetAttribute(gemm_tc<2>, cudaFuncAttributeMaxDynamicSharedMemorySize, NST * 20480);
        smem_set = 1;
    }

    cvt_w16<<<2048, 256>>>(x, x16, MROWS * CCH / 4);
    cvt_w16<<<256, 256>>>(q_w, wq16, CCH * CCH / 4);
    cvt_w16<<<512, 256>>>(kv_w, wkv16, 2 * CCH * CCH / 4);
    cvt_w16<<<256, 256>>>(proj_w, wp16, CCH * CCH / 4);

    gemm_tc<1><<<dim3(8, MROWS / 128), 256, NST * 12288>>>(x16, nullptr, wq16, Qp, nullptr, 512);
    gemm_tc<1><<<dim3(16, MROWS / 128), 256, NST * 12288>>>(x16, nullptr, wkv16, KVp, nullptr, 1024);

    pool_kernel<<<NB * AG, 256>>>();
    bias_resize_kernel<<<dim3(AG, HEADS, 2), 256>>>(an_b, na_b);
    agent_logits_kernel<<<dim3(NTOK / 64, NB * HEADS), 256>>>(ah_b, aw_b);
    softmax_n_kernel<<<NB * HEADS * AG, 256>>>();
    agent_v_split_kernel<<<dim3(NB * HEADS, 7), 256>>>();
    avp_reduce_kernel<<<(NB * HEADS * AG * HD + 255) / 256, 256>>>();
    qside_kernel<<<dim3(NTOK / 32, NB * HEADS), 256>>>(ha_b, wa_b);
    dwc_kernel<<<dim3(HW, NB), 256>>>(dwc_w, dwc_b);

    gemm_tc<2><<<dim3(8, MROWS / 128), 256, NST * 20480>>>(ahi, alo, wp16, out, proj_b, 512);
}

// round 10
// speedup vs baseline: 4.5293x; 1.8603x over previous
#include <cuda_runtime.h>
#include <cuda_fp16.h>
#include <math.h>
#include <stdint.h>

#define HEADS 8
#define HD 64
#define CCH 512
#define HW 56
#define NTOK 3136
#define AG 49
#define NB 16
#define MROWS (NB*NTOK)
#define KDIM 512

// ---------------- scratch (static device globals; zero-initialized) --------------
__device__ float g_PB1[HEADS * AG * NTOK];          // agent-side resized bias [h][a][t]
__device__ float g_NB1T[HEADS * NTOK * 64];         // q-side resized bias [h][t][a pad64]
__device__ float g_LOG[(size_t)NB * HEADS * AG * NTOK];
__device__ float g_AVP[7 * NB * HEADS * AG * HD];
__device__ float g_AOUT[(size_t)MROWS * CCH];
__device__ __half g_x16[(size_t)MROWS * CCH];
__device__ __half g_q16[(size_t)MROWS * CCH];
__device__ __half g_kv16[(size_t)MROWS * 2 * CCH];
__device__ __half g_v16t[(size_t)NB * HEADS * HD * NTOK];    // [b][h][d][t]
__device__ __half g_at16[NB * HEADS * 64 * 64];              // [b][h][a pad64][d], x0.125
__device__ __half g_p16[(size_t)NB * HEADS * 64 * NTOK];     // [bh][a pad64][t], pad rows 0
__device__ __half g_avt16[NB * HEADS * 64 * 64];             // [bh][d][a pad64], pad 0
__device__ __half g_ahi[(size_t)MROWS * CCH];
__device__ __half g_alo[(size_t)MROWS * CCH];
__device__ __half g_wq16[CCH * CCH];
__device__ __half g_wkv16[2 * CCH * CCH];
__device__ __half g_wp16[CCH * CCH];

// ================= low-level helpers =================
__device__ __forceinline__ uint32_t smem_u32(const void* p) {
    uint32_t a;
    asm("{ .reg .u64 t; cvta.to.shared.u64 t, %1; cvt.u32.u64 %0, t; }" : "=r"(a) : "l"(p));
    return a;
}
__device__ __forceinline__ void cpa16(uint32_t s, const void* g) {
    asm volatile("cp.async.cg.shared.global [%0], [%1], 16;" :: "r"(s), "l"(g));
}
#define CP_COMMIT() asm volatile("cp.async.commit_group;" ::: "memory")
#define CP_WAIT0()  asm volatile("cp.async.wait_group 0;" ::: "memory")

#define LDSM_X4(r0, r1, r2, r3, a) \
    asm volatile("ldmatrix.sync.aligned.m8n8.x4.shared.b16 {%0,%1,%2,%3}, [%4];" \
                 : "=r"(r0), "=r"(r1), "=r"(r2), "=r"(r3) : "r"(a))

#define MMA16816(d, a, b) \
    asm volatile("mma.sync.aligned.m16n8k16.row.col.f32.f16.f16.f32 " \
                 "{%0,%1,%2,%3}, {%4,%5,%6,%7}, {%8,%9}, {%0,%1,%2,%3};" \
                 : "+f"((d)[0]), "+f"((d)[1]), "+f"((d)[2]), "+f"((d)[3]) \
                 : "r"((a)[0]), "r"((a)[1]), "r"((a)[2]), "r"((a)[3]), \
                   "r"((b)[0]), "r"((b)[1]))

// 64B-row swizzle (k=32 halves/row) for the big GEMM
#define SWZC(r, c) ((c) ^ (((r) >> 1) & 3))
// 128B-row swizzle (k=64 halves/row, chunk c in 0..7) for attention tiles
#define SW8(r, c) ((c) ^ ((r) & 7))

#define NST 3

// ================= fp16 tensor-core GEMM (projections) ==========================
// MODE 0: fp32 out + bias;  1: fp16 out;  2: fp16 out + V^T fp16 side-copy
template<int NT, int MODE>
__global__ void __launch_bounds__(256, (NT == 1) ? 3 : 2) gemm_tc(
    const __half* __restrict__ Ahi, const __half* __restrict__ Alo,
    const __half* __restrict__ B16,
    float* __restrict__ Cf, const float* __restrict__ bias,
    __half* __restrict__ C16, __half* __restrict__ V16T, int Nout)
{
    constexpr uint32_t STG = (NT == 2) ? 20480u : 12288u;
    constexpr uint32_t BOFF = NT * 8192u;
    extern __shared__ __align__(1024) char smem[];
    int tid = threadIdx.x;
    int wid = tid >> 5, lane = tid & 31;
    int bn0 = blockIdx.x * 64, m0 = blockIdx.y * 128;
    int wr = wid >> 1, wc = wid & 1;
    uint32_t sbase = smem_u32(smem);

    float acc[2][4][4] = {};

    int rA0 = tid >> 2,         cA0 = tid & 3;
    int rA1 = (tid + 256) >> 2, cA1 = tid & 3;
    int rB  = tid >> 2,         cB  = tid & 3;
    uint32_t soA0 = rA0 * 64 + (SWZC(rA0, cA0) << 4);
    uint32_t soA1 = rA1 * 64 + (SWZC(rA1, cA1) << 4);
    uint32_t soB  = rB * 64 + (SWZC(rB, cB) << 4);

#pragma unroll
    for (int pc = 0; pc < 2; pc++) {
        int k0 = pc * 32;
        uint32_t sb = sbase + pc * STG;
        cpa16(sb + soA0, Ahi + (size_t)(m0 + rA0) * KDIM + k0 + cA0 * 8);
        cpa16(sb + soA1, Ahi + (size_t)(m0 + rA1) * KDIM + k0 + cA1 * 8);
        if (NT == 2) {
            cpa16(sb + 8192 + soA0, Alo + (size_t)(m0 + rA0) * KDIM + k0 + cA0 * 8);
            cpa16(sb + 8192 + soA1, Alo + (size_t)(m0 + rA1) * KDIM + k0 + cA1 * 8);
        }
        cpa16(sb + BOFF + soB, B16 + (size_t)(bn0 + rB) * KDIM + k0 + cB * 8);
        CP_COMMIT();
    }

    int g = lane >> 3, lr = lane & 7;

    for (int ch = 0; ch < 16; ch++) {
        __syncthreads();
        if (ch + 2 < 16) {
            int k0 = (ch + 2) * 32;
            uint32_t nb = sbase + ((ch + 2) % NST) * STG;
            cpa16(nb + soA0, Ahi + (size_t)(m0 + rA0) * KDIM + k0 + cA0 * 8);
            cpa16(nb + soA1, Ahi + (size_t)(m0 + rA1) * KDIM + k0 + cA1 * 8);
            if (NT == 2) {
                cpa16(nb + 8192 + soA0, Alo + (size_t)(m0 + rA0) * KDIM + k0 + cA0 * 8);
                cpa16(nb + 8192 + soA1, Alo + (size_t)(m0 + rA1) * KDIM + k0 + cA1 * 8);
            }
            cpa16(nb + BOFF + soB, B16 + (size_t)(bn0 + rB) * KDIM + k0 + cB * 8);
            CP_COMMIT();
        }
        if (ch <= 13)      asm volatile("cp.async.wait_group 2;" ::: "memory");
        else if (ch == 14) asm volatile("cp.async.wait_group 1;" ::: "memory");
        else               asm volatile("cp.async.wait_group 0;" ::: "memory");
        __syncthreads();

        uint32_t base = sbase + (ch % NST) * STG;

#pragma unroll
        for (int ks = 0; ks < 2; ks++) {
            uint32_t af[2][4], al[2][4], bf[4][2];
#pragma unroll
            for (int mt = 0; mt < 2; mt++) {
                int row = wr * 32 + mt * 16 + ((g & 1) << 3) + lr;
                int c = ks * 2 + (g >> 1);
                uint32_t off = row * 64 + (SWZC(row, c) << 4);
                LDSM_X4(af[mt][0], af[mt][1], af[mt][2], af[mt][3], base + off);
                if (NT == 2)
                    LDSM_X4(al[mt][0], al[mt][1], al[mt][2], al[mt][3], base + 8192 + off);
            }
#pragma unroll
            for (int np = 0; np < 2; np++) {
                int row = wc * 32 + np * 16 + ((g >> 1) << 3) + lr;
                int c = ks * 2 + (g & 1);
                uint32_t off = row * 64 + (SWZC(row, c) << 4);
                uint32_t r0, r1, r2, r3;
                LDSM_X4(r0, r1, r2, r3, base + BOFF + off);
                bf[np * 2][0] = r0; bf[np * 2][1] = r1;
                bf[np * 2 + 1][0] = r2; bf[np * 2 + 1][1] = r3;
            }
#pragma unroll
            for (int mt = 0; mt < 2; mt++)
#pragma unroll
                for (int nt = 0; nt < 4; nt++)
                    MMA16816(acc[mt][nt], af[mt], bf[nt]);
            if (NT == 2) {
#pragma unroll
                for (int mt = 0; mt < 2; mt++)
#pragma unroll
                    for (int nt = 0; nt < 4; nt++)
                        MMA16816(acc[mt][nt], al[mt], bf[nt]);
            }
        }
    }

    // epilogue
#pragma unroll
    for (int mt = 0; mt < 2; mt++) {
#pragma unroll
        for (int nt = 0; nt < 4; nt++) {
            int gm0 = m0 + wr * 32 + mt * 16 + (lane >> 2);
            int gn = bn0 + wc * 32 + nt * 8 + ((lane & 3) << 1);
#pragma unroll
            for (int half = 0; half < 2; half++) {
                int gm = gm0 + half * 8;
                float v0 = acc[mt][nt][half * 2], v1 = acc[mt][nt][half * 2 + 1];
                if (MODE == 0) {
                    v0 += bias[gn]; v1 += bias[gn + 1];
                    *(float2*)(Cf + (size_t)gm * Nout + gn) = make_float2(v0, v1);
                } else {
                    __half h0 = __float2half_rn(v0), h1 = __float2half_rn(v1);
                    *(__half2*)(C16 + (size_t)gm * Nout + gn) = __halves2half2(h0, h1);
                    if (MODE == 2 && gn >= 512) {
                        int b = gm / NTOK, n = gm % NTOK;
                        int hh = (gn - 512) >> 6, dd = (gn - 512) & 63;
                        size_t vb = (((size_t)b * 8 + hh) * 64 + dd) * NTOK + n;
                        V16T[vb] = h0;
                        V16T[vb + NTOK] = h1;
                    }
                }
            }
        }
    }
}

// ---------------- fp32 -> fp16 -----------------------------------------------
__global__ __launch_bounds__(256) void cvt_w16(
    const float* __restrict__ src, __half* __restrict__ dst, int n4)
{
    for (int i = blockIdx.x * 256 + threadIdx.x; i < n4; i += gridDim.x * 256) {
        float4 v = ((const float4*)src)[i];
        ((__half2*)dst)[2 * i]     = __halves2half2(__float2half_rn(v.x), __float2half_rn(v.y));
        ((__half2*)dst)[2 * i + 1] = __halves2half2(__float2half_rn(v.z), __float2half_rn(v.w));
    }
}

// ---------------- pooling: q16 -> at16 (x0.125, pad rows zero) -------------------
__global__ __launch_bounds__(256) void pool_kernel()
{
    int b = blockIdx.x, a = blockIdx.y;   // NB x 64
    if (a >= AG) {
        for (int c = threadIdx.x; c < CCH; c += 256)
            g_at16[(((b * 8 + (c >> 6)) * 64) + a) * 64 + (c & 63)] = __float2half(0.f);
        return;
    }
    int p1 = a / 7, p2 = a % 7;
    for (int c = threadIdx.x; c < CCH; c += 256) {
        float s = 0.f;
#pragma unroll
        for (int r = 0; r < 8; r++)
#pragma unroll
            for (int ss = 0; ss < 8; ss++)
                s += __half2float(g_q16[((size_t)(b * NTOK + (p1 * 8 + r) * HW + p2 * 8 + ss)) * CCH + c]);
        g_at16[(((b * 8 + (c >> 6)) * 64) + a) * 64 + (c & 63)] =
            __float2half_rn(s * (1.0f / 64.0f) * 0.125f);
    }
}

// ---------------- jax bilinear resize -------------------------------------------
__device__ __forceinline__ void lin_w(int o, int& i0, int& i1, float& w0, float& w1)
{
    float p = (o + 0.5f) * 0.125f - 0.5f;
    float fp = floorf(p);
    int i = (int)fp;
    float f = p - fp;
    if (i < 0)       { i0 = 0; i1 = 0; w0 = 1.f; w1 = 0.f; }
    else if (i >= 6) { i0 = 6; i1 = 6; w0 = 1.f; w1 = 0.f; }
    else             { i0 = i; i1 = i + 1; w0 = 1.f - f; w1 = f; }
}

__global__ __launch_bounds__(256) void bias_resize_kernel(
    const float* __restrict__ an, const float* __restrict__ na)
{
    int a = blockIdx.x, h = blockIdx.y, src = blockIdx.z;
    const float* S = (src == 0 ? an : na) + (h * AG + a) * 49;
    __shared__ float s[49];
    if (threadIdx.x < 49) s[threadIdx.x] = S[threadIdx.x];
    __syncthreads();
    for (int o = threadIdx.x; o < NTOK; o += 256) {
        int oh = o / HW, ow = o % HW;
        int r0, r1, c0, c1; float wr0, wr1, wc0, wc1;
        lin_w(oh, r0, r1, wr0, wr1);
        lin_w(ow, c0, c1, wc0, wc1);
        float v = wr0 * (wc0 * s[r0 * 7 + c0] + wc1 * s[r0 * 7 + c1]) +
                  wr1 * (wc0 * s[r1 * 7 + c0] + wc1 * s[r1 * 7 + c1]);
        if (src == 0) g_PB1[((size_t)(h * AG + a)) * NTOK + o] = v;
        else          g_NB1T[((size_t)h * NTOK + o) * 64 + a] = v;
    }
}

// ---------------- agent logits via MMA: L[a][t] = AT(x0.125) . K^T + biases ------
__global__ __launch_bounds__(128) void agent_logits_mma(
    const float* __restrict__ ahb, const float* __restrict__ awb)
{
    __shared__ __align__(1024) char sm[16384];   // [AT 8KB][K 8KB]
    int bh = blockIdx.y, b = bh >> 3, h = bh & 7;
    int i0 = blockIdx.x * 64;
    int tid = threadIdx.x, wid = tid >> 5, lane = tid & 31;
    int wr = wid >> 1, wc = wid & 1;
    uint32_t sbase = smem_u32(sm);

    const __half* atp = g_at16 + (size_t)bh * 64 * 64;
    // load tiles (each 64 rows x 128B = 512 chunks; 4/thread)
#pragma unroll
    for (int it = 0; it < 4; it++) {
        int idx = tid + it * 128;
        int r = idx >> 3, c = idx & 7;
        cpa16(sbase + r * 128 + (SW8(r, c) << 4), atp + r * 64 + c * 8);
        cpa16(sbase + 8192 + r * 128 + (SW8(r, c) << 4),
              g_kv16 + (size_t)(b * NTOK + i0 + r) * 1024 + h * 64 + c * 8);
    }
    CP_COMMIT(); CP_WAIT0();
    __syncthreads();

    int g = lane >> 3, lr = lane & 7;
    float acc[2][4][4] = {};
#pragma unroll
    for (int ks = 0; ks < 4; ks++) {
        uint32_t af[2][4], bf[4][2];
#pragma unroll
        for (int mt = 0; mt < 2; mt++) {
            int row = wr * 32 + mt * 16 + ((g & 1) << 3) + lr;
            int c = ks * 2 + (g >> 1);
            LDSM_X4(af[mt][0], af[mt][1], af[mt][2], af[mt][3],
                    sbase + row * 128 + (SW8(row, c) << 4));
        }
#pragma unroll
        for (int np = 0; np < 2; np++) {
            int row = wc * 32 + np * 16 + ((g >> 1) << 3) + lr;
            int c = ks * 2 + (g & 1);
            uint32_t r0, r1, r2, r3;
            LDSM_X4(r0, r1, r2, r3, sbase + 8192 + row * 128 + (SW8(row, c) << 4));
            bf[np * 2][0] = r0; bf[np * 2][1] = r1;
            bf[np * 2 + 1][0] = r2; bf[np * 2 + 1][1] = r3;
        }
#pragma unroll
        for (int mt = 0; mt < 2; mt++)
#pragma unroll
            for (int nt = 0; nt < 4; nt++)
                MMA16816(acc[mt][nt], af[mt], bf[nt]);
    }

#pragma unroll
    for (int mt = 0; mt < 2; mt++)
#pragma unroll
        for (int nt = 0; nt < 4; nt++)
#pragma unroll
            for (int half = 0; half < 2; half++) {
                int a = wr * 32 + mt * 16 + (lane >> 2) + half * 8;
                if (a >= AG) continue;
                int t = i0 + wc * 32 + nt * 8 + ((lane & 3) << 1);
                int oh = t / HW, ow = t % HW;
                int oh1 = (t + 1) / HW, ow1 = (t + 1) % HW;
                size_t lbase = ((size_t)bh * AG + a) * NTOK + t;
                const float* pb = g_PB1 + ((size_t)(h * AG + a)) * NTOK + t;
                float v0 = acc[mt][nt][half * 2] + pb[0]
                         + ahb[(h * AG + a) * HW + oh] + awb[(h * AG + a) * HW + ow];
                float v1 = acc[mt][nt][half * 2 + 1] + pb[1]
                         + ahb[(h * AG + a) * HW + oh1] + awb[(h * AG + a) * HW + ow1];
                *(float2*)(g_LOG + lbase) = make_float2(v0, v1);
            }
}

// ---------------- row softmax, emits fp16 probs ----------------------------------
__global__ __launch_bounds__(256) void softmax_n_kernel()
{
    int row = blockIdx.x;             // 128*49
    int bh = row / AG, a = row % AG;
    const float* p = g_LOG + (size_t)row * NTOK;
    __half* po = g_p16 + ((size_t)bh * 64 + a) * NTOK;
    __shared__ float buf[NTOK];
    __shared__ float red[8];
    int tid = threadIdx.x;
    float m = -1e30f;
    for (int i = tid; i < NTOK; i += 256) { float v = p[i]; buf[i] = v; m = fmaxf(m, v); }
#pragma unroll
    for (int o = 16; o; o >>= 1) m = fmaxf(m, __shfl_xor_sync(~0u, m, o));
    if ((tid & 31) == 0) red[tid >> 5] = m;
    __syncthreads();
    m = fmaxf(fmaxf(fmaxf(red[0], red[1]), fmaxf(red[2], red[3])),
              fmaxf(fmaxf(red[4], red[5]), fmaxf(red[6], red[7])));
    __syncthreads();
    float s = 0.f;
    for (int i = tid; i < NTOK; i += 256) { float e = __expf(buf[i] - m); buf[i] = e; s += e; }
#pragma unroll
    for (int o = 16; o; o >>= 1) s += __shfl_xor_sync(~0u, s, o);
    if ((tid & 31) == 0) red[tid >> 5] = s;
    __syncthreads();
    s = red[0] + red[1] + red[2] + red[3] + red[4] + red[5] + red[6] + red[7];
    float inv = 1.0f / s;
    for (int i = tid; i < NTOK; i += 256) po[i] = __float2half_rn(buf[i] * inv);
}

// ---------------- agent_v via MMA, split-K ---------------------------------------
__global__ __launch_bounds__(128) void agent_v_mma()
{
    __shared__ __align__(1024) char sm[NST * 16384];   // stage: [P 8KB][VT 8KB]
    int bh = blockIdx.x, sp = blockIdx.y;
    int b = bh >> 3, h = bh & 7;
    int kbeg = sp * 448;
    int tid = threadIdx.x, wid = tid >> 5, lane = tid & 31;
    int wr = wid >> 1, wc = wid & 1;
    uint32_t sbase = smem_u32(sm);
    const __half* pp = g_p16 + (size_t)bh * 64 * NTOK + kbeg;
    const __half* vp = g_v16t + ((size_t)b * 8 + h) * 64 * NTOK + kbeg;

    int rl = tid >> 3, cl = tid & 7;   // 128 threads -> 16 rows/iter, 4 iters for 64 rows
    uint32_t sofs = rl * 128 + (SW8(rl, cl) << 4);

#pragma unroll
    for (int pc = 0; pc < 2; pc++) {
        uint32_t sb = sbase + pc * 16384;
#pragma unroll
        for (int it = 0; it < 4; it++) {
            int r = rl + it * 16;
            uint32_t o = (r << 7) + (SW8(r, cl) << 4);
            cpa16(sb + o, pp + (size_t)r * NTOK + pc * 64 + cl * 8);
            cpa16(sb + 8192 + o, vp + (size_t)r * NTOK + pc * 64 + cl * 8);
        }
        CP_COMMIT();
    }

    int g = lane >> 3, lr = lane & 7;
    float acc[2][4][4] = {};
    for (int ch = 0; ch < 7; ch++) {
        __syncthreads();
        if (ch + 2 < 7) {
            uint32_t nb = sbase + ((ch + 2) % NST) * 16384;
#pragma unroll
            for (int it = 0; it < 4; it++) {
                int r = rl + it * 16;
                uint32_t o = (r << 7) + (SW8(r, cl) << 4);
                cpa16(nb + o, pp + (size_t)r * NTOK + (ch + 2) * 64 + cl * 8);
                cpa16(nb + 8192 + o, vp + (size_t)r * NTOK + (ch + 2) * 64 + cl * 8);
            }
            CP_COMMIT();
        }
        if (ch <= 4)      asm volatile("cp.async.wait_group 2;" ::: "memory");
        else if (ch == 5) asm volatile("cp.async.wait_group 1;" ::: "memory");
        else              asm volatile("cp.async.wait_group 0;" ::: "memory");
        __syncthreads();

        uint32_t base = sbase + (ch % NST) * 16384;
#pragma unroll
        for (int ks = 0; ks < 4; ks++) {
            uint32_t af[2][4], bf[4][2];
#pragma unroll
            for (int mt = 0; mt < 2; mt++) {
                int row = wr * 32 + mt * 16 + ((g & 1) << 3) + lr;
                int c = ks * 2 + (g >> 1);
                LDSM_X4(af[mt][0], af[mt][1], af[mt][2], af[mt][3],
                        base + row * 128 + (SW8(row, c) << 4));
            }
#pragma unroll
            for (int np = 0; np < 2; np++) {
                int row = wc * 32 + np * 16 + ((g >> 1) << 3) + lr;
                int c = ks * 2 + (g & 1);
                uint32_t r0, r1, r2, r3;
                LDSM_X4(r0, r1, r2, r3, base + 8192 + row * 128 + (SW8(row, c) << 4));
                bf[np * 2][0] = r0; bf[np * 2][1] = r1;
                bf[np * 2 + 1][0] = r2; bf[np * 2 + 1][1] = r3;
            }
#pragma unroll
            for (int mt = 0; mt < 2; mt++)
#pragma unroll
                for (int nt = 0; nt < 4; nt++)
                    MMA16816(acc[mt][nt], af[mt], bf[nt]);
        }
    }

#pragma unroll
    for (int mt = 0; mt < 2; mt++)
#pragma unroll
        for (int nt = 0; nt < 4; nt++)
#pragma unroll
            for (int half = 0; half < 2; half++) {
                int a = wr * 32 + mt * 16 + (lane >> 2) + half * 8;
                if (a >= AG) continue;
                int d = wc * 32 + nt * 8 + ((lane & 3) << 1);
                size_t o = ((size_t)sp * 128 + bh) * (AG * HD) + a * HD + d;
                *(float2*)(g_AVP + o) =
                    make_float2(acc[mt][nt][half * 2], acc[mt][nt][half * 2 + 1]);
            }
}

// ---------------- reduce partials -> AV^T fp16 -----------------------------------
__global__ __launch_bounds__(256) void avp_reduce_kernel()
{
    int i = blockIdx.x * 256 + threadIdx.x;
    if (i >= 128 * 64 * 64) return;
    int bh = i >> 12, rest = i & 4095, d = rest >> 6, a = rest & 63;
    float s = 0.f;
    if (a < AG) {
#pragma unroll
        for (int sp = 0; sp < 7; sp++)
            s += g_AVP[((size_t)sp * 128 + bh) * (AG * HD) + a * HD + d];
    }
    g_avt16[((size_t)bh * 64 + d) * 64 + a] = __float2half_rn(s);
}

// ---------------- q-side: MMA logits + reg softmax + MMA out ---------------------
__global__ __launch_bounds__(128) void qside_mma(
    const float* __restrict__ hab, const float* __restrict__ wab)
{
    __shared__ __align__(1024) char sm[32768]; // [Q 8K][AT 8K][AVT 8K][P 8K]
    int bh = blockIdx.y, b = bh >> 3, h = bh & 7;
    int i0 = blockIdx.x * 64;
    int tid = threadIdx.x, wid = tid >> 5, lane = tid & 31;
    uint32_t sQ = smem_u32(sm), sAT = sQ + 8192, sAVT = sQ + 16384, sP = sQ + 24576;

    const __half* atp = g_at16 + (size_t)bh * 64 * 64;
    const __half* avtp = g_avt16 + (size_t)bh * 64 * 64;
#pragma unroll
    for (int it = 0; it < 4; it++) {
        int idx = tid + it * 128;
        int r = idx >> 3, c = idx & 7;
        uint32_t o = r * 128 + (SW8(r, c) << 4);
        cpa16(sQ + o, g_q16 + (size_t)(b * NTOK + i0 + r) * 512 + h * 64 + c * 8);
        cpa16(sAT + o, atp + r * 64 + c * 8);
        cpa16(sAVT + o, avtp + r * 64 + c * 8);
    }
    CP_COMMIT(); CP_WAIT0();
    __syncthreads();

    int g = lane >> 3, lr = lane & 7;
    // MMA1: warp wid handles token rows wid*16..+15; cols = 64 agents
    float acc1[8][4] = {};
#pragma unroll
    for (int ks = 0; ks < 4; ks++) {
        uint32_t af[4], bf[8][2];
        {
            int row = wid * 16 + ((g & 1) << 3) + lr;
            int c = ks * 2 + (g >> 1);
            LDSM_X4(af[0], af[1], af[2], af[3], sQ + row * 128 + (SW8(row, c) << 4));
        }
#pragma unroll
        for (int np = 0; np < 4; np++) {
            int row = np * 16 + ((g >> 1) << 3) + lr;
            int c = ks * 2 + (g & 1);
            uint32_t r0, r1, r2, r3;
            LDSM_X4(r0, r1, r2, r3, sAT + row * 128 + (SW8(row, c) << 4));
            bf[np * 2][0] = r0; bf[np * 2][1] = r1;
            bf[np * 2 + 1][0] = r2; bf[np * 2 + 1][1] = r3;
        }
#pragma unroll
        for (int nt = 0; nt < 8; nt++)
            MMA16816(acc1[nt], af, bf[nt]);
    }

    // biases + mask + per-row softmax (rows r1 = wid*16 + lane>>2, r2 = r1+8)
    int r1 = wid * 16 + (lane >> 2), r2 = r1 + 8;
    int t1 = i0 + r1, t2 = i0 + r2;
    int oh1 = t1 / HW, ow1 = t1 % HW, oh2 = t2 / HW, ow2 = t2 % HW;
#pragma unroll
    for (int nt = 0; nt < 8; nt++)
#pragma unroll
        for (int j = 0; j < 4; j++) {
            int a = nt * 8 + ((lane & 3) << 1) + (j & 1);
            if (a < AG) {
                if (j < 2)
                    acc1[nt][j] += g_NB1T[((size_t)h * NTOK + t1) * 64 + a]
                                 + hab[(h * HW + oh1) * AG + a] + wab[(h * HW + ow1) * AG + a];
                else
                    acc1[nt][j] += g_NB1T[((size_t)h * NTOK + t2) * 64 + a]
                                 + hab[(h * HW + oh2) * AG + a] + wab[(h * HW + ow2) * AG + a];
            } else acc1[nt][j] = -INFINITY;
        }
    float m1 = -1e30f, m2 = -1e30f;
#pragma unroll
    for (int nt = 0; nt < 8; nt++) {
        m1 = fmaxf(m1, fmaxf(acc1[nt][0], acc1[nt][1]));
        m2 = fmaxf(m2, fmaxf(acc1[nt][2], acc1[nt][3]));
    }
    m1 = fmaxf(m1, __shfl_xor_sync(~0u, m1, 1)); m1 = fmaxf(m1, __shfl_xor_sync(~0u, m1, 2));
    m2 = fmaxf(m2, __shfl_xor_sync(~0u, m2, 1)); m2 = fmaxf(m2, __shfl_xor_sync(~0u, m2, 2));
    float s1 = 0.f, s2 = 0.f;
#pragma unroll
    for (int nt = 0; nt < 8; nt++) {
        acc1[nt][0] = __expf(acc1[nt][0] - m1); s1 += acc1[nt][0];
        acc1[nt][1] = __expf(acc1[nt][1] - m1); s1 += acc1[nt][1];
        acc1[nt][2] = __expf(acc1[nt][2] - m2); s2 += acc1[nt][2];
        acc1[nt][3] = __expf(acc1[nt][3] - m2); s2 += acc1[nt][3];
    }
    s1 += __shfl_xor_sync(~0u, s1, 1); s1 += __shfl_xor_sync(~0u, s1, 2);
    s2 += __shfl_xor_sync(~0u, s2, 1); s2 += __shfl_xor_sync(~0u, s2, 2);
    float i1 = 1.0f / s1, i2 = 1.0f / s2;

    // store P tile (fp16, swizzled rows = tokens, cols = agents)
#pragma unroll
    for (int nt = 0; nt < 8; nt++) {
        int colb = nt * 8 + ((lane & 3) << 1);
        uint32_t o1 = r1 * 128 + (SW8(r1, nt) << 4) + (colb & 7) * 2;
        uint32_t o2 = r2 * 128 + (SW8(r2, nt) << 4) + (colb & 7) * 2;
        __half2 p1 = __halves2half2(__float2half_rn(acc1[nt][0] * i1),
                                    __float2half_rn(acc1[nt][1] * i1));
        __half2 p2 = __halves2half2(__float2half_rn(acc1[nt][2] * i2),
                                    __float2half_rn(acc1[nt][3] * i2));
        asm volatile("st.shared.b32 [%0], %1;" :: "r"(sP + o1), "r"(*(uint32_t*)&p1));
        asm volatile("st.shared.b32 [%0], %1;" :: "r"(sP + o2), "r"(*(uint32_t*)&p2));
    }
    __syncwarp();

    // MMA2: O[t][d] = P . AVT^T
    float acc2[8][4] = {};
#pragma unroll
    for (int ks = 0; ks < 4; ks++) {
        uint32_t af[4], bf[8][2];
        {
            int row = wid * 16 + ((g & 1) << 3) + lr;
            int c = ks * 2 + (g >> 1);
            LDSM_X4(af[0], af[1], af[2], af[3], sP + row * 128 + (SW8(row, c) << 4));
        }
#pragma unroll
        for (int np = 0; np < 4; np++) {
            int row = np * 16 + ((g >> 1) << 3) + lr;
            int c = ks * 2 + (g & 1);
            uint32_t r0, r1x, r2x, r3;
            LDSM_X4(r0, r1x, r2x, r3, sAVT + row * 128 + (SW8(row, c) << 4));
            bf[np * 2][0] = r0; bf[np * 2][1] = r1x;
            bf[np * 2 + 1][0] = r2x; bf[np * 2 + 1][1] = r3;
        }
#pragma unroll
        for (int nt = 0; nt < 8; nt++)
            MMA16816(acc2[nt], af, bf[nt]);
    }

#pragma unroll
    for (int nt = 0; nt < 8; nt++) {
        int d = nt * 8 + ((lane & 3) << 1);
        *(float2*)(g_AOUT + (size_t)(b * NTOK + t1) * CCH + h * 64 + d) =
            make_float2(acc2[nt][0], acc2[nt][1]);
        *(float2*)(g_AOUT + (size_t)(b * NTOK + t2) * CCH + h * 64 + d) =
            make_float2(acc2[nt][2], acc2[nt][3]);
    }
}

// ---------------- 3x3 depthwise conv (v fp16) + fused fp16 split output ----------
__global__ __launch_bounds__(256) void dwc_kernel(
    const float* __restrict__ dwc_w, const float* __restrict__ dwc_b)
{
    int oh = blockIdx.x, b = blockIdx.y;
    __shared__ float w_s[CCH * 9];
    __shared__ float b_s[CCH];
    int tid = threadIdx.x;
    for (int t = tid; t < CCH * 9; t += 256) w_s[t] = dwc_w[t];
    for (int t = tid; t < CCH; t += 256) b_s[t] = dwc_b[t];
    __syncthreads();
    for (int idx = tid; idx < HW * CCH; idx += 256) {
        int ow = idx >> 9, c = idx & 511;
        float acc = b_s[c];
#pragma unroll
        for (int ky = 0; ky < 3; ky++) {
            int h2 = oh + ky - 1;
            if (h2 < 0 || h2 >= HW) continue;
#pragma unroll
            for (int kx = 0; kx < 3; kx++) {
                int w2 = ow + kx - 1;
                if (w2 < 0 || w2 >= HW) continue;
                acc += __half2float(g_kv16[((size_t)(b * NTOK + h2 * HW + w2)) * 1024 + 512 + c])
                     * w_s[c * 9 + ky * 3 + kx];
            }
        }
        size_t gi = ((size_t)(b * NTOK + oh * HW + ow)) * CCH + c;
        float v = g_AOUT[gi] + acc;
        __half h = __float2half_rn(v);
        g_ahi[gi] = h;
        g_alo[gi] = __float2half_rn(v - __half2float(h));
    }
}

// ---------------- launch ---------------------------------------------------------
extern "C" void kernel_launch(void* const* d_in, const int* in_sizes, int n_in,
                              void* d_out, int out_size)
{
    const float* x = (const float*)d_in[0];
    int off = 1;
    if (n_in >= 15 && in_sizes[1] == 1) off = 3;
    const float* q_w    = (const float*)d_in[off + 0];
    const float* kv_w   = (const float*)d_in[off + 1];
    const float* proj_w = (const float*)d_in[off + 2];
    const float* proj_b = (const float*)d_in[off + 3];
    const float* dwc_w  = (const float*)d_in[off + 4];
    const float* dwc_b  = (const float*)d_in[off + 5];
    const float* an_b   = (const float*)d_in[off + 6];
    const float* na_b   = (const float*)d_in[off + 7];
    const float* ah_b   = (const float*)d_in[off + 8];
    const float* aw_b   = (const float*)d_in[off + 9];
    const float* ha_b   = (const float*)d_in[off + 10];
    const float* wa_b   = (const float*)d_in[off + 11];
    float* out = (float*)d_out;

    __half *x16, *q16, *kv16, *v16t, *ahi, *alo, *wq16, *wkv16, *wp16;
    cudaGetSymbolAddress((void**)&x16, g_x16);
    cudaGetSymbolAddress((void**)&q16, g_q16);
    cudaGetSymbolAddress((void**)&kv16, g_kv16);
    cudaGetSymbolAddress((void**)&v16t, g_v16t);
    cudaGetSymbolAddress((void**)&ahi, g_ahi);
    cudaGetSymbolAddress((void**)&alo, g_alo);
    cudaGetSymbolAddress((void**)&wq16, g_wq16);
    cudaGetSymbolAddress((void**)&wkv16, g_wkv16);
    cudaGetSymbolAddress((void**)&wp16, g_wp16);

    static int smem_set = 0;
    if (!smem_set) {
        cudaFuncSetAttribute(gemm_tc<1,1>, cudaFuncAttributeMaxDynamicSharedMemorySize, NST * 12288);
        cudaFuncSetAttribute(gemm_tc<1,2>, cudaFuncAttributeMaxDynamicSharedMemorySize, NST * 12288);
        cudaFuncSetAttribute(gemm_tc<2,0>, cudaFuncAttributeMaxDynamicSharedMemorySize, NST * 20480);
        smem_set = 1;
    }

    cvt_w16<<<2048, 256>>>(x, x16, MROWS * CCH / 4);
    cvt_w16<<<256, 256>>>(q_w, wq16, CCH * CCH / 4);
    cvt_w16<<<512, 256>>>(kv_w, wkv16, 2 * CCH * CCH / 4);
    cvt_w16<<<256, 256>>>(proj_w, wp16, CCH * CCH / 4);

    gemm_tc<1,1><<<dim3(8, MROWS / 128), 256, NST * 12288>>>(
        x16, nullptr, wq16, nullptr, nullptr, q16, nullptr, 512);
    gemm_tc<1,2><<<dim3(16, MROWS / 128), 256, NST * 12288>>>(
        x16, nullptr, wkv16, nullptr, nullptr, kv16, v16t, 1024);

    pool_kernel<<<dim3(NB, 64), 256>>>();
    bias_resize_kernel<<<dim3(AG, HEADS, 2), 256>>>(an_b, na_b);
    agent_logits_mma<<<dim3(NTOK / 64, NB * HEADS), 128>>>(ah_b, aw_b);
    softmax_n_kernel<<<NB * HEADS * AG, 256>>>();
    agent_v_mma<<<dim3(NB * HEADS, 7), 128>>>();
    avp_reduce_kernel<<<(128 * 64 * 64 + 255) / 256, 256>>>();
    qside_mma<<<dim3(NTOK / 64, NB * HEADS), 128>>>(ha_b, wa_b);
    dwc_kernel<<<dim3(HW, NB), 256>>>(dwc_w, dwc_b);

    gemm_tc<2,0><<<dim3(8, MROWS / 128), 256, NST * 20480>>>(
        ahi, alo, wp16, out, proj_b, nullptr, nullptr, 512);
}

// round 11
// speedup vs baseline: 4.7252x; 1.0432x over previous
#include <cuda_runtime.h>
#include <cuda_fp16.h>
#include <math.h>
#include <stdint.h>

#define HEADS 8
#define HD 64
#define CCH 512
#define HW 56
#define NTOK 3136
#define AG 49
#define NB 16
#define MROWS (NB*NTOK)
#define KDIM 512

// ---------------- scratch (static device globals; zero-initialized) --------------
__device__ float g_PB1[HEADS * AG * NTOK];          // agent-side resized bias [h][a][t]
__device__ float g_NB1T[HEADS * NTOK * 64];         // q-side resized bias [h][t][a pad64]
__device__ float g_LOG[(size_t)NB * HEADS * AG * NTOK];
__device__ float g_AVP[7 * NB * HEADS * AG * HD];
__device__ __half g_x16[(size_t)MROWS * CCH];
__device__ __half g_q16[(size_t)MROWS * CCH];
__device__ __half g_kv16[(size_t)MROWS * 2 * CCH];
__device__ __half g_v16t[(size_t)NB * HEADS * HD * NTOK];    // [bh][d][t]
__device__ __half g_at16[NB * HEADS * 64 * 64];              // [bh][a pad64][d], x0.125
__device__ __half g_p16[(size_t)NB * HEADS * 64 * NTOK];     // [bh][a pad64][t], pad rows 0
__device__ __half g_avt16[NB * HEADS * 64 * 64];             // [bh][d][a pad64], pad 0
__device__ __half g_ao16[(size_t)MROWS * CCH];               // attention out fp16
__device__ __half g_ahi[(size_t)MROWS * CCH];                // proj input fp16
__device__ __half g_wq16[CCH * CCH];
__device__ __half g_wkv16[2 * CCH * CCH];
__device__ __half g_wp16[CCH * CCH];

// ================= low-level helpers =================
__device__ __forceinline__ uint32_t smem_u32(const void* p) {
    uint32_t a;
    asm("{ .reg .u64 t; cvta.to.shared.u64 t, %1; cvt.u32.u64 %0, t; }" : "=r"(a) : "l"(p));
    return a;
}
__device__ __forceinline__ void cpa16(uint32_t s, const void* g) {
    asm volatile("cp.async.cg.shared.global [%0], [%1], 16;" :: "r"(s), "l"(g));
}
#define CP_COMMIT() asm volatile("cp.async.commit_group;" ::: "memory")
#define CP_WAIT0()  asm volatile("cp.async.wait_group 0;" ::: "memory")

#define LDSM_X4(r0, r1, r2, r3, a) \
    asm volatile("ldmatrix.sync.aligned.m8n8.x4.shared.b16 {%0,%1,%2,%3}, [%4];" \
                 : "=r"(r0), "=r"(r1), "=r"(r2), "=r"(r3) : "r"(a))

#define MMA16816(d, a, b) \
    asm volatile("mma.sync.aligned.m16n8k16.row.col.f32.f16.f16.f32 " \
                 "{%0,%1,%2,%3}, {%4,%5,%6,%7}, {%8,%9}, {%0,%1,%2,%3};" \
                 : "+f"((d)[0]), "+f"((d)[1]), "+f"((d)[2]), "+f"((d)[3]) \
                 : "r"((a)[0]), "r"((a)[1]), "r"((a)[2]), "r"((a)[3]), \
                   "r"((b)[0]), "r"((b)[1]))

// 64B-row swizzle (k=32 halves/row) for the big GEMM
#define SWZC(r, c) ((c) ^ (((r) >> 1) & 3))
// 128B-row swizzle (k=64 halves/row, chunk c in 0..7) for attention tiles
#define SW8(r, c) ((c) ^ ((r) & 7))

#define NST 3
#define STG1 12288u

// ================= fp16 tensor-core GEMM (projections), 1-term ==================
// MODE 0: fp32 out + bias;  1: fp16 out
template<int MODE>
__global__ void __launch_bounds__(256, 3) gemm_tc(
    const __half* __restrict__ A16, const __half* __restrict__ B16,
    float* __restrict__ Cf, const float* __restrict__ bias,
    __half* __restrict__ C16, int Nout)
{
    extern __shared__ __align__(1024) char smem[];
    int tid = threadIdx.x;
    int wid = tid >> 5, lane = tid & 31;
    int bn0 = blockIdx.x * 64, m0 = blockIdx.y * 128;
    int wr = wid >> 1, wc = wid & 1;
    uint32_t sbase = smem_u32(smem);

    float acc[2][4][4] = {};

    int rA0 = tid >> 2,         cA0 = tid & 3;
    int rA1 = (tid + 256) >> 2, cA1 = tid & 3;
    int rB  = tid >> 2,         cB  = tid & 3;
    uint32_t soA0 = rA0 * 64 + (SWZC(rA0, cA0) << 4);
    uint32_t soA1 = rA1 * 64 + (SWZC(rA1, cA1) << 4);
    uint32_t soB  = rB * 64 + (SWZC(rB, cB) << 4);

#pragma unroll
    for (int pc = 0; pc < 2; pc++) {
        int k0 = pc * 32;
        uint32_t sb = sbase + pc * STG1;
        cpa16(sb + soA0, A16 + (size_t)(m0 + rA0) * KDIM + k0 + cA0 * 8);
        cpa16(sb + soA1, A16 + (size_t)(m0 + rA1) * KDIM + k0 + cA1 * 8);
        cpa16(sb + 8192 + soB, B16 + (size_t)(bn0 + rB) * KDIM + k0 + cB * 8);
        CP_COMMIT();
    }

    int g = lane >> 3, lr = lane & 7;

    for (int ch = 0; ch < 16; ch++) {
        __syncthreads();
        if (ch + 2 < 16) {
            int k0 = (ch + 2) * 32;
            uint32_t nb = sbase + ((ch + 2) % NST) * STG1;
            cpa16(nb + soA0, A16 + (size_t)(m0 + rA0) * KDIM + k0 + cA0 * 8);
            cpa16(nb + soA1, A16 + (size_t)(m0 + rA1) * KDIM + k0 + cA1 * 8);
            cpa16(nb + 8192 + soB, B16 + (size_t)(bn0 + rB) * KDIM + k0 + cB * 8);
            CP_COMMIT();
        }
        if (ch <= 13)      asm volatile("cp.async.wait_group 2;" ::: "memory");
        else if (ch == 14) asm volatile("cp.async.wait_group 1;" ::: "memory");
        else               asm volatile("cp.async.wait_group 0;" ::: "memory");
        __syncthreads();

        uint32_t base = sbase + (ch % NST) * STG1;

#pragma unroll
        for (int ks = 0; ks < 2; ks++) {
            uint32_t af[2][4], bf[4][2];
#pragma unroll
            for (int mt = 0; mt < 2; mt++) {
                int row = wr * 32 + mt * 16 + ((g & 1) << 3) + lr;
                int c = ks * 2 + (g >> 1);
                uint32_t off = row * 64 + (SWZC(row, c) << 4);
                LDSM_X4(af[mt][0], af[mt][1], af[mt][2], af[mt][3], base + off);
            }
#pragma unroll
            for (int np = 0; np < 2; np++) {
                int row = wc * 32 + np * 16 + ((g >> 1) << 3) + lr;
                int c = ks * 2 + (g & 1);
                uint32_t off = row * 64 + (SWZC(row, c) << 4);
                uint32_t r0, r1, r2, r3;
                LDSM_X4(r0, r1, r2, r3, base + 8192 + off);
                bf[np * 2][0] = r0; bf[np * 2][1] = r1;
                bf[np * 2 + 1][0] = r2; bf[np * 2 + 1][1] = r3;
            }
#pragma unroll
            for (int mt = 0; mt < 2; mt++)
#pragma unroll
                for (int nt = 0; nt < 4; nt++)
                    MMA16816(acc[mt][nt], af[mt], bf[nt]);
        }
    }

    // epilogue
#pragma unroll
    for (int mt = 0; mt < 2; mt++) {
#pragma unroll
        for (int nt = 0; nt < 4; nt++) {
            int gm0 = m0 + wr * 32 + mt * 16 + (lane >> 2);
            int gn = bn0 + wc * 32 + nt * 8 + ((lane & 3) << 1);
#pragma unroll
            for (int half = 0; half < 2; half++) {
                int gm = gm0 + half * 8;
                float v0 = acc[mt][nt][half * 2], v1 = acc[mt][nt][half * 2 + 1];
                if (MODE == 0) {
                    v0 += bias[gn]; v1 += bias[gn + 1];
                    *(float2*)(Cf + (size_t)gm * Nout + gn) = make_float2(v0, v1);
                } else {
                    *(__half2*)(C16 + (size_t)gm * Nout + gn) =
                        __halves2half2(__float2half_rn(v0), __float2half_rn(v1));
                }
            }
        }
    }
}

// ---------------- fp32 -> fp16 ---------------------------------------------------
__global__ __launch_bounds__(256) void cvt_w16(
    const float* __restrict__ src, __half* __restrict__ dst, int n4)
{
    for (int i = blockIdx.x * 256 + threadIdx.x; i < n4; i += gridDim.x * 256) {
        float4 v = ((const float4*)src)[i];
        ((__half2*)dst)[2 * i]     = __halves2half2(__float2half_rn(v.x), __float2half_rn(v.y));
        ((__half2*)dst)[2 * i + 1] = __halves2half2(__float2half_rn(v.z), __float2half_rn(v.w));
    }
}

// ---------------- coalesced V transpose: kv16[t][512+h*64+d] -> v16t[bh][d][t] ---
__global__ __launch_bounds__(256) void v_transpose()
{
    __shared__ __half tile[64][72];   // pitch 144B (16B aligned)
    int t0 = blockIdx.x * 64;         // 49
    int bh = blockIdx.y;              // 128
    int b = bh >> 3, h = bh & 7;
    int tid = threadIdx.x;
    int r = tid >> 3, cg = tid & 7;
#pragma unroll
    for (int it = 0; it < 2; it++) {
        int rr = r + it * 32;
        *(uint4*)&tile[rr][cg * 8] =
            *(const uint4*)(g_kv16 + (size_t)(b * NTOK + t0 + rr) * 1024 + 512 + h * 64 + cg * 8);
    }
    __syncthreads();
#pragma unroll
    for (int it = 0; it < 2; it++) {
        int dd = r + it * 32;
        __half vals[8];
#pragma unroll
        for (int i = 0; i < 8; i++) vals[i] = tile[cg * 8 + i][dd];
        *(uint4*)(g_v16t + ((size_t)bh * 64 + dd) * NTOK + t0 + cg * 8) = *(uint4*)vals;
    }
}

// ---------------- pooling: q16 -> at16 (x0.125, pad rows zero) -------------------
__global__ __launch_bounds__(256) void pool_kernel()
{
    int b = blockIdx.x, a = blockIdx.y;   // NB x 64
    if (a >= AG) {
        for (int c = threadIdx.x; c < CCH; c += 256)
            g_at16[(((b * 8 + (c >> 6)) * 64) + a) * 64 + (c & 63)] = __float2half(0.f);
        return;
    }
    int p1 = a / 7, p2 = a % 7;
    for (int c = threadIdx.x; c < CCH; c += 256) {
        float s = 0.f;
#pragma unroll
        for (int r = 0; r < 8; r++)
#pragma unroll
            for (int ss = 0; ss < 8; ss++)
                s += __half2float(g_q16[((size_t)(b * NTOK + (p1 * 8 + r) * HW + p2 * 8 + ss)) * CCH + c]);
        g_at16[(((b * 8 + (c >> 6)) * 64) + a) * 64 + (c & 63)] =
            __float2half_rn(s * (1.0f / 64.0f) * 0.125f);
    }
}

// ---------------- jax bilinear resize -------------------------------------------
__device__ __forceinline__ void lin_w(int o, int& i0, int& i1, float& w0, float& w1)
{
    float p = (o + 0.5f) * 0.125f - 0.5f;
    float fp = floorf(p);
    int i = (int)fp;
    float f = p - fp;
    if (i < 0)       { i0 = 0; i1 = 0; w0 = 1.f; w1 = 0.f; }
    else if (i >= 6) { i0 = 6; i1 = 6; w0 = 1.f; w1 = 0.f; }
    else             { i0 = i; i1 = i + 1; w0 = 1.f - f; w1 = f; }
}

__global__ __launch_bounds__(256) void bias_resize_kernel(
    const float* __restrict__ an, const float* __restrict__ na)
{
    int a = blockIdx.x, h = blockIdx.y, src = blockIdx.z;
    const float* S = (src == 0 ? an : na) + (h * AG + a) * 49;
    __shared__ float s[49];
    if (threadIdx.x < 49) s[threadIdx.x] = S[threadIdx.x];
    __syncthreads();
    for (int o = threadIdx.x; o < NTOK; o += 256) {
        int oh = o / HW, ow = o % HW;
        int r0, r1, c0, c1; float wr0, wr1, wc0, wc1;
        lin_w(oh, r0, r1, wr0, wr1);
        lin_w(ow, c0, c1, wc0, wc1);
        float v = wr0 * (wc0 * s[r0 * 7 + c0] + wc1 * s[r0 * 7 + c1]) +
                  wr1 * (wc0 * s[r1 * 7 + c0] + wc1 * s[r1 * 7 + c1]);
        if (src == 0) g_PB1[((size_t)(h * AG + a)) * NTOK + o] = v;
        else          g_NB1T[((size_t)h * NTOK + o) * 64 + a] = v;
    }
}

// ---------------- agent logits via MMA -------------------------------------------
__global__ __launch_bounds__(128) void agent_logits_mma(
    const float* __restrict__ ahb, const float* __restrict__ awb)
{
    __shared__ __align__(1024) char sm[16384];   // [AT 8KB][K 8KB]
    int bh = blockIdx.y, b = bh >> 3, h = bh & 7;
    int i0 = blockIdx.x * 64;
    int tid = threadIdx.x, wid = tid >> 5, lane = tid & 31;
    int wr = wid >> 1, wc = wid & 1;
    uint32_t sbase = smem_u32(sm);

    const __half* atp = g_at16 + (size_t)bh * 64 * 64;
#pragma unroll
    for (int it = 0; it < 4; it++) {
        int idx = tid + it * 128;
        int r = idx >> 3, c = idx & 7;
        cpa16(sbase + r * 128 + (SW8(r, c) << 4), atp + r * 64 + c * 8);
        cpa16(sbase + 8192 + r * 128 + (SW8(r, c) << 4),
              g_kv16 + (size_t)(b * NTOK + i0 + r) * 1024 + h * 64 + c * 8);
    }
    CP_COMMIT(); CP_WAIT0();
    __syncthreads();

    int g = lane >> 3, lr = lane & 7;
    float acc[2][4][4] = {};
#pragma unroll
    for (int ks = 0; ks < 4; ks++) {
        uint32_t af[2][4], bf[4][2];
#pragma unroll
        for (int mt = 0; mt < 2; mt++) {
            int row = wr * 32 + mt * 16 + ((g & 1) << 3) + lr;
            int c = ks * 2 + (g >> 1);
            LDSM_X4(af[mt][0], af[mt][1], af[mt][2], af[mt][3],
                    sbase + row * 128 + (SW8(row, c) << 4));
        }
#pragma unroll
        for (int np = 0; np < 2; np++) {
            int row = wc * 32 + np * 16 + ((g >> 1) << 3) + lr;
            int c = ks * 2 + (g & 1);
            uint32_t r0, r1, r2, r3;
            LDSM_X4(r0, r1, r2, r3, sbase + 8192 + row * 128 + (SW8(row, c) << 4));
            bf[np * 2][0] = r0; bf[np * 2][1] = r1;
            bf[np * 2 + 1][0] = r2; bf[np * 2 + 1][1] = r3;
        }
#pragma unroll
        for (int mt = 0; mt < 2; mt++)
#pragma unroll
            for (int nt = 0; nt < 4; nt++)
                MMA16816(acc[mt][nt], af[mt], bf[nt]);
    }

#pragma unroll
    for (int mt = 0; mt < 2; mt++)
#pragma unroll
        for (int nt = 0; nt < 4; nt++)
#pragma unroll
            for (int half = 0; half < 2; half++) {
                int a = wr * 32 + mt * 16 + (lane >> 2) + half * 8;
                if (a >= AG) continue;
                int t = i0 + wc * 32 + nt * 8 + ((lane & 3) << 1);
                int oh = t / HW, ow = t % HW;
                int oh1 = (t + 1) / HW, ow1 = (t + 1) % HW;
                size_t lbase = ((size_t)bh * AG + a) * NTOK + t;
                const float* pb = g_PB1 + ((size_t)(h * AG + a)) * NTOK + t;
                float v0 = acc[mt][nt][half * 2] + pb[0]
                         + ahb[(h * AG + a) * HW + oh] + awb[(h * AG + a) * HW + ow];
                float v1 = acc[mt][nt][half * 2 + 1] + pb[1]
                         + ahb[(h * AG + a) * HW + oh1] + awb[(h * AG + a) * HW + ow1];
                *(float2*)(g_LOG + lbase) = make_float2(v0, v1);
            }
}

// ---------------- row softmax, emits fp16 probs ----------------------------------
__global__ __launch_bounds__(256) void softmax_n_kernel()
{
    int row = blockIdx.x;             // 128*49
    int bh = row / AG, a = row % AG;
    const float* p = g_LOG + (size_t)row * NTOK;
    __half* po = g_p16 + ((size_t)bh * 64 + a) * NTOK;
    __shared__ float buf[NTOK];
    __shared__ float red[8];
    int tid = threadIdx.x;
    float m = -1e30f;
    for (int i = tid; i < NTOK; i += 256) { float v = p[i]; buf[i] = v; m = fmaxf(m, v); }
#pragma unroll
    for (int o = 16; o; o >>= 1) m = fmaxf(m, __shfl_xor_sync(~0u, m, o));
    if ((tid & 31) == 0) red[tid >> 5] = m;
    __syncthreads();
    m = fmaxf(fmaxf(fmaxf(red[0], red[1]), fmaxf(red[2], red[3])),
              fmaxf(fmaxf(red[4], red[5]), fmaxf(red[6], red[7])));
    __syncthreads();
    float s = 0.f;
    for (int i = tid; i < NTOK; i += 256) { float e = __expf(buf[i] - m); buf[i] = e; s += e; }
#pragma unroll
    for (int o = 16; o; o >>= 1) s += __shfl_xor_sync(~0u, s, o);
    if ((tid & 31) == 0) red[tid >> 5] = s;
    __syncthreads();
    s = red[0] + red[1] + red[2] + red[3] + red[4] + red[5] + red[6] + red[7];
    float inv = 1.0f / s;
    for (int i = tid; i < NTOK; i += 256) po[i] = __float2half_rn(buf[i] * inv);
}

// ---------------- agent_v via MMA, split-K ---------------------------------------
__global__ __launch_bounds__(128) void agent_v_mma()
{
    __shared__ __align__(1024) char sm[NST * 16384];   // stage: [P 8KB][VT 8KB]
    int bh = blockIdx.x, sp = blockIdx.y;
    int kbeg = sp * 448;
    int tid = threadIdx.x, wid = tid >> 5, lane = tid & 31;
    int wr = wid >> 1, wc = wid & 1;
    uint32_t sbase = smem_u32(sm);
    const __half* pp = g_p16 + (size_t)bh * 64 * NTOK + kbeg;
    const __half* vp = g_v16t + (size_t)bh * 64 * NTOK + kbeg;

    int rl = tid >> 3, cl = tid & 7;

#pragma unroll
    for (int pc = 0; pc < 2; pc++) {
        uint32_t sb = sbase + pc * 16384;
#pragma unroll
        for (int it = 0; it < 4; it++) {
            int r = rl + it * 16;
            uint32_t o = (r << 7) + (SW8(r, cl) << 4);
            cpa16(sb + o, pp + (size_t)r * NTOK + pc * 64 + cl * 8);
            cpa16(sb + 8192 + o, vp + (size_t)r * NTOK + pc * 64 + cl * 8);
        }
        CP_COMMIT();
    }

    int g = lane >> 3, lr = lane & 7;
    float acc[2][4][4] = {};
    for (int ch = 0; ch < 7; ch++) {
        __syncthreads();
        if (ch + 2 < 7) {
            uint32_t nb = sbase + ((ch + 2) % NST) * 16384;
#pragma unroll
            for (int it = 0; it < 4; it++) {
                int r = rl + it * 16;
                uint32_t o = (r << 7) + (SW8(r, cl) << 4);
                cpa16(nb + o, pp + (size_t)r * NTOK + (ch + 2) * 64 + cl * 8);
                cpa16(nb + 8192 + o, vp + (size_t)r * NTOK + (ch + 2) * 64 + cl * 8);
            }
            CP_COMMIT();
        }
        if (ch <= 4)      asm volatile("cp.async.wait_group 2;" ::: "memory");
        else if (ch == 5) asm volatile("cp.async.wait_group 1;" ::: "memory");
        else              asm volatile("cp.async.wait_group 0;" ::: "memory");
        __syncthreads();

        uint32_t base = sbase + (ch % NST) * 16384;
#pragma unroll
        for (int ks = 0; ks < 4; ks++) {
            uint32_t af[2][4], bf[4][2];
#pragma unroll
            for (int mt = 0; mt < 2; mt++) {
                int row = wr * 32 + mt * 16 + ((g & 1) << 3) + lr;
                int c = ks * 2 + (g >> 1);
                LDSM_X4(af[mt][0], af[mt][1], af[mt][2], af[mt][3],
                        base + row * 128 + (SW8(row, c) << 4));
            }
#pragma unroll
            for (int np = 0; np < 2; np++) {
                int row = wc * 32 + np * 16 + ((g >> 1) << 3) + lr;
                int c = ks * 2 + (g & 1);
                uint32_t r0, r1, r2, r3;
                LDSM_X4(r0, r1, r2, r3, base + 8192 + row * 128 + (SW8(row, c) << 4));
                bf[np * 2][0] = r0; bf[np * 2][1] = r1;
                bf[np * 2 + 1][0] = r2; bf[np * 2 + 1][1] = r3;
            }
#pragma unroll
            for (int mt = 0; mt < 2; mt++)
#pragma unroll
                for (int nt = 0; nt < 4; nt++)
                    MMA16816(acc[mt][nt], af[mt], bf[nt]);
        }
    }

#pragma unroll
    for (int mt = 0; mt < 2; mt++)
#pragma unroll
        for (int nt = 0; nt < 4; nt++)
#pragma unroll
            for (int half = 0; half < 2; half++) {
                int a = wr * 32 + mt * 16 + (lane >> 2) + half * 8;
                if (a >= AG) continue;
                int d = wc * 32 + nt * 8 + ((lane & 3) << 1);
                size_t o = ((size_t)sp * 128 + bh) * (AG * HD) + a * HD + d;
                *(float2*)(g_AVP + o) =
                    make_float2(acc[mt][nt][half * 2], acc[mt][nt][half * 2 + 1]);
            }
}

// ---------------- reduce partials -> AV^T fp16 -----------------------------------
__global__ __launch_bounds__(256) void avp_reduce_kernel()
{
    int i = blockIdx.x * 256 + threadIdx.x;
    if (i >= 128 * 64 * 64) return;
    int bh = i >> 12, rest = i & 4095, d = rest >> 6, a = rest & 63;
    float s = 0.f;
    if (a < AG) {
#pragma unroll
        for (int sp = 0; sp < 7; sp++)
            s += g_AVP[((size_t)sp * 128 + bh) * (AG * HD) + a * HD + d];
    }
    g_avt16[((size_t)bh * 64 + d) * 64 + a] = __float2half_rn(s);
}

// ---------------- q-side: MMA logits + reg softmax + MMA out ---------------------
__global__ __launch_bounds__(128) void qside_mma(
    const float* __restrict__ hab, const float* __restrict__ wab)
{
    __shared__ __align__(1024) char sm[32768]; // [Q 8K][AT 8K][AVT 8K][P 8K]
    int bh = blockIdx.y, b = bh >> 3, h = bh & 7;
    int i0 = blockIdx.x * 64;
    int tid = threadIdx.x, wid = tid >> 5, lane = tid & 31;
    uint32_t sQ = smem_u32(sm), sAT = sQ + 8192, sAVT = sQ + 16384, sP = sQ + 24576;

    const __half* atp = g_at16 + (size_t)bh * 64 * 64;
    const __half* avtp = g_avt16 + (size_t)bh * 64 * 64;
#pragma unroll
    for (int it = 0; it < 4; it++) {
        int idx = tid + it * 128;
        int r = idx >> 3, c = idx & 7;
        uint32_t o = r * 128 + (SW8(r, c) << 4);
        cpa16(sQ + o, g_q16 + (size_t)(b * NTOK + i0 + r) * 512 + h * 64 + c * 8);
        cpa16(sAT + o, atp + r * 64 + c * 8);
        cpa16(sAVT + o, avtp + r * 64 + c * 8);
    }
    CP_COMMIT(); CP_WAIT0();
    __syncthreads();

    int g = lane >> 3, lr = lane & 7;
    float acc1[8][4] = {};
#pragma unroll
    for (int ks = 0; ks < 4; ks++) {
        uint32_t af[4], bf[8][2];
        {
            int row = wid * 16 + ((g & 1) << 3) + lr;
            int c = ks * 2 + (g >> 1);
            LDSM_X4(af[0], af[1], af[2], af[3], sQ + row * 128 + (SW8(row, c) << 4));
        }
#pragma unroll
        for (int np = 0; np < 4; np++) {
            int row = np * 16 + ((g >> 1) << 3) + lr;
            int c = ks * 2 + (g & 1);
            uint32_t r0, r1, r2, r3;
            LDSM_X4(r0, r1, r2, r3, sAT + row * 128 + (SW8(row, c) << 4));
            bf[np * 2][0] = r0; bf[np * 2][1] = r1;
            bf[np * 2 + 1][0] = r2; bf[np * 2 + 1][1] = r3;
        }
#pragma unroll
        for (int nt = 0; nt < 8; nt++)
            MMA16816(acc1[nt], af, bf[nt]);
    }

    int r1 = wid * 16 + (lane >> 2), r2 = r1 + 8;
    int t1 = i0 + r1, t2 = i0 + r2;
    int oh1 = t1 / HW, ow1 = t1 % HW, oh2 = t2 / HW, ow2 = t2 % HW;
#pragma unroll
    for (int nt = 0; nt < 8; nt++)
#pragma unroll
        for (int j = 0; j < 4; j++) {
            int a = nt * 8 + ((lane & 3) << 1) + (j & 1);
            if (a < AG) {
                if (j < 2)
                    acc1[nt][j] += g_NB1T[((size_t)h * NTOK + t1) * 64 + a]
                                 + hab[(h * HW + oh1) * AG + a] + wab[(h * HW + ow1) * AG + a];
                else
                    acc1[nt][j] += g_NB1T[((size_t)h * NTOK + t2) * 64 + a]
                                 + hab[(h * HW + oh2) * AG + a] + wab[(h * HW + ow2) * AG + a];
            } else acc1[nt][j] = -INFINITY;
        }
    float m1 = -1e30f, m2 = -1e30f;
#pragma unroll
    for (int nt = 0; nt < 8; nt++) {
        m1 = fmaxf(m1, fmaxf(acc1[nt][0], acc1[nt][1]));
        m2 = fmaxf(m2, fmaxf(acc1[nt][2], acc1[nt][3]));
    }
    m1 = fmaxf(m1, __shfl_xor_sync(~0u, m1, 1)); m1 = fmaxf(m1, __shfl_xor_sync(~0u, m1, 2));
    m2 = fmaxf(m2, __shfl_xor_sync(~0u, m2, 1)); m2 = fmaxf(m2, __shfl_xor_sync(~0u, m2, 2));
    float s1 = 0.f, s2 = 0.f;
#pragma unroll
    for (int nt = 0; nt < 8; nt++) {
        acc1[nt][0] = __expf(acc1[nt][0] - m1); s1 += acc1[nt][0];
        acc1[nt][1] = __expf(acc1[nt][1] - m1); s1 += acc1[nt][1];
        acc1[nt][2] = __expf(acc1[nt][2] - m2); s2 += acc1[nt][2];
        acc1[nt][3] = __expf(acc1[nt][3] - m2); s2 += acc1[nt][3];
    }
    s1 += __shfl_xor_sync(~0u, s1, 1); s1 += __shfl_xor_sync(~0u, s1, 2);
    s2 += __shfl_xor_sync(~0u, s2, 1); s2 += __shfl_xor_sync(~0u, s2, 2);
    float i1 = 1.0f / s1, i2 = 1.0f / s2;

#pragma unroll
    for (int nt = 0; nt < 8; nt++) {
        int colb = nt * 8 + ((lane & 3) << 1);
        uint32_t o1 = r1 * 128 + (SW8(r1, nt) << 4) + (colb & 7) * 2;
        uint32_t o2 = r2 * 128 + (SW8(r2, nt) << 4) + (colb & 7) * 2;
        __half2 p1 = __halves2half2(__float2half_rn(acc1[nt][0] * i1),
                                    __float2half_rn(acc1[nt][1] * i1));
        __half2 p2 = __halves2half2(__float2half_rn(acc1[nt][2] * i2),
                                    __float2half_rn(acc1[nt][3] * i2));
        asm volatile("st.shared.b32 [%0], %1;" :: "r"(sP + o1), "r"(*(uint32_t*)&p1));
        asm volatile("st.shared.b32 [%0], %1;" :: "r"(sP + o2), "r"(*(uint32_t*)&p2));
    }
    __syncwarp();

    float acc2[8][4] = {};
#pragma unroll
    for (int ks = 0; ks < 4; ks++) {
        uint32_t af[4], bf[8][2];
        {
            int row = wid * 16 + ((g & 1) << 3) + lr;
            int c = ks * 2 + (g >> 1);
            LDSM_X4(af[0], af[1], af[2], af[3], sP + row * 128 + (SW8(row, c) << 4));
        }
#pragma unroll
        for (int np = 0; np < 4; np++) {
            int row = np * 16 + ((g >> 1) << 3) + lr;
            int c = ks * 2 + (g & 1);
            uint32_t r0, r1x, r2x, r3;
            LDSM_X4(r0, r1x, r2x, r3, sAVT + row * 128 + (SW8(row, c) << 4));
            bf[np * 2][0] = r0; bf[np * 2][1] = r1x;
            bf[np * 2 + 1][0] = r2x; bf[np * 2 + 1][1] = r3;
        }
#pragma unroll
        for (int nt = 0; nt < 8; nt++)
            MMA16816(acc2[nt], af, bf[nt]);
    }

#pragma unroll
    for (int nt = 0; nt < 8; nt++) {
        int d = nt * 8 + ((lane & 3) << 1);
        *(__half2*)(g_ao16 + (size_t)(b * NTOK + t1) * CCH + h * 64 + d) =
            __halves2half2(__float2half_rn(acc2[nt][0]), __float2half_rn(acc2[nt][1]));
        *(__half2*)(g_ao16 + (size_t)(b * NTOK + t2) * CCH + h * 64 + d) =
            __halves2half2(__float2half_rn(acc2[nt][2]), __float2half_rn(acc2[nt][3]));
    }
}

// ---------------- 3x3 depthwise conv (v fp16) + attn-out add -> fp16 proj input --
__global__ __launch_bounds__(256) void dwc_kernel(
    const float* __restrict__ dwc_w, const float* __restrict__ dwc_b)
{
    int oh = blockIdx.x, b = blockIdx.y;
    __shared__ float w_s[CCH * 9];
    __shared__ float b_s[CCH];
    int tid = threadIdx.x;
    for (int t = tid; t < CCH * 9; t += 256) w_s[t] = dwc_w[t];
    for (int t = tid; t < CCH; t += 256) b_s[t] = dwc_b[t];
    __syncthreads();
    for (int idx = tid; idx < HW * CCH; idx += 256) {
        int ow = idx >> 9, c = idx & 511;
        float acc = b_s[c];
#pragma unroll
        for (int ky = 0; ky < 3; ky++) {
            int h2 = oh + ky - 1;
            if (h2 < 0 || h2 >= HW) continue;
#pragma unroll
            for (int kx = 0; kx < 3; kx++) {
                int w2 = ow + kx - 1;
                if (w2 < 0 || w2 >= HW) continue;
                acc += __half2float(g_kv16[((size_t)(b * NTOK + h2 * HW + w2)) * 1024 + 512 + c])
                     * w_s[c * 9 + ky * 3 + kx];
            }
        }
        size_t gi = ((size_t)(b * NTOK + oh * HW + ow)) * CCH + c;
        g_ahi[gi] = __float2half_rn(__half2float(g_ao16[gi]) + acc);
    }
}

// ---------------- launch ---------------------------------------------------------
extern "C" void kernel_launch(void* const* d_in, const int* in_sizes, int n_in,
                              void* d_out, int out_size)
{
    const float* x = (const float*)d_in[0];
    int off = 1;
    if (n_in >= 15 && in_sizes[1] == 1) off = 3;
    const float* q_w    = (const float*)d_in[off + 0];
    const float* kv_w   = (const float*)d_in[off + 1];
    const float* proj_w = (const float*)d_in[off + 2];
    const float* proj_b = (const float*)d_in[off + 3];
    const float* dwc_w  = (const float*)d_in[off + 4];
    const float* dwc_b  = (const float*)d_in[off + 5];
    const float* an_b   = (const float*)d_in[off + 6];
    const float* na_b   = (const float*)d_in[off + 7];
    const float* ah_b   = (const float*)d_in[off + 8];
    const float* aw_b   = (const float*)d_in[off + 9];
    const float* ha_b   = (const float*)d_in[off + 10];
    const float* wa_b   = (const float*)d_in[off + 11];
    float* out = (float*)d_out;

    __half *x16, *q16, *kv16, *ahi, *wq16, *wkv16, *wp16;
    cudaGetSymbolAddress((void**)&x16, g_x16);
    cudaGetSymbolAddress((void**)&q16, g_q16);
    cudaGetSymbolAddress((void**)&kv16, g_kv16);
    cudaGetSymbolAddress((void**)&ahi, g_ahi);
    cudaGetSymbolAddress((void**)&wq16, g_wq16);
    cudaGetSymbolAddress((void**)&wkv16, g_wkv16);
    cudaGetSymbolAddress((void**)&wp16, g_wp16);

    static int smem_set = 0;
    if (!smem_set) {
        cudaFuncSetAttribute(gemm_tc<0>, cudaFuncAttributeMaxDynamicSharedMemorySize, NST * STG1);
        cudaFuncSetAttribute(gemm_tc<1>, cudaFuncAttributeMaxDynamicSharedMemorySize, NST * STG1);
        smem_set = 1;
    }

    cvt_w16<<<2048, 256>>>(x, x16, MROWS * CCH / 4);
    cvt_w16<<<256, 256>>>(q_w, wq16, CCH * CCH / 4);
    cvt_w16<<<512, 256>>>(kv_w, wkv16, 2 * CCH * CCH / 4);
    cvt_w16<<<256, 256>>>(proj_w, wp16, CCH * CCH / 4);

    gemm_tc<1><<<dim3(8, MROWS / 128), 256, NST * STG1>>>(
        x16, wq16, nullptr, nullptr, q16, 512);
    gemm_tc<1><<<dim3(16, MROWS / 128), 256, NST * STG1>>>(
        x16, wkv16, nullptr, nullptr, kv16, 1024);

    v_transpose<<<dim3(NTOK / 64, NB * HEADS), 256>>>();
    pool_kernel<<<dim3(NB, 64), 256>>>();
    bias_resize_kernel<<<dim3(AG, HEADS, 2), 256>>>(an_b, na_b);
    agent_logits_mma<<<dim3(NTOK / 64, NB * HEADS), 128>>>(ah_b, aw_b);
    softmax_n_kernel<<<NB * HEADS * AG, 256>>>();
    agent_v_mma<<<dim3(NB * HEADS, 7), 128>>>();
    avp_reduce_kernel<<<(128 * 64 * 64 + 255) / 256, 256>>>();
    qside_mma<<<dim3(NTOK / 64, NB * HEADS), 128>>>(ha_b, wa_b);
    dwc_kernel<<<dim3(HW, NB), 256>>>(dwc_w, dwc_b);

    gemm_tc<0><<<dim3(8, MROWS / 128), 256, NST * STG1>>>(
        ahi, wp16, out, proj_b, nullptr, 512);
}

// round 12
// speedup vs baseline: 4.9178x; 1.0408x over previous
#include <cuda_runtime.h>
#include <cuda_fp16.h>
#include <math.h>
#include <stdint.h>

#define HEADS 8
#define HD 64
#define CCH 512
#define HW 56
#define NTOK 3136
#define AG 49
#define NB 16
#define MROWS (NB*NTOK)
#define KDIM 512
#define QKVW 1536

// ---------------- scratch (static device globals; zero-initialized) --------------
__device__ float g_LOG[(size_t)NB * HEADS * AG * NTOK];
__device__ float g_AVP[7 * NB * HEADS * AG * HD];
__device__ __half g_PB1h[HEADS * AG * NTOK];         // agent-side bias, pb1+ah+aw folded
__device__ __half g_NB1Th[HEADS * NTOK * 64];        // q-side bias [h][t][a pad64], folded
__device__ __half g_x16[(size_t)MROWS * CCH];
__device__ __half g_qkv16[(size_t)MROWS * QKVW];     // q | k | v packed
__device__ __half g_v16t[(size_t)NB * HEADS * HD * NTOK];    // [bh][d][t]
__device__ __half g_at16[NB * HEADS * 64 * 64];              // [bh][a pad64][d], x0.125
__device__ __half g_p16[(size_t)NB * HEADS * 64 * NTOK];     // [bh][a pad64][t]
__device__ __half g_avt16[NB * HEADS * 64 * 64];             // [bh][d][a pad64]
__device__ __half g_ao16[(size_t)MROWS * CCH];
__device__ __half g_ahi[(size_t)MROWS * CCH];
__device__ __half g_wqkv16[QKVW * CCH];
__device__ __half g_wp16[CCH * CCH];

// ================= low-level helpers =================
__device__ __forceinline__ uint32_t smem_u32(const void* p) {
    uint32_t a;
    asm("{ .reg .u64 t; cvta.to.shared.u64 t, %1; cvt.u32.u64 %0, t; }" : "=r"(a) : "l"(p));
    return a;
}
__device__ __forceinline__ void cpa16(uint32_t s, const void* g) {
    asm volatile("cp.async.cg.shared.global [%0], [%1], 16;" :: "r"(s), "l"(g));
}
#define CP_COMMIT() asm volatile("cp.async.commit_group;" ::: "memory")
#define CP_WAIT0()  asm volatile("cp.async.wait_group 0;" ::: "memory")

#define LDSM_X4(r0, r1, r2, r3, a) \
    asm volatile("ldmatrix.sync.aligned.m8n8.x4.shared.b16 {%0,%1,%2,%3}, [%4];" \
                 : "=r"(r0), "=r"(r1), "=r"(r2), "=r"(r3) : "r"(a))

#define MMA16816(d, a, b) \
    asm volatile("mma.sync.aligned.m16n8k16.row.col.f32.f16.f16.f32 " \
                 "{%0,%1,%2,%3}, {%4,%5,%6,%7}, {%8,%9}, {%0,%1,%2,%3};" \
                 : "+f"((d)[0]), "+f"((d)[1]), "+f"((d)[2]), "+f"((d)[3]) \
                 : "r"((a)[0]), "r"((a)[1]), "r"((a)[2]), "r"((a)[3]), \
                   "r"((b)[0]), "r"((b)[1]))

#define SWZC(r, c) ((c) ^ (((r) >> 1) & 3))
#define SW8(r, c) ((c) ^ ((r) & 7))

#define NST 3
#define STG1 12288u

// ================= fp16 tensor-core GEMM, 1-term ================================
// MODE 0: fp32 out + bias;  1: fp16 out
template<int MODE>
__global__ void __launch_bounds__(256, 3) gemm_tc(
    const __half* __restrict__ A16, const __half* __restrict__ B16,
    float* __restrict__ Cf, const float* __restrict__ bias,
    __half* __restrict__ C16, int Nout)
{
    extern __shared__ __align__(1024) char smem[];
    int tid = threadIdx.x;
    int wid = tid >> 5, lane = tid & 31;
    int bn0 = blockIdx.x * 64, m0 = blockIdx.y * 128;
    int wr = wid >> 1, wc = wid & 1;
    uint32_t sbase = smem_u32(smem);

    float acc[2][4][4] = {};

    int rA0 = tid >> 2,         cA0 = tid & 3;
    int rA1 = (tid + 256) >> 2, cA1 = tid & 3;
    int rB  = tid >> 2,         cB  = tid & 3;
    uint32_t soA0 = rA0 * 64 + (SWZC(rA0, cA0) << 4);
    uint32_t soA1 = rA1 * 64 + (SWZC(rA1, cA1) << 4);
    uint32_t soB  = rB * 64 + (SWZC(rB, cB) << 4);

#pragma unroll
    for (int pc = 0; pc < 2; pc++) {
        int k0 = pc * 32;
        uint32_t sb = sbase + pc * STG1;
        cpa16(sb + soA0, A16 + (size_t)(m0 + rA0) * KDIM + k0 + cA0 * 8);
        cpa16(sb + soA1, A16 + (size_t)(m0 + rA1) * KDIM + k0 + cA1 * 8);
        cpa16(sb + 8192 + soB, B16 + (size_t)(bn0 + rB) * KDIM + k0 + cB * 8);
        CP_COMMIT();
    }

    int g = lane >> 3, lr = lane & 7;

    for (int ch = 0; ch < 16; ch++) {
        __syncthreads();
        if (ch + 2 < 16) {
            int k0 = (ch + 2) * 32;
            uint32_t nb = sbase + ((ch + 2) % NST) * STG1;
            cpa16(nb + soA0, A16 + (size_t)(m0 + rA0) * KDIM + k0 + cA0 * 8);
            cpa16(nb + soA1, A16 + (size_t)(m0 + rA1) * KDIM + k0 + cA1 * 8);
            cpa16(nb + 8192 + soB, B16 + (size_t)(bn0 + rB) * KDIM + k0 + cB * 8);
            CP_COMMIT();
        }
        if (ch <= 13)      asm volatile("cp.async.wait_group 2;" ::: "memory");
        else if (ch == 14) asm volatile("cp.async.wait_group 1;" ::: "memory");
        else               asm volatile("cp.async.wait_group 0;" ::: "memory");
        __syncthreads();

        uint32_t base = sbase + (ch % NST) * STG1;

#pragma unroll
        for (int ks = 0; ks < 2; ks++) {
            uint32_t af[2][4], bf[4][2];
#pragma unroll
            for (int mt = 0; mt < 2; mt++) {
                int row = wr * 32 + mt * 16 + ((g & 1) << 3) + lr;
                int c = ks * 2 + (g >> 1);
                uint32_t off = row * 64 + (SWZC(row, c) << 4);
                LDSM_X4(af[mt][0], af[mt][1], af[mt][2], af[mt][3], base + off);
            }
#pragma unroll
            for (int np = 0; np < 2; np++) {
                int row = wc * 32 + np * 16 + ((g >> 1) << 3) + lr;
                int c = ks * 2 + (g & 1);
                uint32_t off = row * 64 + (SWZC(row, c) << 4);
                uint32_t r0, r1, r2, r3;
                LDSM_X4(r0, r1, r2, r3, base + 8192 + off);
                bf[np * 2][0] = r0; bf[np * 2][1] = r1;
                bf[np * 2 + 1][0] = r2; bf[np * 2 + 1][1] = r3;
            }
#pragma unroll
            for (int mt = 0; mt < 2; mt++)
#pragma unroll
                for (int nt = 0; nt < 4; nt++)
                    MMA16816(acc[mt][nt], af[mt], bf[nt]);
        }
    }

#pragma unroll
    for (int mt = 0; mt < 2; mt++) {
#pragma unroll
        for (int nt = 0; nt < 4; nt++) {
            int gm0 = m0 + wr * 32 + mt * 16 + (lane >> 2);
            int gn = bn0 + wc * 32 + nt * 8 + ((lane & 3) << 1);
#pragma unroll
            for (int half = 0; half < 2; half++) {
                int gm = gm0 + half * 8;
                float v0 = acc[mt][nt][half * 2], v1 = acc[mt][nt][half * 2 + 1];
                if (MODE == 0) {
                    v0 += bias[gn]; v1 += bias[gn + 1];
                    *(float2*)(Cf + (size_t)gm * Nout + gn) = make_float2(v0, v1);
                } else {
                    *(__half2*)(C16 + (size_t)gm * Nout + gn) =
                        __halves2half2(__float2half_rn(v0), __float2half_rn(v1));
                }
            }
        }
    }
}

// ---------------- fp32 -> fp16 ---------------------------------------------------
__global__ __launch_bounds__(256) void cvt_w16(
    const float* __restrict__ src, __half* __restrict__ dst, int n4)
{
    for (int i = blockIdx.x * 256 + threadIdx.x; i < n4; i += gridDim.x * 256) {
        float4 v = ((const float4*)src)[i];
        ((__half2*)dst)[2 * i]     = __halves2half2(__float2half_rn(v.x), __float2half_rn(v.y));
        ((__half2*)dst)[2 * i + 1] = __halves2half2(__float2half_rn(v.z), __float2half_rn(v.w));
    }
}

// ---------------- coalesced V transpose ------------------------------------------
__global__ __launch_bounds__(256) void v_transpose()
{
    __shared__ __half tile[64][72];
    int t0 = blockIdx.x * 64;
    int bh = blockIdx.y;
    int b = bh >> 3, h = bh & 7;
    int tid = threadIdx.x;
    int r = tid >> 3, cg = tid & 7;
#pragma unroll
    for (int it = 0; it < 2; it++) {
        int rr = r + it * 32;
        *(uint4*)&tile[rr][cg * 8] =
            *(const uint4*)(g_qkv16 + (size_t)(b * NTOK + t0 + rr) * QKVW + 1024 + h * 64 + cg * 8);
    }
    __syncthreads();
#pragma unroll
    for (int it = 0; it < 2; it++) {
        int dd = r + it * 32;
        __half vals[8];
#pragma unroll
        for (int i = 0; i < 8; i++) vals[i] = tile[cg * 8 + i][dd];
        *(uint4*)(g_v16t + ((size_t)bh * 64 + dd) * NTOK + t0 + cg * 8) = *(uint4*)vals;
    }
}

// ---------------- pooling: q -> at16 (x0.125, pad rows zero) ---------------------
__global__ __launch_bounds__(256) void pool_kernel()
{
    int b = blockIdx.x, a = blockIdx.y;
    if (a >= AG) {
        for (int c = threadIdx.x; c < CCH; c += 256)
            g_at16[(((b * 8 + (c >> 6)) * 64) + a) * 64 + (c & 63)] = __float2half(0.f);
        return;
    }
    int p1 = a / 7, p2 = a % 7;
    for (int c = threadIdx.x; c < CCH; c += 256) {
        float s = 0.f;
#pragma unroll
        for (int r = 0; r < 8; r++)
#pragma unroll
            for (int ss = 0; ss < 8; ss++)
                s += __half2float(g_qkv16[((size_t)(b * NTOK + (p1 * 8 + r) * HW + p2 * 8 + ss)) * QKVW + c]);
        g_at16[(((b * 8 + (c >> 6)) * 64) + a) * 64 + (c & 63)] =
            __float2half_rn(s * (1.0f / 64.0f) * 0.125f);
    }
}

// ---------------- jax bilinear resize + bias folding, fp16 out -------------------
__device__ __forceinline__ void lin_w(int o, int& i0, int& i1, float& w0, float& w1)
{
    float p = (o + 0.5f) * 0.125f - 0.5f;
    float fp = floorf(p);
    int i = (int)fp;
    float f = p - fp;
    if (i < 0)       { i0 = 0; i1 = 0; w0 = 1.f; w1 = 0.f; }
    else if (i >= 6) { i0 = 6; i1 = 6; w0 = 1.f; w1 = 0.f; }
    else             { i0 = i; i1 = i + 1; w0 = 1.f - f; w1 = f; }
}

__global__ __launch_bounds__(256) void bias_resize_kernel(
    const float* __restrict__ an, const float* __restrict__ na,
    const float* __restrict__ ahb, const float* __restrict__ awb,
    const float* __restrict__ hab, const float* __restrict__ wab)
{
    int a = blockIdx.x, h = blockIdx.y, src = blockIdx.z;
    const float* S = (src == 0 ? an : na) + (h * AG + a) * 49;
    __shared__ float s[49];
    if (threadIdx.x < 49) s[threadIdx.x] = S[threadIdx.x];
    __syncthreads();
    for (int o = threadIdx.x; o < NTOK; o += 256) {
        int oh = o / HW, ow = o % HW;
        int r0, r1, c0, c1; float wr0, wr1, wc0, wc1;
        lin_w(oh, r0, r1, wr0, wr1);
        lin_w(ow, c0, c1, wc0, wc1);
        float v = wr0 * (wc0 * s[r0 * 7 + c0] + wc1 * s[r0 * 7 + c1]) +
                  wr1 * (wc0 * s[r1 * 7 + c0] + wc1 * s[r1 * 7 + c1]);
        if (src == 0) {
            v += ahb[(h * AG + a) * HW + oh] + awb[(h * AG + a) * HW + ow];
            g_PB1h[((size_t)(h * AG + a)) * NTOK + o] = __float2half_rn(v);
        } else {
            v += hab[(h * HW + oh) * AG + a] + wab[(h * HW + ow) * AG + a];
            g_NB1Th[((size_t)h * NTOK + o) * 64 + a] = __float2half_rn(v);
        }
    }
}

// ---------------- agent logits via MMA -------------------------------------------
__global__ __launch_bounds__(128) void agent_logits_mma()
{
    __shared__ __align__(1024) char sm[16384];
    int bh = blockIdx.y, b = bh >> 3, h = bh & 7;
    int i0 = blockIdx.x * 64;
    int tid = threadIdx.x, wid = tid >> 5, lane = tid & 31;
    int wr = wid >> 1, wc = wid & 1;
    uint32_t sbase = smem_u32(sm);

    const __half* atp = g_at16 + (size_t)bh * 64 * 64;
#pragma unroll
    for (int it = 0; it < 4; it++) {
        int idx = tid + it * 128;
        int r = idx >> 3, c = idx & 7;
        cpa16(sbase + r * 128 + (SW8(r, c) << 4), atp + r * 64 + c * 8);
        cpa16(sbase + 8192 + r * 128 + (SW8(r, c) << 4),
              g_qkv16 + (size_t)(b * NTOK + i0 + r) * QKVW + 512 + h * 64 + c * 8);
    }
    CP_COMMIT(); CP_WAIT0();
    __syncthreads();

    int g = lane >> 3, lr = lane & 7;
    float acc[2][4][4] = {};
#pragma unroll
    for (int ks = 0; ks < 4; ks++) {
        uint32_t af[2][4], bf[4][2];
#pragma unroll
        for (int mt = 0; mt < 2; mt++) {
            int row = wr * 32 + mt * 16 + ((g & 1) << 3) + lr;
            int c = ks * 2 + (g >> 1);
            LDSM_X4(af[mt][0], af[mt][1], af[mt][2], af[mt][3],
                    sbase + row * 128 + (SW8(row, c) << 4));
        }
#pragma unroll
        for (int np = 0; np < 2; np++) {
            int row = wc * 32 + np * 16 + ((g >> 1) << 3) + lr;
            int c = ks * 2 + (g & 1);
            uint32_t r0, r1, r2, r3;
            LDSM_X4(r0, r1, r2, r3, sbase + 8192 + row * 128 + (SW8(row, c) << 4));
            bf[np * 2][0] = r0; bf[np * 2][1] = r1;
            bf[np * 2 + 1][0] = r2; bf[np * 2 + 1][1] = r3;
        }
#pragma unroll
        for (int mt = 0; mt < 2; mt++)
#pragma unroll
            for (int nt = 0; nt < 4; nt++)
                MMA16816(acc[mt][nt], af[mt], bf[nt]);
    }

#pragma unroll
    for (int mt = 0; mt < 2; mt++)
#pragma unroll
        for (int nt = 0; nt < 4; nt++)
#pragma unroll
            for (int half = 0; half < 2; half++) {
                int a = wr * 32 + mt * 16 + (lane >> 2) + half * 8;
                if (a >= AG) continue;
                int t = i0 + wc * 32 + nt * 8 + ((lane & 3) << 1);
                size_t lbase = ((size_t)bh * AG + a) * NTOK + t;
                __half2 pb = *(const __half2*)(g_PB1h + ((size_t)(h * AG + a)) * NTOK + t);
                float v0 = acc[mt][nt][half * 2] + __low2float(pb);
                float v1 = acc[mt][nt][half * 2 + 1] + __high2float(pb);
                *(float2*)(g_LOG + lbase) = make_float2(v0, v1);
            }
}

// ---------------- row softmax, emits fp16 probs ----------------------------------
__global__ __launch_bounds__(256) void softmax_n_kernel()
{
    int row = blockIdx.x;
    int bh = row / AG, a = row % AG;
    const float* p = g_LOG + (size_t)row * NTOK;
    __half* po = g_p16 + ((size_t)bh * 64 + a) * NTOK;
    __shared__ float buf[NTOK];
    __shared__ float red[8];
    int tid = threadIdx.x;
    float m = -1e30f;
    for (int i = tid; i < NTOK; i += 256) { float v = p[i]; buf[i] = v; m = fmaxf(m, v); }
#pragma unroll
    for (int o = 16; o; o >>= 1) m = fmaxf(m, __shfl_xor_sync(~0u, m, o));
    if ((tid & 31) == 0) red[tid >> 5] = m;
    __syncthreads();
    m = fmaxf(fmaxf(fmaxf(red[0], red[1]), fmaxf(red[2], red[3])),
              fmaxf(fmaxf(red[4], red[5]), fmaxf(red[6], red[7])));
    __syncthreads();
    float s = 0.f;
    for (int i = tid; i < NTOK; i += 256) { float e = __expf(buf[i] - m); buf[i] = e; s += e; }
#pragma unroll
    for (int o = 16; o; o >>= 1) s += __shfl_xor_sync(~0u, s, o);
    if ((tid & 31) == 0) red[tid >> 5] = s;
    __syncthreads();
    s = red[0] + red[1] + red[2] + red[3] + red[4] + red[5] + red[6] + red[7];
    float inv = 1.0f / s;
    for (int i = tid; i < NTOK; i += 256) po[i] = __float2half_rn(buf[i] * inv);
}

// ---------------- agent_v via MMA, split-K ---------------------------------------
__global__ __launch_bounds__(128) void agent_v_mma()
{
    __shared__ __align__(1024) char sm[NST * 16384];
    int bh = blockIdx.x, sp = blockIdx.y;
    int kbeg = sp * 448;
    int tid = threadIdx.x, wid = tid >> 5, lane = tid & 31;
    int wr = wid >> 1, wc = wid & 1;
    uint32_t sbase = smem_u32(sm);
    const __half* pp = g_p16 + (size_t)bh * 64 * NTOK + kbeg;
    const __half* vp = g_v16t + (size_t)bh * 64 * NTOK + kbeg;

    int rl = tid >> 3, cl = tid & 7;

#pragma unroll
    for (int pc = 0; pc < 2; pc++) {
        uint32_t sb = sbase + pc * 16384;
#pragma unroll
        for (int it = 0; it < 4; it++) {
            int r = rl + it * 16;
            uint32_t o = (r << 7) + (SW8(r, cl) << 4);
            cpa16(sb + o, pp + (size_t)r * NTOK + pc * 64 + cl * 8);
            cpa16(sb + 8192 + o, vp + (size_t)r * NTOK + pc * 64 + cl * 8);
        }
        CP_COMMIT();
    }

    int g = lane >> 3, lr = lane & 7;
    float acc[2][4][4] = {};
    for (int ch = 0; ch < 7; ch++) {
        __syncthreads();
        if (ch + 2 < 7) {
            uint32_t nb = sbase + ((ch + 2) % NST) * 16384;
#pragma unroll
            for (int it = 0; it < 4; it++) {
                int r = rl + it * 16;
                uint32_t o = (r << 7) + (SW8(r, cl) << 4);
                cpa16(nb + o, pp + (size_t)r * NTOK + (ch + 2) * 64 + cl * 8);
                cpa16(nb + 8192 + o, vp + (size_t)r * NTOK + (ch + 2) * 64 + cl * 8);
            }
            CP_COMMIT();
        }
        if (ch <= 4)      asm volatile("cp.async.wait_group 2;" ::: "memory");
        else if (ch == 5) asm volatile("cp.async.wait_group 1;" ::: "memory");
        else              asm volatile("cp.async.wait_group 0;" ::: "memory");
        __syncthreads();

        uint32_t base = sbase + (ch % NST) * 16384;
#pragma unroll
        for (int ks = 0; ks < 4; ks++) {
            uint32_t af[2][4], bf[4][2];
#pragma unroll
            for (int mt = 0; mt < 2; mt++) {
                int row = wr * 32 + mt * 16 + ((g & 1) << 3) + lr;
                int c = ks * 2 + (g >> 1);
                LDSM_X4(af[mt][0], af[mt][1], af[mt][2], af[mt][3],
                        base + row * 128 + (SW8(row, c) << 4));
            }
#pragma unroll
            for (int np = 0; np < 2; np++) {
                int row = wc * 32 + np * 16 + ((g >> 1) << 3) + lr;
                int c = ks * 2 + (g & 1);
                uint32_t r0, r1, r2, r3;
                LDSM_X4(r0, r1, r2, r3, base + 8192 + row * 128 + (SW8(row, c) << 4));
                bf[np * 2][0] = r0; bf[np * 2][1] = r1;
                bf[np * 2 + 1][0] = r2; bf[np * 2 + 1][1] = r3;
            }
#pragma unroll
            for (int mt = 0; mt < 2; mt++)
#pragma unroll
                for (int nt = 0; nt < 4; nt++)
                    MMA16816(acc[mt][nt], af[mt], bf[nt]);
        }
    }

#pragma unroll
    for (int mt = 0; mt < 2; mt++)
#pragma unroll
        for (int nt = 0; nt < 4; nt++)
#pragma unroll
            for (int half = 0; half < 2; half++) {
                int a = wr * 32 + mt * 16 + (lane >> 2) + half * 8;
                if (a >= AG) continue;
                int d = wc * 32 + nt * 8 + ((lane & 3) << 1);
                size_t o = ((size_t)sp * 128 + bh) * (AG * HD) + a * HD + d;
                *(float2*)(g_AVP + o) =
                    make_float2(acc[mt][nt][half * 2], acc[mt][nt][half * 2 + 1]);
            }
}

// ---------------- reduce partials -> AV^T fp16 -----------------------------------
__global__ __launch_bounds__(256) void avp_reduce_kernel()
{
    int i = blockIdx.x * 256 + threadIdx.x;
    if (i >= 128 * 64 * 64) return;
    int bh = i >> 12, rest = i & 4095, d = rest >> 6, a = rest & 63;
    float s = 0.f;
    if (a < AG) {
#pragma unroll
        for (int sp = 0; sp < 7; sp++)
            s += g_AVP[((size_t)sp * 128 + bh) * (AG * HD) + a * HD + d];
    }
    g_avt16[((size_t)bh * 64 + d) * 64 + a] = __float2half_rn(s);
}

// ---------------- q-side: MMA logits + reg softmax + MMA out ---------------------
__global__ __launch_bounds__(128) void qside_mma()
{
    __shared__ __align__(1024) char sm[32768];
    int bh = blockIdx.y, b = bh >> 3, h = bh & 7;
    int i0 = blockIdx.x * 64;
    int tid = threadIdx.x, wid = tid >> 5, lane = tid & 31;
    uint32_t sQ = smem_u32(sm), sAT = sQ + 8192, sAVT = sQ + 16384, sP = sQ + 24576;

    const __half* atp = g_at16 + (size_t)bh * 64 * 64;
    const __half* avtp = g_avt16 + (size_t)bh * 64 * 64;
#pragma unroll
    for (int it = 0; it < 4; it++) {
        int idx = tid + it * 128;
        int r = idx >> 3, c = idx & 7;
        uint32_t o = r * 128 + (SW8(r, c) << 4);
        cpa16(sQ + o, g_qkv16 + (size_t)(b * NTOK + i0 + r) * QKVW + h * 64 + c * 8);
        cpa16(sAT + o, atp + r * 64 + c * 8);
        cpa16(sAVT + o, avtp + r * 64 + c * 8);
    }
    CP_COMMIT(); CP_WAIT0();
    __syncthreads();

    int g = lane >> 3, lr = lane & 7;
    float acc1[8][4] = {};
#pragma unroll
    for (int ks = 0; ks < 4; ks++) {
        uint32_t af[4], bf[8][2];
        {
            int row = wid * 16 + ((g & 1) << 3) + lr;
            int c = ks * 2 + (g >> 1);
            LDSM_X4(af[0], af[1], af[2], af[3], sQ + row * 128 + (SW8(row, c) << 4));
        }
#pragma unroll
        for (int np = 0; np < 4; np++) {
            int row = np * 16 + ((g >> 1) << 3) + lr;
            int c = ks * 2 + (g & 1);
            uint32_t r0, r1, r2, r3;
            LDSM_X4(r0, r1, r2, r3, sAT + row * 128 + (SW8(row, c) << 4));
            bf[np * 2][0] = r0; bf[np * 2][1] = r1;
            bf[np * 2 + 1][0] = r2; bf[np * 2 + 1][1] = r3;
        }
#pragma unroll
        for (int nt = 0; nt < 8; nt++)
            MMA16816(acc1[nt], af, bf[nt]);
    }

    int r1 = wid * 16 + (lane >> 2), r2 = r1 + 8;
    int t1 = i0 + r1, t2 = i0 + r2;
#pragma unroll
    for (int nt = 0; nt < 8; nt++) {
        int abase = nt * 8 + ((lane & 3) << 1);
        __half2 b1 = *(const __half2*)(g_NB1Th + ((size_t)h * NTOK + t1) * 64 + abase);
        __half2 b2 = *(const __half2*)(g_NB1Th + ((size_t)h * NTOK + t2) * 64 + abase);
        acc1[nt][0] += __low2float(b1); acc1[nt][1] += __high2float(b1);
        acc1[nt][2] += __low2float(b2); acc1[nt][3] += __high2float(b2);
        if (abase >= AG) {
            acc1[nt][0] = acc1[nt][1] = acc1[nt][2] = acc1[nt][3] = -INFINITY;
        } else if (abase + 1 >= AG) {
            acc1[nt][1] = acc1[nt][3] = -INFINITY;
        }
    }
    float m1 = -1e30f, m2 = -1e30f;
#pragma unroll
    for (int nt = 0; nt < 8; nt++) {
        m1 = fmaxf(m1, fmaxf(acc1[nt][0], acc1[nt][1]));
        m2 = fmaxf(m2, fmaxf(acc1[nt][2], acc1[nt][3]));
    }
    m1 = fmaxf(m1, __shfl_xor_sync(~0u, m1, 1)); m1 = fmaxf(m1, __shfl_xor_sync(~0u, m1, 2));
    m2 = fmaxf(m2, __shfl_xor_sync(~0u, m2, 1)); m2 = fmaxf(m2, __shfl_xor_sync(~0u, m2, 2));
    float s1 = 0.f, s2 = 0.f;
#pragma unroll
    for (int nt = 0; nt < 8; nt++) {
        acc1[nt][0] = __expf(acc1[nt][0] - m1); s1 += acc1[nt][0];
        acc1[nt][1] = __expf(acc1[nt][1] - m1); s1 += acc1[nt][1];
        acc1[nt][2] = __expf(acc1[nt][2] - m2); s2 += acc1[nt][2];
        acc1[nt][3] = __expf(acc1[nt][3] - m2); s2 += acc1[nt][3];
    }
    s1 += __shfl_xor_sync(~0u, s1, 1); s1 += __shfl_xor_sync(~0u, s1, 2);
    s2 += __shfl_xor_sync(~0u, s2, 1); s2 += __shfl_xor_sync(~0u, s2, 2);
    float i1 = 1.0f / s1, i2 = 1.0f / s2;

#pragma unroll
    for (int nt = 0; nt < 8; nt++) {
        int colb = nt * 8 + ((lane & 3) << 1);
        uint32_t o1 = r1 * 128 + (SW8(r1, nt) << 4) + (colb & 7) * 2;
        uint32_t o2 = r2 * 128 + (SW8(r2, nt) << 4) + (colb & 7) * 2;
        __half2 p1 = __halves2half2(__float2half_rn(acc1[nt][0] * i1),
                                    __float2half_rn(acc1[nt][1] * i1));
        __half2 p2 = __halves2half2(__float2half_rn(acc1[nt][2] * i2),
                                    __float2half_rn(acc1[nt][3] * i2));
        asm volatile("st.shared.b32 [%0], %1;" :: "r"(sP + o1), "r"(*(uint32_t*)&p1));
        asm volatile("st.shared.b32 [%0], %1;" :: "r"(sP + o2), "r"(*(uint32_t*)&p2));
    }
    __syncwarp();

    float acc2[8][4] = {};
#pragma unroll
    for (int ks = 0; ks < 4; ks++) {
        uint32_t af[4], bf[8][2];
        {
            int row = wid * 16 + ((g & 1) << 3) + lr;
            int c = ks * 2 + (g >> 1);
            LDSM_X4(af[0], af[1], af[2], af[3], sP + row * 128 + (SW8(row, c) << 4));
        }
#pragma unroll
        for (int np = 0; np < 4; np++) {
            int row = np * 16 + ((g >> 1) << 3) + lr;
            int c = ks * 2 + (g & 1);
            uint32_t r0, r1x, r2x, r3;
            LDSM_X4(r0, r1x, r2x, r3, sAVT + row * 128 + (SW8(row, c) << 4));
            bf[np * 2][0] = r0; bf[np * 2][1] = r1x;
            bf[np * 2 + 1][0] = r2x; bf[np * 2 + 1][1] = r3;
        }
#pragma unroll
        for (int nt = 0; nt < 8; nt++)
            MMA16816(acc2[nt], af, bf[nt]);
    }

#pragma unroll
    for (int nt = 0; nt < 8; nt++) {
        int d = nt * 8 + ((lane & 3) << 1);
        *(__half2*)(g_ao16 + (size_t)(b * NTOK + t1) * CCH + h * 64 + d) =
            __halves2half2(__float2half_rn(acc2[nt][0]), __float2half_rn(acc2[nt][1]));
        *(__half2*)(g_ao16 + (size_t)(b * NTOK + t2) * CCH + h * 64 + d) =
            __halves2half2(__float2half_rn(acc2[nt][2]), __float2half_rn(acc2[nt][3]));
    }
}

// ---------------- 3x3 depthwise conv + attn-out add -> fp16 proj input -----------
__global__ __launch_bounds__(256) void dwc_kernel(
    const float* __restrict__ dwc_w, const float* __restrict__ dwc_b)
{
    int oh = blockIdx.x, b = blockIdx.y;
    __shared__ float w_s[CCH * 9];
    __shared__ float b_s[CCH];
    int tid = threadIdx.x;
    for (int t = tid; t < CCH * 9; t += 256) w_s[t] = dwc_w[t];
    for (int t = tid; t < CCH; t += 256) b_s[t] = dwc_b[t];
    __syncthreads();
    for (int idx = tid; idx < HW * CCH; idx += 256) {
        int ow = idx >> 9, c = idx & 511;
        float acc = b_s[c];
#pragma unroll
        for (int ky = 0; ky < 3; ky++) {
            int h2 = oh + ky - 1;
            if (h2 < 0 || h2 >= HW) continue;
#pragma unroll
            for (int kx = 0; kx < 3; kx++) {
                int w2 = ow + kx - 1;
                if (w2 < 0 || w2 >= HW) continue;
                acc += __half2float(g_qkv16[((size_t)(b * NTOK + h2 * HW + w2)) * QKVW + 1024 + c])
                     * w_s[c * 9 + ky * 3 + kx];
            }
        }
        size_t gi = ((size_t)(b * NTOK + oh * HW + ow)) * CCH + c;
        g_ahi[gi] = __float2half_rn(__half2float(g_ao16[gi]) + acc);
    }
}

// ---------------- launch ---------------------------------------------------------
extern "C" void kernel_launch(void* const* d_in, const int* in_sizes, int n_in,
                              void* d_out, int out_size)
{
    const float* x = (const float*)d_in[0];
    int off = 1;
    if (n_in >= 15 && in_sizes[1] == 1) off = 3;
    const float* q_w    = (const float*)d_in[off + 0];
    const float* kv_w   = (const float*)d_in[off + 1];
    const float* proj_w = (const float*)d_in[off + 2];
    const float* proj_b = (const float*)d_in[off + 3];
    const float* dwc_w  = (const float*)d_in[off + 4];
    const float* dwc_b  = (const float*)d_in[off + 5];
    const float* an_b   = (const float*)d_in[off + 6];
    const float* na_b   = (const float*)d_in[off + 7];
    const float* ah_b   = (const float*)d_in[off + 8];
    const float* aw_b   = (const float*)d_in[off + 9];
    const float* ha_b   = (const float*)d_in[off + 10];
    const float* wa_b   = (const float*)d_in[off + 11];
    float* out = (float*)d_out;

    __half *x16, *qkv16, *ahi, *wqkv16, *wp16;
    cudaGetSymbolAddress((void**)&x16, g_x16);
    cudaGetSymbolAddress((void**)&qkv16, g_qkv16);
    cudaGetSymbolAddress((void**)&ahi, g_ahi);
    cudaGetSymbolAddress((void**)&wqkv16, g_wqkv16);
    cudaGetSymbolAddress((void**)&wp16, g_wp16);

    static int smem_set = 0;
    if (!smem_set) {
        cudaFuncSetAttribute(gemm_tc<0>, cudaFuncAttributeMaxDynamicSharedMemorySize, NST * STG1);
        cudaFuncSetAttribute(gemm_tc<1>, cudaFuncAttributeMaxDynamicSharedMemorySize, NST * STG1);
        smem_set = 1;
    }

    cvt_w16<<<2048, 256>>>(x, x16, MROWS * CCH / 4);
    cvt_w16<<<256, 256>>>(q_w, wqkv16, CCH * CCH / 4);
    cvt_w16<<<512, 256>>>(kv_w, wqkv16 + CCH * CCH, 2 * CCH * CCH / 4);
    cvt_w16<<<256, 256>>>(proj_w, wp16, CCH * CCH / 4);
    bias_resize_kernel<<<dim3(AG, HEADS, 2), 256>>>(an_b, na_b, ah_b, aw_b, ha_b, wa_b);

    gemm_tc<1><<<dim3(24, MROWS / 128), 256, NST * STG1>>>(
        x16, wqkv16, nullptr, nullptr, qkv16, QKVW);

    v_transpose<<<dim3(NTOK / 64, NB * HEADS), 256>>>();
    pool_kernel<<<dim3(NB, 64), 256>>>();
    agent_logits_mma<<<dim3(NTOK / 64, NB * HEADS), 128>>>();
    softmax_n_kernel<<<NB * HEADS * AG, 256>>>();
    agent_v_mma<<<dim3(NB * HEADS, 7), 128>>>();
    avp_reduce_kernel<<<(128 * 64 * 64 + 255) / 256, 256>>>();
    qside_mma<<<dim3(NTOK / 64, NB * HEADS), 128>>>();
    dwc_kernel<<<dim3(HW, NB), 256>>>(dwc_w, dwc_b);

    gemm_tc<0><<<dim3(8, MROWS / 128), 256, NST * STG1>>>(
        ahi, wp16, out, proj_b, nullptr, 512);
}

// round 13
// speedup vs baseline: 5.2281x; 1.0631x over previous
#include <cuda_runtime.h>
#include <cuda_fp16.h>
#include <math.h>
#include <stdint.h>

#define HEADS 8
#define HD 64
#define CCH 512
#define HW 56
#define NTOK 3136
#define AG 49
#define NB 16
#define MROWS (NB*NTOK)
#define KDIM 512
#define QKVW 1536
#define NTILE 49            // NTOK / 64

// ---------------- scratch (static device globals; zero-initialized) --------------
__device__ float g_AVP[7 * NB * HEADS * AG * HD];
__device__ float2 g_TMS[(size_t)NB * HEADS * 64 * NTILE];   // per-tile (max, sum)
__device__ float g_F[(size_t)NB * HEADS * 64 * NTILE];      // per-tile softmax factor
__device__ __half g_PB1h[HEADS * AG * NTOK];
__device__ __half g_NB1Th[HEADS * NTOK * 64];
__device__ __half g_x16[(size_t)MROWS * CCH];
__device__ __half g_qkv16[(size_t)MROWS * QKVW];
__device__ __half g_v16t[(size_t)NB * HEADS * HD * NTOK];
__device__ __half g_at16[NB * HEADS * 64 * 64];
__device__ __half g_p16[(size_t)NB * HEADS * 64 * NTOK];    // e = exp(l - tilemax); pad rows 0
__device__ __half g_avt16[NB * HEADS * 64 * 64];
__device__ __half g_ao16[(size_t)MROWS * CCH];
__device__ __half g_ahi[(size_t)MROWS * CCH];
__device__ __half g_wqkv16[QKVW * CCH];
__device__ __half g_wp16[CCH * CCH];

// ================= low-level helpers =================
__device__ __forceinline__ uint32_t smem_u32(const void* p) {
    uint32_t a;
    asm("{ .reg .u64 t; cvta.to.shared.u64 t, %1; cvt.u32.u64 %0, t; }" : "=r"(a) : "l"(p));
    return a;
}
__device__ __forceinline__ void cpa16(uint32_t s, const void* g) {
    asm volatile("cp.async.cg.shared.global [%0], [%1], 16;" :: "r"(s), "l"(g));
}
#define CP_COMMIT() asm volatile("cp.async.commit_group;" ::: "memory")
#define CP_WAIT0()  asm volatile("cp.async.wait_group 0;" ::: "memory")

#define LDSM_X4(r0, r1, r2, r3, a) \
    asm volatile("ldmatrix.sync.aligned.m8n8.x4.shared.b16 {%0,%1,%2,%3}, [%4];" \
                 : "=r"(r0), "=r"(r1), "=r"(r2), "=r"(r3) : "r"(a))

#define MMA16816(d, a, b) \
    asm volatile("mma.sync.aligned.m16n8k16.row.col.f32.f16.f16.f32 " \
                 "{%0,%1,%2,%3}, {%4,%5,%6,%7}, {%8,%9}, {%0,%1,%2,%3};" \
                 : "+f"((d)[0]), "+f"((d)[1]), "+f"((d)[2]), "+f"((d)[3]) \
                 : "r"((a)[0]), "r"((a)[1]), "r"((a)[2]), "r"((a)[3]), \
                   "r"((b)[0]), "r"((b)[1]))

#define SWZC(r, c) ((c) ^ (((r) >> 1) & 3))
#define SW8(r, c) ((c) ^ ((r) & 7))

#define NST 3
#define STG1 12288u

// ================= fp16 tensor-core GEMM, 1-term ================================
template<int MODE>
__global__ void __launch_bounds__(256, 3) gemm_tc(
    const __half* __restrict__ A16, const __half* __restrict__ B16,
    float* __restrict__ Cf, const float* __restrict__ bias,
    __half* __restrict__ C16, int Nout)
{
    extern __shared__ __align__(1024) char smem[];
    int tid = threadIdx.x;
    int wid = tid >> 5, lane = tid & 31;
    int bn0 = blockIdx.x * 64, m0 = blockIdx.y * 128;
    int wr = wid >> 1, wc = wid & 1;
    uint32_t sbase = smem_u32(smem);

    float acc[2][4][4] = {};

    int rA0 = tid >> 2,         cA0 = tid & 3;
    int rA1 = (tid + 256) >> 2, cA1 = tid & 3;
    int rB  = tid >> 2,         cB  = tid & 3;
    uint32_t soA0 = rA0 * 64 + (SWZC(rA0, cA0) << 4);
    uint32_t soA1 = rA1 * 64 + (SWZC(rA1, cA1) << 4);
    uint32_t soB  = rB * 64 + (SWZC(rB, cB) << 4);

#pragma unroll
    for (int pc = 0; pc < 2; pc++) {
        int k0 = pc * 32;
        uint32_t sb = sbase + pc * STG1;
        cpa16(sb + soA0, A16 + (size_t)(m0 + rA0) * KDIM + k0 + cA0 * 8);
        cpa16(sb + soA1, A16 + (size_t)(m0 + rA1) * KDIM + k0 + cA1 * 8);
        cpa16(sb + 8192 + soB, B16 + (size_t)(bn0 + rB) * KDIM + k0 + cB * 8);
        CP_COMMIT();
    }

    int g = lane >> 3, lr = lane & 7;

    for (int ch = 0; ch < 16; ch++) {
        __syncthreads();
        if (ch + 2 < 16) {
            int k0 = (ch + 2) * 32;
            uint32_t nb = sbase + ((ch + 2) % NST) * STG1;
            cpa16(nb + soA0, A16 + (size_t)(m0 + rA0) * KDIM + k0 + cA0 * 8);
            cpa16(nb + soA1, A16 + (size_t)(m0 + rA1) * KDIM + k0 + cA1 * 8);
            cpa16(nb + 8192 + soB, B16 + (size_t)(bn0 + rB) * KDIM + k0 + cB * 8);
            CP_COMMIT();
        }
        if (ch <= 13)      asm volatile("cp.async.wait_group 2;" ::: "memory");
        else if (ch == 14) asm volatile("cp.async.wait_group 1;" ::: "memory");
        else               asm volatile("cp.async.wait_group 0;" ::: "memory");
        __syncthreads();

        uint32_t base = sbase + (ch % NST) * STG1;

#pragma unroll
        for (int ks = 0; ks < 2; ks++) {
            uint32_t af[2][4], bf[4][2];
#pragma unroll
            for (int mt = 0; mt < 2; mt++) {
                int row = wr * 32 + mt * 16 + ((g & 1) << 3) + lr;
                int c = ks * 2 + (g >> 1);
                uint32_t off = row * 64 + (SWZC(row, c) << 4);
                LDSM_X4(af[mt][0], af[mt][1], af[mt][2], af[mt][3], base + off);
            }
#pragma unroll
            for (int np = 0; np < 2; np++) {
                int row = wc * 32 + np * 16 + ((g >> 1) << 3) + lr;
                int c = ks * 2 + (g & 1);
                uint32_t off = row * 64 + (SWZC(row, c) << 4);
                uint32_t r0, r1, r2, r3;
                LDSM_X4(r0, r1, r2, r3, base + 8192 + off);
                bf[np * 2][0] = r0; bf[np * 2][1] = r1;
                bf[np * 2 + 1][0] = r2; bf[np * 2 + 1][1] = r3;
            }
#pragma unroll
            for (int mt = 0; mt < 2; mt++)
#pragma unroll
                for (int nt = 0; nt < 4; nt++)
                    MMA16816(acc[mt][nt], af[mt], bf[nt]);
        }
    }

#pragma unroll
    for (int mt = 0; mt < 2; mt++) {
#pragma unroll
        for (int nt = 0; nt < 4; nt++) {
            int gm0 = m0 + wr * 32 + mt * 16 + (lane >> 2);
            int gn = bn0 + wc * 32 + nt * 8 + ((lane & 3) << 1);
#pragma unroll
            for (int half = 0; half < 2; half++) {
                int gm = gm0 + half * 8;
                float v0 = acc[mt][nt][half * 2], v1 = acc[mt][nt][half * 2 + 1];
                if (MODE == 0) {
                    v0 += bias[gn]; v1 += bias[gn + 1];
                    *(float2*)(Cf + (size_t)gm * Nout + gn) = make_float2(v0, v1);
                } else {
                    *(__half2*)(C16 + (size_t)gm * Nout + gn) =
                        __halves2half2(__float2half_rn(v0), __float2half_rn(v1));
                }
            }
        }
    }
}

// ---------------- fp32 -> fp16 ---------------------------------------------------
__global__ __launch_bounds__(256) void cvt_w16(
    const float* __restrict__ src, __half* __restrict__ dst, int n4)
{
    for (int i = blockIdx.x * 256 + threadIdx.x; i < n4; i += gridDim.x * 256) {
        float4 v = ((const float4*)src)[i];
        ((__half2*)dst)[2 * i]     = __halves2half2(__float2half_rn(v.x), __float2half_rn(v.y));
        ((__half2*)dst)[2 * i + 1] = __halves2half2(__float2half_rn(v.z), __float2half_rn(v.w));
    }
}

// ---------------- coalesced V transpose ------------------------------------------
__global__ __launch_bounds__(256) void v_transpose()
{
    __shared__ __half tile[64][72];
    int t0 = blockIdx.x * 64;
    int bh = blockIdx.y;
    int b = bh >> 3, h = bh & 7;
    int tid = threadIdx.x;
    int r = tid >> 3, cg = tid & 7;
#pragma unroll
    for (int it = 0; it < 2; it++) {
        int rr = r + it * 32;
        *(uint4*)&tile[rr][cg * 8] =
            *(const uint4*)(g_qkv16 + (size_t)(b * NTOK + t0 + rr) * QKVW + 1024 + h * 64 + cg * 8);
    }
    __syncthreads();
#pragma unroll
    for (int it = 0; it < 2; it++) {
        int dd = r + it * 32;
        __half vals[8];
#pragma unroll
        for (int i = 0; i < 8; i++) vals[i] = tile[cg * 8 + i][dd];
        *(uint4*)(g_v16t + ((size_t)bh * 64 + dd) * NTOK + t0 + cg * 8) = *(uint4*)vals;
    }
}

// ---------------- pooling: q -> at16 (x0.125, pad rows zero) ---------------------
__global__ __launch_bounds__(256) void pool_kernel()
{
    int b = blockIdx.x, a = blockIdx.y;
    if (a >= AG) {
        for (int c = threadIdx.x; c < CCH; c += 256)
            g_at16[(((b * 8 + (c >> 6)) * 64) + a) * 64 + (c & 63)] = __float2half(0.f);
        return;
    }
    int p1 = a / 7, p2 = a % 7;
    for (int c = threadIdx.x; c < CCH; c += 256) {
        float s = 0.f;
#pragma unroll
        for (int r = 0; r < 8; r++)
#pragma unroll
            for (int ss = 0; ss < 8; ss++)
                s += __half2float(g_qkv16[((size_t)(b * NTOK + (p1 * 8 + r) * HW + p2 * 8 + ss)) * QKVW + c]);
        g_at16[(((b * 8 + (c >> 6)) * 64) + a) * 64 + (c & 63)] =
            __float2half_rn(s * (1.0f / 64.0f) * 0.125f);
    }
}

// ---------------- jax bilinear resize + bias folding, fp16 out -------------------
__device__ __forceinline__ void lin_w(int o, int& i0, int& i1, float& w0, float& w1)
{
    float p = (o + 0.5f) * 0.125f - 0.5f;
    float fp = floorf(p);
    int i = (int)fp;
    float f = p - fp;
    if (i < 0)       { i0 = 0; i1 = 0; w0 = 1.f; w1 = 0.f; }
    else if (i >= 6) { i0 = 6; i1 = 6; w0 = 1.f; w1 = 0.f; }
    else             { i0 = i; i1 = i + 1; w0 = 1.f - f; w1 = f; }
}

__global__ __launch_bounds__(256) void bias_resize_kernel(
    const float* __restrict__ an, const float* __restrict__ na,
    const float* __restrict__ ahb, const float* __restrict__ awb,
    const float* __restrict__ hab, const float* __restrict__ wab)
{
    int a = blockIdx.x, h = blockIdx.y, src = blockIdx.z;
    const float* S = (src == 0 ? an : na) + (h * AG + a) * 49;
    __shared__ float s[49];
    if (threadIdx.x < 49) s[threadIdx.x] = S[threadIdx.x];
    __syncthreads();
    for (int o = threadIdx.x; o < NTOK; o += 256) {
        int oh = o / HW, ow = o % HW;
        int r0, r1, c0, c1; float wr0, wr1, wc0, wc1;
        lin_w(oh, r0, r1, wr0, wr1);
        lin_w(ow, c0, c1, wc0, wc1);
        float v = wr0 * (wc0 * s[r0 * 7 + c0] + wc1 * s[r0 * 7 + c1]) +
                  wr1 * (wc0 * s[r1 * 7 + c0] + wc1 * s[r1 * 7 + c1]);
        if (src == 0) {
            v += ahb[(h * AG + a) * HW + oh] + awb[(h * AG + a) * HW + ow];
            g_PB1h[((size_t)(h * AG + a)) * NTOK + o] = __float2half_rn(v);
        } else {
            v += hab[(h * HW + oh) * AG + a] + wab[(h * HW + ow) * AG + a];
            g_NB1Th[((size_t)h * NTOK + o) * 64 + a] = __float2half_rn(v);
        }
    }
}

// ---------------- agent logits + tile-local exp, stats out -----------------------
// warp wid handles agent rows wid*16..+15; cols = 64 tokens of this tile.
__global__ __launch_bounds__(128) void agent_logits_mma()
{
    __shared__ __align__(1024) char sm[16384];   // [AT 8KB][K 8KB]
    int bh = blockIdx.y, b = bh >> 3, h = bh & 7;
    int tile = blockIdx.x;
    int i0 = tile * 64;
    int tid = threadIdx.x, wid = tid >> 5, lane = tid & 31;
    uint32_t sAT = smem_u32(sm), sK = sAT + 8192;

    const __half* atp = g_at16 + (size_t)bh * 64 * 64;
#pragma unroll
    for (int it = 0; it < 4; it++) {
        int idx = tid + it * 128;
        int r = idx >> 3, c = idx & 7;
        uint32_t o = r * 128 + (SW8(r, c) << 4);
        cpa16(sAT + o, atp + r * 64 + c * 8);
        cpa16(sK + o, g_qkv16 + (size_t)(b * NTOK + i0 + r) * QKVW + 512 + h * 64 + c * 8);
    }
    CP_COMMIT(); CP_WAIT0();
    __syncthreads();

    int g = lane >> 3, lr = lane & 7;
    float acc1[8][4] = {};
#pragma unroll
    for (int ks = 0; ks < 4; ks++) {
        uint32_t af[4], bf[8][2];
        {
            int row = wid * 16 + ((g & 1) << 3) + lr;
            int c = ks * 2 + (g >> 1);
            LDSM_X4(af[0], af[1], af[2], af[3], sAT + row * 128 + (SW8(row, c) << 4));
        }
#pragma unroll
        for (int np = 0; np < 4; np++) {
            int row = np * 16 + ((g >> 1) << 3) + lr;
            int c = ks * 2 + (g & 1);
            uint32_t r0, r1, r2, r3;
            LDSM_X4(r0, r1, r2, r3, sK + row * 128 + (SW8(row, c) << 4));
            bf[np * 2][0] = r0; bf[np * 2][1] = r1;
            bf[np * 2 + 1][0] = r2; bf[np * 2 + 1][1] = r3;
        }
#pragma unroll
        for (int nt = 0; nt < 8; nt++)
            MMA16816(acc1[nt], af, bf[nt]);
    }

    int a1 = wid * 16 + (lane >> 2), a2 = a1 + 8;
    bool v1 = a1 < AG, v2 = a2 < AG;
    // add folded bias
#pragma unroll
    for (int nt = 0; nt < 8; nt++) {
        int tb = i0 + nt * 8 + ((lane & 3) << 1);
        if (v1) {
            __half2 pb = *(const __half2*)(g_PB1h + ((size_t)(h * AG + a1)) * NTOK + tb);
            acc1[nt][0] += __low2float(pb); acc1[nt][1] += __high2float(pb);
        }
        if (v2) {
            __half2 pb = *(const __half2*)(g_PB1h + ((size_t)(h * AG + a2)) * NTOK + tb);
            acc1[nt][2] += __low2float(pb); acc1[nt][3] += __high2float(pb);
        }
    }
    // per-row tile max (quad reduce)
    float m1 = -1e30f, m2 = -1e30f;
#pragma unroll
    for (int nt = 0; nt < 8; nt++) {
        m1 = fmaxf(m1, fmaxf(acc1[nt][0], acc1[nt][1]));
        m2 = fmaxf(m2, fmaxf(acc1[nt][2], acc1[nt][3]));
    }
    m1 = fmaxf(m1, __shfl_xor_sync(~0u, m1, 1)); m1 = fmaxf(m1, __shfl_xor_sync(~0u, m1, 2));
    m2 = fmaxf(m2, __shfl_xor_sync(~0u, m2, 1)); m2 = fmaxf(m2, __shfl_xor_sync(~0u, m2, 2));
    // exp + tile sums
    float s1 = 0.f, s2 = 0.f;
#pragma unroll
    for (int nt = 0; nt < 8; nt++) {
        acc1[nt][0] = __expf(acc1[nt][0] - m1); s1 += acc1[nt][0];
        acc1[nt][1] = __expf(acc1[nt][1] - m1); s1 += acc1[nt][1];
        acc1[nt][2] = __expf(acc1[nt][2] - m2); s2 += acc1[nt][2];
        acc1[nt][3] = __expf(acc1[nt][3] - m2); s2 += acc1[nt][3];
    }
    s1 += __shfl_xor_sync(~0u, s1, 1); s1 += __shfl_xor_sync(~0u, s1, 2);
    s2 += __shfl_xor_sync(~0u, s2, 1); s2 += __shfl_xor_sync(~0u, s2, 2);
    // store e values (fp16) and stats
#pragma unroll
    for (int nt = 0; nt < 8; nt++) {
        int tb = i0 + nt * 8 + ((lane & 3) << 1);
        if (v1)
            *(__half2*)(g_p16 + ((size_t)bh * 64 + a1) * NTOK + tb) =
                __halves2half2(__float2half_rn(acc1[nt][0]), __float2half_rn(acc1[nt][1]));
        if (v2)
            *(__half2*)(g_p16 + ((size_t)bh * 64 + a2) * NTOK + tb) =
                __halves2half2(__float2half_rn(acc1[nt][2]), __float2half_rn(acc1[nt][3]));
    }
    if ((lane & 3) == 0) {
        if (v1) g_TMS[((size_t)bh * 64 + a1) * NTILE + tile] = make_float2(m1, s1);
        if (v2) g_TMS[((size_t)bh * 64 + a2) * NTILE + tile] = make_float2(m2, s2);
    }
}

// ---------------- per-row softmax stats -> per-tile factors ----------------------
__global__ __launch_bounds__(64) void softmax_stats()
{
    int bh = blockIdx.x;
    int a = threadIdx.x;
    if (a >= AG) return;
    const float2* tms = g_TMS + ((size_t)bh * 64 + a) * NTILE;
    float gmax = -1e30f;
#pragma unroll 7
    for (int i = 0; i < NTILE; i++) gmax = fmaxf(gmax, tms[i].x);
    float total = 0.f;
#pragma unroll 7
    for (int i = 0; i < NTILE; i++) total += tms[i].y * __expf(tms[i].x - gmax);
    float inv = 1.0f / total;
    float* f = g_F + ((size_t)bh * 64 + a) * NTILE;
#pragma unroll 7
    for (int i = 0; i < NTILE; i++) f[i] = __expf(tms[i].x - gmax) * inv;
}

// ---------------- agent_v via MMA, split-K, per-tile factor fold -----------------
__global__ __launch_bounds__(128) void agent_v_mma()
{
    __shared__ __align__(1024) char sm[NST * 16384];
    int bh = blockIdx.x, sp = blockIdx.y;
    int kbeg = sp * 448;
    int tid = threadIdx.x, wid = tid >> 5, lane = tid & 31;
    int wr = wid >> 1, wc = wid & 1;
    uint32_t sbase = smem_u32(sm);
    const __half* pp = g_p16 + (size_t)bh * 64 * NTOK + kbeg;
    const __half* vp = g_v16t + (size_t)bh * 64 * NTOK + kbeg;

    int rl = tid >> 3, cl = tid & 7;

#pragma unroll
    for (int pc = 0; pc < 2; pc++) {
        uint32_t sb = sbase + pc * 16384;
#pragma unroll
        for (int it = 0; it < 4; it++) {
            int r = rl + it * 16;
            uint32_t o = (r << 7) + (SW8(r, cl) << 4);
            cpa16(sb + o, pp + (size_t)r * NTOK + pc * 64 + cl * 8);
            cpa16(sb + 8192 + o, vp + (size_t)r * NTOK + pc * 64 + cl * 8);
        }
        CP_COMMIT();
    }

    int g = lane >> 3, lr = lane & 7;
    int ra = lane >> 2;
    float acc[2][4][4] = {};
    for (int ch = 0; ch < 7; ch++) {
        __syncthreads();
        if (ch + 2 < 7) {
            uint32_t nb = sbase + ((ch + 2) % NST) * 16384;
#pragma unroll
            for (int it = 0; it < 4; it++) {
                int r = rl + it * 16;
                uint32_t o = (r << 7) + (SW8(r, cl) << 4);
                cpa16(nb + o, pp + (size_t)r * NTOK + (ch + 2) * 64 + cl * 8);
                cpa16(nb + 8192 + o, vp + (size_t)r * NTOK + (ch + 2) * 64 + cl * 8);
            }
            CP_COMMIT();
        }
        if (ch <= 4)      asm volatile("cp.async.wait_group 2;" ::: "memory");
        else if (ch == 5) asm volatile("cp.async.wait_group 1;" ::: "memory");
        else              asm volatile("cp.async.wait_group 0;" ::: "memory");
        __syncthreads();

        uint32_t base = sbase + (ch % NST) * 16384;
        int tileIdx = sp * 7 + ch;
        // per-row softmax factors for this tile (pad rows -> 0 from zero-init g_F)
        float fv[2][2];
#pragma unroll
        for (int mt = 0; mt < 2; mt++)
#pragma unroll
            for (int half = 0; half < 2; half++) {
                int a = wr * 32 + mt * 16 + ra + half * 8;
                fv[mt][half] = g_F[((size_t)bh * 64 + a) * NTILE + tileIdx];
            }

        float accc[2][4][4] = {};
#pragma unroll
        for (int ks = 0; ks < 4; ks++) {
            uint32_t af[2][4], bf[4][2];
#pragma unroll
            for (int mt = 0; mt < 2; mt++) {
                int row = wr * 32 + mt * 16 + ((g & 1) << 3) + lr;
                int c = ks * 2 + (g >> 1);
                LDSM_X4(af[mt][0], af[mt][1], af[mt][2], af[mt][3],
                        base + row * 128 + (SW8(row, c) << 4));
            }
#pragma unroll
            for (int np = 0; np < 2; np++) {
                int row = wc * 32 + np * 16 + ((g >> 1) << 3) + lr;
                int c = ks * 2 + (g & 1);
                uint32_t r0, r1, r2, r3;
                LDSM_X4(r0, r1, r2, r3, base + 8192 + row * 128 + (SW8(row, c) << 4));
                bf[np * 2][0] = r0; bf[np * 2][1] = r1;
                bf[np * 2 + 1][0] = r2; bf[np * 2 + 1][1] = r3;
            }
#pragma unroll
            for (int mt = 0; mt < 2; mt++)
#pragma unroll
                for (int nt = 0; nt < 4; nt++)
                    MMA16816(accc[mt][nt], af[mt], bf[nt]);
        }
#pragma unroll
        for (int mt = 0; mt < 2; mt++)
#pragma unroll
            for (int nt = 0; nt < 4; nt++) {
                acc[mt][nt][0] += fv[mt][0] * accc[mt][nt][0];
                acc[mt][nt][1] += fv[mt][0] * accc[mt][nt][1];
                acc[mt][nt][2] += fv[mt][1] * accc[mt][nt][2];
                acc[mt][nt][3] += fv[mt][1] * accc[mt][nt][3];
            }
    }

#pragma unroll
    for (int mt = 0; mt < 2; mt++)
#pragma unroll
        for (int nt = 0; nt < 4; nt++)
#pragma unroll
            for (int half = 0; half < 2; half++) {
                int a = wr * 32 + mt * 16 + (lane >> 2) + half * 8;
                if (a >= AG) continue;
                int d = wc * 32 + nt * 8 + ((lane & 3) << 1);
                size_t o = ((size_t)sp * 128 + bh) * (AG * HD) + a * HD + d;
                *(float2*)(g_AVP + o) =
                    make_float2(acc[mt][nt][half * 2], acc[mt][nt][half * 2 + 1]);
            }
}

// ---------------- reduce partials -> AV^T fp16 -----------------------------------
__global__ __launch_bounds__(256) void avp_reduce_kernel()
{
    int i = blockIdx.x * 256 + threadIdx.x;
    if (i >= 128 * 64 * 64) return;
    int bh = i >> 12, rest = i & 4095, d = rest >> 6, a = rest & 63;
    float s = 0.f;
    if (a < AG) {
#pragma unroll
        for (int sp = 0; sp < 7; sp++)
            s += g_AVP[((size_t)sp * 128 + bh) * (AG * HD) + a * HD + d];
    }
    g_avt16[((size_t)bh * 64 + d) * 64 + a] = __float2half_rn(s);
}

// ---------------- q-side: MMA logits + reg softmax + MMA out ---------------------
__global__ __launch_bounds__(128) void qside_mma()
{
    __shared__ __align__(1024) char sm[32768];
    int bh = blockIdx.y, b = bh >> 3, h = bh & 7;
    int i0 = blockIdx.x * 64;
    int tid = threadIdx.x, wid = tid >> 5, lane = tid & 31;
    uint32_t sQ = smem_u32(sm), sAT = sQ + 8192, sAVT = sQ + 16384, sP = sQ + 24576;

    const __half* atp = g_at16 + (size_t)bh * 64 * 64;
    const __half* avtp = g_avt16 + (size_t)bh * 64 * 64;
#pragma unroll
    for (int it = 0; it < 4; it++) {
        int idx = tid + it * 128;
        int r = idx >> 3, c = idx & 7;
        uint32_t o = r * 128 + (SW8(r, c) << 4);
        cpa16(sQ + o, g_qkv16 + (size_t)(b * NTOK + i0 + r) * QKVW + h * 64 + c * 8);
        cpa16(sAT + o, atp + r * 64 + c * 8);
        cpa16(sAVT + o, avtp + r * 64 + c * 8);
    }
    CP_COMMIT(); CP_WAIT0();
    __syncthreads();

    int g = lane >> 3, lr = lane & 7;
    float acc1[8][4] = {};
#pragma unroll
    for (int ks = 0; ks < 4; ks++) {
        uint32_t af[4], bf[8][2];
        {
            int row = wid * 16 + ((g & 1) << 3) + lr;
            int c = ks * 2 + (g >> 1);
            LDSM_X4(af[0], af[1], af[2], af[3], sQ + row * 128 + (SW8(row, c) << 4));
        }
#pragma unroll
        for (int np = 0; np < 4; np++) {
            int row = np * 16 + ((g >> 1) << 3) + lr;
            int c = ks * 2 + (g & 1);
            uint32_t r0, r1, r2, r3;
            LDSM_X4(r0, r1, r2, r3, sAT + row * 128 + (SW8(row, c) << 4));
            bf[np * 2][0] = r0; bf[np * 2][1] = r1;
            bf[np * 2 + 1][0] = r2; bf[np * 2 + 1][1] = r3;
        }
#pragma unroll
        for (int nt = 0; nt < 8; nt++)
            MMA16816(acc1[nt], af, bf[nt]);
    }

    int r1 = wid * 16 + (lane >> 2), r2 = r1 + 8;
    int t1 = i0 + r1, t2 = i0 + r2;
#pragma unroll
    for (int nt = 0; nt < 8; nt++) {
        int abase = nt * 8 + ((lane & 3) << 1);
        __half2 b1 = *(const __half2*)(g_NB1Th + ((size_t)h * NTOK + t1) * 64 + abase);
        __half2 b2 = *(const __half2*)(g_NB1Th + ((size_t)h * NTOK + t2) * 64 + abase);
        acc1[nt][0] += __low2float(b1); acc1[nt][1] += __high2float(b1);
        acc1[nt][2] += __low2float(b2); acc1[nt][3] += __high2float(b2);
        if (abase >= AG) {
            acc1[nt][0] = acc1[nt][1] = acc1[nt][2] = acc1[nt][3] = -INFINITY;
        } else if (abase + 1 >= AG) {
            acc1[nt][1] = acc1[nt][3] = -INFINITY;
        }
    }
    float m1 = -1e30f, m2 = -1e30f;
#pragma unroll
    for (int nt = 0; nt < 8; nt++) {
        m1 = fmaxf(m1, fmaxf(acc1[nt][0], acc1[nt][1]));
        m2 = fmaxf(m2, fmaxf(acc1[nt][2], acc1[nt][3]));
    }
    m1 = fmaxf(m1, __shfl_xor_sync(~0u, m1, 1)); m1 = fmaxf(m1, __shfl_xor_sync(~0u, m1, 2));
    m2 = fmaxf(m2, __shfl_xor_sync(~0u, m2, 1)); m2 = fmaxf(m2, __shfl_xor_sync(~0u, m2, 2));
    float s1 = 0.f, s2 = 0.f;
#pragma unroll
    for (int nt = 0; nt < 8; nt++) {
        acc1[nt][0] = __expf(acc1[nt][0] - m1); s1 += acc1[nt][0];
        acc1[nt][1] = __expf(acc1[nt][1] - m1); s1 += acc1[nt][1];
        acc1[nt][2] = __expf(acc1[nt][2] - m2); s2 += acc1[nt][2];
        acc1[nt][3] = __expf(acc1[nt][3] - m2); s2 += acc1[nt][3];
    }
    s1 += __shfl_xor_sync(~0u, s1, 1); s1 += __shfl_xor_sync(~0u, s1, 2);
    s2 += __shfl_xor_sync(~0u, s2, 1); s2 += __shfl_xor_sync(~0u, s2, 2);
    float i1 = 1.0f / s1, i2 = 1.0f / s2;

#pragma unroll
    for (int nt = 0; nt < 8; nt++) {
        int colb = nt * 8 + ((lane & 3) << 1);
        uint32_t o1 = r1 * 128 + (SW8(r1, nt) << 4) + (colb & 7) * 2;
        uint32_t o2 = r2 * 128 + (SW8(r2, nt) << 4) + (colb & 7) * 2;
        __half2 p1 = __halves2half2(__float2half_rn(acc1[nt][0] * i1),
                                    __float2half_rn(acc1[nt][1] * i1));
        __half2 p2 = __halves2half2(__float2half_rn(acc1[nt][2] * i2),
                                    __float2half_rn(acc1[nt][3] * i2));
        asm volatile("st.shared.b32 [%0], %1;" :: "r"(sP + o1), "r"(*(uint32_t*)&p1));
        asm volatile("st.shared.b32 [%0], %1;" :: "r"(sP + o2), "r"(*(uint32_t*)&p2));
    }
    __syncwarp();

    float acc2[8][4] = {};
#pragma unroll
    for (int ks = 0; ks < 4; ks++) {
        uint32_t af[4], bf[8][2];
        {
            int row = wid * 16 + ((g & 1) << 3) + lr;
            int c = ks * 2 + (g >> 1);
            LDSM_X4(af[0], af[1], af[2], af[3], sP + row * 128 + (SW8(row, c) << 4));
        }
#pragma unroll
        for (int np = 0; np < 4; np++) {
            int row = np * 16 + ((g >> 1) << 3) + lr;
            int c = ks * 2 + (g & 1);
            uint32_t r0, r1x, r2x, r3;
            LDSM_X4(r0, r1x, r2x, r3, sAVT + row * 128 + (SW8(row, c) << 4));
            bf[np * 2][0] = r0; bf[np * 2][1] = r1x;
            bf[np * 2 + 1][0] = r2x; bf[np * 2 + 1][1] = r3;
        }
#pragma unroll
        for (int nt = 0; nt < 8; nt++)
            MMA16816(acc2[nt], af, bf[nt]);
    }

#pragma unroll
    for (int nt = 0; nt < 8; nt++) {
        int d = nt * 8 + ((lane & 3) << 1);
        *(__half2*)(g_ao16 + (size_t)(b * NTOK + t1) * CCH + h * 64 + d) =
            __halves2half2(__float2half_rn(acc2[nt][0]), __float2half_rn(acc2[nt][1]));
        *(__half2*)(g_ao16 + (size_t)(b * NTOK + t2) * CCH + h * 64 + d) =
            __halves2half2(__float2half_rn(acc2[nt][2]), __float2half_rn(acc2[nt][3]));
    }
}

// ---------------- 3x3 depthwise conv + attn-out add -> fp16 proj input -----------
__global__ __launch_bounds__(256) void dwc_kernel(
    const float* __restrict__ dwc_w, const float* __restrict__ dwc_b)
{
    int oh = blockIdx.x, b = blockIdx.y;
    __shared__ float w_s[CCH * 9];
    __shared__ float b_s[CCH];
    int tid = threadIdx.x;
    for (int t = tid; t < CCH * 9; t += 256) w_s[t] = dwc_w[t];
    for (int t = tid; t < CCH; t += 256) b_s[t] = dwc_b[t];
    __syncthreads();
    for (int idx = tid; idx < HW * CCH; idx += 256) {
        int ow = idx >> 9, c = idx & 511;
        float acc = b_s[c];
#pragma unroll
        for (int ky = 0; ky < 3; ky++) {
            int h2 = oh + ky - 1;
            if (h2 < 0 || h2 >= HW) continue;
#pragma unroll
            for (int kx = 0; kx < 3; kx++) {
                int w2 = ow + kx - 1;
                if (w2 < 0 || w2 >= HW) continue;
                acc += __half2float(g_qkv16[((size_t)(b * NTOK + h2 * HW + w2)) * QKVW + 1024 + c])
                     * w_s[c * 9 + ky * 3 + kx];
            }
        }
        size_t gi = ((size_t)(b * NTOK + oh * HW + ow)) * CCH + c;
        g_ahi[gi] = __float2half_rn(__half2float(g_ao16[gi]) + acc);
    }
}

// ---------------- launch ---------------------------------------------------------
extern "C" void kernel_launch(void* const* d_in, const int* in_sizes, int n_in,
                              void* d_out, int out_size)
{
    const float* x = (const float*)d_in[0];
    int off = 1;
    if (n_in >= 15 && in_sizes[1] == 1) off = 3;
    const float* q_w    = (const float*)d_in[off + 0];
    const float* kv_w   = (const float*)d_in[off + 1];
    const float* proj_w = (const float*)d_in[off + 2];
    const float* proj_b = (const float*)d_in[off + 3];
    const float* dwc_w  = (const float*)d_in[off + 4];
    const float* dwc_b  = (const float*)d_in[off + 5];
    const float* an_b   = (const float*)d_in[off + 6];
    const float* na_b   = (const float*)d_in[off + 7];
    const float* ah_b   = (const float*)d_in[off + 8];
    const float* aw_b   = (const float*)d_in[off + 9];
    const float* ha_b   = (const float*)d_in[off + 10];
    const float* wa_b   = (const float*)d_in[off + 11];
    float* out = (float*)d_out;

    __half *x16, *qkv16, *ahi, *wqkv16, *wp16;
    cudaGetSymbolAddress((void**)&x16, g_x16);
    cudaGetSymbolAddress((void**)&qkv16, g_qkv16);
    cudaGetSymbolAddress((void**)&ahi, g_ahi);
    cudaGetSymbolAddress((void**)&wqkv16, g_wqkv16);
    cudaGetSymbolAddress((void**)&wp16, g_wp16);

    static int smem_set = 0;
    if (!smem_set) {
        cudaFuncSetAttribute(gemm_tc<0>, cudaFuncAttributeMaxDynamicSharedMemorySize, NST * STG1);
        cudaFuncSetAttribute(gemm_tc<1>, cudaFuncAttributeMaxDynamicSharedMemorySize, NST * STG1);
        smem_set = 1;
    }

    cvt_w16<<<2048, 256>>>(x, x16, MROWS * CCH / 4);
    cvt_w16<<<256, 256>>>(q_w, wqkv16, CCH * CCH / 4);
    cvt_w16<<<512, 256>>>(kv_w, wqkv16 + CCH * CCH, 2 * CCH * CCH / 4);
    cvt_w16<<<256, 256>>>(proj_w, wp16, CCH * CCH / 4);
    bias_resize_kernel<<<dim3(AG, HEADS, 2), 256>>>(an_b, na_b, ah_b, aw_b, ha_b, wa_b);

    gemm_tc<1><<<dim3(24, MROWS / 128), 256, NST * STG1>>>(
        x16, wqkv16, nullptr, nullptr, qkv16, QKVW);

    v_transpose<<<dim3(NTOK / 64, NB * HEADS), 256>>>();
    pool_kernel<<<dim3(NB, 64), 256>>>();
    agent_logits_mma<<<dim3(NTILE, NB * HEADS), 128>>>();
    softmax_stats<<<NB * HEADS, 64>>>();
    agent_v_mma<<<dim3(NB * HEADS, 7), 128>>>();
    avp_reduce_kernel<<<(128 * 64 * 64 + 255) / 256, 256>>>();
    qside_mma<<<dim3(NTOK / 64, NB * HEADS), 128>>>();
    dwc_kernel<<<dim3(HW, NB), 256>>>(dwc_w, dwc_b);

    gemm_tc<0><<<dim3(8, MROWS / 128), 256, NST * STG1>>>(
        ahi, wp16, out, proj_b, nullptr, 512);
}

// round 14
// speedup vs baseline: 5.4966x; 1.0514x over previous
#include <cuda_runtime.h>
#include <cuda_fp16.h>
#include <math.h>
#include <stdint.h>

#define HEADS 8
#define HD 64
#define CCH 512
#define HW 56
#define NTOK 3136
#define AG 49
#define NB 16
#define MROWS (NB*NTOK)
#define KDIM 512
#define QKVW 1536
#define NTILE 49            // NTOK / 64

// ---------------- scratch (static device globals; zero-initialized) --------------
__device__ float g_AVP[7 * NB * HEADS * AG * HD];
__device__ float2 g_TMS[(size_t)NB * HEADS * 64 * NTILE];   // per-tile (max, sum)
__device__ float g_F[(size_t)NB * HEADS * 64 * NTILE];      // per-tile softmax factor
__device__ __half g_PB1h[HEADS * AG * NTOK];
__device__ __half g_NB1Th[HEADS * NTOK * 64];
__device__ __half g_x16[(size_t)MROWS * CCH];
__device__ __half g_qkv16[(size_t)MROWS * QKVW];
__device__ __half g_at16[NB * HEADS * 64 * 64];
__device__ __half g_p16[(size_t)NB * HEADS * 64 * NTOK];    // e = exp(l - tilemax); pad rows 0
__device__ __half g_avt16[NB * HEADS * 64 * 64];
__device__ __half g_ao16[(size_t)MROWS * CCH];
__device__ __half g_ahi[(size_t)MROWS * CCH];
__device__ __half g_wqkv16[QKVW * CCH];
__device__ __half g_wp16[CCH * CCH];

// ================= low-level helpers =================
__device__ __forceinline__ uint32_t smem_u32(const void* p) {
    uint32_t a;
    asm("{ .reg .u64 t; cvta.to.shared.u64 t, %1; cvt.u32.u64 %0, t; }" : "=r"(a) : "l"(p));
    return a;
}
__device__ __forceinline__ void cpa16(uint32_t s, const void* g) {
    asm volatile("cp.async.cg.shared.global [%0], [%1], 16;" :: "r"(s), "l"(g));
}
#define CP_COMMIT() asm volatile("cp.async.commit_group;" ::: "memory")
#define CP_WAIT0()  asm volatile("cp.async.wait_group 0;" ::: "memory")

#define LDSM_X4(r0, r1, r2, r3, a) \
    asm volatile("ldmatrix.sync.aligned.m8n8.x4.shared.b16 {%0,%1,%2,%3}, [%4];" \
                 : "=r"(r0), "=r"(r1), "=r"(r2), "=r"(r3) : "r"(a))

#define LDSM_X4_T(r0, r1, r2, r3, a) \
    asm volatile("ldmatrix.sync.aligned.m8n8.x4.trans.shared.b16 {%0,%1,%2,%3}, [%4];" \
                 : "=r"(r0), "=r"(r1), "=r"(r2), "=r"(r3) : "r"(a))

#define MMA16816(d, a, b) \
    asm volatile("mma.sync.aligned.m16n8k16.row.col.f32.f16.f16.f32 " \
                 "{%0,%1,%2,%3}, {%4,%5,%6,%7}, {%8,%9}, {%0,%1,%2,%3};" \
                 : "+f"((d)[0]), "+f"((d)[1]), "+f"((d)[2]), "+f"((d)[3]) \
                 : "r"((a)[0]), "r"((a)[1]), "r"((a)[2]), "r"((a)[3]), \
                   "r"((b)[0]), "r"((b)[1]))

#define SWZC(r, c) ((c) ^ (((r) >> 1) & 3))
#define SW8(r, c) ((c) ^ ((r) & 7))

#define NST 3
#define STG1 12288u

// ================= fp16 tensor-core GEMM, 1-term ================================
template<int MODE>
__global__ void __launch_bounds__(256, 3) gemm_tc(
    const __half* __restrict__ A16, const __half* __restrict__ B16,
    float* __restrict__ Cf, const float* __restrict__ bias,
    __half* __restrict__ C16, int Nout)
{
    extern __shared__ __align__(1024) char smem[];
    int tid = threadIdx.x;
    int wid = tid >> 5, lane = tid & 31;
    int bn0 = blockIdx.x * 64, m0 = blockIdx.y * 128;
    int wr = wid >> 1, wc = wid & 1;
    uint32_t sbase = smem_u32(smem);

    float acc[2][4][4] = {};

    int rA0 = tid >> 2,         cA0 = tid & 3;
    int rA1 = (tid + 256) >> 2, cA1 = tid & 3;
    int rB  = tid >> 2,         cB  = tid & 3;
    uint32_t soA0 = rA0 * 64 + (SWZC(rA0, cA0) << 4);
    uint32_t soA1 = rA1 * 64 + (SWZC(rA1, cA1) << 4);
    uint32_t soB  = rB * 64 + (SWZC(rB, cB) << 4);

#pragma unroll
    for (int pc = 0; pc < 2; pc++) {
        int k0 = pc * 32;
        uint32_t sb = sbase + pc * STG1;
        cpa16(sb + soA0, A16 + (size_t)(m0 + rA0) * KDIM + k0 + cA0 * 8);
        cpa16(sb + soA1, A16 + (size_t)(m0 + rA1) * KDIM + k0 + cA1 * 8);
        cpa16(sb + 8192 + soB, B16 + (size_t)(bn0 + rB) * KDIM + k0 + cB * 8);
        CP_COMMIT();
    }

    int g = lane >> 3, lr = lane & 7;

    for (int ch = 0; ch < 16; ch++) {
        __syncthreads();
        if (ch + 2 < 16) {
            int k0 = (ch + 2) * 32;
            uint32_t nb = sbase + ((ch + 2) % NST) * STG1;
            cpa16(nb + soA0, A16 + (size_t)(m0 + rA0) * KDIM + k0 + cA0 * 8);
            cpa16(nb + soA1, A16 + (size_t)(m0 + rA1) * KDIM + k0 + cA1 * 8);
            cpa16(nb + 8192 + soB, B16 + (size_t)(bn0 + rB) * KDIM + k0 + cB * 8);
            CP_COMMIT();
        }
        if (ch <= 13)      asm volatile("cp.async.wait_group 2;" ::: "memory");
        else if (ch == 14) asm volatile("cp.async.wait_group 1;" ::: "memory");
        else               asm volatile("cp.async.wait_group 0;" ::: "memory");
        __syncthreads();

        uint32_t base = sbase + (ch % NST) * STG1;

#pragma unroll
        for (int ks = 0; ks < 2; ks++) {
            uint32_t af[2][4], bf[4][2];
#pragma unroll
            for (int mt = 0; mt < 2; mt++) {
                int row = wr * 32 + mt * 16 + ((g & 1) << 3) + lr;
                int c = ks * 2 + (g >> 1);
                uint32_t off = row * 64 + (SWZC(row, c) << 4);
                LDSM_X4(af[mt][0], af[mt][1], af[mt][2], af[mt][3], base + off);
            }
#pragma unroll
            for (int np = 0; np < 2; np++) {
                int row = wc * 32 + np * 16 + ((g >> 1) << 3) + lr;
                int c = ks * 2 + (g & 1);
                uint32_t off = row * 64 + (SWZC(row, c) << 4);
                uint32_t r0, r1, r2, r3;
                LDSM_X4(r0, r1, r2, r3, base + 8192 + off);
                bf[np * 2][0] = r0; bf[np * 2][1] = r1;
                bf[np * 2 + 1][0] = r2; bf[np * 2 + 1][1] = r3;
            }
#pragma unroll
            for (int mt = 0; mt < 2; mt++)
#pragma unroll
                for (int nt = 0; nt < 4; nt++)
                    MMA16816(acc[mt][nt], af[mt], bf[nt]);
        }
    }

#pragma unroll
    for (int mt = 0; mt < 2; mt++) {
#pragma unroll
        for (int nt = 0; nt < 4; nt++) {
            int gm0 = m0 + wr * 32 + mt * 16 + (lane >> 2);
            int gn = bn0 + wc * 32 + nt * 8 + ((lane & 3) << 1);
#pragma unroll
            for (int half = 0; half < 2; half++) {
                int gm = gm0 + half * 8;
                float v0 = acc[mt][nt][half * 2], v1 = acc[mt][nt][half * 2 + 1];
                if (MODE == 0) {
                    v0 += bias[gn]; v1 += bias[gn + 1];
                    *(float2*)(Cf + (size_t)gm * Nout + gn) = make_float2(v0, v1);
                } else {
                    *(__half2*)(C16 + (size_t)gm * Nout + gn) =
                        __halves2half2(__float2half_rn(v0), __float2half_rn(v1));
                }
            }
        }
    }
}

// ---------------- fp32 -> fp16 (activation) --------------------------------------
__global__ __launch_bounds__(256) void cvt_w16(
    const float* __restrict__ src, __half* __restrict__ dst, int n4)
{
    for (int i = blockIdx.x * 256 + threadIdx.x; i < n4; i += gridDim.x * 256) {
        float4 v = ((const float4*)src)[i];
        ((__half2*)dst)[2 * i]     = __halves2half2(__float2half_rn(v.x), __float2half_rn(v.y));
        ((__half2*)dst)[2 * i + 1] = __halves2half2(__float2half_rn(v.z), __float2half_rn(v.w));
    }
}

// ---------------- all weight conversions in one launch ---------------------------
__global__ __launch_bounds__(256) void cvt_weights(
    const float* __restrict__ q_w, const float* __restrict__ kv_w,
    const float* __restrict__ proj_w)
{
    const int NQ = CCH * CCH / 4, NKV = 2 * CCH * CCH / 4, NP = CCH * CCH / 4;
    for (int i = blockIdx.x * 256 + threadIdx.x; i < NQ + NKV + NP; i += gridDim.x * 256) {
        const float* src; __half* dst; int j;
        if (i < NQ)            { src = q_w;    dst = g_wqkv16;             j = i; }
        else if (i < NQ + NKV) { src = kv_w;   dst = g_wqkv16 + CCH * CCH; j = i - NQ; }
        else                   { src = proj_w; dst = g_wp16;               j = i - NQ - NKV; }
        float4 v = ((const float4*)src)[j];
        ((__half2*)dst)[2 * j]     = __halves2half2(__float2half_rn(v.x), __float2half_rn(v.y));
        ((__half2*)dst)[2 * j + 1] = __halves2half2(__float2half_rn(v.z), __float2half_rn(v.w));
    }
}

// ---------------- pooling: q -> at16 (x0.125, pad rows zero) ---------------------
__global__ __launch_bounds__(256) void pool_kernel()
{
    int b = blockIdx.x, a = blockIdx.y;
    if (a >= AG) {
        for (int c = threadIdx.x; c < CCH; c += 256)
            g_at16[(((b * 8 + (c >> 6)) * 64) + a) * 64 + (c & 63)] = __float2half(0.f);
        return;
    }
    int p1 = a / 7, p2 = a % 7;
    for (int c = threadIdx.x; c < CCH; c += 256) {
        float s = 0.f;
#pragma unroll
        for (int r = 0; r < 8; r++)
#pragma unroll
            for (int ss = 0; ss < 8; ss++)
                s += __half2float(g_qkv16[((size_t)(b * NTOK + (p1 * 8 + r) * HW + p2 * 8 + ss)) * QKVW + c]);
        g_at16[(((b * 8 + (c >> 6)) * 64) + a) * 64 + (c & 63)] =
            __float2half_rn(s * (1.0f / 64.0f) * 0.125f);
    }
}

// ---------------- jax bilinear resize + bias folding, fp16 out -------------------
__device__ __forceinline__ void lin_w(int o, int& i0, int& i1, float& w0, float& w1)
{
    float p = (o + 0.5f) * 0.125f - 0.5f;
    float fp = floorf(p);
    int i = (int)fp;
    float f = p - fp;
    if (i < 0)       { i0 = 0; i1 = 0; w0 = 1.f; w1 = 0.f; }
    else if (i >= 6) { i0 = 6; i1 = 6; w0 = 1.f; w1 = 0.f; }
    else             { i0 = i; i1 = i + 1; w0 = 1.f - f; w1 = f; }
}

__global__ __launch_bounds__(256) void bias_resize_kernel(
    const float* __restrict__ an, const float* __restrict__ na,
    const float* __restrict__ ahb, const float* __restrict__ awb,
    const float* __restrict__ hab, const float* __restrict__ wab)
{
    int a = blockIdx.x, h = blockIdx.y, src = blockIdx.z;
    const float* S = (src == 0 ? an : na) + (h * AG + a) * 49;
    __shared__ float s[49];
    if (threadIdx.x < 49) s[threadIdx.x] = S[threadIdx.x];
    __syncthreads();
    for (int o = threadIdx.x; o < NTOK; o += 256) {
        int oh = o / HW, ow = o % HW;
        int r0, r1, c0, c1; float wr0, wr1, wc0, wc1;
        lin_w(oh, r0, r1, wr0, wr1);
        lin_w(ow, c0, c1, wc0, wc1);
        float v = wr0 * (wc0 * s[r0 * 7 + c0] + wc1 * s[r0 * 7 + c1]) +
                  wr1 * (wc0 * s[r1 * 7 + c0] + wc1 * s[r1 * 7 + c1]);
        if (src == 0) {
            v += ahb[(h * AG + a) * HW + oh] + awb[(h * AG + a) * HW + ow];
            g_PB1h[((size_t)(h * AG + a)) * NTOK + o] = __float2half_rn(v);
        } else {
            v += hab[(h * HW + oh) * AG + a] + wab[(h * HW + ow) * AG + a];
            g_NB1Th[((size_t)h * NTOK + o) * 64 + a] = __float2half_rn(v);
        }
    }
}

// ---------------- agent logits + tile-local exp, stats out -----------------------
__global__ __launch_bounds__(128) void agent_logits_mma()
{
    __shared__ __align__(1024) char sm[16384];   // [AT 8KB][K 8KB]
    int bh = blockIdx.y, b = bh >> 3, h = bh & 7;
    int tile = blockIdx.x;
    int i0 = tile * 64;
    int tid = threadIdx.x, wid = tid >> 5, lane = tid & 31;
    uint32_t sAT = smem_u32(sm), sK = sAT + 8192;

    const __half* atp = g_at16 + (size_t)bh * 64 * 64;
#pragma unroll
    for (int it = 0; it < 4; it++) {
        int idx = tid + it * 128;
        int r = idx >> 3, c = idx & 7;
        uint32_t o = r * 128 + (SW8(r, c) << 4);
        cpa16(sAT + o, atp + r * 64 + c * 8);
        cpa16(sK + o, g_qkv16 + (size_t)(b * NTOK + i0 + r) * QKVW + 512 + h * 64 + c * 8);
    }
    CP_COMMIT(); CP_WAIT0();
    __syncthreads();

    int g = lane >> 3, lr = lane & 7;
    float acc1[8][4] = {};
#pragma unroll
    for (int ks = 0; ks < 4; ks++) {
        uint32_t af[4], bf[8][2];
        {
            int row = wid * 16 + ((g & 1) << 3) + lr;
            int c = ks * 2 + (g >> 1);
            LDSM_X4(af[0], af[1], af[2], af[3], sAT + row * 128 + (SW8(row, c) << 4));
        }
#pragma unroll
        for (int np = 0; np < 4; np++) {
            int row = np * 16 + ((g >> 1) << 3) + lr;
            int c = ks * 2 + (g & 1);
            uint32_t r0, r1, r2, r3;
            LDSM_X4(r0, r1, r2, r3, sK + row * 128 + (SW8(row, c) << 4));
            bf[np * 2][0] = r0; bf[np * 2][1] = r1;
            bf[np * 2 + 1][0] = r2; bf[np * 2 + 1][1] = r3;
        }
#pragma unroll
        for (int nt = 0; nt < 8; nt++)
            MMA16816(acc1[nt], af, bf[nt]);
    }

    int a1 = wid * 16 + (lane >> 2), a2 = a1 + 8;
    bool v1 = a1 < AG, v2 = a2 < AG;
#pragma unroll
    for (int nt = 0; nt < 8; nt++) {
        int tb = i0 + nt * 8 + ((lane & 3) << 1);
        if (v1) {
            __half2 pb = *(const __half2*)(g_PB1h + ((size_t)(h * AG + a1)) * NTOK + tb);
            acc1[nt][0] += __low2float(pb); acc1[nt][1] += __high2float(pb);
        }
        if (v2) {
            __half2 pb = *(const __half2*)(g_PB1h + ((size_t)(h * AG + a2)) * NTOK + tb);
            acc1[nt][2] += __low2float(pb); acc1[nt][3] += __high2float(pb);
        }
    }
    float m1 = -1e30f, m2 = -1e30f;
#pragma unroll
    for (int nt = 0; nt < 8; nt++) {
        m1 = fmaxf(m1, fmaxf(acc1[nt][0], acc1[nt][1]));
        m2 = fmaxf(m2, fmaxf(acc1[nt][2], acc1[nt][3]));
    }
    m1 = fmaxf(m1, __shfl_xor_sync(~0u, m1, 1)); m1 = fmaxf(m1, __shfl_xor_sync(~0u, m1, 2));
    m2 = fmaxf(m2, __shfl_xor_sync(~0u, m2, 1)); m2 = fmaxf(m2, __shfl_xor_sync(~0u, m2, 2));
    float s1 = 0.f, s2 = 0.f;
#pragma unroll
    for (int nt = 0; nt < 8; nt++) {
        acc1[nt][0] = __expf(acc1[nt][0] - m1); s1 += acc1[nt][0];
        acc1[nt][1] = __expf(acc1[nt][1] - m1); s1 += acc1[nt][1];
        acc1[nt][2] = __expf(acc1[nt][2] - m2); s2 += acc1[nt][2];
        acc1[nt][3] = __expf(acc1[nt][3] - m2); s2 += acc1[nt][3];
    }
    s1 += __shfl_xor_sync(~0u, s1, 1); s1 += __shfl_xor_sync(~0u, s1, 2);
    s2 += __shfl_xor_sync(~0u, s2, 1); s2 += __shfl_xor_sync(~0u, s2, 2);
#pragma unroll
    for (int nt = 0; nt < 8; nt++) {
        int tb = i0 + nt * 8 + ((lane & 3) << 1);
        if (v1)
            *(__half2*)(g_p16 + ((size_t)bh * 64 + a1) * NTOK + tb) =
                __halves2half2(__float2half_rn(acc1[nt][0]), __float2half_rn(acc1[nt][1]));
        if (v2)
            *(__half2*)(g_p16 + ((size_t)bh * 64 + a2) * NTOK + tb) =
                __halves2half2(__float2half_rn(acc1[nt][2]), __float2half_rn(acc1[nt][3]));
    }
    if ((lane & 3) == 0) {
        if (v1) g_TMS[((size_t)bh * 64 + a1) * NTILE + tile] = make_float2(m1, s1);
        if (v2) g_TMS[((size_t)bh * 64 + a2) * NTILE + tile] = make_float2(m2, s2);
    }
}

// ---------------- per-row softmax stats -> per-tile factors ----------------------
__global__ __launch_bounds__(64) void softmax_stats()
{
    int bh = blockIdx.x;
    int a = threadIdx.x;
    if (a >= AG) return;
    const float2* tms = g_TMS + ((size_t)bh * 64 + a) * NTILE;
    float gmax = -1e30f;
#pragma unroll 7
    for (int i = 0; i < NTILE; i++) gmax = fmaxf(gmax, tms[i].x);
    float total = 0.f;
#pragma unroll 7
    for (int i = 0; i < NTILE; i++) total += tms[i].y * __expf(tms[i].x - gmax);
    float inv = 1.0f / total;
    float* f = g_F + ((size_t)bh * 64 + a) * NTILE;
#pragma unroll 7
    for (int i = 0; i < NTILE; i++) f[i] = __expf(tms[i].x - gmax) * inv;
}

// ---------------- agent_v via MMA, split-K; V loaded [t][d] + trans ldmatrix -----
__global__ __launch_bounds__(128) void agent_v_mma()
{
    __shared__ __align__(1024) char sm[NST * 16384];
    int bh = blockIdx.x, sp = blockIdx.y;
    int b = bh >> 3, h = bh & 7;
    int kbeg = sp * 448;
    int tid = threadIdx.x, wid = tid >> 5, lane = tid & 31;
    int wr = wid >> 1, wc = wid & 1;
    uint32_t sbase = smem_u32(sm);
    const __half* pp = g_p16 + (size_t)bh * 64 * NTOK + kbeg;
    const __half* vp = g_qkv16 + (size_t)(b * NTOK + kbeg) * QKVW + 1024 + h * 64;

    int rl = tid >> 3, cl = tid & 7;

#pragma unroll
    for (int pc = 0; pc < 2; pc++) {
        uint32_t sb = sbase + pc * 16384;
#pragma unroll
        for (int it = 0; it < 4; it++) {
            int r = rl + it * 16;
            uint32_t o = (r << 7) + (SW8(r, cl) << 4);
            cpa16(sb + o, pp + (size_t)r * NTOK + pc * 64 + cl * 8);
            cpa16(sb + 8192 + o, vp + (size_t)(pc * 64 + r) * QKVW + cl * 8);
        }
        CP_COMMIT();
    }

    int g = lane >> 3, lr = lane & 7;
    int ra = lane >> 2;
    float acc[2][4][4] = {};
    for (int ch = 0; ch < 7; ch++) {
        __syncthreads();
        if (ch + 2 < 7) {
            uint32_t nb = sbase + ((ch + 2) % NST) * 16384;
#pragma unroll
            for (int it = 0; it < 4; it++) {
                int r = rl + it * 16;
                uint32_t o = (r << 7) + (SW8(r, cl) << 4);
                cpa16(nb + o, pp + (size_t)r * NTOK + (ch + 2) * 64 + cl * 8);
                cpa16(nb + 8192 + o, vp + (size_t)((ch + 2) * 64 + r) * QKVW + cl * 8);
            }
            CP_COMMIT();
        }
        if (ch <= 4)      asm volatile("cp.async.wait_group 2;" ::: "memory");
        else if (ch == 5) asm volatile("cp.async.wait_group 1;" ::: "memory");
        else              asm volatile("cp.async.wait_group 0;" ::: "memory");
        __syncthreads();

        uint32_t base = sbase + (ch % NST) * 16384;
        int tileIdx = sp * 7 + ch;
        float fv[2][2];
#pragma unroll
        for (int mt = 0; mt < 2; mt++)
#pragma unroll
            for (int half = 0; half < 2; half++) {
                int a = wr * 32 + mt * 16 + ra + half * 8;
                fv[mt][half] = g_F[((size_t)bh * 64 + a) * NTILE + tileIdx];
            }

        float accc[2][4][4] = {};
#pragma unroll
        for (int ks = 0; ks < 4; ks++) {
            uint32_t af[2][4], bf[4][2];
#pragma unroll
            for (int mt = 0; mt < 2; mt++) {
                int row = wr * 32 + mt * 16 + ((g & 1) << 3) + lr;
                int c = ks * 2 + (g >> 1);
                LDSM_X4(af[mt][0], af[mt][1], af[mt][2], af[mt][3],
                        base + row * 128 + (SW8(row, c) << 4));
            }
            // V tile is [t=k rows][d cols]; trans-ldmatrix delivers B fragments.
#pragma unroll
            for (int np = 0; np < 2; np++) {
                int row = ks * 16 + ((g & 1) << 3) + lr;         // k-local row
                int c = wc * 4 + np * 2 + (g >> 1);              // d-chunk
                uint32_t r0, r1, r2, r3;
                LDSM_X4_T(r0, r1, r2, r3, base + 8192 + row * 128 + (SW8(row, c) << 4));
                bf[np * 2][0] = r0; bf[np * 2][1] = r1;
                bf[np * 2 + 1][0] = r2; bf[np * 2 + 1][1] = r3;
            }
#pragma unroll
            for (int mt = 0; mt < 2; mt++)
#pragma unroll
                for (int nt = 0; nt < 4; nt++)
                    MMA16816(accc[mt][nt], af[mt], bf[nt]);
        }
#pragma unroll
        for (int mt = 0; mt < 2; mt++)
#pragma unroll
            for (int nt = 0; nt < 4; nt++) {
                acc[mt][nt][0] += fv[mt][0] * accc[mt][nt][0];
                acc[mt][nt][1] += fv[mt][0] * accc[mt][nt][1];
                acc[mt][nt][2] += fv[mt][1] * accc[mt][nt][2];
                acc[mt][nt][3] += fv[mt][1] * accc[mt][nt][3];
            }
    }

#pragma unroll
    for (int mt = 0; mt < 2; mt++)
#pragma unroll
        for (int nt = 0; nt < 4; nt++)
#pragma unroll
            for (int half = 0; half < 2; half++) {
                int a = wr * 32 + mt * 16 + (lane >> 2) + half * 8;
                if (a >= AG) continue;
                int d = wc * 32 + nt * 8 + ((lane & 3) << 1);
                size_t o = ((size_t)sp * 128 + bh) * (AG * HD) + a * HD + d;
                *(float2*)(g_AVP + o) =
                    make_float2(acc[mt][nt][half * 2], acc[mt][nt][half * 2 + 1]);
            }
}

// ---------------- reduce partials -> AV^T fp16 -----------------------------------
__global__ __launch_bounds__(256) void avp_reduce_kernel()
{
    int i = blockIdx.x * 256 + threadIdx.x;
    if (i >= 128 * 64 * 64) return;
    int bh = i >> 12, rest = i & 4095, d = rest >> 6, a = rest & 63;
    float s = 0.f;
    if (a < AG) {
#pragma unroll
        for (int sp = 0; sp < 7; sp++)
            s += g_AVP[((size_t)sp * 128 + bh) * (AG * HD) + a * HD + d];
    }
    g_avt16[((size_t)bh * 64 + d) * 64 + a] = __float2half_rn(s);
}

// ---------------- q-side: MMA logits + reg softmax + MMA out ---------------------
__global__ __launch_bounds__(128) void qside_mma()
{
    __shared__ __align__(1024) char sm[32768];
    int bh = blockIdx.y, b = bh >> 3, h = bh & 7;
    int i0 = blockIdx.x * 64;
    int tid = threadIdx.x, wid = tid >> 5, lane = tid & 31;
    uint32_t sQ = smem_u32(sm), sAT = sQ + 8192, sAVT = sQ + 16384, sP = sQ + 24576;

    const __half* atp = g_at16 + (size_t)bh * 64 * 64;
    const __half* avtp = g_avt16 + (size_t)bh * 64 * 64;
#pragma unroll
    for (int it = 0; it < 4; it++) {
        int idx = tid + it * 128;
        int r = idx >> 3, c = idx & 7;
        uint32_t o = r * 128 + (SW8(r, c) << 4);
        cpa16(sQ + o, g_qkv16 + (size_t)(b * NTOK + i0 + r) * QKVW + h * 64 + c * 8);
        cpa16(sAT + o, atp + r * 64 + c * 8);
        cpa16(sAVT + o, avtp + r * 64 + c * 8);
    }
    CP_COMMIT(); CP_WAIT0();
    __syncthreads();

    int g = lane >> 3, lr = lane & 7;
    float acc1[8][4] = {};
#pragma unroll
    for (int ks = 0; ks < 4; ks++) {
        uint32_t af[4], bf[8][2];
        {
            int row = wid * 16 + ((g & 1) << 3) + lr;
            int c = ks * 2 + (g >> 1);
            LDSM_X4(af[0], af[1], af[2], af[3], sQ + row * 128 + (SW8(row, c) << 4));
        }
#pragma unroll
        for (int np = 0; np < 4; np++) {
            int row = np * 16 + ((g >> 1) << 3) + lr;
            int c = ks * 2 + (g & 1);
            uint32_t r0, r1, r2, r3;
            LDSM_X4(r0, r1, r2, r3, sAT + row * 128 + (SW8(row, c) << 4));
            bf[np * 2][0] = r0; bf[np * 2][1] = r1;
            bf[np * 2 + 1][0] = r2; bf[np * 2 + 1][1] = r3;
        }
#pragma unroll
        for (int nt = 0; nt < 8; nt++)
            MMA16816(acc1[nt], af, bf[nt]);
    }

    int r1 = wid * 16 + (lane >> 2), r2 = r1 + 8;
    int t1 = i0 + r1, t2 = i0 + r2;
#pragma unroll
    for (int nt = 0; nt < 8; nt++) {
        int abase = nt * 8 + ((lane & 3) << 1);
        __half2 b1 = *(const __half2*)(g_NB1Th + ((size_t)h * NTOK + t1) * 64 + abase);
        __half2 b2 = *(const __half2*)(g_NB1Th + ((size_t)h * NTOK + t2) * 64 + abase);
        acc1[nt][0] += __low2float(b1); acc1[nt][1] += __high2float(b1);
        acc1[nt][2] += __low2float(b2); acc1[nt][3] += __high2float(b2);
        if (abase >= AG) {
            acc1[nt][0] = acc1[nt][1] = acc1[nt][2] = acc1[nt][3] = -INFINITY;
        } else if (abase + 1 >= AG) {
            acc1[nt][1] = acc1[nt][3] = -INFINITY;
        }
    }
    float m1 = -1e30f, m2 = -1e30f;
#pragma unroll
    for (int nt = 0; nt < 8; nt++) {
        m1 = fmaxf(m1, fmaxf(acc1[nt][0], acc1[nt][1]));
        m2 = fmaxf(m2, fmaxf(acc1[nt][2], acc1[nt][3]));
    }
    m1 = fmaxf(m1, __shfl_xor_sync(~0u, m1, 1)); m1 = fmaxf(m1, __shfl_xor_sync(~0u, m1, 2));
    m2 = fmaxf(m2, __shfl_xor_sync(~0u, m2, 1)); m2 = fmaxf(m2, __shfl_xor_sync(~0u, m2, 2));
    float s1 = 0.f, s2 = 0.f;
#pragma unroll
    for (int nt = 0; nt < 8; nt++) {
        acc1[nt][0] = __expf(acc1[nt][0] - m1); s1 += acc1[nt][0];
        acc1[nt][1] = __expf(acc1[nt][1] - m1); s1 += acc1[nt][1];
        acc1[nt][2] = __expf(acc1[nt][2] - m2); s2 += acc1[nt][2];
        acc1[nt][3] = __expf(acc1[nt][3] - m2); s2 += acc1[nt][3];
    }
    s1 += __shfl_xor_sync(~0u, s1, 1); s1 += __shfl_xor_sync(~0u, s1, 2);
    s2 += __shfl_xor_sync(~0u, s2, 1); s2 += __shfl_xor_sync(~0u, s2, 2);
    float i1 = 1.0f / s1, i2 = 1.0f / s2;

#pragma unroll
    for (int nt = 0; nt < 8; nt++) {
        int colb = nt * 8 + ((lane & 3) << 1);
        uint32_t o1 = r1 * 128 + (SW8(r1, nt) << 4) + (colb & 7) * 2;
        uint32_t o2 = r2 * 128 + (SW8(r2, nt) << 4) + (colb & 7) * 2;
        __half2 p1 = __halves2half2(__float2half_rn(acc1[nt][0] * i1),
                                    __float2half_rn(acc1[nt][1] * i1));
        __half2 p2 = __halves2half2(__float2half_rn(acc1[nt][2] * i2),
                                    __float2half_rn(acc1[nt][3] * i2));
        asm volatile("st.shared.b32 [%0], %1;" :: "r"(sP + o1), "r"(*(uint32_t*)&p1));
        asm volatile("st.shared.b32 [%0], %1;" :: "r"(sP + o2), "r"(*(uint32_t*)&p2));
    }
    __syncwarp();

    float acc2[8][4] = {};
#pragma unroll
    for (int ks = 0; ks < 4; ks++) {
        uint32_t af[4], bf[8][2];
        {
            int row = wid * 16 + ((g & 1) << 3) + lr;
            int c = ks * 2 + (g >> 1);
            LDSM_X4(af[0], af[1], af[2], af[3], sP + row * 128 + (SW8(row, c) << 4));
        }
#pragma unroll
        for (int np = 0; np < 4; np++) {
            int row = np * 16 + ((g >> 1) << 3) + lr;
            int c = ks * 2 + (g & 1);
            uint32_t r0, r1x, r2x, r3;
            LDSM_X4(r0, r1x, r2x, r3, sAVT + row * 128 + (SW8(row, c) << 4));
            bf[np * 2][0] = r0; bf[np * 2][1] = r1x;
            bf[np * 2 + 1][0] = r2x; bf[np * 2 + 1][1] = r3;
        }
#pragma unroll
        for (int nt = 0; nt < 8; nt++)
            MMA16816(acc2[nt], af, bf[nt]);
    }

#pragma unroll
    for (int nt = 0; nt < 8; nt++) {
        int d = nt * 8 + ((lane & 3) << 1);
        *(__half2*)(g_ao16 + (size_t)(b * NTOK + t1) * CCH + h * 64 + d) =
            __halves2half2(__float2half_rn(acc2[nt][0]), __float2half_rn(acc2[nt][1]));
        *(__half2*)(g_ao16 + (size_t)(b * NTOK + t2) * CCH + h * 64 + d) =
            __halves2half2(__float2half_rn(acc2[nt][2]), __float2half_rn(acc2[nt][3]));
    }
}

// ---------------- 3x3 depthwise conv + attn-out add -> fp16 proj input -----------
__global__ __launch_bounds__(256) void dwc_kernel(
    const float* __restrict__ dwc_w, const float* __restrict__ dwc_b)
{
    int oh = blockIdx.x, b = blockIdx.y;
    __shared__ float w_s[CCH * 9];
    __shared__ float b_s[CCH];
    int tid = threadIdx.x;
    for (int t = tid; t < CCH * 9; t += 256) w_s[t] = dwc_w[t];
    for (int t = tid; t < CCH; t += 256) b_s[t] = dwc_b[t];
    __syncthreads();
    for (int idx = tid; idx < HW * CCH; idx += 256) {
        int ow = idx >> 9, c = idx & 511;
        float acc = b_s[c];
#pragma unroll
        for (int ky = 0; ky < 3; ky++) {
            int h2 = oh + ky - 1;
            if (h2 < 0 || h2 >= HW) continue;
#pragma unroll
            for (int kx = 0; kx < 3; kx++) {
                int w2 = ow + kx - 1;
                if (w2 < 0 || w2 >= HW) continue;
                acc += __half2float(g_qkv16[((size_t)(b * NTOK + h2 * HW + w2)) * QKVW + 1024 + c])
                     * w_s[c * 9 + ky * 3 + kx];
            }
        }
        size_t gi = ((size_t)(b * NTOK + oh * HW + ow)) * CCH + c;
        g_ahi[gi] = __float2half_rn(__half2float(g_ao16[gi]) + acc);
    }
}

// ---------------- launch ---------------------------------------------------------
extern "C" void kernel_launch(void* const* d_in, const int* in_sizes, int n_in,
                              void* d_out, int out_size)
{
    const float* x = (const float*)d_in[0];
    int off = 1;
    if (n_in >= 15 && in_sizes[1] == 1) off = 3;
    const float* q_w    = (const float*)d_in[off + 0];
    const float* kv_w   = (const float*)d_in[off + 1];
    const float* proj_w = (const float*)d_in[off + 2];
    const float* proj_b = (const float*)d_in[off + 3];
    const float* dwc_w  = (const float*)d_in[off + 4];
    const float* dwc_b  = (const float*)d_in[off + 5];
    const float* an_b   = (const float*)d_in[off + 6];
    const float* na_b   = (const float*)d_in[off + 7];
    const float* ah_b   = (const float*)d_in[off + 8];
    const float* aw_b   = (const float*)d_in[off + 9];
    const float* ha_b   = (const float*)d_in[off + 10];
    const float* wa_b   = (const float*)d_in[off + 11];
    float* out = (float*)d_out;

    __half *x16, *qkv16, *ahi, *wqkv16, *wp16;
    cudaGetSymbolAddress((void**)&x16, g_x16);
    cudaGetSymbolAddress((void**)&qkv16, g_qkv16);
    cudaGetSymbolAddress((void**)&ahi, g_ahi);
    cudaGetSymbolAddress((void**)&wqkv16, g_wqkv16);
    cudaGetSymbolAddress((void**)&wp16, g_wp16);

    static int smem_set = 0;
    if (!smem_set) {
        cudaFuncSetAttribute(gemm_tc<0>, cudaFuncAttributeMaxDynamicSharedMemorySize, NST * STG1);
        cudaFuncSetAttribute(gemm_tc<1>, cudaFuncAttributeMaxDynamicSharedMemorySize, NST * STG1);
        smem_set = 1;
    }

    cvt_w16<<<2048, 256>>>(x, x16, MROWS * CCH / 4);
    cvt_weights<<<1024, 256>>>(q_w, kv_w, proj_w);
    bias_resize_kernel<<<dim3(AG, HEADS, 2), 256>>>(an_b, na_b, ah_b, aw_b, ha_b, wa_b);

    gemm_tc<1><<<dim3(24, MROWS / 128), 256, NST * STG1>>>(
        x16, wqkv16, nullptr, nullptr, qkv16, QKVW);

    pool_kernel<<<dim3(NB, 64), 256>>>();
    agent_logits_mma<<<dim3(NTILE, NB * HEADS), 128>>>();
    softmax_stats<<<NB * HEADS, 64>>>();
    agent_v_mma<<<dim3(NB * HEADS, 7), 128>>>();
    avp_reduce_kernel<<<(128 * 64 * 64 + 255) / 256, 256>>>();
    qside_mma<<<dim3(NTOK / 64, NB * HEADS), 128>>>();
    dwc_kernel<<<dim3(HW, NB), 256>>>(dwc_w, dwc_b);

    gemm_tc<0><<<dim3(8, MROWS / 128), 256, NST * STG1>>>(
        ahi, wp16, out, proj_b, nullptr, 512);
}

// round 15
// speedup vs baseline: 5.8982x; 1.0731x over previous
#include <cuda_runtime.h>
#include <cuda_fp16.h>
#include <math.h>
#include <stdint.h>

#define HEADS 8
#define HD 64
#define CCH 512
#define HW 56
#define NTOK 3136
#define AG 49
#define NB 16
#define MROWS (NB*NTOK)
#define KDIM 512
#define QKVW 1536
#define NTILE 49            // NTOK / 64

// ---------------- scratch (static device globals; zero-initialized) --------------
__device__ float g_AVP[7 * NB * HEADS * AG * HD];
__device__ float2 g_TMS[(size_t)NB * HEADS * 64 * NTILE];   // per-tile (max, sum)
__device__ float g_F[(size_t)NB * HEADS * 64 * NTILE];      // per-tile softmax factor
__device__ __half g_PB1h[HEADS * AG * NTOK];
__device__ __half g_NB1Th[HEADS * NTOK * 64];
__device__ __half g_x16[(size_t)MROWS * CCH];
__device__ __half g_qkv16[(size_t)MROWS * QKVW];
__device__ __half g_at16[NB * HEADS * 64 * 64];
__device__ __half g_p16[(size_t)NB * HEADS * 64 * NTOK];    // e = exp(l - tilemax); pad rows 0
__device__ __half g_avt16[NB * HEADS * 64 * 64];
__device__ __half g_ao16[(size_t)MROWS * CCH];
__device__ __half g_ahi[(size_t)MROWS * CCH];
__device__ __half g_wqkv16[QKVW * CCH];
__device__ __half g_wp16[CCH * CCH];

// ================= low-level helpers =================
__device__ __forceinline__ uint32_t smem_u32(const void* p) {
    uint32_t a;
    asm("{ .reg .u64 t; cvta.to.shared.u64 t, %1; cvt.u32.u64 %0, t; }" : "=r"(a) : "l"(p));
    return a;
}
__device__ __forceinline__ void cpa16(uint32_t s, const void* g) {
    asm volatile("cp.async.cg.shared.global [%0], [%1], 16;" :: "r"(s), "l"(g));
}
#define CP_COMMIT() asm volatile("cp.async.commit_group;" ::: "memory")
#define CP_WAIT0()  asm volatile("cp.async.wait_group 0;" ::: "memory")

#define LDSM_X4(r0, r1, r2, r3, a) \
    asm volatile("ldmatrix.sync.aligned.m8n8.x4.shared.b16 {%0,%1,%2,%3}, [%4];" \
                 : "=r"(r0), "=r"(r1), "=r"(r2), "=r"(r3) : "r"(a))

#define LDSM_X4_T(r0, r1, r2, r3, a) \
    asm volatile("ldmatrix.sync.aligned.m8n8.x4.trans.shared.b16 {%0,%1,%2,%3}, [%4];" \
                 : "=r"(r0), "=r"(r1), "=r"(r2), "=r"(r3) : "r"(a))

#define MMA16816(d, a, b) \
    asm volatile("mma.sync.aligned.m16n8k16.row.col.f32.f16.f16.f32 " \
                 "{%0,%1,%2,%3}, {%4,%5,%6,%7}, {%8,%9}, {%0,%1,%2,%3};" \
                 : "+f"((d)[0]), "+f"((d)[1]), "+f"((d)[2]), "+f"((d)[3]) \
                 : "r"((a)[0]), "r"((a)[1]), "r"((a)[2]), "r"((a)[3]), \
                   "r"((b)[0]), "r"((b)[1]))

#define SW8(r, c) ((c) ^ ((r) & 7))

#define NST 3
#define STG2 32768u          // [A 16KB][B 16KB], K-chunk 64, 128B rows

// ================= fp16 tensor-core GEMM, 1-term, CTA 128x128 ===================
// warp tile 32(M) x 64(N); 8 warps (4x2); K-chunk 64; grid (Nout/128, M/128)
template<int MODE>
__global__ void __launch_bounds__(256, 2) gemm_tc(
    const __half* __restrict__ A16, const __half* __restrict__ B16,
    float* __restrict__ Cf, const float* __restrict__ bias,
    __half* __restrict__ C16, int Nout)
{
    extern __shared__ __align__(1024) char smem[];
    int tid = threadIdx.x;
    int wid = tid >> 5, lane = tid & 31;
    int bn0 = blockIdx.x * 128, m0 = blockIdx.y * 128;
    int wr = wid >> 1, wc = wid & 1;       // warp tile: rows wr*32, cols wc*64
    uint32_t sbase = smem_u32(smem);

    float acc[2][8][4] = {};

    int rl = tid >> 3, cl = tid & 7;       // 32 rows x 8 chunks per iter, 4 iters

    // prologue: chunks 0, 1
#pragma unroll
    for (int pc = 0; pc < 2; pc++) {
        int k0 = pc * 64;
        uint32_t sb = sbase + pc * STG2;
#pragma unroll
        for (int it = 0; it < 4; it++) {
            int r = rl + it * 32;
            uint32_t o = (r << 7) + (SW8(r, cl) << 4);
            cpa16(sb + o,         A16 + (size_t)(m0 + r) * KDIM + k0 + cl * 8);
            cpa16(sb + 16384 + o, B16 + (size_t)(bn0 + r) * KDIM + k0 + cl * 8);
        }
        CP_COMMIT();
    }

    int g = lane >> 3, lr = lane & 7;

    for (int ch = 0; ch < 8; ch++) {
        __syncthreads();
        if (ch + 2 < 8) {
            int k0 = (ch + 2) * 64;
            uint32_t nb = sbase + ((ch + 2) % NST) * STG2;
#pragma unroll
            for (int it = 0; it < 4; it++) {
                int r = rl + it * 32;
                uint32_t o = (r << 7) + (SW8(r, cl) << 4);
                cpa16(nb + o,         A16 + (size_t)(m0 + r) * KDIM + k0 + cl * 8);
                cpa16(nb + 16384 + o, B16 + (size_t)(bn0 + r) * KDIM + k0 + cl * 8);
            }
            CP_COMMIT();
        }
        if (ch <= 5)      asm volatile("cp.async.wait_group 2;" ::: "memory");
        else if (ch == 6) asm volatile("cp.async.wait_group 1;" ::: "memory");
        else              asm volatile("cp.async.wait_group 0;" ::: "memory");
        __syncthreads();

        uint32_t base = sbase + (ch % NST) * STG2;

#pragma unroll
        for (int ks = 0; ks < 4; ks++) {
            uint32_t af[2][4], bf[8][2];
#pragma unroll
            for (int mt = 0; mt < 2; mt++) {
                int row = wr * 32 + mt * 16 + ((g & 1) << 3) + lr;
                int c = ks * 2 + (g >> 1);
                LDSM_X4(af[mt][0], af[mt][1], af[mt][2], af[mt][3],
                        base + (row << 7) + (SW8(row, c) << 4));
            }
#pragma unroll
            for (int np = 0; np < 4; np++) {
                int row = wc * 64 + np * 16 + ((g >> 1) << 3) + lr;
                int c = ks * 2 + (g & 1);
                uint32_t r0, r1, r2, r3;
                LDSM_X4(r0, r1, r2, r3, base + 16384 + (row << 7) + (SW8(row, c) << 4));
                bf[np * 2][0] = r0; bf[np * 2][1] = r1;
                bf[np * 2 + 1][0] = r2; bf[np * 2 + 1][1] = r3;
            }
#pragma unroll
            for (int mt = 0; mt < 2; mt++)
#pragma unroll
                for (int nt = 0; nt < 8; nt++)
                    MMA16816(acc[mt][nt], af[mt], bf[nt]);
        }
    }

    // epilogue
#pragma unroll
    for (int mt = 0; mt < 2; mt++) {
#pragma unroll
        for (int nt = 0; nt < 8; nt++) {
            int gm0 = m0 + wr * 32 + mt * 16 + (lane >> 2);
            int gn = bn0 + wc * 64 + nt * 8 + ((lane & 3) << 1);
#pragma unroll
            for (int half = 0; half < 2; half++) {
                int gm = gm0 + half * 8;
                float v0 = acc[mt][nt][half * 2], v1 = acc[mt][nt][half * 2 + 1];
                if (MODE == 0) {
                    v0 += bias[gn]; v1 += bias[gn + 1];
                    *(float2*)(Cf + (size_t)gm * Nout + gn) = make_float2(v0, v1);
                } else {
                    *(__half2*)(C16 + (size_t)gm * Nout + gn) =
                        __halves2half2(__float2half_rn(v0), __float2half_rn(v1));
                }
            }
        }
    }
}

// ---------------- fp32 -> fp16 (activation) --------------------------------------
__global__ __launch_bounds__(256) void cvt_w16(
    const float* __restrict__ src, __half* __restrict__ dst, int n4)
{
    for (int i = blockIdx.x * 256 + threadIdx.x; i < n4; i += gridDim.x * 256) {
        float4 v = ((const float4*)src)[i];
        ((__half2*)dst)[2 * i]     = __halves2half2(__float2half_rn(v.x), __float2half_rn(v.y));
        ((__half2*)dst)[2 * i + 1] = __halves2half2(__float2half_rn(v.z), __float2half_rn(v.w));
    }
}

// ---------------- all weight conversions in one launch ---------------------------
__global__ __launch_bounds__(256) void cvt_weights(
    const float* __restrict__ q_w, const float* __restrict__ kv_w,
    const float* __restrict__ proj_w)
{
    const int NQ = CCH * CCH / 4, NKV = 2 * CCH * CCH / 4, NP = CCH * CCH / 4;
    for (int i = blockIdx.x * 256 + threadIdx.x; i < NQ + NKV + NP; i += gridDim.x * 256) {
        const float* src; __half* dst; int j;
        if (i < NQ)            { src = q_w;    dst = g_wqkv16;             j = i; }
        else if (i < NQ + NKV) { src = kv_w;   dst = g_wqkv16 + CCH * CCH; j = i - NQ; }
        else                   { src = proj_w; dst = g_wp16;               j = i - NQ - NKV; }
        float4 v = ((const float4*)src)[j];
        ((__half2*)dst)[2 * j]     = __halves2half2(__float2half_rn(v.x), __float2half_rn(v.y));
        ((__half2*)dst)[2 * j + 1] = __halves2half2(__float2half_rn(v.z), __float2half_rn(v.w));
    }
}

// ---------------- pooling: q -> at16 (x0.125, pad rows zero) ---------------------
__global__ __launch_bounds__(256) void pool_kernel()
{
    int b = blockIdx.x, a = blockIdx.y;
    if (a >= AG) {
        for (int c = threadIdx.x; c < CCH; c += 256)
            g_at16[(((b * 8 + (c >> 6)) * 64) + a) * 64 + (c & 63)] = __float2half(0.f);
        return;
    }
    int p1 = a / 7, p2 = a % 7;
    for (int c = threadIdx.x; c < CCH; c += 256) {
        float s = 0.f;
#pragma unroll
        for (int r = 0; r < 8; r++)
#pragma unroll
            for (int ss = 0; ss < 8; ss++)
                s += __half2float(g_qkv16[((size_t)(b * NTOK + (p1 * 8 + r) * HW + p2 * 8 + ss)) * QKVW + c]);
        g_at16[(((b * 8 + (c >> 6)) * 64) + a) * 64 + (c & 63)] =
            __float2half_rn(s * (1.0f / 64.0f) * 0.125f);
    }
}

// ---------------- jax bilinear resize + bias folding, fp16 out -------------------
__device__ __forceinline__ void lin_w(int o, int& i0, int& i1, float& w0, float& w1)
{
    float p = (o + 0.5f) * 0.125f - 0.5f;
    float fp = floorf(p);
    int i = (int)fp;
    float f = p - fp;
    if (i < 0)       { i0 = 0; i1 = 0; w0 = 1.f; w1 = 0.f; }
    else if (i >= 6) { i0 = 6; i1 = 6; w0 = 1.f; w1 = 0.f; }
    else             { i0 = i; i1 = i + 1; w0 = 1.f - f; w1 = f; }
}

__global__ __launch_bounds__(256) void bias_resize_kernel(
    const float* __restrict__ an, const float* __restrict__ na,
    const float* __restrict__ ahb, const float* __restrict__ awb,
    const float* __restrict__ hab, const float* __restrict__ wab)
{
    int a = blockIdx.x, h = blockIdx.y, src = blockIdx.z;
    const float* S = (src == 0 ? an : na) + (h * AG + a) * 49;
    __shared__ float s[49];
    if (threadIdx.x < 49) s[threadIdx.x] = S[threadIdx.x];
    __syncthreads();
    for (int o = threadIdx.x; o < NTOK; o += 256) {
        int oh = o / HW, ow = o % HW;
        int r0, r1, c0, c1; float wr0, wr1, wc0, wc1;
        lin_w(oh, r0, r1, wr0, wr1);
        lin_w(ow, c0, c1, wc0, wc1);
        float v = wr0 * (wc0 * s[r0 * 7 + c0] + wc1 * s[r0 * 7 + c1]) +
                  wr1 * (wc0 * s[r1 * 7 + c0] + wc1 * s[r1 * 7 + c1]);
        if (src == 0) {
            v += ahb[(h * AG + a) * HW + oh] + awb[(h * AG + a) * HW + ow];
            g_PB1h[((size_t)(h * AG + a)) * NTOK + o] = __float2half_rn(v);
        } else {
            v += hab[(h * HW + oh) * AG + a] + wab[(h * HW + ow) * AG + a];
            g_NB1Th[((size_t)h * NTOK + o) * 64 + a] = __float2half_rn(v);
        }
    }
}

// ---------------- agent logits + tile-local exp, stats out -----------------------
__global__ __launch_bounds__(128) void agent_logits_mma()
{
    __shared__ __align__(1024) char sm[16384];   // [AT 8KB][K 8KB]
    int bh = blockIdx.y, b = bh >> 3, h = bh & 7;
    int tile = blockIdx.x;
    int i0 = tile * 64;
    int tid = threadIdx.x, wid = tid >> 5, lane = tid & 31;
    uint32_t sAT = smem_u32(sm), sK = sAT + 8192;

    const __half* atp = g_at16 + (size_t)bh * 64 * 64;
#pragma unroll
    for (int it = 0; it < 4; it++) {
        int idx = tid + it * 128;
        int r = idx >> 3, c = idx & 7;
        uint32_t o = r * 128 + (SW8(r, c) << 4);
        cpa16(sAT + o, atp + r * 64 + c * 8);
        cpa16(sK + o, g_qkv16 + (size_t)(b * NTOK + i0 + r) * QKVW + 512 + h * 64 + c * 8);
    }
    CP_COMMIT(); CP_WAIT0();
    __syncthreads();

    int g = lane >> 3, lr = lane & 7;
    float acc1[8][4] = {};
#pragma unroll
    for (int ks = 0; ks < 4; ks++) {
        uint32_t af[4], bf[8][2];
        {
            int row = wid * 16 + ((g & 1) << 3) + lr;
            int c = ks * 2 + (g >> 1);
            LDSM_X4(af[0], af[1], af[2], af[3], sAT + row * 128 + (SW8(row, c) << 4));
        }
#pragma unroll
        for (int np = 0; np < 4; np++) {
            int row = np * 16 + ((g >> 1) << 3) + lr;
            int c = ks * 2 + (g & 1);
            uint32_t r0, r1, r2, r3;
            LDSM_X4(r0, r1, r2, r3, sK + row * 128 + (SW8(row, c) << 4));
            bf[np * 2][0] = r0; bf[np * 2][1] = r1;
            bf[np * 2 + 1][0] = r2; bf[np * 2 + 1][1] = r3;
        }
#pragma unroll
        for (int nt = 0; nt < 8; nt++)
            MMA16816(acc1[nt], af, bf[nt]);
    }

    int a1 = wid * 16 + (lane >> 2), a2 = a1 + 8;
    bool v1 = a1 < AG, v2 = a2 < AG;
#pragma unroll
    for (int nt = 0; nt < 8; nt++) {
        int tb = i0 + nt * 8 + ((lane & 3) << 1);
        if (v1) {
            __half2 pb = *(const __half2*)(g_PB1h + ((size_t)(h * AG + a1)) * NTOK + tb);
            acc1[nt][0] += __low2float(pb); acc1[nt][1] += __high2float(pb);
        }
        if (v2) {
            __half2 pb = *(const __half2*)(g_PB1h + ((size_t)(h * AG + a2)) * NTOK + tb);
            acc1[nt][2] += __low2float(pb); acc1[nt][3] += __high2float(pb);
        }
    }
    float m1 = -1e30f, m2 = -1e30f;
#pragma unroll
    for (int nt = 0; nt < 8; nt++) {
        m1 = fmaxf(m1, fmaxf(acc1[nt][0], acc1[nt][1]));
        m2 = fmaxf(m2, fmaxf(acc1[nt][2], acc1[nt][3]));
    }
    m1 = fmaxf(m1, __shfl_xor_sync(~0u, m1, 1)); m1 = fmaxf(m1, __shfl_xor_sync(~0u, m1, 2));
    m2 = fmaxf(m2, __shfl_xor_sync(~0u, m2, 1)); m2 = fmaxf(m2, __shfl_xor_sync(~0u, m2, 2));
    float s1 = 0.f, s2 = 0.f;
#pragma unroll
    for (int nt = 0; nt < 8; nt++) {
        acc1[nt][0] = __expf(acc1[nt][0] - m1); s1 += acc1[nt][0];
        acc1[nt][1] = __expf(acc1[nt][1] - m1); s1 += acc1[nt][1];
        acc1[nt][2] = __expf(acc1[nt][2] - m2); s2 += acc1[nt][2];
        acc1[nt][3] = __expf(acc1[nt][3] - m2); s2 += acc1[nt][3];
    }
    s1 += __shfl_xor_sync(~0u, s1, 1); s1 += __shfl_xor_sync(~0u, s1, 2);
    s2 += __shfl_xor_sync(~0u, s2, 1); s2 += __shfl_xor_sync(~0u, s2, 2);
#pragma unroll
    for (int nt = 0; nt < 8; nt++) {
        int tb = i0 + nt * 8 + ((lane & 3) << 1);
        if (v1)
            *(__half2*)(g_p16 + ((size_t)bh * 64 + a1) * NTOK + tb) =
                __halves2half2(__float2half_rn(acc1[nt][0]), __float2half_rn(acc1[nt][1]));
        if (v2)
            *(__half2*)(g_p16 + ((size_t)bh * 64 + a2) * NTOK + tb) =
                __halves2half2(__float2half_rn(acc1[nt][2]), __float2half_rn(acc1[nt][3]));
    }
    if ((lane & 3) == 0) {
        if (v1) g_TMS[((size_t)bh * 64 + a1) * NTILE + tile] = make_float2(m1, s1);
        if (v2) g_TMS[((size_t)bh * 64 + a2) * NTILE + tile] = make_float2(m2, s2);
    }
}

// ---------------- per-row softmax stats -> per-tile factors ----------------------
__global__ __launch_bounds__(64) void softmax_stats()
{
    int bh = blockIdx.x;
    int a = threadIdx.x;
    if (a >= AG) return;
    const float2* tms = g_TMS + ((size_t)bh * 64 + a) * NTILE;
    float gmax = -1e30f;
#pragma unroll 7
    for (int i = 0; i < NTILE; i++) gmax = fmaxf(gmax, tms[i].x);
    float total = 0.f;
#pragma unroll 7
    for (int i = 0; i < NTILE; i++) total += tms[i].y * __expf(tms[i].x - gmax);
    float inv = 1.0f / total;
    float* f = g_F + ((size_t)bh * 64 + a) * NTILE;
#pragma unroll 7
    for (int i = 0; i < NTILE; i++) f[i] = __expf(tms[i].x - gmax) * inv;
}

// ---------------- agent_v via MMA, split-K; V loaded [t][d] + trans ldmatrix -----
__global__ __launch_bounds__(128) void agent_v_mma()
{
    __shared__ __align__(1024) char sm[NST * 16384];
    int bh = blockIdx.x, sp = blockIdx.y;
    int b = bh >> 3, h = bh & 7;
    int kbeg = sp * 448;
    int tid = threadIdx.x, wid = tid >> 5, lane = tid & 31;
    int wr = wid >> 1, wc = wid & 1;
    uint32_t sbase = smem_u32(sm);
    const __half* pp = g_p16 + (size_t)bh * 64 * NTOK + kbeg;
    const __half* vp = g_qkv16 + (size_t)(b * NTOK + kbeg) * QKVW + 1024 + h * 64;

    int rl = tid >> 3, cl = tid & 7;

#pragma unroll
    for (int pc = 0; pc < 2; pc++) {
        uint32_t sb = sbase + pc * 16384;
#pragma unroll
        for (int it = 0; it < 4; it++) {
            int r = rl + it * 16;
            uint32_t o = (r << 7) + (SW8(r, cl) << 4);
            cpa16(sb + o, pp + (size_t)r * NTOK + pc * 64 + cl * 8);
            cpa16(sb + 8192 + o, vp + (size_t)(pc * 64 + r) * QKVW + cl * 8);
        }
        CP_COMMIT();
    }

    int g = lane >> 3, lr = lane & 7;
    int ra = lane >> 2;
    float acc[2][4][4] = {};
    for (int ch = 0; ch < 7; ch++) {
        __syncthreads();
        if (ch + 2 < 7) {
            uint32_t nb = sbase + ((ch + 2) % NST) * 16384;
#pragma unroll
            for (int it = 0; it < 4; it++) {
                int r = rl + it * 16;
                uint32_t o = (r << 7) + (SW8(r, cl) << 4);
                cpa16(nb + o, pp + (size_t)r * NTOK + (ch + 2) * 64 + cl * 8);
                cpa16(nb + 8192 + o, vp + (size_t)((ch + 2) * 64 + r) * QKVW + cl * 8);
            }
            CP_COMMIT();
        }
        if (ch <= 4)      asm volatile("cp.async.wait_group 2;" ::: "memory");
        else if (ch == 5) asm volatile("cp.async.wait_group 1;" ::: "memory");
        else              asm volatile("cp.async.wait_group 0;" ::: "memory");
        __syncthreads();

        uint32_t base = sbase + (ch % NST) * 16384;
        int tileIdx = sp * 7 + ch;
        float fv[2][2];
#pragma unroll
        for (int mt = 0; mt < 2; mt++)
#pragma unroll
            for (int half = 0; half < 2; half++) {
                int a = wr * 32 + mt * 16 + ra + half * 8;
                fv[mt][half] = g_F[((size_t)bh * 64 + a) * NTILE + tileIdx];
            }

        float accc[2][4][4] = {};
#pragma unroll
        for (int ks = 0; ks < 4; ks++) {
            uint32_t af[2][4], bf[4][2];
#pragma unroll
            for (int mt = 0; mt < 2; mt++) {
                int row = wr * 32 + mt * 16 + ((g & 1) << 3) + lr;
                int c = ks * 2 + (g >> 1);
                LDSM_X4(af[mt][0], af[mt][1], af[mt][2], af[mt][3],
                        base + row * 128 + (SW8(row, c) << 4));
            }
#pragma unroll
            for (int np = 0; np < 2; np++) {
                int row = ks * 16 + ((g & 1) << 3) + lr;
                int c = wc * 4 + np * 2 + (g >> 1);
                uint32_t r0, r1, r2, r3;
                LDSM_X4_T(r0, r1, r2, r3, base + 8192 + row * 128 + (SW8(row, c) << 4));
                bf[np * 2][0] = r0; bf[np * 2][1] = r1;
                bf[np * 2 + 1][0] = r2; bf[np * 2 + 1][1] = r3;
            }
#pragma unroll
            for (int mt = 0; mt < 2; mt++)
#pragma unroll
                for (int nt = 0; nt < 4; nt++)
                    MMA16816(accc[mt][nt], af[mt], bf[nt]);
        }
#pragma unroll
        for (int mt = 0; mt < 2; mt++)
#pragma unroll
            for (int nt = 0; nt < 4; nt++) {
                acc[mt][nt][0] += fv[mt][0] * accc[mt][nt][0];
                acc[mt][nt][1] += fv[mt][0] * accc[mt][nt][1];
                acc[mt][nt][2] += fv[mt][1] * accc[mt][nt][2];
                acc[mt][nt][3] += fv[mt][1] * accc[mt][nt][3];
            }
    }

#pragma unroll
    for (int mt = 0; mt < 2; mt++)
#pragma unroll
        for (int nt = 0; nt < 4; nt++)
#pragma unroll
            for (int half = 0; half < 2; half++) {
                int a = wr * 32 + mt * 16 + (lane >> 2) + half * 8;
                if (a >= AG) continue;
                int d = wc * 32 + nt * 8 + ((lane & 3) << 1);
                size_t o = ((size_t)sp * 128 + bh) * (AG * HD) + a * HD + d;
                *(float2*)(g_AVP + o) =
                    make_float2(acc[mt][nt][half * 2], acc[mt][nt][half * 2 + 1]);
            }
}

// ---------------- reduce partials -> AV^T fp16 -----------------------------------
__global__ __launch_bounds__(256) void avp_reduce_kernel()
{
    int i = blockIdx.x * 256 + threadIdx.x;
    if (i >= 128 * 64 * 64) return;
    int bh = i >> 12, rest = i & 4095, d = rest >> 6, a = rest & 63;
    float s = 0.f;
    if (a < AG) {
#pragma unroll
        for (int sp = 0; sp < 7; sp++)
            s += g_AVP[((size_t)sp * 128 + bh) * (AG * HD) + a * HD + d];
    }
    g_avt16[((size_t)bh * 64 + d) * 64 + a] = __float2half_rn(s);
}

// ---------------- q-side: MMA logits + reg softmax + MMA out ---------------------
__global__ __launch_bounds__(128) void qside_mma()
{
    __shared__ __align__(1024) char sm[32768];
    int bh = blockIdx.y, b = bh >> 3, h = bh & 7;
    int i0 = blockIdx.x * 64;
    int tid = threadIdx.x, wid = tid >> 5, lane = tid & 31;
    uint32_t sQ = smem_u32(sm), sAT = sQ + 8192, sAVT = sQ + 16384, sP = sQ + 24576;

    const __half* atp = g_at16 + (size_t)bh * 64 * 64;
    const __half* avtp = g_avt16 + (size_t)bh * 64 * 64;
#pragma unroll
    for (int it = 0; it < 4; it++) {
        int idx = tid + it * 128;
        int r = idx >> 3, c = idx & 7;
        uint32_t o = r * 128 + (SW8(r, c) << 4);
        cpa16(sQ + o, g_qkv16 + (size_t)(b * NTOK + i0 + r) * QKVW + h * 64 + c * 8);
        cpa16(sAT + o, atp + r * 64 + c * 8);
        cpa16(sAVT + o, avtp + r * 64 + c * 8);
    }
    CP_COMMIT(); CP_WAIT0();
    __syncthreads();

    int g = lane >> 3, lr = lane & 7;
    float acc1[8][4] = {};
#pragma unroll
    for (int ks = 0; ks < 4; ks++) {
        uint32_t af[4], bf[8][2];
        {
            int row = wid * 16 + ((g & 1) << 3) + lr;
            int c = ks * 2 + (g >> 1);
            LDSM_X4(af[0], af[1], af[2], af[3], sQ + row * 128 + (SW8(row, c) << 4));
        }
#pragma unroll
        for (int np = 0; np < 4; np++) {
            int row = np * 16 + ((g >> 1) << 3) + lr;
            int c = ks * 2 + (g & 1);
            uint32_t r0, r1, r2, r3;
            LDSM_X4(r0, r1, r2, r3, sAT + row * 128 + (SW8(row, c) << 4));
            bf[np * 2][0] = r0; bf[np * 2][1] = r1;
            bf[np * 2 + 1][0] = r2; bf[np * 2 + 1][1] = r3;
        }
#pragma unroll
        for (int nt = 0; nt < 8; nt++)
            MMA16816(acc1[nt], af, bf[nt]);
    }

    int r1 = wid * 16 + (lane >> 2), r2 = r1 + 8;
    int t1 = i0 + r1, t2 = i0 + r2;
#pragma unroll
    for (int nt = 0; nt < 8; nt++) {
        int abase = nt * 8 + ((lane & 3) << 1);
        __half2 b1 = *(const __half2*)(g_NB1Th + ((size_t)h * NTOK + t1) * 64 + abase);
        __half2 b2 = *(const __half2*)(g_NB1Th + ((size_t)h * NTOK + t2) * 64 + abase);
        acc1[nt][0] += __low2float(b1); acc1[nt][1] += __high2float(b1);
        acc1[nt][2] += __low2float(b2); acc1[nt][3] += __high2float(b2);
        if (abase >= AG) {
            acc1[nt][0] = acc1[nt][1] = acc1[nt][2] = acc1[nt][3] = -INFINITY;
        } else if (abase + 1 >= AG) {
            acc1[nt][1] = acc1[nt][3] = -INFINITY;
        }
    }
    float m1 = -1e30f, m2 = -1e30f;
#pragma unroll
    for (int nt = 0; nt < 8; nt++) {
        m1 = fmaxf(m1, fmaxf(acc1[nt][0], acc1[nt][1]));
        m2 = fmaxf(m2, fmaxf(acc1[nt][2], acc1[nt][3]));
    }
    m1 = fmaxf(m1, __shfl_xor_sync(~0u, m1, 1)); m1 = fmaxf(m1, __shfl_xor_sync(~0u, m1, 2));
    m2 = fmaxf(m2, __shfl_xor_sync(~0u, m2, 1)); m2 = fmaxf(m2, __shfl_xor_sync(~0u, m2, 2));
    float s1 = 0.f, s2 = 0.f;
#pragma unroll
    for (int nt = 0; nt < 8; nt++) {
        acc1[nt][0] = __expf(acc1[nt][0] - m1); s1 += acc1[nt][0];
        acc1[nt][1] = __expf(acc1[nt][1] - m1); s1 += acc1[nt][1];
        acc1[nt][2] = __expf(acc1[nt][2] - m2); s2 += acc1[nt][2];
        acc1[nt][3] = __expf(acc1[nt][3] - m2); s2 += acc1[nt][3];
    }
    s1 += __shfl_xor_sync(~0u, s1, 1); s1 += __shfl_xor_sync(~0u, s1, 2);
    s2 += __shfl_xor_sync(~0u, s2, 1); s2 += __shfl_xor_sync(~0u, s2, 2);
    float i1 = 1.0f / s1, i2 = 1.0f / s2;

#pragma unroll
    for (int nt = 0; nt < 8; nt++) {
        int colb = nt * 8 + ((lane & 3) << 1);
        uint32_t o1 = r1 * 128 + (SW8(r1, nt) << 4) + (colb & 7) * 2;
        uint32_t o2 = r2 * 128 + (SW8(r2, nt) << 4) + (colb & 7) * 2;
        __half2 p1 = __halves2half2(__float2half_rn(acc1[nt][0] * i1),
                                    __float2half_rn(acc1[nt][1] * i1));
        __half2 p2 = __halves2half2(__float2half_rn(acc1[nt][2] * i2),
                                    __float2half_rn(acc1[nt][3] * i2));
        asm volatile("st.shared.b32 [%0], %1;" :: "r"(sP + o1), "r"(*(uint32_t*)&p1));
        asm volatile("st.shared.b32 [%0], %1;" :: "r"(sP + o2), "r"(*(uint32_t*)&p2));
    }
    __syncwarp();

    float acc2[8][4] = {};
#pragma unroll
    for (int ks = 0; ks < 4; ks++) {
        uint32_t af[4], bf[8][2];
        {
            int row = wid * 16 + ((g & 1) << 3) + lr;
            int c = ks * 2 + (g >> 1);
            LDSM_X4(af[0], af[1], af[2], af[3], sP + row * 128 + (SW8(row, c) << 4));
        }
#pragma unroll
        for (int np = 0; np < 4; np++) {
            int row = np * 16 + ((g >> 1) << 3) + lr;
            int c = ks * 2 + (g & 1);
            uint32_t r0, r1x, r2x, r3;
            LDSM_X4(r0, r1x, r2x, r3, sAVT + row * 128 + (SW8(row, c) << 4));
            bf[np * 2][0] = r0; bf[np * 2][1] = r1x;
            bf[np * 2 + 1][0] = r2x; bf[np * 2 + 1][1] = r3;
        }
#pragma unroll
        for (int nt = 0; nt < 8; nt++)
            MMA16816(acc2[nt], af, bf[nt]);
    }

#pragma unroll
    for (int nt = 0; nt < 8; nt++) {
        int d = nt * 8 + ((lane & 3) << 1);
        *(__half2*)(g_ao16 + (size_t)(b * NTOK + t1) * CCH + h * 64 + d) =
            __halves2half2(__float2half_rn(acc2[nt][0]), __float2half_rn(acc2[nt][1]));
        *(__half2*)(g_ao16 + (size_t)(b * NTOK + t2) * CCH + h * 64 + d) =
            __halves2half2(__float2half_rn(acc2[nt][2]), __float2half_rn(acc2[nt][3]));
    }
}

// ---------------- 3x3 depthwise conv + attn-out add -> fp16 proj input -----------
__global__ __launch_bounds__(256) void dwc_kernel(
    const float* __restrict__ dwc_w, const float* __restrict__ dwc_b)
{
    int oh = blockIdx.x, b = blockIdx.y;
    __shared__ float w_s[CCH * 9];
    __shared__ float b_s[CCH];
    int tid = threadIdx.x;
    for (int t = tid; t < CCH * 9; t += 256) w_s[t] = dwc_w[t];
    for (int t = tid; t < CCH; t += 256) b_s[t] = dwc_b[t];
    __syncthreads();
    for (int idx = tid; idx < HW * CCH; idx += 256) {
        int ow = idx >> 9, c = idx & 511;
        float acc = b_s[c];
#pragma unroll
        for (int ky = 0; ky < 3; ky++) {
            int h2 = oh + ky - 1;
            if (h2 < 0 || h2 >= HW) continue;
#pragma unroll
            for (int kx = 0; kx < 3; kx++) {
                int w2 = ow + kx - 1;
                if (w2 < 0 || w2 >= HW) continue;
                acc += __half2float(g_qkv16[((size_t)(b * NTOK + h2 * HW + w2)) * QKVW + 1024 + c])
                     * w_s[c * 9 + ky * 3 + kx];
            }
        }
        size_t gi = ((size_t)(b * NTOK + oh * HW + ow)) * CCH + c;
        g_ahi[gi] = __float2half_rn(__half2float(g_ao16[gi]) + acc);
    }
}

// ---------------- launch ---------------------------------------------------------
extern "C" void kernel_launch(void* const* d_in, const int* in_sizes, int n_in,
                              void* d_out, int out_size)
{
    const float* x = (const float*)d_in[0];
    int off = 1;
    if (n_in >= 15 && in_sizes[1] == 1) off = 3;
    const float* q_w    = (const float*)d_in[off + 0];
    const float* kv_w   = (const float*)d_in[off + 1];
    const float* proj_w = (const float*)d_in[off + 2];
    const float* proj_b = (const float*)d_in[off + 3];
    const float* dwc_w  = (const float*)d_in[off + 4];
    const float* dwc_b  = (const float*)d_in[off + 5];
    const float* an_b   = (const float*)d_in[off + 6];
    const float* na_b   = (const float*)d_in[off + 7];
    const float* ah_b   = (const float*)d_in[off + 8];
    const float* aw_b   = (const float*)d_in[off + 9];
    const float* ha_b   = (const float*)d_in[off + 10];
    const float* wa_b   = (const float*)d_in[off + 11];
    float* out = (float*)d_out;

    __half *x16, *qkv16, *ahi, *wqkv16, *wp16;
    cudaGetSymbolAddress((void**)&x16, g_x16);
    cudaGetSymbolAddress((void**)&qkv16, g_qkv16);
    cudaGetSymbolAddress((void**)&ahi, g_ahi);
    cudaGetSymbolAddress((void**)&wqkv16, g_wqkv16);
    cudaGetSymbolAddress((void**)&wp16, g_wp16);

    static int smem_set = 0;
    if (!smem_set) {
        cudaFuncSetAttribute(gemm_tc<0>, cudaFuncAttributeMaxDynamicSharedMemorySize, NST * STG2);
        cudaFuncSetAttribute(gemm_tc<1>, cudaFuncAttributeMaxDynamicSharedMemorySize, NST * STG2);
        smem_set = 1;
    }

    cvt_w16<<<2048, 256>>>(x, x16, MROWS * CCH / 4);
    cvt_weights<<<1024, 256>>>(q_w, kv_w, proj_w);
    bias_resize_kernel<<<dim3(AG, HEADS, 2), 256>>>(an_b, na_b, ah_b, aw_b, ha_b, wa_b);

    gemm_tc<1><<<dim3(QKVW / 128, MROWS / 128), 256, NST * STG2>>>(
        x16, wqkv16, nullptr, nullptr, qkv16, QKVW);

    pool_kernel<<<dim3(NB, 64), 256>>>();
    agent_logits_mma<<<dim3(NTILE, NB * HEADS), 128>>>();
    softmax_stats<<<NB * HEADS, 64>>>();
    agent_v_mma<<<dim3(NB * HEADS, 7), 128>>>();
    avp_reduce_kernel<<<(128 * 64 * 64 + 255) / 256, 256>>>();
    qside_mma<<<dim3(NTOK / 64, NB * HEADS), 128>>>();
    dwc_kernel<<<dim3(HW, NB), 256>>>(dwc_w, dwc_b);

    gemm_tc<0><<<dim3(512 / 128, MROWS / 128), 256, NST * STG2>>>(
        ahi, wp16, out, proj_b, nullptr, 512);
}

// round 16
// speedup vs baseline: 6.4906x; 1.1004x over previous
#include <cuda_runtime.h>
#include <cuda_fp16.h>
#include <math.h>
#include <stdint.h>

#define HEADS 8
#define HD 64
#define CCH 512
#define HW 56
#define NTOK 3136
#define AG 49
#define NB 16
#define MROWS (NB*NTOK)
#define KDIM 512
#define QKVW 1536
#define NTILE 49            // NTOK / 64

// ---------------- scratch (static device globals; zero-initialized) --------------
__device__ float g_AVP[7 * NB * HEADS * AG * HD];
__device__ float2 g_TMS[(size_t)NB * HEADS * 64 * NTILE];   // per-tile (max, sum)
__device__ float g_F[(size_t)NB * HEADS * 64 * NTILE];      // per-tile softmax factor
__device__ __half g_PB1h[HEADS * AG * NTOK];
__device__ __half g_NB1Th[HEADS * NTOK * 64];
__device__ __half g_x16[(size_t)MROWS * CCH];
__device__ __half g_qkv16[(size_t)MROWS * QKVW];
__device__ __half g_at16[NB * HEADS * 64 * 64];
__device__ __half g_p16[(size_t)NB * HEADS * 64 * NTOK];    // e = exp(l - tilemax); pad rows 0
__device__ __half g_avt16[NB * HEADS * 64 * 64];
__device__ __half g_cv16[(size_t)MROWS * CCH];              // depthwise conv output
__device__ __half g_ahi[(size_t)MROWS * CCH];               // proj input (attn + conv)
__device__ __half g_wqkv16[QKVW * CCH];
__device__ __half g_wp16[CCH * CCH];

// ================= low-level helpers =================
__device__ __forceinline__ uint32_t smem_u32(const void* p) {
    uint32_t a;
    asm("{ .reg .u64 t; cvta.to.shared.u64 t, %1; cvt.u32.u64 %0, t; }" : "=r"(a) : "l"(p));
    return a;
}
__device__ __forceinline__ void cpa16(uint32_t s, const void* g) {
    asm volatile("cp.async.cg.shared.global [%0], [%1], 16;" :: "r"(s), "l"(g));
}
#define CP_COMMIT() asm volatile("cp.async.commit_group;" ::: "memory")
#define CP_WAIT0()  asm volatile("cp.async.wait_group 0;" ::: "memory")

#define LDSM_X4(r0, r1, r2, r3, a) \
    asm volatile("ldmatrix.sync.aligned.m8n8.x4.shared.b16 {%0,%1,%2,%3}, [%4];" \
                 : "=r"(r0), "=r"(r1), "=r"(r2), "=r"(r3) : "r"(a))

#define LDSM_X4_T(r0, r1, r2, r3, a) \
    asm volatile("ldmatrix.sync.aligned.m8n8.x4.trans.shared.b16 {%0,%1,%2,%3}, [%4];" \
                 : "=r"(r0), "=r"(r1), "=r"(r2), "=r"(r3) : "r"(a))

#define MMA16816(d, a, b) \
    asm volatile("mma.sync.aligned.m16n8k16.row.col.f32.f16.f16.f32 " \
                 "{%0,%1,%2,%3}, {%4,%5,%6,%7}, {%8,%9}, {%0,%1,%2,%3};" \
                 : "+f"((d)[0]), "+f"((d)[1]), "+f"((d)[2]), "+f"((d)[3]) \
                 : "r"((a)[0]), "r"((a)[1]), "r"((a)[2]), "r"((a)[3]), \
                   "r"((b)[0]), "r"((b)[1]))

#define SW8(r, c) ((c) ^ ((r) & 7))

#define NST 3
#define STG2 32768u          // [A 16KB][B 16KB], K-chunk 64, 128B rows

// ================= fp16 tensor-core GEMM, 1-term, CTA 128x128 ===================
// warp tile 32(M) x 64(N); 8 warps (4x2); K-chunk 64; single-sync multistage.
template<int MODE>
__global__ void __launch_bounds__(256, 2) gemm_tc(
    const __half* __restrict__ A16, const __half* __restrict__ B16,
    float* __restrict__ Cf, const float* __restrict__ bias,
    __half* __restrict__ C16, int Nout)
{
    extern __shared__ __align__(1024) char smem[];
    int tid = threadIdx.x;
    int wid = tid >> 5, lane = tid & 31;
    int bn0 = blockIdx.x * 128, m0 = blockIdx.y * 128;
    int wr = wid >> 1, wc = wid & 1;
    uint32_t sbase = smem_u32(smem);

    float acc[2][8][4] = {};

    int rl = tid >> 3, cl = tid & 7;

    // prologue: chunks 0, 1
#pragma unroll
    for (int pc = 0; pc < 2; pc++) {
        int k0 = pc * 64;
        uint32_t sb = sbase + pc * STG2;
#pragma unroll
        for (int it = 0; it < 4; it++) {
            int r = rl + it * 32;
            uint32_t o = (r << 7) + (SW8(r, cl) << 4);
            cpa16(sb + o,         A16 + (size_t)(m0 + r) * KDIM + k0 + cl * 8);
            cpa16(sb + 16384 + o, B16 + (size_t)(bn0 + r) * KDIM + k0 + cl * 8);
        }
        CP_COMMIT();
    }

    int g = lane >> 3, lr = lane & 7;

    for (int ch = 0; ch < 8; ch++) {
        if (ch < 7) asm volatile("cp.async.wait_group 1;" ::: "memory");
        else        asm volatile("cp.async.wait_group 0;" ::: "memory");
        __syncthreads();
        if (ch + 2 < 8) {
            int k0 = (ch + 2) * 64;
            uint32_t nb = sbase + ((ch + 2) % NST) * STG2;
#pragma unroll
            for (int it = 0; it < 4; it++) {
                int r = rl + it * 32;
                uint32_t o = (r << 7) + (SW8(r, cl) << 4);
                cpa16(nb + o,         A16 + (size_t)(m0 + r) * KDIM + k0 + cl * 8);
                cpa16(nb + 16384 + o, B16 + (size_t)(bn0 + r) * KDIM + k0 + cl * 8);
            }
            CP_COMMIT();
        }

        uint32_t base = sbase + (ch % NST) * STG2;

#pragma unroll
        for (int ks = 0; ks < 4; ks++) {
            uint32_t af[2][4], bf[8][2];
#pragma unroll
            for (int mt = 0; mt < 2; mt++) {
                int row = wr * 32 + mt * 16 + ((g & 1) << 3) + lr;
                int c = ks * 2 + (g >> 1);
                LDSM_X4(af[mt][0], af[mt][1], af[mt][2], af[mt][3],
                        base + (row << 7) + (SW8(row, c) << 4));
            }
#pragma unroll
            for (int np = 0; np < 4; np++) {
                int row = wc * 64 + np * 16 + ((g >> 1) << 3) + lr;
                int c = ks * 2 + (g & 1);
                uint32_t r0, r1, r2, r3;
                LDSM_X4(r0, r1, r2, r3, base + 16384 + (row << 7) + (SW8(row, c) << 4));
                bf[np * 2][0] = r0; bf[np * 2][1] = r1;
                bf[np * 2 + 1][0] = r2; bf[np * 2 + 1][1] = r3;
            }
#pragma unroll
            for (int mt = 0; mt < 2; mt++)
#pragma unroll
                for (int nt = 0; nt < 8; nt++)
                    MMA16816(acc[mt][nt], af[mt], bf[nt]);
        }
    }

    // epilogue
#pragma unroll
    for (int mt = 0; mt < 2; mt++) {
#pragma unroll
        for (int nt = 0; nt < 8; nt++) {
            int gm0 = m0 + wr * 32 + mt * 16 + (lane >> 2);
            int gn = bn0 + wc * 64 + nt * 8 + ((lane & 3) << 1);
#pragma unroll
            for (int half = 0; half < 2; half++) {
                int gm = gm0 + half * 8;
                float v0 = acc[mt][nt][half * 2], v1 = acc[mt][nt][half * 2 + 1];
                if (MODE == 0) {
                    v0 += bias[gn]; v1 += bias[gn + 1];
                    *(float2*)(Cf + (size_t)gm * Nout + gn) = make_float2(v0, v1);
                } else {
                    *(__half2*)(C16 + (size_t)gm * Nout + gn) =
                        __halves2half2(__float2half_rn(v0), __float2half_rn(v1));
                }
            }
        }
    }
}

// ---------------- fp32 -> fp16 (activation) --------------------------------------
__global__ __launch_bounds__(256) void cvt_w16(
    const float* __restrict__ src, __half* __restrict__ dst, int n4)
{
    for (int i = blockIdx.x * 256 + threadIdx.x; i < n4; i += gridDim.x * 256) {
        float4 v = ((const float4*)src)[i];
        ((__half2*)dst)[2 * i]     = __halves2half2(__float2half_rn(v.x), __float2half_rn(v.y));
        ((__half2*)dst)[2 * i + 1] = __halves2half2(__float2half_rn(v.z), __float2half_rn(v.w));
    }
}

// ---------------- all weight conversions in one launch ---------------------------
__global__ __launch_bounds__(256) void cvt_weights(
    const float* __restrict__ q_w, const float* __restrict__ kv_w,
    const float* __restrict__ proj_w)
{
    const int NQ = CCH * CCH / 4, NKV = 2 * CCH * CCH / 4, NP = CCH * CCH / 4;
    for (int i = blockIdx.x * 256 + threadIdx.x; i < NQ + NKV + NP; i += gridDim.x * 256) {
        const float* src; __half* dst; int j;
        if (i < NQ)            { src = q_w;    dst = g_wqkv16;             j = i; }
        else if (i < NQ + NKV) { src = kv_w;   dst = g_wqkv16 + CCH * CCH; j = i - NQ; }
        else                   { src = proj_w; dst = g_wp16;               j = i - NQ - NKV; }
        float4 v = ((const float4*)src)[j];
        ((__half2*)dst)[2 * j]     = __halves2half2(__float2half_rn(v.x), __float2half_rn(v.y));
        ((__half2*)dst)[2 * j + 1] = __halves2half2(__float2half_rn(v.z), __float2half_rn(v.w));
    }
}

// ---------------- pooling: q -> at16 (x0.125, pad rows zero) ---------------------
__global__ __launch_bounds__(256) void pool_kernel()
{
    int b = blockIdx.x, a = blockIdx.y;
    if (a >= AG) {
        for (int c = threadIdx.x; c < CCH; c += 256)
            g_at16[(((b * 8 + (c >> 6)) * 64) + a) * 64 + (c & 63)] = __float2half(0.f);
        return;
    }
    int p1 = a / 7, p2 = a % 7;
    for (int c = threadIdx.x; c < CCH; c += 256) {
        float s = 0.f;
#pragma unroll
        for (int r = 0; r < 8; r++)
#pragma unroll
            for (int ss = 0; ss < 8; ss++)
                s += __half2float(g_qkv16[((size_t)(b * NTOK + (p1 * 8 + r) * HW + p2 * 8 + ss)) * QKVW + c]);
        g_at16[(((b * 8 + (c >> 6)) * 64) + a) * 64 + (c & 63)] =
            __float2half_rn(s * (1.0f / 64.0f) * 0.125f);
    }
}

// ---------------- jax bilinear resize + bias folding, fp16 out -------------------
__device__ __forceinline__ void lin_w(int o, int& i0, int& i1, float& w0, float& w1)
{
    float p = (o + 0.5f) * 0.125f - 0.5f;
    float fp = floorf(p);
    int i = (int)fp;
    float f = p - fp;
    if (i < 0)       { i0 = 0; i1 = 0; w0 = 1.f; w1 = 0.f; }
    else if (i >= 6) { i0 = 6; i1 = 6; w0 = 1.f; w1 = 0.f; }
    else             { i0 = i; i1 = i + 1; w0 = 1.f - f; w1 = f; }
}

__global__ __launch_bounds__(256) void bias_resize_kernel(
    const float* __restrict__ an, const float* __restrict__ na,
    const float* __restrict__ ahb, const float* __restrict__ awb,
    const float* __restrict__ hab, const float* __restrict__ wab)
{
    int a = blockIdx.x, h = blockIdx.y, src = blockIdx.z;
    const float* S = (src == 0 ? an : na) + (h * AG + a) * 49;
    __shared__ float s[49];
    if (threadIdx.x < 49) s[threadIdx.x] = S[threadIdx.x];
    __syncthreads();
    for (int o = threadIdx.x; o < NTOK; o += 256) {
        int oh = o / HW, ow = o % HW;
        int r0, r1, c0, c1; float wr0, wr1, wc0, wc1;
        lin_w(oh, r0, r1, wr0, wr1);
        lin_w(ow, c0, c1, wc0, wc1);
        float v = wr0 * (wc0 * s[r0 * 7 + c0] + wc1 * s[r0 * 7 + c1]) +
                  wr1 * (wc0 * s[r1 * 7 + c0] + wc1 * s[r1 * 7 + c1]);
        if (src == 0) {
            v += ahb[(h * AG + a) * HW + oh] + awb[(h * AG + a) * HW + ow];
            g_PB1h[((size_t)(h * AG + a)) * NTOK + o] = __float2half_rn(v);
        } else {
            v += hab[(h * HW + oh) * AG + a] + wab[(h * HW + ow) * AG + a];
            g_NB1Th[((size_t)h * NTOK + o) * 64 + a] = __float2half_rn(v);
        }
    }
}

// ---------------- agent logits + tile-local exp, stats out -----------------------
__global__ __launch_bounds__(128) void agent_logits_mma()
{
    __shared__ __align__(1024) char sm[16384];   // [AT 8KB][K 8KB]
    int bh = blockIdx.y, b = bh >> 3, h = bh & 7;
    int tile = blockIdx.x;
    int i0 = tile * 64;
    int tid = threadIdx.x, wid = tid >> 5, lane = tid & 31;
    uint32_t sAT = smem_u32(sm), sK = sAT + 8192;

    const __half* atp = g_at16 + (size_t)bh * 64 * 64;
#pragma unroll
    for (int it = 0; it < 4; it++) {
        int idx = tid + it * 128;
        int r = idx >> 3, c = idx & 7;
        uint32_t o = r * 128 + (SW8(r, c) << 4);
        cpa16(sAT + o, atp + r * 64 + c * 8);
        cpa16(sK + o, g_qkv16 + (size_t)(b * NTOK + i0 + r) * QKVW + 512 + h * 64 + c * 8);
    }
    CP_COMMIT(); CP_WAIT0();
    __syncthreads();

    int g = lane >> 3, lr = lane & 7;
    float acc1[8][4] = {};
#pragma unroll
    for (int ks = 0; ks < 4; ks++) {
        uint32_t af[4], bf[8][2];
        {
            int row = wid * 16 + ((g & 1) << 3) + lr;
            int c = ks * 2 + (g >> 1);
            LDSM_X4(af[0], af[1], af[2], af[3], sAT + row * 128 + (SW8(row, c) << 4));
        }
#pragma unroll
        for (int np = 0; np < 4; np++) {
            int row = np * 16 + ((g >> 1) << 3) + lr;
            int c = ks * 2 + (g & 1);
            uint32_t r0, r1, r2, r3;
            LDSM_X4(r0, r1, r2, r3, sK + row * 128 + (SW8(row, c) << 4));
            bf[np * 2][0] = r0; bf[np * 2][1] = r1;
            bf[np * 2 + 1][0] = r2; bf[np * 2 + 1][1] = r3;
        }
#pragma unroll
        for (int nt = 0; nt < 8; nt++)
            MMA16816(acc1[nt], af, bf[nt]);
    }

    int a1 = wid * 16 + (lane >> 2), a2 = a1 + 8;
    bool v1 = a1 < AG, v2 = a2 < AG;
#pragma unroll
    for (int nt = 0; nt < 8; nt++) {
        int tb = i0 + nt * 8 + ((lane & 3) << 1);
        if (v1) {
            __half2 pb = *(const __half2*)(g_PB1h + ((size_t)(h * AG + a1)) * NTOK + tb);
            acc1[nt][0] += __low2float(pb); acc1[nt][1] += __high2float(pb);
        }
        if (v2) {
            __half2 pb = *(const __half2*)(g_PB1h + ((size_t)(h * AG + a2)) * NTOK + tb);
            acc1[nt][2] += __low2float(pb); acc1[nt][3] += __high2float(pb);
        }
    }
    float m1 = -1e30f, m2 = -1e30f;
#pragma unroll
    for (int nt = 0; nt < 8; nt++) {
        m1 = fmaxf(m1, fmaxf(acc1[nt][0], acc1[nt][1]));
        m2 = fmaxf(m2, fmaxf(acc1[nt][2], acc1[nt][3]));
    }
    m1 = fmaxf(m1, __shfl_xor_sync(~0u, m1, 1)); m1 = fmaxf(m1, __shfl_xor_sync(~0u, m1, 2));
    m2 = fmaxf(m2, __shfl_xor_sync(~0u, m2, 1)); m2 = fmaxf(m2, __shfl_xor_sync(~0u, m2, 2));
    float s1 = 0.f, s2 = 0.f;
#pragma unroll
    for (int nt = 0; nt < 8; nt++) {
        acc1[nt][0] = __expf(acc1[nt][0] - m1); s1 += acc1[nt][0];
        acc1[nt][1] = __expf(acc1[nt][1] - m1); s1 += acc1[nt][1];
        acc1[nt][2] = __expf(acc1[nt][2] - m2); s2 += acc1[nt][2];
        acc1[nt][3] = __expf(acc1[nt][3] - m2); s2 += acc1[nt][3];
    }
    s1 += __shfl_xor_sync(~0u, s1, 1); s1 += __shfl_xor_sync(~0u, s1, 2);
    s2 += __shfl_xor_sync(~0u, s2, 1); s2 += __shfl_xor_sync(~0u, s2, 2);
#pragma unroll
    for (int nt = 0; nt < 8; nt++) {
        int tb = i0 + nt * 8 + ((lane & 3) << 1);
        if (v1)
            *(__half2*)(g_p16 + ((size_t)bh * 64 + a1) * NTOK + tb) =
                __halves2half2(__float2half_rn(acc1[nt][0]), __float2half_rn(acc1[nt][1]));
        if (v2)
            *(__half2*)(g_p16 + ((size_t)bh * 64 + a2) * NTOK + tb) =
                __halves2half2(__float2half_rn(acc1[nt][2]), __float2half_rn(acc1[nt][3]));
    }
    if ((lane & 3) == 0) {
        if (v1) g_TMS[((size_t)bh * 64 + a1) * NTILE + tile] = make_float2(m1, s1);
        if (v2) g_TMS[((size_t)bh * 64 + a2) * NTILE + tile] = make_float2(m2, s2);
    }
}

// ---------------- per-row softmax stats -> per-tile factors ----------------------
__global__ __launch_bounds__(64) void softmax_stats()
{
    int bh = blockIdx.x;
    int a = threadIdx.x;
    if (a >= AG) return;
    const float2* tms = g_TMS + ((size_t)bh * 64 + a) * NTILE;
    float gmax = -1e30f;
#pragma unroll 7
    for (int i = 0; i < NTILE; i++) gmax = fmaxf(gmax, tms[i].x);
    float total = 0.f;
#pragma unroll 7
    for (int i = 0; i < NTILE; i++) total += tms[i].y * __expf(tms[i].x - gmax);
    float inv = 1.0f / total;
    float* f = g_F + ((size_t)bh * 64 + a) * NTILE;
#pragma unroll 7
    for (int i = 0; i < NTILE; i++) f[i] = __expf(tms[i].x - gmax) * inv;
}

// ---------------- agent_v via MMA, split-K; single-sync multistage ---------------
__global__ __launch_bounds__(128) void agent_v_mma()
{
    __shared__ __align__(1024) char sm[NST * 16384];
    int bh = blockIdx.x, sp = blockIdx.y;
    int b = bh >> 3, h = bh & 7;
    int kbeg = sp * 448;
    int tid = threadIdx.x, wid = tid >> 5, lane = tid & 31;
    int wr = wid >> 1, wc = wid & 1;
    uint32_t sbase = smem_u32(sm);
    const __half* pp = g_p16 + (size_t)bh * 64 * NTOK + kbeg;
    const __half* vp = g_qkv16 + (size_t)(b * NTOK + kbeg) * QKVW + 1024 + h * 64;

    int rl = tid >> 3, cl = tid & 7;

#pragma unroll
    for (int pc = 0; pc < 2; pc++) {
        uint32_t sb = sbase + pc * 16384;
#pragma unroll
        for (int it = 0; it < 4; it++) {
            int r = rl + it * 16;
            uint32_t o = (r << 7) + (SW8(r, cl) << 4);
            cpa16(sb + o, pp + (size_t)r * NTOK + pc * 64 + cl * 8);
            cpa16(sb + 8192 + o, vp + (size_t)(pc * 64 + r) * QKVW + cl * 8);
        }
        CP_COMMIT();
    }

    int g = lane >> 3, lr = lane & 7;
    int ra = lane >> 2;
    float acc[2][4][4] = {};
    for (int ch = 0; ch < 7; ch++) {
        if (ch < 6) asm volatile("cp.async.wait_group 1;" ::: "memory");
        else        asm volatile("cp.async.wait_group 0;" ::: "memory");
        __syncthreads();
        if (ch + 2 < 7) {
            uint32_t nb = sbase + ((ch + 2) % NST) * 16384;
#pragma unroll
            for (int it = 0; it < 4; it++) {
                int r = rl + it * 16;
                uint32_t o = (r << 7) + (SW8(r, cl) << 4);
                cpa16(nb + o, pp + (size_t)r * NTOK + (ch + 2) * 64 + cl * 8);
                cpa16(nb + 8192 + o, vp + (size_t)((ch + 2) * 64 + r) * QKVW + cl * 8);
            }
            CP_COMMIT();
        }

        uint32_t base = sbase + (ch % NST) * 16384;
        int tileIdx = sp * 7 + ch;
        float fv[2][2];
#pragma unroll
        for (int mt = 0; mt < 2; mt++)
#pragma unroll
            for (int half = 0; half < 2; half++) {
                int a = wr * 32 + mt * 16 + ra + half * 8;
                fv[mt][half] = g_F[((size_t)bh * 64 + a) * NTILE + tileIdx];
            }

        float accc[2][4][4] = {};
#pragma unroll
        for (int ks = 0; ks < 4; ks++) {
            uint32_t af[2][4], bf[4][2];
#pragma unroll
            for (int mt = 0; mt < 2; mt++) {
                int row = wr * 32 + mt * 16 + ((g & 1) << 3) + lr;
                int c = ks * 2 + (g >> 1);
                LDSM_X4(af[mt][0], af[mt][1], af[mt][2], af[mt][3],
                        base + row * 128 + (SW8(row, c) << 4));
            }
#pragma unroll
            for (int np = 0; np < 2; np++) {
                int row = ks * 16 + ((g & 1) << 3) + lr;
                int c = wc * 4 + np * 2 + (g >> 1);
                uint32_t r0, r1, r2, r3;
                LDSM_X4_T(r0, r1, r2, r3, base + 8192 + row * 128 + (SW8(row, c) << 4));
                bf[np * 2][0] = r0; bf[np * 2][1] = r1;
                bf[np * 2 + 1][0] = r2; bf[np * 2 + 1][1] = r3;
            }
#pragma unroll
            for (int mt = 0; mt < 2; mt++)
#pragma unroll
                for (int nt = 0; nt < 4; nt++)
                    MMA16816(accc[mt][nt], af[mt], bf[nt]);
        }
#pragma unroll
        for (int mt = 0; mt < 2; mt++)
#pragma unroll
            for (int nt = 0; nt < 4; nt++) {
                acc[mt][nt][0] += fv[mt][0] * accc[mt][nt][0];
                acc[mt][nt][1] += fv[mt][0] * accc[mt][nt][1];
                acc[mt][nt][2] += fv[mt][1] * accc[mt][nt][2];
                acc[mt][nt][3] += fv[mt][1] * accc[mt][nt][3];
            }
    }

#pragma unroll
    for (int mt = 0; mt < 2; mt++)
#pragma unroll
        for (int nt = 0; nt < 4; nt++)
#pragma unroll
            for (int half = 0; half < 2; half++) {
                int a = wr * 32 + mt * 16 + (lane >> 2) + half * 8;
                if (a >= AG) continue;
                int d = wc * 32 + nt * 8 + ((lane & 3) << 1);
                size_t o = ((size_t)sp * 128 + bh) * (AG * HD) + a * HD + d;
                *(float2*)(g_AVP + o) =
                    make_float2(acc[mt][nt][half * 2], acc[mt][nt][half * 2 + 1]);
            }
}

// ---------------- reduce partials -> AV^T fp16 -----------------------------------
__global__ __launch_bounds__(256) void avp_reduce_kernel()
{
    int i = blockIdx.x * 256 + threadIdx.x;
    if (i >= 128 * 64 * 64) return;
    int bh = i >> 12, rest = i & 4095, d = rest >> 6, a = rest & 63;
    float s = 0.f;
    if (a < AG) {
#pragma unroll
        for (int sp = 0; sp < 7; sp++)
            s += g_AVP[((size_t)sp * 128 + bh) * (AG * HD) + a * HD + d];
    }
    g_avt16[((size_t)bh * 64 + d) * 64 + a] = __float2half_rn(s);
}

// ---------------- q-side: MMA logits + reg softmax + MMA out + conv add ----------
__global__ __launch_bounds__(128) void qside_mma()
{
    __shared__ __align__(1024) char sm[32768];
    int bh = blockIdx.y, b = bh >> 3, h = bh & 7;
    int i0 = blockIdx.x * 64;
    int tid = threadIdx.x, wid = tid >> 5, lane = tid & 31;
    uint32_t sQ = smem_u32(sm), sAT = sQ + 8192, sAVT = sQ + 16384, sP = sQ + 24576;

    const __half* atp = g_at16 + (size_t)bh * 64 * 64;
    const __half* avtp = g_avt16 + (size_t)bh * 64 * 64;
#pragma unroll
    for (int it = 0; it < 4; it++) {
        int idx = tid + it * 128;
        int r = idx >> 3, c = idx & 7;
        uint32_t o = r * 128 + (SW8(r, c) << 4);
        cpa16(sQ + o, g_qkv16 + (size_t)(b * NTOK + i0 + r) * QKVW + h * 64 + c * 8);
        cpa16(sAT + o, atp + r * 64 + c * 8);
        cpa16(sAVT + o, avtp + r * 64 + c * 8);
    }
    CP_COMMIT(); CP_WAIT0();
    __syncthreads();

    int g = lane >> 3, lr = lane & 7;
    float acc1[8][4] = {};
#pragma unroll
    for (int ks = 0; ks < 4; ks++) {
        uint32_t af[4], bf[8][2];
        {
            int row = wid * 16 + ((g & 1) << 3) + lr;
            int c = ks * 2 + (g >> 1);
            LDSM_X4(af[0], af[1], af[2], af[3], sQ + row * 128 + (SW8(row, c) << 4));
        }
#pragma unroll
        for (int np = 0; np < 4; np++) {
            int row = np * 16 + ((g >> 1) << 3) + lr;
            int c = ks * 2 + (g & 1);
            uint32_t r0, r1, r2, r3;
            LDSM_X4(r0, r1, r2, r3, sAT + row * 128 + (SW8(row, c) << 4));
            bf[np * 2][0] = r0; bf[np * 2][1] = r1;
            bf[np * 2 + 1][0] = r2; bf[np * 2 + 1][1] = r3;
        }
#pragma unroll
        for (int nt = 0; nt < 8; nt++)
            MMA16816(acc1[nt], af, bf[nt]);
    }

    int r1 = wid * 16 + (lane >> 2), r2 = r1 + 8;
    int t1 = i0 + r1, t2 = i0 + r2;
#pragma unroll
    for (int nt = 0; nt < 8; nt++) {
        int abase = nt * 8 + ((lane & 3) << 1);
        __half2 b1 = *(const __half2*)(g_NB1Th + ((size_t)h * NTOK + t1) * 64 + abase);
        __half2 b2 = *(const __half2*)(g_NB1Th + ((size_t)h * NTOK + t2) * 64 + abase);
        acc1[nt][0] += __low2float(b1); acc1[nt][1] += __high2float(b1);
        acc1[nt][2] += __low2float(b2); acc1[nt][3] += __high2float(b2);
        if (abase >= AG) {
            acc1[nt][0] = acc1[nt][1] = acc1[nt][2] = acc1[nt][3] = -INFINITY;
        } else if (abase + 1 >= AG) {
            acc1[nt][1] = acc1[nt][3] = -INFINITY;
        }
    }
    float m1 = -1e30f, m2 = -1e30f;
#pragma unroll
    for (int nt = 0; nt < 8; nt++) {
        m1 = fmaxf(m1, fmaxf(acc1[nt][0], acc1[nt][1]));
        m2 = fmaxf(m2, fmaxf(acc1[nt][2], acc1[nt][3]));
    }
    m1 = fmaxf(m1, __shfl_xor_sync(~0u, m1, 1)); m1 = fmaxf(m1, __shfl_xor_sync(~0u, m1, 2));
    m2 = fmaxf(m2, __shfl_xor_sync(~0u, m2, 1)); m2 = fmaxf(m2, __shfl_xor_sync(~0u, m2, 2));
    float s1 = 0.f, s2 = 0.f;
#pragma unroll
    for (int nt = 0; nt < 8; nt++) {
        acc1[nt][0] = __expf(acc1[nt][0] - m1); s1 += acc1[nt][0];
        acc1[nt][1] = __expf(acc1[nt][1] - m1); s1 += acc1[nt][1];
        acc1[nt][2] = __expf(acc1[nt][2] - m2); s2 += acc1[nt][2];
        acc1[nt][3] = __expf(acc1[nt][3] - m2); s2 += acc1[nt][3];
    }
    s1 += __shfl_xor_sync(~0u, s1, 1); s1 += __shfl_xor_sync(~0u, s1, 2);
    s2 += __shfl_xor_sync(~0u, s2, 1); s2 += __shfl_xor_sync(~0u, s2, 2);
    float i1 = 1.0f / s1, i2 = 1.0f / s2;

#pragma unroll
    for (int nt = 0; nt < 8; nt++) {
        int colb = nt * 8 + ((lane & 3) << 1);
        uint32_t o1 = r1 * 128 + (SW8(r1, nt) << 4) + (colb & 7) * 2;
        uint32_t o2 = r2 * 128 + (SW8(r2, nt) << 4) + (colb & 7) * 2;
        __half2 p1 = __halves2half2(__float2half_rn(acc1[nt][0] * i1),
                                    __float2half_rn(acc1[nt][1] * i1));
        __half2 p2 = __halves2half2(__float2half_rn(acc1[nt][2] * i2),
                                    __float2half_rn(acc1[nt][3] * i2));
        asm volatile("st.shared.b32 [%0], %1;" :: "r"(sP + o1), "r"(*(uint32_t*)&p1));
        asm volatile("st.shared.b32 [%0], %1;" :: "r"(sP + o2), "r"(*(uint32_t*)&p2));
    }
    __syncwarp();

    float acc2[8][4] = {};
#pragma unroll
    for (int ks = 0; ks < 4; ks++) {
        uint32_t af[4], bf[8][2];
        {
            int row = wid * 16 + ((g & 1) << 3) + lr;
            int c = ks * 2 + (g >> 1);
            LDSM_X4(af[0], af[1], af[2], af[3], sP + row * 128 + (SW8(row, c) << 4));
        }
#pragma unroll
        for (int np = 0; np < 4; np++) {
            int row = np * 16 + ((g >> 1) << 3) + lr;
            int c = ks * 2 + (g & 1);
            uint32_t r0, r1x, r2x, r3;
            LDSM_X4(r0, r1x, r2x, r3, sAVT + row * 128 + (SW8(row, c) << 4));
            bf[np * 2][0] = r0; bf[np * 2][1] = r1x;
            bf[np * 2 + 1][0] = r2x; bf[np * 2 + 1][1] = r3;
        }
#pragma unroll
        for (int nt = 0; nt < 8; nt++)
            MMA16816(acc2[nt], af, bf[nt]);
    }

#pragma unroll
    for (int nt = 0; nt < 8; nt++) {
        int d = nt * 8 + ((lane & 3) << 1);
        size_t o1 = (size_t)(b * NTOK + t1) * CCH + h * 64 + d;
        size_t o2 = (size_t)(b * NTOK + t2) * CCH + h * 64 + d;
        __half2 c1 = *(const __half2*)(g_cv16 + o1);
        __half2 c2 = *(const __half2*)(g_cv16 + o2);
        *(__half2*)(g_ahi + o1) =
            __halves2half2(__float2half_rn(acc2[nt][0] + __low2float(c1)),
                           __float2half_rn(acc2[nt][1] + __high2float(c1)));
        *(__half2*)(g_ahi + o2) =
            __halves2half2(__float2half_rn(acc2[nt][2] + __low2float(c2)),
                           __float2half_rn(acc2[nt][3] + __high2float(c2)));
    }
}

// ---------------- 3x3 depthwise conv (pure) -> g_cv16 ----------------------------
__global__ __launch_bounds__(256) void dwc_conv(
    const float* __restrict__ dwc_w, const float* __restrict__ dwc_b)
{
    int oh = blockIdx.x, b = blockIdx.y;
    __shared__ float w_s[CCH * 9];
    __shared__ float b_s[CCH];
    int tid = threadIdx.x;
    for (int t = tid; t < CCH * 9; t += 256) w_s[t] = dwc_w[t];
    for (int t = tid; t < CCH; t += 256) b_s[t] = dwc_b[t];
    __syncthreads();
    for (int idx = tid; idx < HW * CCH; idx += 256) {
        int ow = idx >> 9, c = idx & 511;
        float acc = b_s[c];
#pragma unroll
        for (int ky = 0; ky < 3; ky++) {
            int h2 = oh + ky - 1;
            if (h2 < 0 || h2 >= HW) continue;
#pragma unroll
            for (int kx = 0; kx < 3; kx++) {
                int w2 = ow + kx - 1;
                if (w2 < 0 || w2 >= HW) continue;
                acc += __half2float(g_qkv16[((size_t)(b * NTOK + h2 * HW + w2)) * QKVW + 1024 + c])
                     * w_s[c * 9 + ky * 3 + kx];
            }
        }
        g_cv16[((size_t)(b * NTOK + oh * HW + ow)) * CCH + c] = __float2half_rn(acc);
    }
}

// ---------------- launch ---------------------------------------------------------
extern "C" void kernel_launch(void* const* d_in, const int* in_sizes, int n_in,
                              void* d_out, int out_size)
{
    const float* x = (const float*)d_in[0];
    int off = 1;
    if (n_in >= 15 && in_sizes[1] == 1) off = 3;
    const float* q_w    = (const float*)d_in[off + 0];
    const float* kv_w   = (const float*)d_in[off + 1];
    const float* proj_w = (const float*)d_in[off + 2];
    const float* proj_b = (const float*)d_in[off + 3];
    const float* dwc_w  = (const float*)d_in[off + 4];
    const float* dwc_b  = (const float*)d_in[off + 5];
    const float* an_b   = (const float*)d_in[off + 6];
    const float* na_b   = (const float*)d_in[off + 7];
    const float* ah_b   = (const float*)d_in[off + 8];
    const float* aw_b   = (const float*)d_in[off + 9];
    const float* ha_b   = (const float*)d_in[off + 10];
    const float* wa_b   = (const float*)d_in[off + 11];
    float* out = (float*)d_out;

    __half *x16, *qkv16, *ahi, *wqkv16, *wp16;
    cudaGetSymbolAddress((void**)&x16, g_x16);
    cudaGetSymbolAddress((void**)&qkv16, g_qkv16);
    cudaGetSymbolAddress((void**)&ahi, g_ahi);
    cudaGetSymbolAddress((void**)&wqkv16, g_wqkv16);
    cudaGetSymbolAddress((void**)&wp16, g_wp16);

    static int init_done = 0;
    static cudaStream_t s2;
    static cudaEvent_t evFork, evJoin;
    if (!init_done) {
        cudaFuncSetAttribute(gemm_tc<0>, cudaFuncAttributeMaxDynamicSharedMemorySize, NST * STG2);
        cudaFuncSetAttribute(gemm_tc<1>, cudaFuncAttributeMaxDynamicSharedMemorySize, NST * STG2);
        cudaStreamCreateWithFlags(&s2, cudaStreamNonBlocking);
        cudaEventCreateWithFlags(&evFork, cudaEventDisableTiming);
        cudaEventCreateWithFlags(&evJoin, cudaEventDisableTiming);
        init_done = 1;
    }

    cvt_w16<<<2048, 256>>>(x, x16, MROWS * CCH / 4);
    cvt_weights<<<1024, 256>>>(q_w, kv_w, proj_w);
    bias_resize_kernel<<<dim3(AG, HEADS, 2), 256>>>(an_b, na_b, ah_b, aw_b, ha_b, wa_b);

    gemm_tc<1><<<dim3(QKVW / 128, MROWS / 128), 256, NST * STG2>>>(
        x16, wqkv16, nullptr, nullptr, qkv16, QKVW);

    // fork: depthwise conv on V runs concurrently with the attention chain
    cudaEventRecord(evFork, 0);
    cudaStreamWaitEvent(s2, evFork, 0);
    dwc_conv<<<dim3(HW, NB), 256, 0, s2>>>(dwc_w, dwc_b);
    cudaEventRecord(evJoin, s2);

    pool_kernel<<<dim3(NB, 64), 256>>>();
    agent_logits_mma<<<dim3(NTILE, NB * HEADS), 128>>>();
    softmax_stats<<<NB * HEADS, 64>>>();
    agent_v_mma<<<dim3(NB * HEADS, 7), 128>>>();
    avp_reduce_kernel<<<(128 * 64 * 64 + 255) / 256, 256>>>();

    // join: qside consumes the conv output
    cudaStreamWaitEvent(0, evJoin, 0);
    qside_mma<<<dim3(NTOK / 64, NB * HEADS), 128>>>();

    gemm_tc<0><<<dim3(512 / 128, MROWS / 128), 256, NST * STG2>>>(
        ahi, wp16, out, proj_b, nullptr, 512);
}